// round 1
// baseline (speedup 1.0000x reference)
#include <cuda_runtime.h>
#include <math.h>
#include <stdint.h>

// ---------------------------------------------------------------------------
// Problem constants
//   x: (64,256,1024)  h/x_emb: (64,256,512)  qkv: (64,256,1536)
//   heads=4, dim_head=128, depth=2, mem rows=60, topk(t)=17, top4 of 60
// ---------------------------------------------------------------------------

// ------------------------- scratch (single device array) -------------------
constexpr size_t SZ_ROWS   = 16384ull;           // b*t
constexpr size_t SZ_H      = SZ_ROWS * 512;      // 8388608
constexpr size_t OFF_H     = 0;
constexpr size_t OFF_LN    = OFF_H    + SZ_H;
constexpr size_t OFF_QKV   = OFF_LN   + SZ_H;                 // 16384*1536
constexpr size_t OFF_SC    = OFF_QKV  + SZ_ROWS * 1536;       // 256*256*256
constexpr size_t OFF_AO    = OFF_SC   + 256ull * 256 * 256;
constexpr size_t OFF_FF    = OFF_AO   + SZ_H;
constexpr size_t OFF_WC    = OFF_FF   + SZ_H;                 // 3072*512
constexpr size_t OFF_AUGA  = OFF_WC   + 3072ull * 512;
constexpr size_t OFF_AUGNA = OFF_AUGA + 8192ull * 512;
constexpr size_t OFF_AUGAN = OFF_AUGNA + 8192ull * 512;
constexpr size_t OFF_AUGN  = OFF_AUGAN + 8192ull * 512;
constexpr size_t OFF_MU    = OFF_AUGN + 8192ull * 512;
constexpr size_t OFF_VAR   = OFF_MU   + 8192ull * 512;
constexpr size_t OFF_NEW   = OFF_VAR  + 8192ull * 512;
constexpr size_t OFF_ANEW  = OFF_NEW  + 8192ull * 512;
constexpr size_t OFF_ANM   = OFF_ANEW + 8192ull * 512;
constexpr size_t OFF_NAM   = OFF_ANM  + 8192ull * 512;
constexpr size_t OFF_ANCH  = OFF_NAM  + 8192ull * 512;
constexpr size_t OFF_NEG   = OFF_ANCH + 32ull * 512;
constexpr size_t OFF_POS   = OFF_NEG  + 32ull * 512;
constexpr size_t OFF_ANCHN = OFF_POS  + 32ull * 512;
constexpr size_t OFF_NEGN  = OFF_ANCHN + 32ull * 512;
constexpr size_t OFF_IDXA  = OFF_NEGN + 32ull * 512;
constexpr size_t OFF_IDXN  = OFF_IDXA + 1024;
constexpr size_t OFF_KLP   = OFF_IDXN + 1024;
constexpr size_t SCRATCH_TOTAL = OFF_KLP + 1024;

__device__ float g_scratch[SCRATCH_TOTAL];

// ------------------------- output offsets ----------------------------------
// order: triplet, kl, distance, A_att, N_att, A_Natt, N_Aatt, cos, x_out, v_feat
constexpr size_t O_TRIP  = 0;
constexpr size_t O_KL    = 1;
constexpr size_t O_DIST  = 2;
constexpr size_t O_AATT  = 3;
constexpr size_t O_NATT  = 3 + 8192;
constexpr size_t O_ANATT = 3 + 16384;
constexpr size_t O_NAATT = 3 + 24576;
constexpr size_t O_COS   = 3 + 32768;
constexpr size_t O_XOUT  = 4 + 32768;
constexpr size_t O_VFEAT = O_XOUT + 64ull * 256 * 1024;

// ---------------------------------------------------------------------------
// Generic 128x128x8 SGEMM, 256 threads, 8x8 per thread.
// EPI: 0=none, 1=+bias, 2=+bias+residual(C itself), 3=+bias+gelu, 4=+bias+relu
// CONV=true: A is gathered from x (64,256,1024) via im2col over 3 taps.
// M,N multiples of 128; K multiple of 8.
// ---------------------------------------------------------------------------
template<int EPI, bool CONV>
__global__ void __launch_bounds__(256) sgemm_k(
    const float* __restrict__ A, const float* __restrict__ Bm,
    float* __restrict__ C, const float* __restrict__ bias,
    int M, int N, int K)
{
    __shared__ float As[8][128];
    __shared__ float Bs[8][128];
    const int tid  = threadIdx.x;
    const int row0 = blockIdx.y * 128;
    const int col0 = blockIdx.x * 128;
    const int tx = tid & 15, ty = tid >> 4;
    const int arow = tid >> 1, acol = (tid & 1) * 4;
    const int brow = tid >> 5, bcol = (tid & 31) * 4;

    float acc[8][8];
#pragma unroll
    for (int i = 0; i < 8; i++)
#pragma unroll
        for (int j = 0; j < 8; j++) acc[i][j] = 0.f;

    for (int kk = 0; kk < K; kk += 8) {
        float4 av;
        if (CONV) {
            int gk = kk + acol;
            int kt = gk >> 10, ci = gk & 1023;   // tap, input-channel
            int m  = row0 + arow;
            int t2 = (m & 255) + kt - 1;
            if (t2 >= 0 && t2 < 256)
                av = *reinterpret_cast<const float4*>(
                        A + ((size_t)((m >> 8) * 256 + t2)) * 1024 + ci);
            else
                av = make_float4(0.f, 0.f, 0.f, 0.f);
        } else {
            av = *reinterpret_cast<const float4*>(A + (size_t)(row0 + arow) * K + kk + acol);
        }
        As[acol + 0][arow] = av.x; As[acol + 1][arow] = av.y;
        As[acol + 2][arow] = av.z; As[acol + 3][arow] = av.w;
        *reinterpret_cast<float4*>(&Bs[brow][bcol]) =
            *reinterpret_cast<const float4*>(Bm + (size_t)(kk + brow) * N + col0 + bcol);
        __syncthreads();
#pragma unroll
        for (int k = 0; k < 8; k++) {
            float a[8], b[8];
            *reinterpret_cast<float4*>(a)     = *reinterpret_cast<const float4*>(&As[k][ty * 8]);
            *reinterpret_cast<float4*>(a + 4) = *reinterpret_cast<const float4*>(&As[k][ty * 8 + 4]);
            *reinterpret_cast<float4*>(b)     = *reinterpret_cast<const float4*>(&Bs[k][tx * 8]);
            *reinterpret_cast<float4*>(b + 4) = *reinterpret_cast<const float4*>(&Bs[k][tx * 8 + 4]);
#pragma unroll
            for (int i = 0; i < 8; i++)
#pragma unroll
                for (int j = 0; j < 8; j++) acc[i][j] = fmaf(a[i], b[j], acc[i][j]);
        }
        __syncthreads();
    }

#pragma unroll
    for (int i = 0; i < 8; i++) {
        int r = row0 + ty * 8 + i;
#pragma unroll
        for (int j = 0; j < 8; j++) {
            int c = col0 + tx * 8 + j;
            float v = acc[i][j];
            if (EPI != 0) v += bias[c];
            if (EPI == 2) v += C[(size_t)r * N + c];
            if (EPI == 3) v = 0.5f * v * (1.f + erff(v * 0.70710678118654752f));
            if (EPI == 4) v = fmaxf(v, 0.f);
            C[(size_t)r * N + c] = v;
        }
    }
}

// ---------------------------------------------------------------------------
// Attention: S = scale * Q K^T  (per (b,h): 256x256x128)
// ---------------------------------------------------------------------------
__global__ void __launch_bounds__(256) qk_kernel(const float* __restrict__ qkv,
                                                 float* __restrict__ S)
{
    __shared__ float Qs[16][64], Ks[16][64];
    const int bh = blockIdx.x, b = bh >> 2, h = bh & 3;
    const int i0 = blockIdx.y * 64, j0 = blockIdx.z * 64;
    const int tid = threadIdx.x;
    const int tx = tid & 15, ty = tid >> 4;
    const int lr = tid >> 2, lc = (tid & 3) * 4;
    const float* qbase = qkv + (size_t)b * 256 * 1536 + h * 128;
    float acc[4][4] = {};
    for (int kk = 0; kk < 128; kk += 16) {
        float4 qv = *reinterpret_cast<const float4*>(qbase + (size_t)(i0 + lr) * 1536 + kk + lc);
        float4 kv = *reinterpret_cast<const float4*>(qbase + 512 + (size_t)(j0 + lr) * 1536 + kk + lc);
        Qs[lc + 0][lr] = qv.x; Qs[lc + 1][lr] = qv.y; Qs[lc + 2][lr] = qv.z; Qs[lc + 3][lr] = qv.w;
        Ks[lc + 0][lr] = kv.x; Ks[lc + 1][lr] = kv.y; Ks[lc + 2][lr] = kv.z; Ks[lc + 3][lr] = kv.w;
        __syncthreads();
#pragma unroll
        for (int k = 0; k < 16; k++) {
            float a[4], bb[4];
#pragma unroll
            for (int i = 0; i < 4; i++) a[i]  = Qs[k][ty * 4 + i];
#pragma unroll
            for (int j = 0; j < 4; j++) bb[j] = Ks[k][tx * 4 + j];
#pragma unroll
            for (int i = 0; i < 4; i++)
#pragma unroll
                for (int j = 0; j < 4; j++) acc[i][j] = fmaf(a[i], bb[j], acc[i][j]);
        }
        __syncthreads();
    }
    float* so = S + (size_t)bh * 65536;
    const float scale = 0.08838834764831845f; // 128^-0.5
#pragma unroll
    for (int i = 0; i < 4; i++)
#pragma unroll
        for (int j = 0; j < 4; j++)
            so[(size_t)(i0 + ty * 4 + i) * 256 + j0 + tx * 4 + j] = acc[i][j] * scale;
}

// Row softmax over 256 columns, one warp per row.
__global__ void __launch_bounds__(256) softmax_kernel(float* __restrict__ S)
{
    const int row  = blockIdx.x * 8 + (threadIdx.x >> 5);
    const int lane = threadIdx.x & 31;
    float* p = S + (size_t)row * 256;
    float v[8]; float mx = -1e30f;
#pragma unroll
    for (int j = 0; j < 8; j++) { v[j] = p[lane + 32 * j]; mx = fmaxf(mx, v[j]); }
#pragma unroll
    for (int o = 16; o; o >>= 1) mx = fmaxf(mx, __shfl_xor_sync(0xffffffffu, mx, o));
    float s = 0.f;
#pragma unroll
    for (int j = 0; j < 8; j++) { v[j] = expf(v[j] - mx); s += v[j]; }
#pragma unroll
    for (int o = 16; o; o >>= 1) s += __shfl_xor_sync(0xffffffffu, s, o);
    const float inv = 1.f / s;
#pragma unroll
    for (int j = 0; j < 8; j++) p[lane + 32 * j] = v[j] * inv;
}

// O = P V  (per (b,h): 256x128x256), written merged-head (b,t,512)
__global__ void __launch_bounds__(256) pv_kernel(const float* __restrict__ S,
                                                 const float* __restrict__ qkv,
                                                 float* __restrict__ O)
{
    __shared__ float Ps[16][64], Vs[16][64];
    const int bh = blockIdx.x, b = bh >> 2, h = bh & 3;
    const int i0 = blockIdx.y * 64, d0 = blockIdx.z * 64;
    const int tid = threadIdx.x;
    const int tx = tid & 15, ty = tid >> 4;
    const int lr = tid >> 2, lc = (tid & 3) * 4;
    const int vr = tid >> 4, vc = (tid & 15) * 4;
    const float* sb = S + (size_t)bh * 65536;
    const float* vbase = qkv + (size_t)b * 256 * 1536 + 1024 + h * 128;
    float acc[4][4] = {};
    for (int kk = 0; kk < 256; kk += 16) {
        float4 pv4 = *reinterpret_cast<const float4*>(sb + (size_t)(i0 + lr) * 256 + kk + lc);
        Ps[lc + 0][lr] = pv4.x; Ps[lc + 1][lr] = pv4.y; Ps[lc + 2][lr] = pv4.z; Ps[lc + 3][lr] = pv4.w;
        *reinterpret_cast<float4*>(&Vs[vr][vc]) =
            *reinterpret_cast<const float4*>(vbase + (size_t)(kk + vr) * 1536 + d0 + vc);
        __syncthreads();
#pragma unroll
        for (int k = 0; k < 16; k++) {
            float a[4], bb[4];
#pragma unroll
            for (int i = 0; i < 4; i++) a[i]  = Ps[k][ty * 4 + i];
#pragma unroll
            for (int j = 0; j < 4; j++) bb[j] = Vs[k][tx * 4 + j];
#pragma unroll
            for (int i = 0; i < 4; i++)
#pragma unroll
                for (int j = 0; j < 4; j++) acc[i][j] = fmaf(a[i], bb[j], acc[i][j]);
        }
        __syncthreads();
    }
#pragma unroll
    for (int i = 0; i < 4; i++)
#pragma unroll
        for (int j = 0; j < 4; j++)
            O[(size_t)(b * 256 + i0 + ty * 4 + i) * 512 + h * 128 + d0 + tx * 4 + j] = acc[i][j];
}

// ---------------------------------------------------------------------------
// LayerNorm over last dim (512), one block per row.
// ---------------------------------------------------------------------------
__global__ void __launch_bounds__(256) ln_kernel(const float* __restrict__ x,
                                                 const float* __restrict__ g,
                                                 const float* __restrict__ bb,
                                                 float* __restrict__ y)
{
    __shared__ float red[256];
    const int row = blockIdx.x, tid = threadIdx.x;
    const float* xr = x + (size_t)row * 512;
    float x0 = xr[tid], x1 = xr[tid + 256];
    red[tid] = x0 + x1; __syncthreads();
    for (int s = 128; s; s >>= 1) { if (tid < s) red[tid] += red[tid + s]; __syncthreads(); }
    float mean = red[0] * (1.f / 512.f);
    __syncthreads();
    red[tid] = x0 * x0 + x1 * x1; __syncthreads();
    for (int s = 128; s; s >>= 1) { if (tid < s) red[tid] += red[tid + s]; __syncthreads(); }
    float var = red[0] * (1.f / 512.f) - mean * mean;
    float inv = rsqrtf(var + 1e-5f);
    float* yr = y + (size_t)row * 512;
    yr[tid]       = (x0 - mean) * inv * g[tid]       + bb[tid];
    yr[tid + 256] = (x1 - mean) * inv * g[tid + 256] + bb[tid + 256];
}

// ---------------------------------------------------------------------------
// Memory attention fused: att=sigmoid(x.mem^T/sqrt512); top4-mean; aug=att@mem
// grid 8192 (rows), 512 threads.
// ---------------------------------------------------------------------------
__global__ void __launch_bounds__(512) memory_kernel(const float* __restrict__ x,
                                                     const float* __restrict__ mem,
                                                     float* __restrict__ att_out,
                                                     float* __restrict__ aug)
{
    __shared__ float xs[512];
    __shared__ float att[60];
    const int row = blockIdx.x, tid = threadIdx.x;
    xs[tid] = x[(size_t)row * 512 + tid];
    __syncthreads();
    if (tid < 60) {
        float s = 0.f;
        const float* mr = mem + tid * 512;
        for (int d = 0; d < 512; d++) s = fmaf(xs[d], mr[d], s);
        att[tid] = 1.f / (1.f + expf(-s * 0.044194173824159216f)); // 1/sqrt(512)
    }
    __syncthreads();
    if (tid == 0) {
        float t0 = -1e30f, t1 = -1e30f, t2 = -1e30f, t3 = -1e30f;
        for (int n = 0; n < 60; n++) {
            float v = att[n];
            if (v > t0)      { t3 = t2; t2 = t1; t1 = t0; t0 = v; }
            else if (v > t1) { t3 = t2; t2 = t1; t1 = v; }
            else if (v > t2) { t3 = t2; t2 = v; }
            else if (v > t3) { t3 = v; }
        }
        att_out[row] = (t0 + t1 + t2 + t3) * 0.25f;
    }
    float s = 0.f;
    for (int n = 0; n < 60; n++) s = fmaf(att[n], mem[n * 512 + tid], s);
    aug[(size_t)row * 512 + tid] = s;
}

// ---------------------------------------------------------------------------
// top-17 over 256, gather rows of feats, mean. One block per batch row.
// ---------------------------------------------------------------------------
__global__ void __launch_bounds__(256) topk_gather(const float* __restrict__ att,
                                                   const float* __restrict__ feats,
                                                   float* __restrict__ meanv,
                                                   int* __restrict__ idx_out)
{
    __shared__ float vals[256], rv[256];
    __shared__ int ri[256], ids[17];
    const int b = blockIdx.x, tid = threadIdx.x;
    vals[tid] = att[b * 256 + tid];
    __syncthreads();
    for (int it = 0; it < 17; it++) {
        rv[tid] = vals[tid]; ri[tid] = tid;
        __syncthreads();
        for (int s = 128; s; s >>= 1) {
            if (tid < s) {
                float ov = rv[tid + s]; int oi = ri[tid + s];
                if (ov > rv[tid] || (ov == rv[tid] && oi < ri[tid])) { rv[tid] = ov; ri[tid] = oi; }
            }
            __syncthreads();
        }
        if (tid == 0) {
            ids[it] = ri[0];
            vals[ri[0]] = -1e30f;
            if (idx_out) idx_out[b * 17 + it] = ri[0];
        }
        __syncthreads();
    }
    for (int d = tid; d < 512; d += 256) {
        float s = 0.f;
        for (int j = 0; j < 17; j++) s += feats[((size_t)b * 256 + ids[j]) * 512 + d];
        meanv[b * 512 + d] = s * (1.f / 17.f);
    }
}

__device__ __forceinline__ float wsum(float v)
{
#pragma unroll
    for (int o = 16; o; o >>= 1) v += __shfl_xor_sync(0xffffffffu, v, o);
    return v;
}

// triplet + cosine loss, 1 block x 1024 threads, warp w <-> row w
__global__ void __launch_bounds__(1024) triplet_cos_kernel(const float* __restrict__ anchor,
                                                           const float* __restrict__ pos,
                                                           const float* __restrict__ neg,
                                                           float* __restrict__ trip_out,
                                                           float* __restrict__ cos_out)
{
    __shared__ float st[32], sc[32];
    const int w = threadIdx.x >> 5, lane = threadIdx.x & 31;
    float sa = 0, sp = 0, sn = 0, dan = 0;
    for (int d = lane; d < 512; d += 32) {
        float a = anchor[w * 512 + d], p = pos[w * 512 + d], n = neg[w * 512 + d];
        sa += a * a; sp += p * p; sn += n * n; dan += a * n;
    }
    sa = wsum(sa); sp = wsum(sp); sn = wsum(sn); dan = wsum(dan);
    float na = sqrtf(sa), npp = sqrtf(sp), ng = sqrtf(sn);
    float ina = 1.f / na, inp = 1.f / npp, ing = 1.f / ng;
    float dp2 = 0, dn2 = 0;
    for (int d = lane; d < 512; d += 32) {
        float a  = anchor[w * 512 + d] * ina;
        float dpv = a - pos[w * 512 + d] * inp + 1e-6f;
        float dnv = a - neg[w * 512 + d] * ing + 1e-6f;
        dp2 += dpv * dpv; dn2 += dnv * dnv;
    }
    dp2 = wsum(dp2); dn2 = wsum(dn2);
    if (lane == 0) {
        st[w] = fmaxf(sqrtf(dp2) - sqrtf(dn2) + 1.f, 0.f);
        sc[w] = 1.f - dan / (fmaxf(na, 1e-6f) * fmaxf(ng, 1e-6f));
    }
    __syncthreads();
    if (threadIdx.x == 0) {
        float a = 0, c = 0;
        for (int i = 0; i < 32; i++) { a += st[i]; c += sc[i]; }
        trip_out[0] = a * (1.f / 32.f);
        cos_out[0]  = c * (1.f / 32.f);
    }
}

__global__ void __launch_bounds__(1024) distance_kernel(const float* __restrict__ anew,
                                                        const float* __restrict__ nnew,
                                                        float* __restrict__ out)
{
    __shared__ float sd[32];
    const int w = threadIdx.x >> 5, lane = threadIdx.x & 31;
    float sa = 0, sn = 0;
    for (int d = lane; d < 512; d += 32) {
        float a = anew[w * 512 + d], n = nnew[w * 512 + d];
        sa += a * a; sn += n * n;
    }
    sa = wsum(sa); sn = wsum(sn);
    if (lane == 0) sd[w] = fmaxf(100.f - sqrtf(sn) + sqrtf(sa), 0.f);
    __syncthreads();
    if (threadIdx.x == 0) {
        float s = 0;
        for (int i = 0; i < 32; i++) s += sd[i];
        out[0] = s * (1.f / 32.f);
    }
}

__global__ void vae_kernel(const float* __restrict__ mu, const float* __restrict__ var,
                           const float* __restrict__ eps, float* __restrict__ o, int n)
{
    for (int i = blockIdx.x * blockDim.x + threadIdx.x; i < n; i += gridDim.x * blockDim.x)
        o[i] = mu[i] + eps[i] * sqrtf(expf(var[i]));
}

__global__ void __launch_bounds__(256) kl_part_kernel(const float* __restrict__ mu,
                                                      const float* __restrict__ var,
                                                      float* __restrict__ part, int n)
{
    __shared__ float red[256];
    float s = 0.f;
    for (int i = blockIdx.x * 256 + threadIdx.x; i < n; i += gridDim.x * 256) {
        float m = mu[i], v = var[i];
        s += 1.f + v - m * m - expf(v);
    }
    red[threadIdx.x] = s; __syncthreads();
    for (int t = 128; t; t >>= 1) { if (threadIdx.x < t) red[threadIdx.x] += red[threadIdx.x + t]; __syncthreads(); }
    if (threadIdx.x == 0) part[blockIdx.x] = red[0];
}

__global__ void __launch_bounds__(1024) kl_final_kernel(const float* __restrict__ part,
                                                        float* __restrict__ out)
{
    __shared__ float red[1024];
    red[threadIdx.x] = part[threadIdx.x]; __syncthreads();
    for (int t = 512; t; t >>= 1) { if (threadIdx.x < t) red[threadIdx.x] += red[threadIdx.x + t]; __syncthreads(); }
    if (threadIdx.x == 0) out[0] = -0.5f * red[0] * (1.f / 16384.f); // mean over (32,512)
}

__global__ void __launch_bounds__(512) gather_mean_kernel(const float* __restrict__ src,
                                                          const int* __restrict__ idx,
                                                          float* __restrict__ out)
{
    __shared__ int ids[17];
    const int b = blockIdx.x, tid = threadIdx.x;
    if (tid < 17) ids[tid] = idx[b * 17 + tid];
    __syncthreads();
    float s = 0.f;
    for (int j = 0; j < 17; j++) s += src[((size_t)b * 256 + ids[j]) * 512 + tid];
    out[b * 512 + tid] = s * (1.f / 17.f);
}

__global__ void xout_kernel(const float* __restrict__ h, const float* __restrict__ nnew,
                            const float* __restrict__ anm, const float* __restrict__ anew,
                            const float* __restrict__ nam, float* __restrict__ xout)
{
    const int n = 64 * 256 * 1024;
    for (int i = blockIdx.x * blockDim.x + threadIdx.x; i < n; i += gridDim.x * blockDim.x) {
        int c  = i & 1023;
        int rt = i >> 10;       // 0..16383  (b*256 + t)
        float v;
        if (c < 512) v = h[(size_t)rt * 512 + c];
        else {
            int cc = c - 512;
            if (rt < 8192) v = nnew[(size_t)rt * 512 + cc] + anm[(size_t)rt * 512 + cc];
            else {
                size_t o = (size_t)(rt - 8192) * 512 + cc;
                v = anew[o] + nam[o];
            }
        }
        xout[i] = v;
    }
}

__global__ void vfeat_kernel(const float* __restrict__ h, float* __restrict__ v)
{
    __shared__ float tile[32][33];
    const int b = blockIdx.x, d0 = blockIdx.y * 32, t0 = blockIdx.z * 32;
    for (int r = threadIdx.y; r < 32; r += 8)
        tile[r][threadIdx.x] = h[((size_t)b * 256 + t0 + r) * 512 + d0 + threadIdx.x];
    __syncthreads();
    for (int r = threadIdx.y; r < 32; r += 8)
        v[((size_t)b * 512 + d0 + r) * 256 + t0 + threadIdx.x] = tile[threadIdx.x][r];
}

__global__ void convw_t_kernel(const float* __restrict__ w, float* __restrict__ wc)
{
    const int n = 512 * 1024 * 3;
    for (int o = blockIdx.x * blockDim.x + threadIdx.x; o < n; o += gridDim.x * blockDim.x) {
        int d  = o & 511;
        int kk = o >> 9;
        int kt = kk >> 10;
        int ci = kk & 1023;
        wc[o] = w[(size_t)d * 3072 + ci * 3 + kt];
    }
}

// ---------------------------------------------------------------------------
extern "C" void kernel_launch(void* const* d_in, const int* in_sizes, int n_in,
                              void* d_out, int out_size)
{
    const float* x      = (const float*)d_in[0];
    const float* eps_in = (const float*)d_in[1];
    const float* conv_w = (const float*)d_in[2];
    const float* conv_b = (const float*)d_in[3];
    const float* ln1_g  = (const float*)d_in[4];
    const float* ln1_b  = (const float*)d_in[5];
    const float* qkv_w  = (const float*)d_in[6];
    const float* out_w  = (const float*)d_in[7];
    const float* out_b  = (const float*)d_in[8];
    const float* ln2_g  = (const float*)d_in[9];
    const float* ln2_b  = (const float*)d_in[10];
    const float* ff1_w  = (const float*)d_in[11];
    const float* ff1_b  = (const float*)d_in[12];
    const float* ff2_w  = (const float*)d_in[13];
    const float* ff2_b  = (const float*)d_in[14];
    const float* a_mem  = (const float*)d_in[15];
    const float* n_mem  = (const float*)d_in[16];
    const float* mu_w   = (const float*)d_in[17];
    const float* mu_b   = (const float*)d_in[18];
    const float* var_w  = (const float*)d_in[19];
    const float* var_b  = (const float*)d_in[20];
    float* out = (float*)d_out;

    float* S = nullptr;
    cudaGetSymbolAddress((void**)&S, g_scratch);
    float* h    = S + OFF_H;
    float* ln   = S + OFF_LN;
    float* qkvp = S + OFF_QKV;
    float* sc   = S + OFF_SC;
    float* ao   = S + OFF_AO;
    float* ff   = S + OFF_FF;
    float* wc   = S + OFF_WC;
    float* augA  = S + OFF_AUGA;
    float* augNA = S + OFF_AUGNA;
    float* augAN = S + OFF_AUGAN;
    float* augN  = S + OFF_AUGN;
    float* muB   = S + OFF_MU;
    float* varB  = S + OFF_VAR;
    float* newN  = S + OFF_NEW;
    float* Anew  = S + OFF_ANEW;
    float* ANm   = S + OFF_ANM;
    float* NAm   = S + OFF_NAM;
    float* anch  = S + OFF_ANCH;
    float* negv  = S + OFF_NEG;
    float* posv  = S + OFF_POS;
    float* anchN = S + OFF_ANCHN;
    float* negN  = S + OFF_NEGN;
    int*   idxA  = (int*)(S + OFF_IDXA);
    int*   idxN  = (int*)(S + OFF_IDXN);
    float* klp   = S + OFF_KLP;

    // conv1d (relu + bias) as implicit-im2col GEMM
    convw_t_kernel<<<256, 256>>>(conv_w, wc);
    sgemm_k<4, true><<<dim3(4, 128), 256>>>(x, wc, h, conv_b, 16384, 512, 3072);

    // transformer x2
    for (int i = 0; i < 2; i++) {
        ln_kernel<<<16384, 256>>>(h, ln1_g + i * 512, ln1_b + i * 512, ln);
        sgemm_k<0, false><<<dim3(12, 128), 256>>>(ln, qkv_w + (size_t)i * 512 * 1536, qkvp,
                                                  nullptr, 16384, 1536, 512);
        qk_kernel<<<dim3(256, 4, 4), 256>>>(qkvp, sc);
        softmax_kernel<<<8192, 256>>>(sc);
        pv_kernel<<<dim3(256, 4, 2), 256>>>(sc, qkvp, ao);
        sgemm_k<2, false><<<dim3(4, 128), 256>>>(ao, out_w + (size_t)i * 512 * 512, h,
                                                 out_b + i * 512, 16384, 512, 512);
        ln_kernel<<<16384, 256>>>(h, ln2_g + i * 512, ln2_b + i * 512, ln);
        sgemm_k<3, false><<<dim3(4, 128), 256>>>(ln, ff1_w + (size_t)i * 512 * 512, ff,
                                                 ff1_b + i * 512, 16384, 512, 512);
        sgemm_k<2, false><<<dim3(4, 128), 256>>>(ff, ff2_w + (size_t)i * 512 * 512, h,
                                                 ff2_b + i * 512, 16384, 512, 512);
    }

    const float* Nx = h;                         // x_emb[:32]
    const float* Ax = h + (size_t)8192 * 512;    // x_emb[32:]

    // memory attention (4 combos) — temporal atts go straight to d_out
    memory_kernel<<<8192, 512>>>(Ax, a_mem, out + O_AATT,  augA);   // A_att,  A_aug
    memory_kernel<<<8192, 512>>>(Ax, n_mem, out + O_NAATT, augNA);  // N_Aatt, N_Aaug
    memory_kernel<<<8192, 512>>>(Nx, a_mem, out + O_ANATT, augAN);  // A_Natt, A_Naug
    memory_kernel<<<8192, 512>>>(Nx, n_mem, out + O_NATT,  augN);   // N_att,  N_aug

    // top-17 gathers
    topk_gather<<<32, 256>>>(out + O_AATT,  Ax, negv, idxA);     // negative_ax, A_idx
    topk_gather<<<32, 256>>>(out + O_NATT,  Nx, anch, idxN);     // anchor_nx,  N_idx
    topk_gather<<<32, 256>>>(out + O_NAATT, Ax, posv, nullptr);  // positive_nx

    triplet_cos_kernel<<<1, 1024>>>(anch, posv, negv, out + O_TRIP, out + O_COS);

    // mu/var projections
    sgemm_k<1, false><<<dim3(4, 64), 256>>>(augN,  mu_w,  muB,  mu_b,  8192, 512, 512);
    sgemm_k<1, false><<<dim3(4, 64), 256>>>(augN,  var_w, varB, var_b, 8192, 512, 512);
    sgemm_k<1, false><<<dim3(4, 64), 256>>>(augA,  mu_w,  Anew, mu_b,  8192, 512, 512);
    sgemm_k<1, false><<<dim3(4, 64), 256>>>(augAN, mu_w,  ANm,  mu_b,  8192, 512, 512);
    sgemm_k<1, false><<<dim3(4, 64), 256>>>(augNA, mu_w,  NAm,  mu_b,  8192, 512, 512);

    vae_kernel<<<4096, 256>>>(muB, varB, eps_in, newN, 8192 * 512);
    kl_part_kernel<<<1024, 256>>>(muB, varB, klp, 8192 * 512);
    kl_final_kernel<<<1, 1024>>>(klp, out + O_KL);

    gather_mean_kernel<<<32, 512>>>(newN, idxN, anchN);  // anchor_nx_new
    gather_mean_kernel<<<32, 512>>>(Anew, idxA, negN);   // negative_ax_new
    distance_kernel<<<1, 1024>>>(anchN, negN, out + O_DIST);

    xout_kernel<<<8192, 256>>>(h, newN, ANm, Anew, NAm, out + O_XOUT);
    vfeat_kernel<<<dim3(64, 16, 8), dim3(32, 8)>>>(h, out + O_VFEAT);
}

// round 3
// speedup vs baseline: 2.4649x; 2.4649x over previous
#include <cuda_runtime.h>
#include <cuda_bf16.h>
#include <math.h>
#include <stdint.h>

// ===========================================================================
// Scratch
// ===========================================================================
constexpr size_t OFF_H     = 0;                    // 16384*512
constexpr size_t OFF_QKV   = 8388608;              // 16384*1536
constexpr size_t OFF_SC    = 33554432;             // 256*256*256
constexpr size_t OFF_MU    = 50331648;             // 8192*512 each below
constexpr size_t OFF_VAR   = 54525952;
constexpr size_t OFF_NEW   = 58720256;
constexpr size_t OFF_ANEW  = 62914560;
constexpr size_t OFF_ANM   = 67108864;
constexpr size_t OFF_NAM   = 71303168;
constexpr size_t OFF_ANCH  = 75497472;             // 32*512 each below
constexpr size_t OFF_NEG   = OFF_ANCH + 16384;
constexpr size_t OFF_POS   = OFF_NEG  + 16384;
constexpr size_t OFF_ANCHN = OFF_POS  + 16384;
constexpr size_t OFF_NEGN  = OFF_ANCHN + 16384;
constexpr size_t OFF_IDXA  = OFF_NEGN + 16384;
constexpr size_t OFF_IDXN  = OFF_IDXA + 1024;
constexpr size_t OFF_KLP   = OFF_IDXN + 1024;
constexpr size_t SCRATCH_TOTAL = OFF_KLP + 1024;
__device__ float g_scratch[SCRATCH_TOTAL];

// bf16 scratch (hi/lo operand buffers + weights)
constexpr size_t B_LNH  = 0;          // 16384*512 each
constexpr size_t B_LNL  = 8388608;
constexpr size_t B_AOH  = 16777216;
constexpr size_t B_AOL  = 25165824;
constexpr size_t B_FFH  = 33554432;
constexpr size_t B_FFL  = 41943040;
constexpr size_t B_AUG  = 50331648;   // 8 x 4194304: Ah,Al, NAh,NAl, ANh,ANl, Nh,Nl
constexpr size_t B_QKVWH = 83886080;  // 2*786432
constexpr size_t B_QKVWL = 85458944;
constexpr size_t B_OUTWH = 87031808;  // 2*262144
constexpr size_t B_OUTWL = 87556096;
constexpr size_t B_FF1WH = 88080384;
constexpr size_t B_FF1WL = 88604672;
constexpr size_t B_FF2WH = 89128960;
constexpr size_t B_FF2WL = 89653248;
constexpr size_t B_MUWH  = 90177536;  // 262144
constexpr size_t B_MUWL  = 90439680;
constexpr size_t B_VARWH = 90701824;
constexpr size_t B_VARWL = 90963968;
constexpr size_t B_CNVWH = 91226112;  // 1572864
constexpr size_t B_CNVWL = 92798976;
constexpr size_t BF_TOTAL = 94371840;
__device__ __nv_bfloat16 g_bf[BF_TOTAL];

// output offsets (triplet, kl, distance, A_att, N_att, A_Natt, N_Aatt, cos, x_out, v_feat)
constexpr size_t O_TRIP  = 0;
constexpr size_t O_KL    = 1;
constexpr size_t O_DIST  = 2;
constexpr size_t O_AATT  = 3;
constexpr size_t O_NATT  = 3 + 8192;
constexpr size_t O_ANATT = 3 + 16384;
constexpr size_t O_NAATT = 3 + 24576;
constexpr size_t O_COS   = 3 + 32768;
constexpr size_t O_XOUT  = 4 + 32768;
constexpr size_t O_VFEAT = O_XOUT + 64ull * 256 * 1024;

// ===========================================================================
// mma.sync helpers
// ===========================================================================
__device__ __forceinline__ void mma16816(float* c, const uint32_t* a, const uint32_t* b)
{
    asm volatile(
        "mma.sync.aligned.m16n8k16.row.col.f32.bf16.bf16.f32 "
        "{%0,%1,%2,%3}, {%4,%5,%6,%7}, {%8,%9}, {%0,%1,%2,%3};"
        : "+f"(c[0]), "+f"(c[1]), "+f"(c[2]), "+f"(c[3])
        : "r"(a[0]), "r"(a[1]), "r"(a[2]), "r"(a[3]), "r"(b[0]), "r"(b[1]));
}

__device__ __forceinline__ void split2(float v, __nv_bfloat16& h, __nv_bfloat16& l) {
    h = __float2bfloat16(v);
    l = __float2bfloat16(v - __bfloat162float(h));
}

// ===========================================================================
// HMMA GEMM: C[M,N] = A[M,K] * B[N,K]^T, bf16 split (hh+hl+lh), fp32 acc.
// CTA 128x128, warp 64x32, K chunk 32. 256 threads.
// EPI: 0=none,1=+bias,2=+bias+residual(C),3=+bias+gelu->bf16 pair,4=+bias+relu
// CONV: gather A from x (64,256,1024) im2col, split in-kernel.
// ===========================================================================
template<int EPI, bool CONV>
__global__ void __launch_bounds__(256, 2) mgemm(
    const __nv_bfloat16* __restrict__ Ah, const __nv_bfloat16* __restrict__ Al,
    const float* __restrict__ Xc,
    const __nv_bfloat16* __restrict__ Bh, const __nv_bfloat16* __restrict__ Bl,
    float* __restrict__ C,
    __nv_bfloat16* __restrict__ Chi, __nv_bfloat16* __restrict__ Clo,
    const float* __restrict__ bias,
    int M, int N, int K)
{
    __shared__ __nv_bfloat16 sA[2][128 * 40];   // [hi/lo][row*40 + k], pad 40
    __shared__ __nv_bfloat16 sB[2][128 * 40];

    const int tid  = threadIdx.x;
    const int wid  = tid >> 5;
    const int lane = tid & 31;
    const int g = lane >> 2, t = lane & 3;
    const int wm = wid >> 2;          // 0..1 : M half
    const int wn = wid & 3;           // 0..3 : N quarter
    const int row0 = blockIdx.y * 128;
    const int col0 = blockIdx.x * 128;

    float acc[4][4][4];
#pragma unroll
    for (int mi = 0; mi < 4; mi++)
#pragma unroll
        for (int ni = 0; ni < 4; ni++)
#pragma unroll
            for (int q = 0; q < 4; q++) acc[mi][ni][q] = 0.f;

    const int nchunks = K >> 5;
    for (int kc = 0; kc < nchunks; kc++) {
        // ---- stage: 128 rows x 32 bf16, hi+lo, A and B
#pragma unroll
        for (int i = 0; i < 2; i++) {
            int chunk = tid * 2 + i;            // 0..511
            int r = chunk >> 2, seg = chunk & 3;
            int so = r * 40 + seg * 8;
            if (CONV) {
                int gk = kc * 32 + seg * 8;
                int tap = gk >> 10, ci = gk & 1023;
                int m = row0 + r;
                int t2 = (m & 255) + tap - 1;
                uint4 hi4, lo4;
                if (t2 >= 0 && t2 < 256) {
                    const float* src = Xc + ((size_t)((m >> 8) * 256 + t2)) * 1024 + ci;
                    float4 f0 = *(const float4*)src;
                    float4 f1 = *(const float4*)(src + 4);
                    float f[8] = {f0.x, f0.y, f0.z, f0.w, f1.x, f1.y, f1.z, f1.w};
                    __nv_bfloat16 hb[8], lb[8];
#pragma unroll
                    for (int q = 0; q < 8; q++) split2(f[q], hb[q], lb[q]);
                    hi4 = *(uint4*)hb; lo4 = *(uint4*)lb;
                } else {
                    hi4 = make_uint4(0, 0, 0, 0); lo4 = hi4;
                }
                *(uint4*)&sA[0][so] = hi4;
                *(uint4*)&sA[1][so] = lo4;
            } else {
                size_t o = (size_t)(row0 + r) * K + kc * 32 + seg * 8;
                *(uint4*)&sA[0][so] = *(const uint4*)(Ah + o);
                *(uint4*)&sA[1][so] = *(const uint4*)(Al + o);
            }
            size_t ob = (size_t)(col0 + r) * K + kc * 32 + seg * 8;
            *(uint4*)&sB[0][so] = *(const uint4*)(Bh + ob);
            *(uint4*)&sB[1][so] = *(const uint4*)(Bl + ob);
        }
        __syncthreads();

#pragma unroll
        for (int ks = 0; ks < 32; ks += 16) {
            uint32_t fa[4][4], fbh[4][2], fbl[4][2];
            // A hi fragments
#pragma unroll
            for (int mi = 0; mi < 4; mi++) {
                int r = (wm * 64 + mi * 16 + g) * 40 + ks + t * 2;
                fa[mi][0] = *(const uint32_t*)&sA[0][r];
                fa[mi][1] = *(const uint32_t*)&sA[0][r + 8 * 40];
                fa[mi][2] = *(const uint32_t*)&sA[0][r + 8];
                fa[mi][3] = *(const uint32_t*)&sA[0][r + 8 * 40 + 8];
            }
#pragma unroll
            for (int ni = 0; ni < 4; ni++) {
                int n = (wn * 32 + ni * 8 + g) * 40 + ks + t * 2;
                fbh[ni][0] = *(const uint32_t*)&sB[0][n];
                fbh[ni][1] = *(const uint32_t*)&sB[0][n + 8];
                fbl[ni][0] = *(const uint32_t*)&sB[1][n];
                fbl[ni][1] = *(const uint32_t*)&sB[1][n + 8];
            }
            // hh + hl
#pragma unroll
            for (int mi = 0; mi < 4; mi++)
#pragma unroll
                for (int ni = 0; ni < 4; ni++) {
                    mma16816(acc[mi][ni], fa[mi], fbh[ni]);
                    mma16816(acc[mi][ni], fa[mi], fbl[ni]);
                }
            // A lo fragments, lh
#pragma unroll
            for (int mi = 0; mi < 4; mi++) {
                int r = (wm * 64 + mi * 16 + g) * 40 + ks + t * 2;
                fa[mi][0] = *(const uint32_t*)&sA[1][r];
                fa[mi][1] = *(const uint32_t*)&sA[1][r + 8 * 40];
                fa[mi][2] = *(const uint32_t*)&sA[1][r + 8];
                fa[mi][3] = *(const uint32_t*)&sA[1][r + 8 * 40 + 8];
            }
#pragma unroll
            for (int mi = 0; mi < 4; mi++)
#pragma unroll
                for (int ni = 0; ni < 4; ni++)
                    mma16816(acc[mi][ni], fa[mi], fbh[ni]);
        }
        __syncthreads();
    }

    // ---- epilogue (fragment-direct)
#pragma unroll
    for (int mi = 0; mi < 4; mi++) {
#pragma unroll
        for (int ni = 0; ni < 4; ni++) {
#pragma unroll
            for (int q = 0; q < 4; q++) {
                int r = row0 + wm * 64 + mi * 16 + g + (q >> 1) * 8;
                int c = col0 + wn * 32 + ni * 8 + t * 2 + (q & 1);
                float v = acc[mi][ni][q];
                size_t o = (size_t)r * N + c;
                if (EPI != 0) v += bias[c];
                if (EPI == 2) v += C[o];
                if (EPI == 3) {
                    v = 0.5f * v * (1.f + erff(v * 0.70710678118654752f));
                    __nv_bfloat16 hb, lb; split2(v, hb, lb);
                    Chi[o] = hb; Clo[o] = lb;
                } else {
                    if (EPI == 4) v = fmaxf(v, 0.f);
                    C[o] = v;
                }
            }
        }
    }
}

// ===========================================================================
// Weight prep: W[K][N] fp32 -> Wh/Wl [N][K] bf16 (tiled transpose + split)
// ===========================================================================
__global__ void wprep_t(const float* __restrict__ W, __nv_bfloat16* __restrict__ Wh,
                        __nv_bfloat16* __restrict__ Wl, int K, int N)
{
    __shared__ float tile[32][33];
    const int k0 = blockIdx.x * 32, n0 = blockIdx.y * 32;
    const int tx = threadIdx.x, ty = threadIdx.y;
    for (int r = ty; r < 32; r += 8)
        tile[r][tx] = W[(size_t)(k0 + r) * N + n0 + tx];
    __syncthreads();
    for (int r = ty; r < 32; r += 8) {
        float v = tile[tx][r];
        size_t o = (size_t)(n0 + r) * K + k0 + tx;
        __nv_bfloat16 hb, lb; split2(v, hb, lb);
        Wh[o] = hb; Wl[o] = lb;
    }
}

// conv_w (512,1024,3) -> B[n=d][k=tap*1024+ci]
__global__ void convprep(const float* __restrict__ w, __nv_bfloat16* __restrict__ Wh,
                         __nv_bfloat16* __restrict__ Wl)
{
    const int n = 512 * 3072;
    for (int idx = blockIdx.x * blockDim.x + threadIdx.x; idx < n; idx += gridDim.x * blockDim.x) {
        int d = idx / 3072, k = idx % 3072;
        int tap = k >> 10, ci = k & 1023;
        float v = w[(size_t)d * 3072 + ci * 3 + tap];
        __nv_bfloat16 hb, lb; split2(v, hb, lb);
        Wh[idx] = hb; Wl[idx] = lb;
    }
}

// ===========================================================================
// Attention (fp32)
// ===========================================================================
__global__ void __launch_bounds__(256) qk_kernel(const float* __restrict__ qkv,
                                                 float* __restrict__ S)
{
    __shared__ float Qs[16][64], Ks[16][64];
    const int bh = blockIdx.x, b = bh >> 2, h = bh & 3;
    const int i0 = blockIdx.y * 64, j0 = blockIdx.z * 64;
    const int tid = threadIdx.x;
    const int tx = tid & 15, ty = tid >> 4;
    const int lr = tid >> 2, lc = (tid & 3) * 4;
    const float* qbase = qkv + (size_t)b * 256 * 1536 + h * 128;
    float acc[4][4] = {};
    for (int kk = 0; kk < 128; kk += 16) {
        float4 qv = *reinterpret_cast<const float4*>(qbase + (size_t)(i0 + lr) * 1536 + kk + lc);
        float4 kv = *reinterpret_cast<const float4*>(qbase + 512 + (size_t)(j0 + lr) * 1536 + kk + lc);
        Qs[lc + 0][lr] = qv.x; Qs[lc + 1][lr] = qv.y; Qs[lc + 2][lr] = qv.z; Qs[lc + 3][lr] = qv.w;
        Ks[lc + 0][lr] = kv.x; Ks[lc + 1][lr] = kv.y; Ks[lc + 2][lr] = kv.z; Ks[lc + 3][lr] = kv.w;
        __syncthreads();
#pragma unroll
        for (int k = 0; k < 16; k++) {
            float a[4], bb[4];
#pragma unroll
            for (int i = 0; i < 4; i++) a[i]  = Qs[k][ty * 4 + i];
#pragma unroll
            for (int j = 0; j < 4; j++) bb[j] = Ks[k][tx * 4 + j];
#pragma unroll
            for (int i = 0; i < 4; i++)
#pragma unroll
                for (int j = 0; j < 4; j++) acc[i][j] = fmaf(a[i], bb[j], acc[i][j]);
        }
        __syncthreads();
    }
    float* so = S + (size_t)bh * 65536;
    const float scale = 0.08838834764831845f;
#pragma unroll
    for (int i = 0; i < 4; i++)
#pragma unroll
        for (int j = 0; j < 4; j++)
            so[(size_t)(i0 + ty * 4 + i) * 256 + j0 + tx * 4 + j] = acc[i][j] * scale;
}

__global__ void __launch_bounds__(256) softmax_kernel(float* __restrict__ S)
{
    const int row  = blockIdx.x * 8 + (threadIdx.x >> 5);
    const int lane = threadIdx.x & 31;
    float* p = S + (size_t)row * 256;
    float v[8]; float mx = -1e30f;
#pragma unroll
    for (int j = 0; j < 8; j++) { v[j] = p[lane + 32 * j]; mx = fmaxf(mx, v[j]); }
#pragma unroll
    for (int o = 16; o; o >>= 1) mx = fmaxf(mx, __shfl_xor_sync(0xffffffffu, mx, o));
    float s = 0.f;
#pragma unroll
    for (int j = 0; j < 8; j++) { v[j] = expf(v[j] - mx); s += v[j]; }
#pragma unroll
    for (int o = 16; o; o >>= 1) s += __shfl_xor_sync(0xffffffffu, s, o);
    const float inv = 1.f / s;
#pragma unroll
    for (int j = 0; j < 8; j++) p[lane + 32 * j] = v[j] * inv;
}

__global__ void __launch_bounds__(256) pv_kernel(const float* __restrict__ S,
                                                 const float* __restrict__ qkv,
                                                 __nv_bfloat16* __restrict__ Oh,
                                                 __nv_bfloat16* __restrict__ Ol)
{
    __shared__ float Ps[16][64], Vs[16][64];
    const int bh = blockIdx.x, b = bh >> 2, h = bh & 3;
    const int i0 = blockIdx.y * 64, d0 = blockIdx.z * 64;
    const int tid = threadIdx.x;
    const int tx = tid & 15, ty = tid >> 4;
    const int lr = tid >> 2, lc = (tid & 3) * 4;
    const int vr = tid >> 4, vc = (tid & 15) * 4;
    const float* sb = S + (size_t)bh * 65536;
    const float* vbase = qkv + (size_t)b * 256 * 1536 + 1024 + h * 128;
    float acc[4][4] = {};
    for (int kk = 0; kk < 256; kk += 16) {
        float4 pv4 = *reinterpret_cast<const float4*>(sb + (size_t)(i0 + lr) * 256 + kk + lc);
        Ps[lc + 0][lr] = pv4.x; Ps[lc + 1][lr] = pv4.y; Ps[lc + 2][lr] = pv4.z; Ps[lc + 3][lr] = pv4.w;
        *reinterpret_cast<float4*>(&Vs[vr][vc]) =
            *reinterpret_cast<const float4*>(vbase + (size_t)(kk + vr) * 1536 + d0 + vc);
        __syncthreads();
#pragma unroll
        for (int k = 0; k < 16; k++) {
            float a[4], bb[4];
#pragma unroll
            for (int i = 0; i < 4; i++) a[i]  = Ps[k][ty * 4 + i];
#pragma unroll
            for (int j = 0; j < 4; j++) bb[j] = Vs[k][tx * 4 + j];
#pragma unroll
            for (int i = 0; i < 4; i++)
#pragma unroll
                for (int j = 0; j < 4; j++) acc[i][j] = fmaf(a[i], bb[j], acc[i][j]);
        }
        __syncthreads();
    }
#pragma unroll
    for (int i = 0; i < 4; i++)
#pragma unroll
        for (int j = 0; j < 4; j++) {
            size_t o = (size_t)(b * 256 + i0 + ty * 4 + i) * 512 + h * 128 + d0 + tx * 4 + j;
            __nv_bfloat16 hb, lb; split2(acc[i][j], hb, lb);
            Oh[o] = hb; Ol[o] = lb;
        }
}

// LayerNorm -> bf16 hi/lo pair
__global__ void __launch_bounds__(256) ln_kernel(const float* __restrict__ x,
                                                 const float* __restrict__ g,
                                                 const float* __restrict__ bb,
                                                 __nv_bfloat16* __restrict__ yh,
                                                 __nv_bfloat16* __restrict__ yl)
{
    __shared__ float red[256];
    const int row = blockIdx.x, tid = threadIdx.x;
    const float* xr = x + (size_t)row * 512;
    float x0 = xr[tid], x1 = xr[tid + 256];
    red[tid] = x0 + x1; __syncthreads();
    for (int s = 128; s; s >>= 1) { if (tid < s) red[tid] += red[tid + s]; __syncthreads(); }
    float mean = red[0] * (1.f / 512.f);
    __syncthreads();
    red[tid] = x0 * x0 + x1 * x1; __syncthreads();
    for (int s = 128; s; s >>= 1) { if (tid < s) red[tid] += red[tid + s]; __syncthreads(); }
    float var = red[0] * (1.f / 512.f) - mean * mean;
    float inv = rsqrtf(var + 1e-5f);
    float v0 = (x0 - mean) * inv * g[tid]       + bb[tid];
    float v1 = (x1 - mean) * inv * g[tid + 256] + bb[tid + 256];
    __nv_bfloat16 hb, lb;
    split2(v0, hb, lb); yh[(size_t)row * 512 + tid] = hb;       yl[(size_t)row * 512 + tid] = lb;
    split2(v1, hb, lb); yh[(size_t)row * 512 + tid + 256] = hb; yl[(size_t)row * 512 + tid + 256] = lb;
}

// Memory attention: att=sigmoid(x.mem^T/sqrt512); top4 mean; aug=att@mem (bf16 pair)
__global__ void __launch_bounds__(512) memory_kernel(const float* __restrict__ x,
                                                     const float* __restrict__ mem,
                                                     float* __restrict__ att_out,
                                                     __nv_bfloat16* __restrict__ augh,
                                                     __nv_bfloat16* __restrict__ augl)
{
    __shared__ float xs[512];
    __shared__ float att[64];
    const int row = blockIdx.x, tid = threadIdx.x;
    const int w = tid >> 5, lane = tid & 31;
    xs[tid] = x[(size_t)row * 512 + tid];
    __syncthreads();
    for (int n = w; n < 60; n += 16) {
        float s = 0.f;
        const float* mr = mem + n * 512;
        for (int d = lane; d < 512; d += 32) s = fmaf(xs[d], mr[d], s);
#pragma unroll
        for (int o = 16; o; o >>= 1) s += __shfl_xor_sync(0xffffffffu, s, o);
        if (lane == 0) att[n] = 1.f / (1.f + expf(-s * 0.044194173824159216f));
    }
    __syncthreads();
    if (tid == 0) {
        float t0 = -1e30f, t1 = -1e30f, t2 = -1e30f, t3 = -1e30f;
        for (int n = 0; n < 60; n++) {
            float v = att[n];
            if (v > t0)      { t3 = t2; t2 = t1; t1 = t0; t0 = v; }
            else if (v > t1) { t3 = t2; t2 = t1; t1 = v; }
            else if (v > t2) { t3 = t2; t2 = v; }
            else if (v > t3) { t3 = v; }
        }
        att_out[row] = (t0 + t1 + t2 + t3) * 0.25f;
    }
    float s = 0.f;
    for (int n = 0; n < 60; n++) s = fmaf(att[n], mem[n * 512 + tid], s);
    __nv_bfloat16 hb, lb; split2(s, hb, lb);
    augh[(size_t)row * 512 + tid] = hb;
    augl[(size_t)row * 512 + tid] = lb;
}

// top-17 over 256, gather, mean
__global__ void __launch_bounds__(256) topk_gather(const float* __restrict__ att,
                                                   const float* __restrict__ feats,
                                                   float* __restrict__ meanv,
                                                   int* __restrict__ idx_out)
{
    __shared__ float vals[256], rv[256];
    __shared__ int ri[256], ids[17];
    const int b = blockIdx.x, tid = threadIdx.x;
    vals[tid] = att[b * 256 + tid];
    __syncthreads();
    for (int it = 0; it < 17; it++) {
        rv[tid] = vals[tid]; ri[tid] = tid;
        __syncthreads();
        for (int s = 128; s; s >>= 1) {
            if (tid < s) {
                float ov = rv[tid + s]; int oi = ri[tid + s];
                if (ov > rv[tid] || (ov == rv[tid] && oi < ri[tid])) { rv[tid] = ov; ri[tid] = oi; }
            }
            __syncthreads();
        }
        if (tid == 0) {
            ids[it] = ri[0];
            vals[ri[0]] = -1e30f;
            if (idx_out) idx_out[b * 17 + it] = ri[0];
        }
        __syncthreads();
    }
    for (int d = tid; d < 512; d += 256) {
        float s = 0.f;
        for (int j = 0; j < 17; j++) s += feats[((size_t)b * 256 + ids[j]) * 512 + d];
        meanv[b * 512 + d] = s * (1.f / 17.f);
    }
}

__device__ __forceinline__ float wsum(float v)
{
#pragma unroll
    for (int o = 16; o; o >>= 1) v += __shfl_xor_sync(0xffffffffu, v, o);
    return v;
}

__global__ void __launch_bounds__(1024) triplet_cos_kernel(const float* __restrict__ anchor,
                                                           const float* __restrict__ pos,
                                                           const float* __restrict__ neg,
                                                           float* __restrict__ trip_out,
                                                           float* __restrict__ cos_out)
{
    __shared__ float st[32], sc[32];
    const int w = threadIdx.x >> 5, lane = threadIdx.x & 31;
    float sa = 0, sp = 0, sn = 0, dan = 0;
    for (int d = lane; d < 512; d += 32) {
        float a = anchor[w * 512 + d], p = pos[w * 512 + d], n = neg[w * 512 + d];
        sa += a * a; sp += p * p; sn += n * n; dan += a * n;
    }
    sa = wsum(sa); sp = wsum(sp); sn = wsum(sn); dan = wsum(dan);
    float na = sqrtf(sa), npp = sqrtf(sp), ng = sqrtf(sn);
    float ina = 1.f / na, inp = 1.f / npp, ing = 1.f / ng;
    float dp2 = 0, dn2 = 0;
    for (int d = lane; d < 512; d += 32) {
        float a  = anchor[w * 512 + d] * ina;
        float dpv = a - pos[w * 512 + d] * inp + 1e-6f;
        float dnv = a - neg[w * 512 + d] * ing + 1e-6f;
        dp2 += dpv * dpv; dn2 += dnv * dnv;
    }
    dp2 = wsum(dp2); dn2 = wsum(dn2);
    if (lane == 0) {
        st[w] = fmaxf(sqrtf(dp2) - sqrtf(dn2) + 1.f, 0.f);
        sc[w] = 1.f - dan / (fmaxf(na, 1e-6f) * fmaxf(ng, 1e-6f));
    }
    __syncthreads();
    if (threadIdx.x == 0) {
        float a = 0, c = 0;
        for (int i = 0; i < 32; i++) { a += st[i]; c += sc[i]; }
        trip_out[0] = a * (1.f / 32.f);
        cos_out[0]  = c * (1.f / 32.f);
    }
}

__global__ void __launch_bounds__(1024) distance_kernel(const float* __restrict__ anew,
                                                        const float* __restrict__ nnew,
                                                        float* __restrict__ out)
{
    __shared__ float sd[32];
    const int w = threadIdx.x >> 5, lane = threadIdx.x & 31;
    float sa = 0, sn = 0;
    for (int d = lane; d < 512; d += 32) {
        float a = anew[w * 512 + d], n = nnew[w * 512 + d];
        sa += a * a; sn += n * n;
    }
    sa = wsum(sa); sn = wsum(sn);
    if (lane == 0) sd[w] = fmaxf(100.f - sqrtf(sn) + sqrtf(sa), 0.f);
    __syncthreads();
    if (threadIdx.x == 0) {
        float s = 0;
        for (int i = 0; i < 32; i++) s += sd[i];
        out[0] = s * (1.f / 32.f);
    }
}

__global__ void vae_kernel(const float* __restrict__ mu, const float* __restrict__ var,
                           const float* __restrict__ eps, float* __restrict__ o, int n)
{
    for (int i = blockIdx.x * blockDim.x + threadIdx.x; i < n; i += gridDim.x * blockDim.x)
        o[i] = mu[i] + eps[i] * sqrtf(expf(var[i]));
}

__global__ void __launch_bounds__(256) kl_part_kernel(const float* __restrict__ mu,
                                                      const float* __restrict__ var,
                                                      float* __restrict__ part, int n)
{
    __shared__ float red[256];
    float s = 0.f;
    for (int i = blockIdx.x * 256 + threadIdx.x; i < n; i += gridDim.x * 256) {
        float m = mu[i], v = var[i];
        s += 1.f + v - m * m - expf(v);
    }
    red[threadIdx.x] = s; __syncthreads();
    for (int t = 128; t; t >>= 1) { if (threadIdx.x < t) red[threadIdx.x] += red[threadIdx.x + t]; __syncthreads(); }
    if (threadIdx.x == 0) part[blockIdx.x] = red[0];
}

__global__ void __launch_bounds__(1024) kl_final_kernel(const float* __restrict__ part,
                                                        float* __restrict__ out)
{
    __shared__ float red[1024];
    red[threadIdx.x] = part[threadIdx.x]; __syncthreads();
    for (int t = 512; t; t >>= 1) { if (threadIdx.x < t) red[threadIdx.x] += red[threadIdx.x + t]; __syncthreads(); }
    if (threadIdx.x == 0) out[0] = -0.5f * red[0] * (1.f / 16384.f);
}

__global__ void __launch_bounds__(512) gather_mean_kernel(const float* __restrict__ src,
                                                          const int* __restrict__ idx,
                                                          float* __restrict__ out)
{
    __shared__ int ids[17];
    const int b = blockIdx.x, tid = threadIdx.x;
    if (tid < 17) ids[tid] = idx[b * 17 + tid];
    __syncthreads();
    float s = 0.f;
    for (int j = 0; j < 17; j++) s += src[((size_t)b * 256 + ids[j]) * 512 + tid];
    out[b * 512 + tid] = s * (1.f / 17.f);
}

__global__ void xout_kernel(const float* __restrict__ h, const float* __restrict__ nnew,
                            const float* __restrict__ anm, const float* __restrict__ anew,
                            const float* __restrict__ nam, float* __restrict__ xout)
{
    const int n = 64 * 256 * 1024;
    for (int i = blockIdx.x * blockDim.x + threadIdx.x; i < n; i += gridDim.x * blockDim.x) {
        int c  = i & 1023;
        int rt = i >> 10;
        float v;
        if (c < 512) v = h[(size_t)rt * 512 + c];
        else {
            int cc = c - 512;
            if (rt < 8192) v = nnew[(size_t)rt * 512 + cc] + anm[(size_t)rt * 512 + cc];
            else {
                size_t o = (size_t)(rt - 8192) * 512 + cc;
                v = anew[o] + nam[o];
            }
        }
        xout[i] = v;
    }
}

__global__ void vfeat_kernel(const float* __restrict__ h, float* __restrict__ v)
{
    __shared__ float tile[32][33];
    const int b = blockIdx.x, d0 = blockIdx.y * 32, t0 = blockIdx.z * 32;
    for (int r = threadIdx.y; r < 32; r += 8)
        tile[r][threadIdx.x] = h[((size_t)b * 256 + t0 + r) * 512 + d0 + threadIdx.x];
    __syncthreads();
    for (int r = threadIdx.y; r < 32; r += 8)
        v[((size_t)b * 512 + d0 + r) * 256 + t0 + threadIdx.x] = tile[threadIdx.x][r];
}

// ===========================================================================
extern "C" void kernel_launch(void* const* d_in, const int* in_sizes, int n_in,
                              void* d_out, int out_size)
{
    const float* x      = (const float*)d_in[0];
    const float* eps_in = (const float*)d_in[1];
    const float* conv_w = (const float*)d_in[2];
    const float* conv_b = (const float*)d_in[3];
    const float* ln1_g  = (const float*)d_in[4];
    const float* ln1_b  = (const float*)d_in[5];
    const float* qkv_w  = (const float*)d_in[6];
    const float* out_w  = (const float*)d_in[7];
    const float* out_b  = (const float*)d_in[8];
    const float* ln2_g  = (const float*)d_in[9];
    const float* ln2_b  = (const float*)d_in[10];
    const float* ff1_w  = (const float*)d_in[11];
    const float* ff1_b  = (const float*)d_in[12];
    const float* ff2_w  = (const float*)d_in[13];
    const float* ff2_b  = (const float*)d_in[14];
    const float* a_mem  = (const float*)d_in[15];
    const float* n_mem  = (const float*)d_in[16];
    const float* mu_w   = (const float*)d_in[17];
    const float* mu_b   = (const float*)d_in[18];
    const float* var_w  = (const float*)d_in[19];
    const float* var_b  = (const float*)d_in[20];
    float* out = (float*)d_out;

    float* S = nullptr;
    cudaGetSymbolAddress((void**)&S, g_scratch);
    __nv_bfloat16* BF = nullptr;
    cudaGetSymbolAddress((void**)&BF, g_bf);

    float* h    = S + OFF_H;
    float* qkvp = S + OFF_QKV;
    float* sc   = S + OFF_SC;
    float* muB  = S + OFF_MU;
    float* varB = S + OFF_VAR;
    float* newN = S + OFF_NEW;
    float* Anew = S + OFF_ANEW;
    float* ANm  = S + OFF_ANM;
    float* NAm  = S + OFF_NAM;
    float* anch = S + OFF_ANCH;
    float* negv = S + OFF_NEG;
    float* posv = S + OFF_POS;
    float* anchN = S + OFF_ANCHN;
    float* negN  = S + OFF_NEGN;
    int*   idxA  = (int*)(S + OFF_IDXA);
    int*   idxN  = (int*)(S + OFF_IDXN);
    float* klp   = S + OFF_KLP;

    __nv_bfloat16* lnh = BF + B_LNH;  __nv_bfloat16* lnl = BF + B_LNL;
    __nv_bfloat16* aoh = BF + B_AOH;  __nv_bfloat16* aol = BF + B_AOL;
    __nv_bfloat16* ffh = BF + B_FFH;  __nv_bfloat16* ffl = BF + B_FFL;
    __nv_bfloat16* augAh  = BF + B_AUG;
    __nv_bfloat16* augAl  = BF + B_AUG + 4194304;
    __nv_bfloat16* augNAh = BF + B_AUG + 2 * 4194304;
    __nv_bfloat16* augNAl = BF + B_AUG + 3 * 4194304;
    __nv_bfloat16* augANh = BF + B_AUG + 4 * 4194304;
    __nv_bfloat16* augANl = BF + B_AUG + 5 * 4194304;
    __nv_bfloat16* augNh  = BF + B_AUG + 6 * 4194304;
    __nv_bfloat16* augNl  = BF + B_AUG + 7 * 4194304;

    // ---- weight prep (transpose + bf16 split)
    convprep<<<1024, 256>>>(conv_w, BF + B_CNVWH, BF + B_CNVWL);
    for (int i = 0; i < 2; i++) {
        wprep_t<<<dim3(16, 48), dim3(32, 8)>>>(qkv_w + (size_t)i * 786432,
                                               BF + B_QKVWH + (size_t)i * 786432,
                                               BF + B_QKVWL + (size_t)i * 786432, 512, 1536);
        wprep_t<<<dim3(16, 16), dim3(32, 8)>>>(out_w + (size_t)i * 262144,
                                               BF + B_OUTWH + (size_t)i * 262144,
                                               BF + B_OUTWL + (size_t)i * 262144, 512, 512);
        wprep_t<<<dim3(16, 16), dim3(32, 8)>>>(ff1_w + (size_t)i * 262144,
                                               BF + B_FF1WH + (size_t)i * 262144,
                                               BF + B_FF1WL + (size_t)i * 262144, 512, 512);
        wprep_t<<<dim3(16, 16), dim3(32, 8)>>>(ff2_w + (size_t)i * 262144,
                                               BF + B_FF2WH + (size_t)i * 262144,
                                               BF + B_FF2WL + (size_t)i * 262144, 512, 512);
    }
    wprep_t<<<dim3(16, 16), dim3(32, 8)>>>(mu_w,  BF + B_MUWH,  BF + B_MUWL,  512, 512);
    wprep_t<<<dim3(16, 16), dim3(32, 8)>>>(var_w, BF + B_VARWH, BF + B_VARWL, 512, 512);

    // ---- conv (implicit im2col, relu+bias)
    mgemm<4, true><<<dim3(4, 128), 256>>>(
        nullptr, nullptr, x, BF + B_CNVWH, BF + B_CNVWL,
        h, nullptr, nullptr, conv_b, 16384, 512, 3072);

    // ---- transformer x2
    for (int i = 0; i < 2; i++) {
        ln_kernel<<<16384, 256>>>(h, ln1_g + i * 512, ln1_b + i * 512, lnh, lnl);
        mgemm<0, false><<<dim3(12, 128), 256>>>(
            lnh, lnl, nullptr, BF + B_QKVWH + (size_t)i * 786432, BF + B_QKVWL + (size_t)i * 786432,
            qkvp, nullptr, nullptr, nullptr, 16384, 1536, 512);
        qk_kernel<<<dim3(256, 4, 4), 256>>>(qkvp, sc);
        softmax_kernel<<<8192, 256>>>(sc);
        pv_kernel<<<dim3(256, 4, 2), 256>>>(sc, qkvp, aoh, aol);
        mgemm<2, false><<<dim3(4, 128), 256>>>(
            aoh, aol, nullptr, BF + B_OUTWH + (size_t)i * 262144, BF + B_OUTWL + (size_t)i * 262144,
            h, nullptr, nullptr, out_b + i * 512, 16384, 512, 512);
        ln_kernel<<<16384, 256>>>(h, ln2_g + i * 512, ln2_b + i * 512, lnh, lnl);
        mgemm<3, false><<<dim3(4, 128), 256>>>(
            lnh, lnl, nullptr, BF + B_FF1WH + (size_t)i * 262144, BF + B_FF1WL + (size_t)i * 262144,
            nullptr, ffh, ffl, ff1_b + i * 512, 16384, 512, 512);
        mgemm<2, false><<<dim3(4, 128), 256>>>(
            ffh, ffl, nullptr, BF + B_FF2WH + (size_t)i * 262144, BF + B_FF2WL + (size_t)i * 262144,
            h, nullptr, nullptr, ff2_b + i * 512, 16384, 512, 512);
    }

    const float* Nx = h;                       // x_emb[:32]
    const float* Ax = h + (size_t)8192 * 512;  // x_emb[32:]

    memory_kernel<<<8192, 512>>>(Ax, a_mem, out + O_AATT,  augAh,  augAl);
    memory_kernel<<<8192, 512>>>(Ax, n_mem, out + O_NAATT, augNAh, augNAl);
    memory_kernel<<<8192, 512>>>(Nx, a_mem, out + O_ANATT, augANh, augANl);
    memory_kernel<<<8192, 512>>>(Nx, n_mem, out + O_NATT,  augNh,  augNl);

    topk_gather<<<32, 256>>>(out + O_AATT,  Ax, negv, idxA);
    topk_gather<<<32, 256>>>(out + O_NATT,  Nx, anch, idxN);
    topk_gather<<<32, 256>>>(out + O_NAATT, Ax, posv, nullptr);

    triplet_cos_kernel<<<1, 1024>>>(anch, posv, negv, out + O_TRIP, out + O_COS);

    // mu/var projections
    mgemm<1, false><<<dim3(4, 64), 256>>>(
        augNh, augNl, nullptr, BF + B_MUWH, BF + B_MUWL, muB, nullptr, nullptr, mu_b, 8192, 512, 512);
    mgemm<1, false><<<dim3(4, 64), 256>>>(
        augNh, augNl, nullptr, BF + B_VARWH, BF + B_VARWL, varB, nullptr, nullptr, var_b, 8192, 512, 512);
    mgemm<1, false><<<dim3(4, 64), 256>>>(
        augAh, augAl, nullptr, BF + B_MUWH, BF + B_MUWL, Anew, nullptr, nullptr, mu_b, 8192, 512, 512);
    mgemm<1, false><<<dim3(4, 64), 256>>>(
        augANh, augANl, nullptr, BF + B_MUWH, BF + B_MUWL, ANm, nullptr, nullptr, mu_b, 8192, 512, 512);
    mgemm<1, false><<<dim3(4, 64), 256>>>(
        augNAh, augNAl, nullptr, BF + B_MUWH, BF + B_MUWL, NAm, nullptr, nullptr, mu_b, 8192, 512, 512);

    vae_kernel<<<4096, 256>>>(muB, varB, eps_in, newN, 8192 * 512);
    kl_part_kernel<<<1024, 256>>>(muB, varB, klp, 8192 * 512);
    kl_final_kernel<<<1, 1024>>>(klp, out + O_KL);

    gather_mean_kernel<<<32, 512>>>(newN, idxN, anchN);
    gather_mean_kernel<<<32, 512>>>(Anew, idxA, negN);
    distance_kernel<<<1, 1024>>>(anchN, negN, out + O_DIST);

    xout_kernel<<<8192, 256>>>(h, newN, ANm, Anew, NAm, out + O_XOUT);
    vfeat_kernel<<<dim3(64, 16, 8), dim3(32, 8)>>>(h, out + O_VFEAT);
}

// round 4
// speedup vs baseline: 2.5449x; 1.0325x over previous
#include <cuda_runtime.h>
#include <cuda_bf16.h>
#include <math.h>
#include <stdint.h>

// ===========================================================================
// fp32 scratch
// ===========================================================================
constexpr size_t OFF_H     = 0;                         // 16384*512
constexpr size_t OFF_SC    = 8388608;                   // 256*256*256 (S fp32)
constexpr size_t OFF_STACK = OFF_SC + 16777216;         // 32768*512: Anew,NAm,ANm,muB
constexpr size_t OFF_VAR   = OFF_STACK + 16777216;      // 8192*512
constexpr size_t OFF_NEW   = OFF_VAR + 4194304;         // 8192*512
constexpr size_t OFF_ANCH  = OFF_NEW + 4194304;         // 32*512 each below
constexpr size_t OFF_NEG   = OFF_ANCH + 16384;
constexpr size_t OFF_POS   = OFF_NEG  + 16384;
constexpr size_t OFF_ANCHN = OFF_POS  + 16384;
constexpr size_t OFF_NEGN  = OFF_ANCHN + 16384;
constexpr size_t OFF_IDXA  = OFF_NEGN + 16384;
constexpr size_t OFF_IDXN  = OFF_IDXA + 1024;
constexpr size_t OFF_KLP   = OFF_IDXN + 1024;
constexpr size_t SCRATCH_TOTAL = OFF_KLP + 1024;
__device__ float g_scratch[SCRATCH_TOTAL];

// ===========================================================================
// bf16 scratch
// ===========================================================================
constexpr size_t SZ_TOK  = 16384ull * 512;    // 8388608
constexpr size_t SZ_QKV  = 16384ull * 1536;   // 25165824
constexpr size_t SZ_P    = 256ull * 65536;    // 16777216
constexpr size_t SZ_VT   = 256ull * 32768;    // 8388608
constexpr size_t SZ_AUG  = 8192ull * 512;     // 4194304

constexpr size_t B_LNH  = 0;
constexpr size_t B_LNL  = B_LNH + SZ_TOK;
constexpr size_t B_AOH  = B_LNL + SZ_TOK;
constexpr size_t B_AOL  = B_AOH + SZ_TOK;
constexpr size_t B_FFH  = B_AOL + SZ_TOK;
constexpr size_t B_FFL  = B_FFH + SZ_TOK;
constexpr size_t B_QKVH = B_FFL + SZ_TOK;
constexpr size_t B_QKVL = B_QKVH + SZ_QKV;
constexpr size_t B_PH   = B_QKVL + SZ_QKV;
constexpr size_t B_PL   = B_PH + SZ_P;
constexpr size_t B_VTH  = B_PL + SZ_P;
constexpr size_t B_VTL  = B_VTH + SZ_VT;
constexpr size_t B_AUGH = B_VTL + SZ_VT;      // [A, NA, AN, N] stacked
constexpr size_t B_AUGL = B_AUGH + 4 * SZ_AUG;
constexpr size_t B_QKVWH = B_AUGL + 4 * SZ_AUG;  // 2*786432
constexpr size_t B_QKVWL = B_QKVWH + 2ull * 786432;
constexpr size_t B_OUTWH = B_QKVWL + 2ull * 786432;
constexpr size_t B_OUTWL = B_OUTWH + 2ull * 262144;
constexpr size_t B_FF1WH = B_OUTWL + 2ull * 262144;
constexpr size_t B_FF1WL = B_FF1WH + 2ull * 262144;
constexpr size_t B_FF2WH = B_FF1WL + 2ull * 262144;
constexpr size_t B_FF2WL = B_FF2WH + 2ull * 262144;
constexpr size_t B_MUWH  = B_FF2WL + 2ull * 262144;
constexpr size_t B_MUWL  = B_MUWH + 262144;
constexpr size_t B_VARWH = B_MUWL + 262144;
constexpr size_t B_VARWL = B_VARWH + 262144;
constexpr size_t B_CNVWH = B_VARWL + 262144;
constexpr size_t B_CNVWL = B_CNVWH + 1572864;
constexpr size_t BF_TOTAL = B_CNVWL + 1572864;
__device__ __nv_bfloat16 g_bf[BF_TOTAL];

// output offsets (triplet, kl, distance, A_att, N_att, A_Natt, N_Aatt, cos, x_out, v_feat)
constexpr size_t O_TRIP  = 0;
constexpr size_t O_KL    = 1;
constexpr size_t O_DIST  = 2;
constexpr size_t O_AATT  = 3;
constexpr size_t O_NATT  = 3 + 8192;
constexpr size_t O_ANATT = 3 + 16384;
constexpr size_t O_NAATT = 3 + 24576;
constexpr size_t O_COS   = 3 + 32768;
constexpr size_t O_XOUT  = 4 + 32768;
constexpr size_t O_VFEAT = O_XOUT + 64ull * 256 * 1024;

// ===========================================================================
// mma helpers
// ===========================================================================
__device__ __forceinline__ void mma16816(float* c, const uint32_t* a, const uint32_t* b)
{
    asm volatile(
        "mma.sync.aligned.m16n8k16.row.col.f32.bf16.bf16.f32 "
        "{%0,%1,%2,%3}, {%4,%5,%6,%7}, {%8,%9}, {%0,%1,%2,%3};"
        : "+f"(c[0]), "+f"(c[1]), "+f"(c[2]), "+f"(c[3])
        : "r"(a[0]), "r"(a[1]), "r"(a[2]), "r"(a[3]), "r"(b[0]), "r"(b[1]));
}

__device__ __forceinline__ void split2(float v, __nv_bfloat16& h, __nv_bfloat16& l) {
    h = __float2bfloat16(v);
    l = __float2bfloat16(v - __bfloat162float(h));
}

// Shared warp-core: compute 64x32 warp tile from sA/sB (hi/lo), padded 40.
// acc[4][4][4], 3 split terms per k16 step.
__device__ __forceinline__ void mma_core_step(
    const __nv_bfloat16 (*sA)[128 * 40], const __nv_bfloat16 (*sB)[128 * 40],
    float acc[4][4][4], int wm, int wn, int g, int t, int ks)
{
    uint32_t fa[4][4], fbh[4][2], fbl[4][2];
#pragma unroll
    for (int mi = 0; mi < 4; mi++) {
        int r = (wm * 64 + mi * 16 + g) * 40 + ks + t * 2;
        fa[mi][0] = *(const uint32_t*)&sA[0][r];
        fa[mi][1] = *(const uint32_t*)&sA[0][r + 8 * 40];
        fa[mi][2] = *(const uint32_t*)&sA[0][r + 8];
        fa[mi][3] = *(const uint32_t*)&sA[0][r + 8 * 40 + 8];
    }
#pragma unroll
    for (int ni = 0; ni < 4; ni++) {
        int n = (wn * 32 + ni * 8 + g) * 40 + ks + t * 2;
        fbh[ni][0] = *(const uint32_t*)&sB[0][n];
        fbh[ni][1] = *(const uint32_t*)&sB[0][n + 8];
        fbl[ni][0] = *(const uint32_t*)&sB[1][n];
        fbl[ni][1] = *(const uint32_t*)&sB[1][n + 8];
    }
#pragma unroll
    for (int mi = 0; mi < 4; mi++)
#pragma unroll
        for (int ni = 0; ni < 4; ni++) {
            mma16816(acc[mi][ni], fa[mi], fbh[ni]);
            mma16816(acc[mi][ni], fa[mi], fbl[ni]);
        }
#pragma unroll
    for (int mi = 0; mi < 4; mi++) {
        int r = (wm * 64 + mi * 16 + g) * 40 + ks + t * 2;
        fa[mi][0] = *(const uint32_t*)&sA[1][r];
        fa[mi][1] = *(const uint32_t*)&sA[1][r + 8 * 40];
        fa[mi][2] = *(const uint32_t*)&sA[1][r + 8];
        fa[mi][3] = *(const uint32_t*)&sA[1][r + 8 * 40 + 8];
    }
#pragma unroll
    for (int mi = 0; mi < 4; mi++)
#pragma unroll
        for (int ni = 0; ni < 4; ni++)
            mma16816(acc[mi][ni], fa[mi], fbh[ni]);
}

// ===========================================================================
// HMMA GEMM: C[M,N] = A[M,K] * B[N,K]^T, bf16 split, fp32 acc.
// EPI: 0=none,1=+bias,2=+bias+residual,3=+bias+gelu->pair,4=+bias+relu,5=->pair
// ===========================================================================
template<int EPI, bool CONV>
__global__ void __launch_bounds__(256, 2) mgemm(
    const __nv_bfloat16* __restrict__ Ah, const __nv_bfloat16* __restrict__ Al,
    const float* __restrict__ Xc,
    const __nv_bfloat16* __restrict__ Bh, const __nv_bfloat16* __restrict__ Bl,
    float* __restrict__ C,
    __nv_bfloat16* __restrict__ Chi, __nv_bfloat16* __restrict__ Clo,
    const float* __restrict__ bias,
    int M, int N, int K)
{
    __shared__ __nv_bfloat16 sA[2][128 * 40];
    __shared__ __nv_bfloat16 sB[2][128 * 40];

    const int tid  = threadIdx.x;
    const int wid  = tid >> 5;
    const int lane = tid & 31;
    const int g = lane >> 2, t = lane & 3;
    const int wm = wid >> 2, wn = wid & 3;
    const int row0 = blockIdx.y * 128;
    const int col0 = blockIdx.x * 128;

    float acc[4][4][4];
#pragma unroll
    for (int mi = 0; mi < 4; mi++)
#pragma unroll
        for (int ni = 0; ni < 4; ni++)
#pragma unroll
            for (int q = 0; q < 4; q++) acc[mi][ni][q] = 0.f;

    const int nchunks = K >> 5;
    for (int kc = 0; kc < nchunks; kc++) {
#pragma unroll
        for (int i = 0; i < 2; i++) {
            int chunk = tid * 2 + i;
            int r = chunk >> 2, seg = chunk & 3;
            int so = r * 40 + seg * 8;
            if (CONV) {
                int gk = kc * 32 + seg * 8;
                int tap = gk >> 10, ci = gk & 1023;
                int m = row0 + r;
                int t2 = (m & 255) + tap - 1;
                uint4 hi4, lo4;
                if (t2 >= 0 && t2 < 256) {
                    const float* src = Xc + ((size_t)((m >> 8) * 256 + t2)) * 1024 + ci;
                    float4 f0 = *(const float4*)src;
                    float4 f1 = *(const float4*)(src + 4);
                    float f[8] = {f0.x, f0.y, f0.z, f0.w, f1.x, f1.y, f1.z, f1.w};
                    __nv_bfloat16 hb[8], lb[8];
#pragma unroll
                    for (int q = 0; q < 8; q++) split2(f[q], hb[q], lb[q]);
                    hi4 = *(uint4*)hb; lo4 = *(uint4*)lb;
                } else {
                    hi4 = make_uint4(0, 0, 0, 0); lo4 = hi4;
                }
                *(uint4*)&sA[0][so] = hi4;
                *(uint4*)&sA[1][so] = lo4;
            } else {
                size_t o = (size_t)(row0 + r) * K + kc * 32 + seg * 8;
                *(uint4*)&sA[0][so] = *(const uint4*)(Ah + o);
                *(uint4*)&sA[1][so] = *(const uint4*)(Al + o);
            }
            size_t ob = (size_t)(col0 + r) * K + kc * 32 + seg * 8;
            *(uint4*)&sB[0][so] = *(const uint4*)(Bh + ob);
            *(uint4*)&sB[1][so] = *(const uint4*)(Bl + ob);
        }
        __syncthreads();
#pragma unroll
        for (int ks = 0; ks < 32; ks += 16)
            mma_core_step(sA, sB, acc, wm, wn, g, t, ks);
        __syncthreads();
    }

#pragma unroll
    for (int mi = 0; mi < 4; mi++) {
#pragma unroll
        for (int ni = 0; ni < 4; ni++) {
#pragma unroll
            for (int q = 0; q < 4; q++) {
                int r = row0 + wm * 64 + mi * 16 + g + (q >> 1) * 8;
                int c = col0 + wn * 32 + ni * 8 + t * 2 + (q & 1);
                float v = acc[mi][ni][q];
                size_t o = (size_t)r * N + c;
                if (EPI != 0 && EPI != 5) v += bias[c];
                if (EPI == 2) v += C[o];
                if (EPI == 3 || EPI == 5) {
                    if (EPI == 3) v = 0.5f * v * (1.f + erff(v * 0.70710678118654752f));
                    __nv_bfloat16 hb, lb; split2(v, hb, lb);
                    Chi[o] = hb; Clo[o] = lb;
                } else {
                    if (EPI == 4) v = fmaxf(v, 0.f);
                    C[o] = v;
                }
            }
        }
    }
}

// ===========================================================================
// Batched QK^T: S[bh][i][j] = scale * q_i . k_j.   grid (mtile2, ntile2, bh256)
// ===========================================================================
__global__ void __launch_bounds__(256, 2) bqk_kernel(
    const __nv_bfloat16* __restrict__ Qh, const __nv_bfloat16* __restrict__ Ql,
    float* __restrict__ S)
{
    __shared__ __nv_bfloat16 sA[2][128 * 40];
    __shared__ __nv_bfloat16 sB[2][128 * 40];
    const int tid  = threadIdx.x;
    const int wid  = tid >> 5;
    const int lane = tid & 31;
    const int g = lane >> 2, t = lane & 3;
    const int wm = wid >> 2, wn = wid & 3;
    const int bh = blockIdx.z, b = bh >> 2, h = bh & 3;
    const int i0 = blockIdx.x * 128, j0 = blockIdx.y * 128;
    const __nv_bfloat16* Ah = Qh + (size_t)b * 256 * 1536 + h * 128;
    const __nv_bfloat16* Al = Ql + (size_t)b * 256 * 1536 + h * 128;

    float acc[4][4][4];
#pragma unroll
    for (int mi = 0; mi < 4; mi++)
#pragma unroll
        for (int ni = 0; ni < 4; ni++)
#pragma unroll
            for (int q = 0; q < 4; q++) acc[mi][ni][q] = 0.f;

    for (int kc = 0; kc < 4; kc++) {
#pragma unroll
        for (int i = 0; i < 2; i++) {
            int chunk = tid * 2 + i;
            int r = chunk >> 2, seg = chunk & 3;
            int so = r * 40 + seg * 8;
            size_t oa = (size_t)(i0 + r) * 1536 + kc * 32 + seg * 8;
            size_t ob = (size_t)(j0 + r) * 1536 + 512 + kc * 32 + seg * 8;
            *(uint4*)&sA[0][so] = *(const uint4*)(Ah + oa);
            *(uint4*)&sA[1][so] = *(const uint4*)(Al + oa);
            *(uint4*)&sB[0][so] = *(const uint4*)(Ah + ob);
            *(uint4*)&sB[1][so] = *(const uint4*)(Al + ob);
        }
        __syncthreads();
#pragma unroll
        for (int ks = 0; ks < 32; ks += 16)
            mma_core_step(sA, sB, acc, wm, wn, g, t, ks);
        __syncthreads();
    }

    float* so2 = S + (size_t)bh * 65536;
    const float scale = 0.08838834764831845f;
#pragma unroll
    for (int mi = 0; mi < 4; mi++)
#pragma unroll
        for (int ni = 0; ni < 4; ni++)
#pragma unroll
            for (int q = 0; q < 4; q++) {
                int r = i0 + wm * 64 + mi * 16 + g + (q >> 1) * 8;
                int c = j0 + wn * 32 + ni * 8 + t * 2 + (q & 1);
                so2[(size_t)r * 256 + c] = acc[mi][ni][q] * scale;
            }
}

// row softmax -> bf16 pair
__global__ void __launch_bounds__(256) softmaxp_kernel(const float* __restrict__ S,
                                                       __nv_bfloat16* __restrict__ Ph,
                                                       __nv_bfloat16* __restrict__ Pl)
{
    const int row  = blockIdx.x * 8 + (threadIdx.x >> 5);
    const int lane = threadIdx.x & 31;
    const float* p = S + (size_t)row * 256;
    float v[8]; float mx = -1e30f;
#pragma unroll
    for (int j = 0; j < 8; j++) { v[j] = p[lane + 32 * j]; mx = fmaxf(mx, v[j]); }
#pragma unroll
    for (int o = 16; o; o >>= 1) mx = fmaxf(mx, __shfl_xor_sync(0xffffffffu, mx, o));
    float s = 0.f;
#pragma unroll
    for (int j = 0; j < 8; j++) { v[j] = expf(v[j] - mx); s += v[j]; }
#pragma unroll
    for (int o = 16; o; o >>= 1) s += __shfl_xor_sync(0xffffffffu, s, o);
    const float inv = 1.f / s;
#pragma unroll
    for (int j = 0; j < 8; j++) {
        __nv_bfloat16 hb, lb; split2(v[j] * inv, hb, lb);
        Ph[(size_t)row * 256 + lane + 32 * j] = hb;
        Pl[(size_t)row * 256 + lane + 32 * j] = lb;
    }
}

// V transpose: vt[bh][d][j] from qkv[token][1536] (v slice). grid (bh, 4, 8), block (32,8)
__global__ void vtrans_kernel(const __nv_bfloat16* __restrict__ Vh,
                              const __nv_bfloat16* __restrict__ Vl,
                              __nv_bfloat16* __restrict__ vth,
                              __nv_bfloat16* __restrict__ vtl)
{
    __shared__ __nv_bfloat16 th[32][33], tl[32][33];
    const int bh = blockIdx.x, b = bh >> 2, h = bh & 3;
    const int d0 = blockIdx.y * 32, j0 = blockIdx.z * 32;
    const int tx = threadIdx.x, ty = threadIdx.y;
    const size_t base = (size_t)b * 256 * 1536 + 1024 + h * 128;
    for (int r = ty; r < 32; r += 8) {
        size_t o = base + (size_t)(j0 + r) * 1536 + d0 + tx;
        th[r][tx] = Vh[o]; tl[r][tx] = Vl[o];
    }
    __syncthreads();
    const size_t obase = (size_t)bh * 32768;
    for (int r = ty; r < 32; r += 8) {
        size_t o = obase + (size_t)(d0 + r) * 256 + j0 + tx;
        vth[o] = th[tx][r]; vtl[o] = tl[tx][r];
    }
}

// Batched PV: O[token][512] (hi/lo pair) = P[bh] @ V^T[bh].  grid (mtile2, 1, bh)
__global__ void __launch_bounds__(256, 2) bpv_kernel(
    const __nv_bfloat16* __restrict__ Ph, const __nv_bfloat16* __restrict__ Pl,
    const __nv_bfloat16* __restrict__ vth, const __nv_bfloat16* __restrict__ vtl,
    __nv_bfloat16* __restrict__ Oh, __nv_bfloat16* __restrict__ Ol)
{
    __shared__ __nv_bfloat16 sA[2][128 * 40];
    __shared__ __nv_bfloat16 sB[2][128 * 40];
    const int tid  = threadIdx.x;
    const int wid  = tid >> 5;
    const int lane = tid & 31;
    const int g = lane >> 2, t = lane & 3;
    const int wm = wid >> 2, wn = wid & 3;
    const int bh = blockIdx.z, b = bh >> 2, h = bh & 3;
    const int i0 = blockIdx.x * 128;
    const __nv_bfloat16* Ah = Ph + (size_t)bh * 65536 + (size_t)i0 * 256;
    const __nv_bfloat16* Al = Pl + (size_t)bh * 65536 + (size_t)i0 * 256;
    const __nv_bfloat16* Bh = vth + (size_t)bh * 32768;
    const __nv_bfloat16* Bl = vtl + (size_t)bh * 32768;

    float acc[4][4][4];
#pragma unroll
    for (int mi = 0; mi < 4; mi++)
#pragma unroll
        for (int ni = 0; ni < 4; ni++)
#pragma unroll
            for (int q = 0; q < 4; q++) acc[mi][ni][q] = 0.f;

    for (int kc = 0; kc < 8; kc++) {
#pragma unroll
        for (int i = 0; i < 2; i++) {
            int chunk = tid * 2 + i;
            int r = chunk >> 2, seg = chunk & 3;
            int so = r * 40 + seg * 8;
            size_t oa = (size_t)r * 256 + kc * 32 + seg * 8;
            *(uint4*)&sA[0][so] = *(const uint4*)(Ah + oa);
            *(uint4*)&sA[1][so] = *(const uint4*)(Al + oa);
            *(uint4*)&sB[0][so] = *(const uint4*)(Bh + oa);
            *(uint4*)&sB[1][so] = *(const uint4*)(Bl + oa);
        }
        __syncthreads();
#pragma unroll
        for (int ks = 0; ks < 32; ks += 16)
            mma_core_step(sA, sB, acc, wm, wn, g, t, ks);
        __syncthreads();
    }

#pragma unroll
    for (int mi = 0; mi < 4; mi++)
#pragma unroll
        for (int ni = 0; ni < 4; ni++)
#pragma unroll
            for (int q = 0; q < 4; q++) {
                int r = i0 + wm * 64 + mi * 16 + g + (q >> 1) * 8;
                int c = wn * 32 + ni * 8 + t * 2 + (q & 1);
                size_t o = ((size_t)b * 256 + r) * 512 + h * 128 + c;
                __nv_bfloat16 hb, lb; split2(acc[mi][ni][q], hb, lb);
                Oh[o] = hb; Ol[o] = lb;
            }
}

// ===========================================================================
// Weight prep
// ===========================================================================
__global__ void wprep_t(const float* __restrict__ W, __nv_bfloat16* __restrict__ Wh,
                        __nv_bfloat16* __restrict__ Wl, int K, int N)
{
    __shared__ float tile[32][33];
    const int k0 = blockIdx.x * 32, n0 = blockIdx.y * 32;
    const int tx = threadIdx.x, ty = threadIdx.y;
    for (int r = ty; r < 32; r += 8)
        tile[r][tx] = W[(size_t)(k0 + r) * N + n0 + tx];
    __syncthreads();
    for (int r = ty; r < 32; r += 8) {
        float v = tile[tx][r];
        size_t o = (size_t)(n0 + r) * K + k0 + tx;
        __nv_bfloat16 hb, lb; split2(v, hb, lb);
        Wh[o] = hb; Wl[o] = lb;
    }
}

__global__ void convprep(const float* __restrict__ w, __nv_bfloat16* __restrict__ Wh,
                         __nv_bfloat16* __restrict__ Wl)
{
    const int n = 512 * 3072;
    for (int idx = blockIdx.x * blockDim.x + threadIdx.x; idx < n; idx += gridDim.x * blockDim.x) {
        int d = idx / 3072, k = idx % 3072;
        int tap = k >> 10, ci = k & 1023;
        float v = w[(size_t)d * 3072 + ci * 3 + tap];
        __nv_bfloat16 hb, lb; split2(v, hb, lb);
        Wh[idx] = hb; Wl[idx] = lb;
    }
}

// ===========================================================================
// LayerNorm -> bf16 hi/lo pair
// ===========================================================================
__global__ void __launch_bounds__(256) ln_kernel(const float* __restrict__ x,
                                                 const float* __restrict__ g,
                                                 const float* __restrict__ bb,
                                                 __nv_bfloat16* __restrict__ yh,
                                                 __nv_bfloat16* __restrict__ yl)
{
    __shared__ float red[256];
    const int row = blockIdx.x, tid = threadIdx.x;
    const float* xr = x + (size_t)row * 512;
    float x0 = xr[tid], x1 = xr[tid + 256];
    red[tid] = x0 + x1; __syncthreads();
    for (int s = 128; s; s >>= 1) { if (tid < s) red[tid] += red[tid + s]; __syncthreads(); }
    float mean = red[0] * (1.f / 512.f);
    __syncthreads();
    red[tid] = x0 * x0 + x1 * x1; __syncthreads();
    for (int s = 128; s; s >>= 1) { if (tid < s) red[tid] += red[tid + s]; __syncthreads(); }
    float var = red[0] * (1.f / 512.f) - mean * mean;
    float inv = rsqrtf(var + 1e-5f);
    float v0 = (x0 - mean) * inv * g[tid]       + bb[tid];
    float v1 = (x1 - mean) * inv * g[tid + 256] + bb[tid + 256];
    __nv_bfloat16 hb, lb;
    split2(v0, hb, lb); yh[(size_t)row * 512 + tid] = hb;       yl[(size_t)row * 512 + tid] = lb;
    split2(v1, hb, lb); yh[(size_t)row * 512 + tid + 256] = hb; yl[(size_t)row * 512 + tid + 256] = lb;
}

// ===========================================================================
// Memory attention (batched over 4 combos via grid.y)
// ===========================================================================
__global__ void __launch_bounds__(512) memory_kernel(const float* __restrict__ Nx,
                                                     const float* __restrict__ Ax,
                                                     const float* __restrict__ a_mem,
                                                     const float* __restrict__ n_mem,
                                                     float* __restrict__ att_base,
                                                     __nv_bfloat16* __restrict__ augh_base,
                                                     __nv_bfloat16* __restrict__ augl_base)
{
    __shared__ float xs[512];
    __shared__ float att[64];
    const int row = blockIdx.x, tid = threadIdx.x;
    const int combo = blockIdx.y;       // 0:A(Ax,a) 1:NA(Ax,n) 2:AN(Nx,a) 3:N(Nx,n)
    const float* x   = (combo < 2) ? Ax : Nx;
    const float* mem = (combo & 1) ? n_mem : a_mem;
    const int att_off[4] = {0, 24576, 16384, 8192};
    float* att_out = att_base + att_off[combo];
    __nv_bfloat16* augh = augh_base + (size_t)combo * SZ_AUG;
    __nv_bfloat16* augl = augl_base + (size_t)combo * SZ_AUG;

    const int w = tid >> 5, lane = tid & 31;
    xs[tid] = x[(size_t)row * 512 + tid];
    __syncthreads();
    for (int n = w; n < 60; n += 16) {
        float s = 0.f;
        const float* mr = mem + n * 512;
        for (int d = lane; d < 512; d += 32) s = fmaf(xs[d], mr[d], s);
#pragma unroll
        for (int o = 16; o; o >>= 1) s += __shfl_xor_sync(0xffffffffu, s, o);
        if (lane == 0) att[n] = 1.f / (1.f + expf(-s * 0.044194173824159216f));
    }
    __syncthreads();
    if (tid == 0) {
        float t0 = -1e30f, t1 = -1e30f, t2 = -1e30f, t3 = -1e30f;
        for (int n = 0; n < 60; n++) {
            float v = att[n];
            if (v > t0)      { t3 = t2; t2 = t1; t1 = t0; t0 = v; }
            else if (v > t1) { t3 = t2; t2 = t1; t1 = v; }
            else if (v > t2) { t3 = t2; t2 = v; }
            else if (v > t3) { t3 = v; }
        }
        att_out[row] = (t0 + t1 + t2 + t3) * 0.25f;
    }
    float s = 0.f;
    for (int n = 0; n < 60; n++) s = fmaf(att[n], mem[n * 512 + tid], s);
    __nv_bfloat16 hb, lb; split2(s, hb, lb);
    augh[(size_t)row * 512 + tid] = hb;
    augl[(size_t)row * 512 + tid] = lb;
}

// ===========================================================================
// top-k / losses / misc (unchanged from r3)
// ===========================================================================
__global__ void __launch_bounds__(256) topk_gather(const float* __restrict__ att,
                                                   const float* __restrict__ feats,
                                                   float* __restrict__ meanv,
                                                   int* __restrict__ idx_out)
{
    __shared__ float vals[256], rv[256];
    __shared__ int ri[256], ids[17];
    const int b = blockIdx.x, tid = threadIdx.x;
    vals[tid] = att[b * 256 + tid];
    __syncthreads();
    for (int it = 0; it < 17; it++) {
        rv[tid] = vals[tid]; ri[tid] = tid;
        __syncthreads();
        for (int s = 128; s; s >>= 1) {
            if (tid < s) {
                float ov = rv[tid + s]; int oi = ri[tid + s];
                if (ov > rv[tid] || (ov == rv[tid] && oi < ri[tid])) { rv[tid] = ov; ri[tid] = oi; }
            }
            __syncthreads();
        }
        if (tid == 0) {
            ids[it] = ri[0];
            vals[ri[0]] = -1e30f;
            if (idx_out) idx_out[b * 17 + it] = ri[0];
        }
        __syncthreads();
    }
    for (int d = tid; d < 512; d += 256) {
        float s = 0.f;
        for (int j = 0; j < 17; j++) s += feats[((size_t)b * 256 + ids[j]) * 512 + d];
        meanv[b * 512 + d] = s * (1.f / 17.f);
    }
}

__device__ __forceinline__ float wsum(float v)
{
#pragma unroll
    for (int o = 16; o; o >>= 1) v += __shfl_xor_sync(0xffffffffu, v, o);
    return v;
}

__global__ void __launch_bounds__(1024) triplet_cos_kernel(const float* __restrict__ anchor,
                                                           const float* __restrict__ pos,
                                                           const float* __restrict__ neg,
                                                           float* __restrict__ trip_out,
                                                           float* __restrict__ cos_out)
{
    __shared__ float st[32], sc[32];
    const int w = threadIdx.x >> 5, lane = threadIdx.x & 31;
    float sa = 0, sp = 0, sn = 0, dan = 0;
    for (int d = lane; d < 512; d += 32) {
        float a = anchor[w * 512 + d], p = pos[w * 512 + d], n = neg[w * 512 + d];
        sa += a * a; sp += p * p; sn += n * n; dan += a * n;
    }
    sa = wsum(sa); sp = wsum(sp); sn = wsum(sn); dan = wsum(dan);
    float na = sqrtf(sa), npp = sqrtf(sp), ng = sqrtf(sn);
    float ina = 1.f / na, inp = 1.f / npp, ing = 1.f / ng;
    float dp2 = 0, dn2 = 0;
    for (int d = lane; d < 512; d += 32) {
        float a  = anchor[w * 512 + d] * ina;
        float dpv = a - pos[w * 512 + d] * inp + 1e-6f;
        float dnv = a - neg[w * 512 + d] * ing + 1e-6f;
        dp2 += dpv * dpv; dn2 += dnv * dnv;
    }
    dp2 = wsum(dp2); dn2 = wsum(dn2);
    if (lane == 0) {
        st[w] = fmaxf(sqrtf(dp2) - sqrtf(dn2) + 1.f, 0.f);
        sc[w] = 1.f - dan / (fmaxf(na, 1e-6f) * fmaxf(ng, 1e-6f));
    }
    __syncthreads();
    if (threadIdx.x == 0) {
        float a = 0, c = 0;
        for (int i = 0; i < 32; i++) { a += st[i]; c += sc[i]; }
        trip_out[0] = a * (1.f / 32.f);
        cos_out[0]  = c * (1.f / 32.f);
    }
}

__global__ void __launch_bounds__(1024) distance_kernel(const float* __restrict__ anew,
                                                        const float* __restrict__ nnew,
                                                        float* __restrict__ out)
{
    __shared__ float sd[32];
    const int w = threadIdx.x >> 5, lane = threadIdx.x & 31;
    float sa = 0, sn = 0;
    for (int d = lane; d < 512; d += 32) {
        float a = anew[w * 512 + d], n = nnew[w * 512 + d];
        sa += a * a; sn += n * n;
    }
    sa = wsum(sa); sn = wsum(sn);
    if (lane == 0) sd[w] = fmaxf(100.f - sqrtf(sn) + sqrtf(sa), 0.f);
    __syncthreads();
    if (threadIdx.x == 0) {
        float s = 0;
        for (int i = 0; i < 32; i++) s += sd[i];
        out[0] = s * (1.f / 32.f);
    }
}

__global__ void vae_kernel(const float* __restrict__ mu, const float* __restrict__ var,
                           const float* __restrict__ eps, float* __restrict__ o, int n)
{
    for (int i = blockIdx.x * blockDim.x + threadIdx.x; i < n; i += gridDim.x * blockDim.x)
        o[i] = mu[i] + eps[i] * sqrtf(expf(var[i]));
}

__global__ void __launch_bounds__(256) kl_part_kernel(const float* __restrict__ mu,
                                                      const float* __restrict__ var,
                                                      float* __restrict__ part, int n)
{
    __shared__ float red[256];
    float s = 0.f;
    for (int i = blockIdx.x * 256 + threadIdx.x; i < n; i += gridDim.x * 256) {
        float m = mu[i], v = var[i];
        s += 1.f + v - m * m - expf(v);
    }
    red[threadIdx.x] = s; __syncthreads();
    for (int t = 128; t; t >>= 1) { if (threadIdx.x < t) red[threadIdx.x] += red[threadIdx.x + t]; __syncthreads(); }
    if (threadIdx.x == 0) part[blockIdx.x] = red[0];
}

__global__ void __launch_bounds__(1024) kl_final_kernel(const float* __restrict__ part,
                                                        float* __restrict__ out)
{
    __shared__ float red[1024];
    red[threadIdx.x] = part[threadIdx.x]; __syncthreads();
    for (int t = 512; t; t >>= 1) { if (threadIdx.x < t) red[threadIdx.x] += red[threadIdx.x + t]; __syncthreads(); }
    if (threadIdx.x == 0) out[0] = -0.5f * red[0] * (1.f / 16384.f);
}

__global__ void __launch_bounds__(512) gather_mean_kernel(const float* __restrict__ src,
                                                          const int* __restrict__ idx,
                                                          float* __restrict__ out)
{
    __shared__ int ids[17];
    const int b = blockIdx.x, tid = threadIdx.x;
    if (tid < 17) ids[tid] = idx[b * 17 + tid];
    __syncthreads();
    float s = 0.f;
    for (int j = 0; j < 17; j++) s += src[((size_t)b * 256 + ids[j]) * 512 + tid];
    out[b * 512 + tid] = s * (1.f / 17.f);
}

__global__ void xout_kernel(const float* __restrict__ h, const float* __restrict__ nnew,
                            const float* __restrict__ anm, const float* __restrict__ anew,
                            const float* __restrict__ nam, float* __restrict__ xout)
{
    const int n = 64 * 256 * 1024;
    for (int i = blockIdx.x * blockDim.x + threadIdx.x; i < n; i += gridDim.x * blockDim.x) {
        int c  = i & 1023;
        int rt = i >> 10;
        float v;
        if (c < 512) v = h[(size_t)rt * 512 + c];
        else {
            int cc = c - 512;
            if (rt < 8192) v = nnew[(size_t)rt * 512 + cc] + anm[(size_t)rt * 512 + cc];
            else {
                size_t o = (size_t)(rt - 8192) * 512 + cc;
                v = anew[o] + nam[o];
            }
        }
        xout[i] = v;
    }
}

__global__ void vfeat_kernel(const float* __restrict__ h, float* __restrict__ v)
{
    __shared__ float tile[32][33];
    const int b = blockIdx.x, d0 = blockIdx.y * 32, t0 = blockIdx.z * 32;
    for (int r = threadIdx.y; r < 32; r += 8)
        tile[r][threadIdx.x] = h[((size_t)b * 256 + t0 + r) * 512 + d0 + threadIdx.x];
    __syncthreads();
    for (int r = threadIdx.y; r < 32; r += 8)
        v[((size_t)b * 512 + d0 + r) * 256 + t0 + threadIdx.x] = tile[threadIdx.x][r];
}

// ===========================================================================
extern "C" void kernel_launch(void* const* d_in, const int* in_sizes, int n_in,
                              void* d_out, int out_size)
{
    const float* x      = (const float*)d_in[0];
    const float* eps_in = (const float*)d_in[1];
    const float* conv_w = (const float*)d_in[2];
    const float* conv_b = (const float*)d_in[3];
    const float* ln1_g  = (const float*)d_in[4];
    const float* ln1_b  = (const float*)d_in[5];
    const float* qkv_w  = (const float*)d_in[6];
    const float* out_w  = (const float*)d_in[7];
    const float* out_b  = (const float*)d_in[8];
    const float* ln2_g  = (const float*)d_in[9];
    const float* ln2_b  = (const float*)d_in[10];
    const float* ff1_w  = (const float*)d_in[11];
    const float* ff1_b  = (const float*)d_in[12];
    const float* ff2_w  = (const float*)d_in[13];
    const float* ff2_b  = (const float*)d_in[14];
    const float* a_mem  = (const float*)d_in[15];
    const float* n_mem  = (const float*)d_in[16];
    const float* mu_w   = (const float*)d_in[17];
    const float* mu_b   = (const float*)d_in[18];
    const float* var_w  = (const float*)d_in[19];
    const float* var_b  = (const float*)d_in[20];
    float* out = (float*)d_out;

    float* S = nullptr;
    cudaGetSymbolAddress((void**)&S, g_scratch);
    __nv_bfloat16* BF = nullptr;
    cudaGetSymbolAddress((void**)&BF, g_bf);

    float* h     = S + OFF_H;
    float* sc    = S + OFF_SC;
    float* stack = S + OFF_STACK;
    float* Anew  = stack;
    float* NAm   = stack + 1ull * 8192 * 512;
    float* ANm   = stack + 2ull * 8192 * 512;
    float* muB   = stack + 3ull * 8192 * 512;
    float* varB  = S + OFF_VAR;
    float* newN  = S + OFF_NEW;
    float* anch  = S + OFF_ANCH;
    float* negv  = S + OFF_NEG;
    float* posv  = S + OFF_POS;
    float* anchN = S + OFF_ANCHN;
    float* negN  = S + OFF_NEGN;
    int*   idxA  = (int*)(S + OFF_IDXA);
    int*   idxN  = (int*)(S + OFF_IDXN);
    float* klp   = S + OFF_KLP;

    __nv_bfloat16* lnh = BF + B_LNH;  __nv_bfloat16* lnl = BF + B_LNL;
    __nv_bfloat16* aoh = BF + B_AOH;  __nv_bfloat16* aol = BF + B_AOL;
    __nv_bfloat16* ffh = BF + B_FFH;  __nv_bfloat16* ffl = BF + B_FFL;
    __nv_bfloat16* qkvh = BF + B_QKVH; __nv_bfloat16* qkvl = BF + B_QKVL;
    __nv_bfloat16* ph = BF + B_PH;     __nv_bfloat16* pl = BF + B_PL;
    __nv_bfloat16* vth = BF + B_VTH;   __nv_bfloat16* vtl = BF + B_VTL;

    // ---- weight prep
    convprep<<<1024, 256>>>(conv_w, BF + B_CNVWH, BF + B_CNVWL);
    for (int i = 0; i < 2; i++) {
        wprep_t<<<dim3(16, 48), dim3(32, 8)>>>(qkv_w + (size_t)i * 786432,
                                               BF + B_QKVWH + (size_t)i * 786432,
                                               BF + B_QKVWL + (size_t)i * 786432, 512, 1536);
        wprep_t<<<dim3(16, 16), dim3(32, 8)>>>(out_w + (size_t)i * 262144,
                                               BF + B_OUTWH + (size_t)i * 262144,
                                               BF + B_OUTWL + (size_t)i * 262144, 512, 512);
        wprep_t<<<dim3(16, 16), dim3(32, 8)>>>(ff1_w + (size_t)i * 262144,
                                               BF + B_FF1WH + (size_t)i * 262144,
                                               BF + B_FF1WL + (size_t)i * 262144, 512, 512);
        wprep_t<<<dim3(16, 16), dim3(32, 8)>>>(ff2_w + (size_t)i * 262144,
                                               BF + B_FF2WH + (size_t)i * 262144,
                                               BF + B_FF2WL + (size_t)i * 262144, 512, 512);
    }
    wprep_t<<<dim3(16, 16), dim3(32, 8)>>>(mu_w,  BF + B_MUWH,  BF + B_MUWL,  512, 512);
    wprep_t<<<dim3(16, 16), dim3(32, 8)>>>(var_w, BF + B_VARWH, BF + B_VARWL, 512, 512);

    // ---- conv (implicit im2col, relu+bias)
    mgemm<4, true><<<dim3(4, 128), 256>>>(
        nullptr, nullptr, x, BF + B_CNVWH, BF + B_CNVWL,
        h, nullptr, nullptr, conv_b, 16384, 512, 3072);

    // ---- transformer x2
    for (int i = 0; i < 2; i++) {
        ln_kernel<<<16384, 256>>>(h, ln1_g + i * 512, ln1_b + i * 512, lnh, lnl);
        mgemm<5, false><<<dim3(12, 128), 256>>>(
            lnh, lnl, nullptr, BF + B_QKVWH + (size_t)i * 786432, BF + B_QKVWL + (size_t)i * 786432,
            nullptr, qkvh, qkvl, nullptr, 16384, 1536, 512);
        vtrans_kernel<<<dim3(256, 4, 8), dim3(32, 8)>>>(qkvh, qkvl, vth, vtl);
        bqk_kernel<<<dim3(2, 2, 256), 256>>>(qkvh, qkvl, sc);
        softmaxp_kernel<<<8192, 256>>>(sc, ph, pl);
        bpv_kernel<<<dim3(2, 1, 256), 256>>>(ph, pl, vth, vtl, aoh, aol);
        mgemm<2, false><<<dim3(4, 128), 256>>>(
            aoh, aol, nullptr, BF + B_OUTWH + (size_t)i * 262144, BF + B_OUTWL + (size_t)i * 262144,
            h, nullptr, nullptr, out_b + i * 512, 16384, 512, 512);
        ln_kernel<<<16384, 256>>>(h, ln2_g + i * 512, ln2_b + i * 512, lnh, lnl);
        mgemm<3, false><<<dim3(4, 128), 256>>>(
            lnh, lnl, nullptr, BF + B_FF1WH + (size_t)i * 262144, BF + B_FF1WL + (size_t)i * 262144,
            nullptr, ffh, ffl, ff1_b + i * 512, 16384, 512, 512);
        mgemm<2, false><<<dim3(4, 128), 256>>>(
            ffh, ffl, nullptr, BF + B_FF2WH + (size_t)i * 262144, BF + B_FF2WL + (size_t)i * 262144,
            h, nullptr, nullptr, ff2_b + i * 512, 16384, 512, 512);
    }

    const float* Nx = h;                       // x_emb[:32]
    const float* Ax = h + (size_t)8192 * 512;  // x_emb[32:]

    // memory attention, 4 combos in one launch
    memory_kernel<<<dim3(8192, 4), 512>>>(Nx, Ax, a_mem, n_mem,
                                          out + O_AATT, BF + B_AUGH, BF + B_AUGL);

    topk_gather<<<32, 256>>>(out + O_AATT,  Ax, negv, idxA);
    topk_gather<<<32, 256>>>(out + O_NATT,  Nx, anch, idxN);
    topk_gather<<<32, 256>>>(out + O_NAATT, Ax, posv, nullptr);

    triplet_cos_kernel<<<1, 1024>>>(anch, posv, negv, out + O_TRIP, out + O_COS);

    // stacked mu projection: [augA; augNA; augAN; augN] @ mu -> [Anew; NAm; ANm; muB]
    mgemm<1, false><<<dim3(4, 256), 256>>>(
        BF + B_AUGH, BF + B_AUGL, nullptr, BF + B_MUWH, BF + B_MUWL,
        stack, nullptr, nullptr, mu_b, 32768, 512, 512);
    // augN @ var -> varB
    mgemm<1, false><<<dim3(4, 64), 256>>>(
        BF + B_AUGH + 3 * SZ_AUG, BF + B_AUGL + 3 * SZ_AUG, nullptr,
        BF + B_VARWH, BF + B_VARWL, varB, nullptr, nullptr, var_b, 8192, 512, 512);

    vae_kernel<<<4096, 256>>>(muB, varB, eps_in, newN, 8192 * 512);
    kl_part_kernel<<<1024, 256>>>(muB, varB, klp, 8192 * 512);
    kl_final_kernel<<<1, 1024>>>(klp, out + O_KL);

    gather_mean_kernel<<<32, 512>>>(newN, idxN, anchN);
    gather_mean_kernel<<<32, 512>>>(Anew, idxA, negN);
    distance_kernel<<<1, 1024>>>(anchN, negN, out + O_DIST);

    xout_kernel<<<8192, 256>>>(h, newN, ANm, Anew, NAm, out + O_XOUT);
    vfeat_kernel<<<dim3(64, 16, 8), dim3(32, 8)>>>(h, out + O_VFEAT);
}

// round 5
// speedup vs baseline: 2.8313x; 1.1125x over previous
#include <cuda_runtime.h>
#include <cuda_bf16.h>
#include <math.h>
#include <stdint.h>

// ===========================================================================
// fp32 scratch
// ===========================================================================
constexpr size_t OFF_H     = 0;                         // 16384*512
constexpr size_t OFF_SC    = 8388608;                   // 256*256*256 (S fp32)
constexpr size_t OFF_STACK = OFF_SC + 16777216;         // 32768*512: Anew,NAm,ANm,muB
constexpr size_t OFF_VAR   = OFF_STACK + 16777216;      // 8192*512
constexpr size_t OFF_NEW   = OFF_VAR + 4194304;         // 8192*512
constexpr size_t OFF_ANCH  = OFF_NEW + 4194304;         // 32*512 each below
constexpr size_t OFF_NEG   = OFF_ANCH + 16384;
constexpr size_t OFF_POS   = OFF_NEG  + 16384;
constexpr size_t OFF_ANCHN = OFF_POS  + 16384;
constexpr size_t OFF_NEGN  = OFF_ANCHN + 16384;
constexpr size_t OFF_IDXA  = OFF_NEGN + 16384;
constexpr size_t OFF_IDXN  = OFF_IDXA + 1024;
constexpr size_t OFF_KLP   = OFF_IDXN + 1024;
constexpr size_t SCRATCH_TOTAL = OFF_KLP + 1024;
__device__ float g_scratch[SCRATCH_TOTAL];

// ===========================================================================
// bf16 scratch
// ===========================================================================
constexpr size_t SZ_TOK  = 16384ull * 512;
constexpr size_t SZ_QKV  = 16384ull * 1536;
constexpr size_t SZ_P    = 256ull * 65536;
constexpr size_t SZ_VT   = 256ull * 32768;
constexpr size_t SZ_AUG  = 8192ull * 512;

constexpr size_t B_LNH  = 0;
constexpr size_t B_LNL  = B_LNH + SZ_TOK;
constexpr size_t B_AOH  = B_LNL + SZ_TOK;
constexpr size_t B_AOL  = B_AOH + SZ_TOK;
constexpr size_t B_FFH  = B_AOL + SZ_TOK;
constexpr size_t B_FFL  = B_FFH + SZ_TOK;
constexpr size_t B_QKVH = B_FFL + SZ_TOK;
constexpr size_t B_QKVL = B_QKVH + SZ_QKV;
constexpr size_t B_PH   = B_QKVL + SZ_QKV;
constexpr size_t B_PL   = B_PH + SZ_P;
constexpr size_t B_VTH  = B_PL + SZ_P;
constexpr size_t B_VTL  = B_VTH + SZ_VT;
constexpr size_t B_AUGH = B_VTL + SZ_VT;      // [A, NA, AN, N] stacked
constexpr size_t B_AUGL = B_AUGH + 4 * SZ_AUG;
constexpr size_t B_QKVWH = B_AUGL + 4 * SZ_AUG;
constexpr size_t B_QKVWL = B_QKVWH + 2ull * 786432;
constexpr size_t B_OUTWH = B_QKVWL + 2ull * 786432;
constexpr size_t B_OUTWL = B_OUTWH + 2ull * 262144;
constexpr size_t B_FF1WH = B_OUTWL + 2ull * 262144;
constexpr size_t B_FF1WL = B_FF1WH + 2ull * 262144;
constexpr size_t B_FF2WH = B_FF1WL + 2ull * 262144;
constexpr size_t B_FF2WL = B_FF2WH + 2ull * 262144;
constexpr size_t B_MUWH  = B_FF2WL + 2ull * 262144;
constexpr size_t B_MUWL  = B_MUWH + 262144;
constexpr size_t B_VARWH = B_MUWL + 262144;
constexpr size_t B_VARWL = B_VARWH + 262144;
constexpr size_t B_CNVWH = B_VARWL + 262144;
constexpr size_t B_CNVWL = B_CNVWH + 1572864;
constexpr size_t BF_TOTAL = B_CNVWL + 1572864;
__device__ __nv_bfloat16 g_bf[BF_TOTAL];

// output offsets (triplet, kl, distance, A_att, N_att, A_Natt, N_Aatt, cos, x_out, v_feat)
constexpr size_t O_TRIP  = 0;
constexpr size_t O_KL    = 1;
constexpr size_t O_DIST  = 2;
constexpr size_t O_AATT  = 3;
constexpr size_t O_NATT  = 3 + 8192;
constexpr size_t O_ANATT = 3 + 16384;
constexpr size_t O_NAATT = 3 + 24576;
constexpr size_t O_COS   = 3 + 32768;
constexpr size_t O_XOUT  = 4 + 32768;
constexpr size_t O_VFEAT = O_XOUT + 64ull * 256 * 1024;

// ===========================================================================
// mma / smem helpers
// ===========================================================================
__device__ __forceinline__ void mma16816(float* c, const uint32_t* a, const uint32_t* b)
{
    asm volatile(
        "mma.sync.aligned.m16n8k16.row.col.f32.bf16.bf16.f32 "
        "{%0,%1,%2,%3}, {%4,%5,%6,%7}, {%8,%9}, {%0,%1,%2,%3};"
        : "+f"(c[0]), "+f"(c[1]), "+f"(c[2]), "+f"(c[3])
        : "r"(a[0]), "r"(a[1]), "r"(a[2]), "r"(a[3]), "r"(b[0]), "r"(b[1]));
}

__device__ __forceinline__ void split2(float v, __nv_bfloat16& h, __nv_bfloat16& l) {
    h = __float2bfloat16(v);
    l = __float2bfloat16(v - __bfloat162float(h));
}

__device__ __forceinline__ uint32_t cvt_smem(const void* p) {
    uint32_t a;
    asm("{ .reg .u64 t; cvta.to.shared.u64 t, %1; cvt.u32.u64 %0, t; }" : "=r"(a) : "l"(p));
    return a;
}

#define LDSM4(r0, r1, r2, r3, a) \
    asm volatile("ldmatrix.sync.aligned.m8n8.x4.shared.b16 {%0,%1,%2,%3}, [%4];" \
        : "=r"(r0), "=r"(r1), "=r"(r2), "=r"(r3) : "r"(a))

#define CP16(sa, gp) \
    asm volatile("cp.async.cg.shared.global [%0], [%1], 16;" :: "r"(sa), "l"(gp))
#define CP_COMMIT() asm volatile("cp.async.commit_group;" ::: "memory")
#define CP_WAIT1()  asm volatile("cp.async.wait_group 1;" ::: "memory")
#define CP_WAIT0()  asm volatile("cp.async.wait_group 0;" ::: "memory")

// one stage layout (bytes): Ah @0, Al @10240, Bh @20480, Bl @30720; rows pad 40 elem (80B)
constexpr uint32_t SM_AL = 10240, SM_BH = 20480, SM_BL = 30720;
constexpr uint32_t STAGE_BYTES = 40960;

// 128x32 tile MMA: A[128x32] x B[128x32]^T contribution via ldmatrix + 3-term split
__device__ __forceinline__ void mma_tile_ldsm(uint32_t sb, float acc[4][4][4],
                                              int arow, int acolB, int brow, int bcolB)
{
#pragma unroll
    for (int ks = 0; ks < 32; ks += 16) {
        uint32_t fa[4][4], fbh[4][2], fbl[4][2];
#pragma unroll
        for (int mi = 0; mi < 4; mi++) {
            uint32_t ad = sb + (uint32_t)((arow + mi * 16) * 80 + (ks + acolB) * 2);
            LDSM4(fa[mi][0], fa[mi][1], fa[mi][2], fa[mi][3], ad);
        }
#pragma unroll
        for (int np = 0; np < 2; np++) {
            uint32_t bd = sb + SM_BH + (uint32_t)((brow + np * 16) * 80 + (ks + bcolB) * 2);
            LDSM4(fbh[np * 2][0], fbh[np * 2][1], fbh[np * 2 + 1][0], fbh[np * 2 + 1][1], bd);
            LDSM4(fbl[np * 2][0], fbl[np * 2][1], fbl[np * 2 + 1][0], fbl[np * 2 + 1][1],
                  bd + (SM_BL - SM_BH));
        }
#pragma unroll
        for (int mi = 0; mi < 4; mi++)
#pragma unroll
            for (int ni = 0; ni < 4; ni++) {
                mma16816(acc[mi][ni], fa[mi], fbh[ni]);
                mma16816(acc[mi][ni], fa[mi], fbl[ni]);
            }
#pragma unroll
        for (int mi = 0; mi < 4; mi++) {
            uint32_t ad = sb + SM_AL + (uint32_t)((arow + mi * 16) * 80 + (ks + acolB) * 2);
            LDSM4(fa[mi][0], fa[mi][1], fa[mi][2], fa[mi][3], ad);
        }
#pragma unroll
        for (int mi = 0; mi < 4; mi++)
#pragma unroll
            for (int ni = 0; ni < 4; ni++)
                mma16816(acc[mi][ni], fa[mi], fbh[ni]);
    }
}

// ===========================================================================
// HMMA GEMM with cp.async double buffering (non-conv) / sync staging (conv)
// EPI: 0=none,1=+bias,2=+bias+residual,3=+bias+gelu->pair,4=+bias+relu,5=->pair
// ===========================================================================
template<int EPI, bool CONV>
__global__ void __launch_bounds__(256, 2) mgemm(
    const __nv_bfloat16* __restrict__ Ah, const __nv_bfloat16* __restrict__ Al,
    const float* __restrict__ Xc,
    const __nv_bfloat16* __restrict__ Bh, const __nv_bfloat16* __restrict__ Bl,
    float* __restrict__ C,
    __nv_bfloat16* __restrict__ Chi, __nv_bfloat16* __restrict__ Clo,
    const float* __restrict__ bias,
    int M, int N, int K)
{
    extern __shared__ char smem[];
    const int tid  = threadIdx.x;
    const int wid  = tid >> 5;
    const int lane = tid & 31;
    const int g = lane >> 2, t = lane & 3;
    const int wm = wid >> 2, wn = wid & 3;
    const int row0 = blockIdx.y * 128;
    const int col0 = blockIdx.x * 128;
    const uint32_t sb0 = cvt_smem(smem);

    const int arow  = wm * 64 + (lane & 7) + ((lane >> 3) & 1) * 8;
    const int acolB = ((lane >> 4) & 1) * 8;
    const int brow  = wn * 32 + ((lane >> 4) & 1) * 8 + (lane & 7);
    const int bcolB = ((lane >> 3) & 1) * 8;

    float acc[4][4][4];
#pragma unroll
    for (int mi = 0; mi < 4; mi++)
#pragma unroll
        for (int ni = 0; ni < 4; ni++)
#pragma unroll
            for (int q = 0; q < 4; q++) acc[mi][ni][q] = 0.f;

    const int nchunks = K >> 5;

    if (!CONV) {
#pragma unroll
        for (int i = 0; i < 2; i++) {
            int chunk = tid * 2 + i;
            int rr = chunk >> 2, sg = chunk & 3;
            uint32_t so = (uint32_t)(rr * 80 + sg * 16);
            size_t oa = (size_t)(row0 + rr) * K + sg * 8;
            size_t ob = (size_t)(col0 + rr) * K + sg * 8;
            CP16(sb0 + so,         Ah + oa);
            CP16(sb0 + SM_AL + so, Al + oa);
            CP16(sb0 + SM_BH + so, Bh + ob);
            CP16(sb0 + SM_BL + so, Bl + ob);
        }
        CP_COMMIT();
    }

    for (int kc = 0; kc < nchunks; kc++) {
        const uint32_t sb = sb0 + (CONV ? 0u : (uint32_t)(kc & 1) * STAGE_BYTES);
        if (CONV) {
#pragma unroll
            for (int i = 0; i < 2; i++) {
                int chunk = tid * 2 + i;
                int rr = chunk >> 2, sg = chunk & 3;
                uint32_t so = (uint32_t)(rr * 80 + sg * 16);
                int gk = kc * 32 + sg * 8;
                int tap = gk >> 10, ci = gk & 1023;
                int m = row0 + rr;
                int t2 = (m & 255) + tap - 1;
                uint4 hi4, lo4;
                if (t2 >= 0 && t2 < 256) {
                    const float* src = Xc + ((size_t)((m >> 8) * 256 + t2)) * 1024 + ci;
                    float4 f0 = *(const float4*)src;
                    float4 f1 = *(const float4*)(src + 4);
                    float f[8] = {f0.x, f0.y, f0.z, f0.w, f1.x, f1.y, f1.z, f1.w};
                    __nv_bfloat16 hb[8], lb[8];
#pragma unroll
                    for (int q = 0; q < 8; q++) split2(f[q], hb[q], lb[q]);
                    hi4 = *(uint4*)hb; lo4 = *(uint4*)lb;
                } else {
                    hi4 = make_uint4(0, 0, 0, 0); lo4 = hi4;
                }
                *(uint4*)(smem + so) = hi4;
                *(uint4*)(smem + SM_AL + so) = lo4;
                size_t ob = (size_t)(col0 + rr) * K + kc * 32 + sg * 8;
                *(uint4*)(smem + SM_BH + so) = *(const uint4*)(Bh + ob);
                *(uint4*)(smem + SM_BL + so) = *(const uint4*)(Bl + ob);
            }
            __syncthreads();
        } else {
            if (kc + 1 < nchunks) {
                const uint32_t sn = sb0 + (uint32_t)((kc + 1) & 1) * STAGE_BYTES;
#pragma unroll
                for (int i = 0; i < 2; i++) {
                    int chunk = tid * 2 + i;
                    int rr = chunk >> 2, sg = chunk & 3;
                    uint32_t so = (uint32_t)(rr * 80 + sg * 16);
                    size_t oa = (size_t)(row0 + rr) * K + (kc + 1) * 32 + sg * 8;
                    size_t ob = (size_t)(col0 + rr) * K + (kc + 1) * 32 + sg * 8;
                    CP16(sn + so,         Ah + oa);
                    CP16(sn + SM_AL + so, Al + oa);
                    CP16(sn + SM_BH + so, Bh + ob);
                    CP16(sn + SM_BL + so, Bl + ob);
                }
                CP_COMMIT();
                CP_WAIT1();
            } else {
                CP_WAIT0();
            }
            __syncthreads();
        }

        mma_tile_ldsm(sb, acc, arow, acolB, brow, bcolB);
        __syncthreads();
    }

#pragma unroll
    for (int mi = 0; mi < 4; mi++) {
#pragma unroll
        for (int ni = 0; ni < 4; ni++) {
#pragma unroll
            for (int q = 0; q < 4; q++) {
                int r = row0 + wm * 64 + mi * 16 + g + (q >> 1) * 8;
                int c = col0 + wn * 32 + ni * 8 + t * 2 + (q & 1);
                float v = acc[mi][ni][q];
                size_t o = (size_t)r * N + c;
                if (EPI != 0 && EPI != 5) v += bias[c];
                if (EPI == 2) v += C[o];
                if (EPI == 3 || EPI == 5) {
                    if (EPI == 3) v = 0.5f * v * (1.f + erff(v * 0.70710678118654752f));
                    __nv_bfloat16 hb, lb; split2(v, hb, lb);
                    Chi[o] = hb; Clo[o] = lb;
                } else {
                    if (EPI == 4) v = fmaxf(v, 0.f);
                    C[o] = v;
                }
            }
        }
    }
}

// ===========================================================================
// Batched QK^T  (static 40KB single-stage, ldmatrix core)
// ===========================================================================
__global__ void __launch_bounds__(256, 2) bqk_kernel(
    const __nv_bfloat16* __restrict__ Qh, const __nv_bfloat16* __restrict__ Ql,
    float* __restrict__ S)
{
    __shared__ alignas(16) char smem[40960];
    const int tid  = threadIdx.x;
    const int wid  = tid >> 5;
    const int lane = tid & 31;
    const int g = lane >> 2, t = lane & 3;
    const int wm = wid >> 2, wn = wid & 3;
    const int bh = blockIdx.z, b = bh >> 2, h = bh & 3;
    const int i0 = blockIdx.x * 128, j0 = blockIdx.y * 128;
    const __nv_bfloat16* Ah = Qh + (size_t)b * 256 * 1536 + h * 128;
    const __nv_bfloat16* Al = Ql + (size_t)b * 256 * 1536 + h * 128;
    const uint32_t sb = cvt_smem(smem);

    const int arow  = wm * 64 + (lane & 7) + ((lane >> 3) & 1) * 8;
    const int acolB = ((lane >> 4) & 1) * 8;
    const int brow  = wn * 32 + ((lane >> 4) & 1) * 8 + (lane & 7);
    const int bcolB = ((lane >> 3) & 1) * 8;

    float acc[4][4][4];
#pragma unroll
    for (int mi = 0; mi < 4; mi++)
#pragma unroll
        for (int ni = 0; ni < 4; ni++)
#pragma unroll
            for (int q = 0; q < 4; q++) acc[mi][ni][q] = 0.f;

    for (int kc = 0; kc < 4; kc++) {
#pragma unroll
        for (int i = 0; i < 2; i++) {
            int chunk = tid * 2 + i;
            int rr = chunk >> 2, sg = chunk & 3;
            uint32_t so = (uint32_t)(rr * 80 + sg * 16);
            size_t oa = (size_t)(i0 + rr) * 1536 + kc * 32 + sg * 8;
            size_t ob = (size_t)(j0 + rr) * 1536 + 512 + kc * 32 + sg * 8;
            *(uint4*)(smem + so)         = *(const uint4*)(Ah + oa);
            *(uint4*)(smem + SM_AL + so) = *(const uint4*)(Al + oa);
            *(uint4*)(smem + SM_BH + so) = *(const uint4*)(Ah + ob);
            *(uint4*)(smem + SM_BL + so) = *(const uint4*)(Al + ob);
        }
        __syncthreads();
        mma_tile_ldsm(sb, acc, arow, acolB, brow, bcolB);
        __syncthreads();
    }

    float* so2 = S + (size_t)bh * 65536;
    const float scale = 0.08838834764831845f;
#pragma unroll
    for (int mi = 0; mi < 4; mi++)
#pragma unroll
        for (int ni = 0; ni < 4; ni++)
#pragma unroll
            for (int q = 0; q < 4; q++) {
                int r = i0 + wm * 64 + mi * 16 + g + (q >> 1) * 8;
                int c = j0 + wn * 32 + ni * 8 + t * 2 + (q & 1);
                so2[(size_t)r * 256 + c] = acc[mi][ni][q] * scale;
            }
}

// row softmax -> bf16 pair
__global__ void __launch_bounds__(256) softmaxp_kernel(const float* __restrict__ S,
                                                       __nv_bfloat16* __restrict__ Ph,
                                                       __nv_bfloat16* __restrict__ Pl)
{
    const int row  = blockIdx.x * 8 + (threadIdx.x >> 5);
    const int lane = threadIdx.x & 31;
    const float* p = S + (size_t)row * 256;
    float v[8]; float mx = -1e30f;
#pragma unroll
    for (int j = 0; j < 8; j++) { v[j] = p[lane + 32 * j]; mx = fmaxf(mx, v[j]); }
#pragma unroll
    for (int o = 16; o; o >>= 1) mx = fmaxf(mx, __shfl_xor_sync(0xffffffffu, mx, o));
    float s = 0.f;
#pragma unroll
    for (int j = 0; j < 8; j++) { v[j] = expf(v[j] - mx); s += v[j]; }
#pragma unroll
    for (int o = 16; o; o >>= 1) s += __shfl_xor_sync(0xffffffffu, s, o);
    const float inv = 1.f / s;
#pragma unroll
    for (int j = 0; j < 8; j++) {
        __nv_bfloat16 hb, lb; split2(v[j] * inv, hb, lb);
        Ph[(size_t)row * 256 + lane + 32 * j] = hb;
        Pl[(size_t)row * 256 + lane + 32 * j] = lb;
    }
}

// V transpose
__global__ void vtrans_kernel(const __nv_bfloat16* __restrict__ Vh,
                              const __nv_bfloat16* __restrict__ Vl,
                              __nv_bfloat16* __restrict__ vth,
                              __nv_bfloat16* __restrict__ vtl)
{
    __shared__ __nv_bfloat16 th[32][33], tl[32][33];
    const int bh = blockIdx.x, b = bh >> 2, h = bh & 3;
    const int d0 = blockIdx.y * 32, j0 = blockIdx.z * 32;
    const int tx = threadIdx.x, ty = threadIdx.y;
    const size_t base = (size_t)b * 256 * 1536 + 1024 + h * 128;
    for (int r = ty; r < 32; r += 8) {
        size_t o = base + (size_t)(j0 + r) * 1536 + d0 + tx;
        th[r][tx] = Vh[o]; tl[r][tx] = Vl[o];
    }
    __syncthreads();
    const size_t obase = (size_t)bh * 32768;
    for (int r = ty; r < 32; r += 8) {
        size_t o = obase + (size_t)(d0 + r) * 256 + j0 + tx;
        vth[o] = th[tx][r]; vtl[o] = tl[tx][r];
    }
}

// Batched PV
__global__ void __launch_bounds__(256, 2) bpv_kernel(
    const __nv_bfloat16* __restrict__ Ph, const __nv_bfloat16* __restrict__ Pl,
    const __nv_bfloat16* __restrict__ vth, const __nv_bfloat16* __restrict__ vtl,
    __nv_bfloat16* __restrict__ Oh, __nv_bfloat16* __restrict__ Ol)
{
    __shared__ alignas(16) char smem[40960];
    const int tid  = threadIdx.x;
    const int wid  = tid >> 5;
    const int lane = tid & 31;
    const int g = lane >> 2, t = lane & 3;
    const int wm = wid >> 2, wn = wid & 3;
    const int bh = blockIdx.z, b = bh >> 2, h = bh & 3;
    const int i0 = blockIdx.x * 128;
    const __nv_bfloat16* Ah = Ph + (size_t)bh * 65536 + (size_t)i0 * 256;
    const __nv_bfloat16* Al = Pl + (size_t)bh * 65536 + (size_t)i0 * 256;
    const __nv_bfloat16* Bh = vth + (size_t)bh * 32768;
    const __nv_bfloat16* Bl = vtl + (size_t)bh * 32768;
    const uint32_t sb = cvt_smem(smem);

    const int arow  = wm * 64 + (lane & 7) + ((lane >> 3) & 1) * 8;
    const int acolB = ((lane >> 4) & 1) * 8;
    const int brow  = wn * 32 + ((lane >> 4) & 1) * 8 + (lane & 7);
    const int bcolB = ((lane >> 3) & 1) * 8;

    float acc[4][4][4];
#pragma unroll
    for (int mi = 0; mi < 4; mi++)
#pragma unroll
        for (int ni = 0; ni < 4; ni++)
#pragma unroll
            for (int q = 0; q < 4; q++) acc[mi][ni][q] = 0.f;

    for (int kc = 0; kc < 8; kc++) {
#pragma unroll
        for (int i = 0; i < 2; i++) {
            int chunk = tid * 2 + i;
            int rr = chunk >> 2, sg = chunk & 3;
            uint32_t so = (uint32_t)(rr * 80 + sg * 16);
            size_t oa = (size_t)rr * 256 + kc * 32 + sg * 8;
            *(uint4*)(smem + so)         = *(const uint4*)(Ah + oa);
            *(uint4*)(smem + SM_AL + so) = *(const uint4*)(Al + oa);
            *(uint4*)(smem + SM_BH + so) = *(const uint4*)(Bh + oa);
            *(uint4*)(smem + SM_BL + so) = *(const uint4*)(Bl + oa);
        }
        __syncthreads();
        mma_tile_ldsm(sb, acc, arow, acolB, brow, bcolB);
        __syncthreads();
    }

#pragma unroll
    for (int mi = 0; mi < 4; mi++)
#pragma unroll
        for (int ni = 0; ni < 4; ni++)
#pragma unroll
            for (int q = 0; q < 4; q++) {
                int r = i0 + wm * 64 + mi * 16 + g + (q >> 1) * 8;
                int c = wn * 32 + ni * 8 + t * 2 + (q & 1);
                size_t o = ((size_t)b * 256 + r) * 512 + h * 128 + c;
                __nv_bfloat16 hb, lb; split2(acc[mi][ni][q], hb, lb);
                Oh[o] = hb; Ol[o] = lb;
            }
}

// ===========================================================================
// Weight prep
// ===========================================================================
__global__ void wprep_t(const float* __restrict__ W, __nv_bfloat16* __restrict__ Wh,
                        __nv_bfloat16* __restrict__ Wl, int K, int N)
{
    __shared__ float tile[32][33];
    const int k0 = blockIdx.x * 32, n0 = blockIdx.y * 32;
    const int tx = threadIdx.x, ty = threadIdx.y;
    for (int r = ty; r < 32; r += 8)
        tile[r][tx] = W[(size_t)(k0 + r) * N + n0 + tx];
    __syncthreads();
    for (int r = ty; r < 32; r += 8) {
        float v = tile[tx][r];
        size_t o = (size_t)(n0 + r) * K + k0 + tx;
        __nv_bfloat16 hb, lb; split2(v, hb, lb);
        Wh[o] = hb; Wl[o] = lb;
    }
}

__global__ void convprep(const float* __restrict__ w, __nv_bfloat16* __restrict__ Wh,
                         __nv_bfloat16* __restrict__ Wl)
{
    const int n = 512 * 3072;
    for (int idx = blockIdx.x * blockDim.x + threadIdx.x; idx < n; idx += gridDim.x * blockDim.x) {
        int d = idx / 3072, k = idx % 3072;
        int tap = k >> 10, ci = k & 1023;
        float v = w[(size_t)d * 3072 + ci * 3 + tap];
        __nv_bfloat16 hb, lb; split2(v, hb, lb);
        Wh[idx] = hb; Wl[idx] = lb;
    }
}

// ===========================================================================
// LayerNorm -> bf16 hi/lo pair
// ===========================================================================
__global__ void __launch_bounds__(256) ln_kernel(const float* __restrict__ x,
                                                 const float* __restrict__ g,
                                                 const float* __restrict__ bb,
                                                 __nv_bfloat16* __restrict__ yh,
                                                 __nv_bfloat16* __restrict__ yl)
{
    __shared__ float red[256];
    const int row = blockIdx.x, tid = threadIdx.x;
    const float* xr = x + (size_t)row * 512;
    float x0 = xr[tid], x1 = xr[tid + 256];
    red[tid] = x0 + x1; __syncthreads();
    for (int s = 128; s; s >>= 1) { if (tid < s) red[tid] += red[tid + s]; __syncthreads(); }
    float mean = red[0] * (1.f / 512.f);
    __syncthreads();
    red[tid] = x0 * x0 + x1 * x1; __syncthreads();
    for (int s = 128; s; s >>= 1) { if (tid < s) red[tid] += red[tid + s]; __syncthreads(); }
    float var = red[0] * (1.f / 512.f) - mean * mean;
    float inv = rsqrtf(var + 1e-5f);
    float v0 = (x0 - mean) * inv * g[tid]       + bb[tid];
    float v1 = (x1 - mean) * inv * g[tid + 256] + bb[tid + 256];
    __nv_bfloat16 hb, lb;
    split2(v0, hb, lb); yh[(size_t)row * 512 + tid] = hb;       yl[(size_t)row * 512 + tid] = lb;
    split2(v1, hb, lb); yh[(size_t)row * 512 + tid + 256] = hb; yl[(size_t)row * 512 + tid + 256] = lb;
}

// ===========================================================================
// Memory attention (batched over 4 combos via grid.y)
// ===========================================================================
__global__ void __launch_bounds__(512) memory_kernel(const float* __restrict__ Nx,
                                                     const float* __restrict__ Ax,
                                                     const float* __restrict__ a_mem,
                                                     const float* __restrict__ n_mem,
                                                     float* __restrict__ att_base,
                                                     __nv_bfloat16* __restrict__ augh_base,
                                                     __nv_bfloat16* __restrict__ augl_base)
{
    __shared__ float xs[512];
    __shared__ float att[64];
    const int row = blockIdx.x, tid = threadIdx.x;
    const int combo = blockIdx.y;       // 0:A(Ax,a) 1:NA(Ax,n) 2:AN(Nx,a) 3:N(Nx,n)
    const float* x   = (combo < 2) ? Ax : Nx;
    const float* mem = (combo & 1) ? n_mem : a_mem;
    const int att_off[4] = {0, 24576, 16384, 8192};
    float* att_out = att_base + att_off[combo];
    __nv_bfloat16* augh = augh_base + (size_t)combo * SZ_AUG;
    __nv_bfloat16* augl = augl_base + (size_t)combo * SZ_AUG;

    const int w = tid >> 5, lane = tid & 31;
    xs[tid] = x[(size_t)row * 512 + tid];
    __syncthreads();
    for (int n = w; n < 60; n += 16) {
        float s = 0.f;
        const float* mr = mem + n * 512;
        for (int d = lane; d < 512; d += 32) s = fmaf(xs[d], mr[d], s);
#pragma unroll
        for (int o = 16; o; o >>= 1) s += __shfl_xor_sync(0xffffffffu, s, o);
        if (lane == 0) att[n] = 1.f / (1.f + expf(-s * 0.044194173824159216f));
    }
    __syncthreads();
    if (tid == 0) {
        float t0 = -1e30f, t1 = -1e30f, t2 = -1e30f, t3 = -1e30f;
        for (int n = 0; n < 60; n++) {
            float v = att[n];
            if (v > t0)      { t3 = t2; t2 = t1; t1 = t0; t0 = v; }
            else if (v > t1) { t3 = t2; t2 = t1; t1 = v; }
            else if (v > t2) { t3 = t2; t2 = v; }
            else if (v > t3) { t3 = v; }
        }
        att_out[row] = (t0 + t1 + t2 + t3) * 0.25f;
    }
    float s = 0.f;
    for (int n = 0; n < 60; n++) s = fmaf(att[n], mem[n * 512 + tid], s);
    __nv_bfloat16 hb, lb; split2(s, hb, lb);
    augh[(size_t)row * 512 + tid] = hb;
    augl[(size_t)row * 512 + tid] = lb;
}

// ===========================================================================
// top-k / losses / misc
// ===========================================================================
__global__ void __launch_bounds__(256) topk_gather(const float* __restrict__ att,
                                                   const float* __restrict__ feats,
                                                   float* __restrict__ meanv,
                                                   int* __restrict__ idx_out)
{
    __shared__ float vals[256], rv[256];
    __shared__ int ri[256], ids[17];
    const int b = blockIdx.x, tid = threadIdx.x;
    vals[tid] = att[b * 256 + tid];
    __syncthreads();
    for (int it = 0; it < 17; it++) {
        rv[tid] = vals[tid]; ri[tid] = tid;
        __syncthreads();
        for (int s = 128; s; s >>= 1) {
            if (tid < s) {
                float ov = rv[tid + s]; int oi = ri[tid + s];
                if (ov > rv[tid] || (ov == rv[tid] && oi < ri[tid])) { rv[tid] = ov; ri[tid] = oi; }
            }
            __syncthreads();
        }
        if (tid == 0) {
            ids[it] = ri[0];
            vals[ri[0]] = -1e30f;
            if (idx_out) idx_out[b * 17 + it] = ri[0];
        }
        __syncthreads();
    }
    for (int d = tid; d < 512; d += 256) {
        float s = 0.f;
        for (int j = 0; j < 17; j++) s += feats[((size_t)b * 256 + ids[j]) * 512 + d];
        meanv[b * 512 + d] = s * (1.f / 17.f);
    }
}

__device__ __forceinline__ float wsum(float v)
{
#pragma unroll
    for (int o = 16; o; o >>= 1) v += __shfl_xor_sync(0xffffffffu, v, o);
    return v;
}

__global__ void __launch_bounds__(1024) triplet_cos_kernel(const float* __restrict__ anchor,
                                                           const float* __restrict__ pos,
                                                           const float* __restrict__ neg,
                                                           float* __restrict__ trip_out,
                                                           float* __restrict__ cos_out)
{
    __shared__ float st[32], sc[32];
    const int w = threadIdx.x >> 5, lane = threadIdx.x & 31;
    float sa = 0, sp = 0, sn = 0, dan = 0;
    for (int d = lane; d < 512; d += 32) {
        float a = anchor[w * 512 + d], p = pos[w * 512 + d], n = neg[w * 512 + d];
        sa += a * a; sp += p * p; sn += n * n; dan += a * n;
    }
    sa = wsum(sa); sp = wsum(sp); sn = wsum(sn); dan = wsum(dan);
    float na = sqrtf(sa), npp = sqrtf(sp), ng = sqrtf(sn);
    float ina = 1.f / na, inp = 1.f / npp, ing = 1.f / ng;
    float dp2 = 0, dn2 = 0;
    for (int d = lane; d < 512; d += 32) {
        float a  = anchor[w * 512 + d] * ina;
        float dpv = a - pos[w * 512 + d] * inp + 1e-6f;
        float dnv = a - neg[w * 512 + d] * ing + 1e-6f;
        dp2 += dpv * dpv; dn2 += dnv * dnv;
    }
    dp2 = wsum(dp2); dn2 = wsum(dn2);
    if (lane == 0) {
        st[w] = fmaxf(sqrtf(dp2) - sqrtf(dn2) + 1.f, 0.f);
        sc[w] = 1.f - dan / (fmaxf(na, 1e-6f) * fmaxf(ng, 1e-6f));
    }
    __syncthreads();
    if (threadIdx.x == 0) {
        float a = 0, c = 0;
        for (int i = 0; i < 32; i++) { a += st[i]; c += sc[i]; }
        trip_out[0] = a * (1.f / 32.f);
        cos_out[0]  = c * (1.f / 32.f);
    }
}

__global__ void __launch_bounds__(1024) distance_kernel(const float* __restrict__ anew,
                                                        const float* __restrict__ nnew,
                                                        float* __restrict__ out)
{
    __shared__ float sd[32];
    const int w = threadIdx.x >> 5, lane = threadIdx.x & 31;
    float sa = 0, sn = 0;
    for (int d = lane; d < 512; d += 32) {
        float a = anew[w * 512 + d], n = nnew[w * 512 + d];
        sa += a * a; sn += n * n;
    }
    sa = wsum(sa); sn = wsum(sn);
    if (lane == 0) sd[w] = fmaxf(100.f - sqrtf(sn) + sqrtf(sa), 0.f);
    __syncthreads();
    if (threadIdx.x == 0) {
        float s = 0;
        for (int i = 0; i < 32; i++) s += sd[i];
        out[0] = s * (1.f / 32.f);
    }
}

__global__ void vae_kernel(const float* __restrict__ mu, const float* __restrict__ var,
                           const float* __restrict__ eps, float* __restrict__ o, int n)
{
    for (int i = blockIdx.x * blockDim.x + threadIdx.x; i < n; i += gridDim.x * blockDim.x)
        o[i] = mu[i] + eps[i] * sqrtf(expf(var[i]));
}

__global__ void __launch_bounds__(256) kl_part_kernel(const float* __restrict__ mu,
                                                      const float* __restrict__ var,
                                                      float* __restrict__ part, int n)
{
    __shared__ float red[256];
    float s = 0.f;
    for (int i = blockIdx.x * 256 + threadIdx.x; i < n; i += gridDim.x * 256) {
        float m = mu[i], v = var[i];
        s += 1.f + v - m * m - expf(v);
    }
    red[threadIdx.x] = s; __syncthreads();
    for (int t = 128; t; t >>= 1) { if (threadIdx.x < t) red[threadIdx.x] += red[threadIdx.x + t]; __syncthreads(); }
    if (threadIdx.x == 0) part[blockIdx.x] = red[0];
}

__global__ void __launch_bounds__(1024) kl_final_kernel(const float* __restrict__ part,
                                                        float* __restrict__ out)
{
    __shared__ float red[1024];
    red[threadIdx.x] = part[threadIdx.x]; __syncthreads();
    for (int t = 512; t; t >>= 1) { if (threadIdx.x < t) red[threadIdx.x] += red[threadIdx.x + t]; __syncthreads(); }
    if (threadIdx.x == 0) out[0] = -0.5f * red[0] * (1.f / 16384.f);
}

__global__ void __launch_bounds__(512) gather_mean_kernel(const float* __restrict__ src,
                                                          const int* __restrict__ idx,
                                                          float* __restrict__ out)
{
    __shared__ int ids[17];
    const int b = blockIdx.x, tid = threadIdx.x;
    if (tid < 17) ids[tid] = idx[b * 17 + tid];
    __syncthreads();
    float s = 0.f;
    for (int j = 0; j < 17; j++) s += src[((size_t)b * 256 + ids[j]) * 512 + tid];
    out[b * 512 + tid] = s * (1.f / 17.f);
}

__global__ void xout_kernel(const float* __restrict__ h, const float* __restrict__ nnew,
                            const float* __restrict__ anm, const float* __restrict__ anew,
                            const float* __restrict__ nam, float* __restrict__ xout)
{
    const int n = 64 * 256 * 1024;
    for (int i = blockIdx.x * blockDim.x + threadIdx.x; i < n; i += gridDim.x * blockDim.x) {
        int c  = i & 1023;
        int rt = i >> 10;
        float v;
        if (c < 512) v = h[(size_t)rt * 512 + c];
        else {
            int cc = c - 512;
            if (rt < 8192) v = nnew[(size_t)rt * 512 + cc] + anm[(size_t)rt * 512 + cc];
            else {
                size_t o = (size_t)(rt - 8192) * 512 + cc;
                v = anew[o] + nam[o];
            }
        }
        xout[i] = v;
    }
}

__global__ void vfeat_kernel(const float* __restrict__ h, float* __restrict__ v)
{
    __shared__ float tile[32][33];
    const int b = blockIdx.x, d0 = blockIdx.y * 32, t0 = blockIdx.z * 32;
    for (int r = threadIdx.y; r < 32; r += 8)
        tile[r][threadIdx.x] = h[((size_t)b * 256 + t0 + r) * 512 + d0 + threadIdx.x];
    __syncthreads();
    for (int r = threadIdx.y; r < 32; r += 8)
        v[((size_t)b * 512 + d0 + r) * 256 + t0 + threadIdx.x] = tile[threadIdx.x][r];
}

// ===========================================================================
extern "C" void kernel_launch(void* const* d_in, const int* in_sizes, int n_in,
                              void* d_out, int out_size)
{
    const float* x      = (const float*)d_in[0];
    const float* eps_in = (const float*)d_in[1];
    const float* conv_w = (const float*)d_in[2];
    const float* conv_b = (const float*)d_in[3];
    const float* ln1_g  = (const float*)d_in[4];
    const float* ln1_b  = (const float*)d_in[5];
    const float* qkv_w  = (const float*)d_in[6];
    const float* out_w  = (const float*)d_in[7];
    const float* out_b  = (const float*)d_in[8];
    const float* ln2_g  = (const float*)d_in[9];
    const float* ln2_b  = (const float*)d_in[10];
    const float* ff1_w  = (const float*)d_in[11];
    const float* ff1_b  = (const float*)d_in[12];
    const float* ff2_w  = (const float*)d_in[13];
    const float* ff2_b  = (const float*)d_in[14];
    const float* a_mem  = (const float*)d_in[15];
    const float* n_mem  = (const float*)d_in[16];
    const float* mu_w   = (const float*)d_in[17];
    const float* mu_b   = (const float*)d_in[18];
    const float* var_w  = (const float*)d_in[19];
    const float* var_b  = (const float*)d_in[20];
    float* out = (float*)d_out;

    float* S = nullptr;
    cudaGetSymbolAddress((void**)&S, g_scratch);
    __nv_bfloat16* BF = nullptr;
    cudaGetSymbolAddress((void**)&BF, g_bf);

    float* h     = S + OFF_H;
    float* sc    = S + OFF_SC;
    float* stack = S + OFF_STACK;
    float* Anew  = stack;
    float* NAm   = stack + 1ull * 8192 * 512;
    float* ANm   = stack + 2ull * 8192 * 512;
    float* muB   = stack + 3ull * 8192 * 512;
    float* varB  = S + OFF_VAR;
    float* newN  = S + OFF_NEW;
    float* anch  = S + OFF_ANCH;
    float* negv  = S + OFF_NEG;
    float* posv  = S + OFF_POS;
    float* anchN = S + OFF_ANCHN;
    float* negN  = S + OFF_NEGN;
    int*   idxA  = (int*)(S + OFF_IDXA);
    int*   idxN  = (int*)(S + OFF_IDXN);
    float* klp   = S + OFF_KLP;

    __nv_bfloat16* lnh = BF + B_LNH;  __nv_bfloat16* lnl = BF + B_LNL;
    __nv_bfloat16* aoh = BF + B_AOH;  __nv_bfloat16* aol = BF + B_AOL;
    __nv_bfloat16* ffh = BF + B_FFH;  __nv_bfloat16* ffl = BF + B_FFL;
    __nv_bfloat16* qkvh = BF + B_QKVH; __nv_bfloat16* qkvl = BF + B_QKVL;
    __nv_bfloat16* ph = BF + B_PH;     __nv_bfloat16* pl = BF + B_PL;
    __nv_bfloat16* vth = BF + B_VTH;   __nv_bfloat16* vtl = BF + B_VTL;

    constexpr int MG_SMEM = 81920;
    cudaFuncSetAttribute(mgemm<0,false>, cudaFuncAttributeMaxDynamicSharedMemorySize, MG_SMEM);
    cudaFuncSetAttribute(mgemm<1,false>, cudaFuncAttributeMaxDynamicSharedMemorySize, MG_SMEM);
    cudaFuncSetAttribute(mgemm<2,false>, cudaFuncAttributeMaxDynamicSharedMemorySize, MG_SMEM);
    cudaFuncSetAttribute(mgemm<3,false>, cudaFuncAttributeMaxDynamicSharedMemorySize, MG_SMEM);
    cudaFuncSetAttribute(mgemm<5,false>, cudaFuncAttributeMaxDynamicSharedMemorySize, MG_SMEM);
    cudaFuncSetAttribute(mgemm<4,true>,  cudaFuncAttributeMaxDynamicSharedMemorySize, MG_SMEM);

    // ---- prep launches 1-5, then conv mgemm as launch #6 (ncu -s 5 -c 1 target)
    convprep<<<1024, 256>>>(conv_w, BF + B_CNVWH, BF + B_CNVWL);
    wprep_t<<<dim3(16, 48), dim3(32, 8)>>>(qkv_w, BF + B_QKVWH, BF + B_QKVWL, 512, 1536);
    wprep_t<<<dim3(16, 16), dim3(32, 8)>>>(out_w, BF + B_OUTWH, BF + B_OUTWL, 512, 512);
    wprep_t<<<dim3(16, 16), dim3(32, 8)>>>(ff1_w, BF + B_FF1WH, BF + B_FF1WL, 512, 512);
    wprep_t<<<dim3(16, 16), dim3(32, 8)>>>(ff2_w, BF + B_FF2WH, BF + B_FF2WL, 512, 512);

    // conv (implicit im2col, relu+bias) — PROFILED LAUNCH
    mgemm<4, true><<<dim3(4, 128), 256, MG_SMEM>>>(
        nullptr, nullptr, x, BF + B_CNVWH, BF + B_CNVWL,
        h, nullptr, nullptr, conv_b, 16384, 512, 3072);

    // remaining weight prep
    wprep_t<<<dim3(16, 48), dim3(32, 8)>>>(qkv_w + 786432,
                                           BF + B_QKVWH + 786432, BF + B_QKVWL + 786432, 512, 1536);
    wprep_t<<<dim3(16, 16), dim3(32, 8)>>>(out_w + 262144,
                                           BF + B_OUTWH + 262144, BF + B_OUTWL + 262144, 512, 512);
    wprep_t<<<dim3(16, 16), dim3(32, 8)>>>(ff1_w + 262144,
                                           BF + B_FF1WH + 262144, BF + B_FF1WL + 262144, 512, 512);
    wprep_t<<<dim3(16, 16), dim3(32, 8)>>>(ff2_w + 262144,
                                           BF + B_FF2WH + 262144, BF + B_FF2WL + 262144, 512, 512);
    wprep_t<<<dim3(16, 16), dim3(32, 8)>>>(mu_w,  BF + B_MUWH,  BF + B_MUWL,  512, 512);
    wprep_t<<<dim3(16, 16), dim3(32, 8)>>>(var_w, BF + B_VARWH, BF + B_VARWL, 512, 512);

    // ---- transformer x2
    for (int i = 0; i < 2; i++) {
        ln_kernel<<<16384, 256>>>(h, ln1_g + i * 512, ln1_b + i * 512, lnh, lnl);
        mgemm<5, false><<<dim3(12, 128), 256, MG_SMEM>>>(
            lnh, lnl, nullptr, BF + B_QKVWH + (size_t)i * 786432, BF + B_QKVWL + (size_t)i * 786432,
            nullptr, qkvh, qkvl, nullptr, 16384, 1536, 512);
        vtrans_kernel<<<dim3(256, 4, 8), dim3(32, 8)>>>(qkvh, qkvl, vth, vtl);
        bqk_kernel<<<dim3(2, 2, 256), 256>>>(qkvh, qkvl, sc);
        softmaxp_kernel<<<8192, 256>>>(sc, ph, pl);
        bpv_kernel<<<dim3(2, 1, 256), 256>>>(ph, pl, vth, vtl, aoh, aol);
        mgemm<2, false><<<dim3(4, 128), 256, MG_SMEM>>>(
            aoh, aol, nullptr, BF + B_OUTWH + (size_t)i * 262144, BF + B_OUTWL + (size_t)i * 262144,
            h, nullptr, nullptr, out_b + i * 512, 16384, 512, 512);
        ln_kernel<<<16384, 256>>>(h, ln2_g + i * 512, ln2_b + i * 512, lnh, lnl);
        mgemm<3, false><<<dim3(4, 128), 256, MG_SMEM>>>(
            lnh, lnl, nullptr, BF + B_FF1WH + (size_t)i * 262144, BF + B_FF1WL + (size_t)i * 262144,
            nullptr, ffh, ffl, ff1_b + i * 512, 16384, 512, 512);
        mgemm<2, false><<<dim3(4, 128), 256, MG_SMEM>>>(
            ffh, ffl, nullptr, BF + B_FF2WH + (size_t)i * 262144, BF + B_FF2WL + (size_t)i * 262144,
            h, nullptr, nullptr, ff2_b + i * 512, 16384, 512, 512);
    }

    const float* Nx = h;                       // x_emb[:32]
    const float* Ax = h + (size_t)8192 * 512;  // x_emb[32:]

    memory_kernel<<<dim3(8192, 4), 512>>>(Nx, Ax, a_mem, n_mem,
                                          out + O_AATT, BF + B_AUGH, BF + B_AUGL);

    topk_gather<<<32, 256>>>(out + O_AATT,  Ax, negv, idxA);
    topk_gather<<<32, 256>>>(out + O_NATT,  Nx, anch, idxN);
    topk_gather<<<32, 256>>>(out + O_NAATT, Ax, posv, nullptr);

    triplet_cos_kernel<<<1, 1024>>>(anch, posv, negv, out + O_TRIP, out + O_COS);

    // stacked mu projection: [augA; augNA; augAN; augN] @ mu -> [Anew; NAm; ANm; muB]
    mgemm<1, false><<<dim3(4, 256), 256, MG_SMEM>>>(
        BF + B_AUGH, BF + B_AUGL, nullptr, BF + B_MUWH, BF + B_MUWL,
        stack, nullptr, nullptr, mu_b, 32768, 512, 512);
    mgemm<1, false><<<dim3(4, 64), 256, MG_SMEM>>>(
        BF + B_AUGH + 3 * SZ_AUG, BF + B_AUGL + 3 * SZ_AUG, nullptr,
        BF + B_VARWH, BF + B_VARWL, varB, nullptr, nullptr, var_b, 8192, 512, 512);

    vae_kernel<<<4096, 256>>>(muB, varB, eps_in, newN, 8192 * 512);
    kl_part_kernel<<<1024, 256>>>(muB, varB, klp, 8192 * 512);
    kl_final_kernel<<<1, 1024>>>(klp, out + O_KL);

    gather_mean_kernel<<<32, 512>>>(newN, idxN, anchN);
    gather_mean_kernel<<<32, 512>>>(Anew, idxA, negN);
    distance_kernel<<<1, 1024>>>(anchN, negN, out + O_DIST);

    xout_kernel<<<8192, 256>>>(h, newN, ANm, Anew, NAm, out + O_XOUT);
    vfeat_kernel<<<dim3(64, 16, 8), dim3(32, 8)>>>(h, out + O_VFEAT);
}

// round 6
// speedup vs baseline: 2.9757x; 1.0510x over previous
#include <cuda_runtime.h>
#include <cuda_bf16.h>
#include <math.h>
#include <stdint.h>

// ===========================================================================
// fp32 scratch
// ===========================================================================
constexpr size_t OFF_H     = 0;                         // 16384*512
constexpr size_t OFF_SC    = 8388608;                   // 256*256*256 (S fp32)
constexpr size_t OFF_STACK = OFF_SC + 16777216;         // 32768*512: Anew,NAm,ANm,muB
constexpr size_t OFF_VAR   = OFF_STACK + 16777216;      // 8192*512
constexpr size_t OFF_NEW   = OFF_VAR + 4194304;         // 8192*512
constexpr size_t OFF_ANCH  = OFF_NEW + 4194304;         // 32*512 each below
constexpr size_t OFF_NEG   = OFF_ANCH + 16384;
constexpr size_t OFF_POS   = OFF_NEG  + 16384;
constexpr size_t OFF_ANCHN = OFF_POS  + 16384;
constexpr size_t OFF_NEGN  = OFF_ANCHN + 16384;
constexpr size_t OFF_IDXA  = OFF_NEGN + 16384;
constexpr size_t OFF_IDXN  = OFF_IDXA + 1024;
constexpr size_t OFF_KLP   = OFF_IDXN + 1024;
constexpr size_t SCRATCH_TOTAL = OFF_KLP + 1024;
__device__ float g_scratch[SCRATCH_TOTAL];

// ===========================================================================
// bf16 scratch
// ===========================================================================
constexpr size_t SZ_TOK  = 16384ull * 512;
constexpr size_t SZ_QKV  = 16384ull * 1536;
constexpr size_t SZ_P    = 256ull * 65536;
constexpr size_t SZ_VT   = 256ull * 32768;
constexpr size_t SZ_AUG  = 8192ull * 512;
constexpr size_t SZ_X    = 64ull * 256 * 1024;   // 16777216

constexpr size_t B_LNH  = 0;
constexpr size_t B_LNL  = B_LNH + SZ_TOK;
constexpr size_t B_AOH  = B_LNL + SZ_TOK;
constexpr size_t B_AOL  = B_AOH + SZ_TOK;
constexpr size_t B_FFH  = B_AOL + SZ_TOK;
constexpr size_t B_FFL  = B_FFH + SZ_TOK;
constexpr size_t B_QKVH = B_FFL + SZ_TOK;
constexpr size_t B_QKVL = B_QKVH + SZ_QKV;
constexpr size_t B_PH   = B_QKVL + SZ_QKV;
constexpr size_t B_PL   = B_PH + SZ_P;
constexpr size_t B_VTH  = B_PL + SZ_P;
constexpr size_t B_VTL  = B_VTH + SZ_VT;
constexpr size_t B_AUGH = B_VTL + SZ_VT;      // [A, NA, AN, N] stacked
constexpr size_t B_AUGL = B_AUGH + 4 * SZ_AUG;
constexpr size_t B_QKVWH = B_AUGL + 4 * SZ_AUG;
constexpr size_t B_QKVWL = B_QKVWH + 2ull * 786432;
constexpr size_t B_OUTWH = B_QKVWL + 2ull * 786432;
constexpr size_t B_OUTWL = B_OUTWH + 2ull * 262144;
constexpr size_t B_FF1WH = B_OUTWL + 2ull * 262144;
constexpr size_t B_FF1WL = B_FF1WH + 2ull * 262144;
constexpr size_t B_FF2WH = B_FF1WL + 2ull * 262144;
constexpr size_t B_FF2WL = B_FF2WH + 2ull * 262144;
constexpr size_t B_MUWH  = B_FF2WL + 2ull * 262144;
constexpr size_t B_MUWL  = B_MUWH + 262144;
constexpr size_t B_VARWH = B_MUWL + 262144;
constexpr size_t B_VARWL = B_VARWH + 262144;
constexpr size_t B_CNVWH = B_VARWL + 262144;
constexpr size_t B_CNVWL = B_CNVWH + 1572864;
constexpr size_t B_XH    = B_CNVWL + 1572864;
constexpr size_t B_XL    = B_XH + SZ_X;
constexpr size_t BF_TOTAL = B_XL + SZ_X;
__device__ __nv_bfloat16 g_bf[BF_TOTAL];

__device__ __align__(16) __nv_bfloat16 g_zero[8];   // zero-initialized

// output offsets (triplet, kl, distance, A_att, N_att, A_Natt, N_Aatt, cos, x_out, v_feat)
constexpr size_t O_TRIP  = 0;
constexpr size_t O_KL    = 1;
constexpr size_t O_DIST  = 2;
constexpr size_t O_AATT  = 3;
constexpr size_t O_NATT  = 3 + 8192;
constexpr size_t O_ANATT = 3 + 16384;
constexpr size_t O_NAATT = 3 + 24576;
constexpr size_t O_COS   = 3 + 32768;
constexpr size_t O_XOUT  = 4 + 32768;
constexpr size_t O_VFEAT = O_XOUT + 64ull * 256 * 1024;

// ===========================================================================
// mma / smem helpers
// ===========================================================================
__device__ __forceinline__ void mma16816(float* c, const uint32_t* a, const uint32_t* b)
{
    asm volatile(
        "mma.sync.aligned.m16n8k16.row.col.f32.bf16.bf16.f32 "
        "{%0,%1,%2,%3}, {%4,%5,%6,%7}, {%8,%9}, {%0,%1,%2,%3};"
        : "+f"(c[0]), "+f"(c[1]), "+f"(c[2]), "+f"(c[3])
        : "r"(a[0]), "r"(a[1]), "r"(a[2]), "r"(a[3]), "r"(b[0]), "r"(b[1]));
}

__device__ __forceinline__ void split2(float v, __nv_bfloat16& h, __nv_bfloat16& l) {
    h = __float2bfloat16(v);
    l = __float2bfloat16(v - __bfloat162float(h));
}

__device__ __forceinline__ uint32_t cvt_smem(const void* p) {
    uint32_t a;
    asm("{ .reg .u64 t; cvta.to.shared.u64 t, %1; cvt.u32.u64 %0, t; }" : "=r"(a) : "l"(p));
    return a;
}

#define LDSM4(r0, r1, r2, r3, a) \
    asm volatile("ldmatrix.sync.aligned.m8n8.x4.shared.b16 {%0,%1,%2,%3}, [%4];" \
        : "=r"(r0), "=r"(r1), "=r"(r2), "=r"(r3) : "r"(a))

#define CP16(sa, gp) \
    asm volatile("cp.async.cg.shared.global [%0], [%1], 16;" :: "r"(sa), "l"(gp))
#define CP_COMMIT() asm volatile("cp.async.commit_group;" ::: "memory")
#define CP_WAIT1()  asm volatile("cp.async.wait_group 1;" ::: "memory")
#define CP_WAIT0()  asm volatile("cp.async.wait_group 0;" ::: "memory")

// one stage layout (bytes): Ah @0, Al @10240, Bh @20480, Bl @30720; rows pad 40 elem (80B)
constexpr uint32_t SM_AL = 10240, SM_BH = 20480, SM_BL = 30720;
constexpr uint32_t STAGE_BYTES = 40960;

// 128x32 tile MMA via ldmatrix + 3-term split
__device__ __forceinline__ void mma_tile_ldsm(uint32_t sb, float acc[4][4][4],
                                              int arow, int acolB, int brow, int bcolB)
{
#pragma unroll
    for (int ks = 0; ks < 32; ks += 16) {
        uint32_t fa[4][4], fbh[4][2], fbl[4][2];
#pragma unroll
        for (int mi = 0; mi < 4; mi++) {
            uint32_t ad = sb + (uint32_t)((arow + mi * 16) * 80 + (ks + acolB) * 2);
            LDSM4(fa[mi][0], fa[mi][1], fa[mi][2], fa[mi][3], ad);
        }
#pragma unroll
        for (int np = 0; np < 2; np++) {
            uint32_t bd = sb + SM_BH + (uint32_t)((brow + np * 16) * 80 + (ks + bcolB) * 2);
            LDSM4(fbh[np * 2][0], fbh[np * 2][1], fbh[np * 2 + 1][0], fbh[np * 2 + 1][1], bd);
            LDSM4(fbl[np * 2][0], fbl[np * 2][1], fbl[np * 2 + 1][0], fbl[np * 2 + 1][1],
                  bd + (SM_BL - SM_BH));
        }
#pragma unroll
        for (int mi = 0; mi < 4; mi++)
#pragma unroll
            for (int ni = 0; ni < 4; ni++) {
                mma16816(acc[mi][ni], fa[mi], fbh[ni]);
                mma16816(acc[mi][ni], fa[mi], fbl[ni]);
            }
#pragma unroll
        for (int mi = 0; mi < 4; mi++) {
            uint32_t ad = sb + SM_AL + (uint32_t)((arow + mi * 16) * 80 + (ks + acolB) * 2);
            LDSM4(fa[mi][0], fa[mi][1], fa[mi][2], fa[mi][3], ad);
        }
#pragma unroll
        for (int mi = 0; mi < 4; mi++)
#pragma unroll
            for (int ni = 0; ni < 4; ni++)
                mma16816(acc[mi][ni], fa[mi], fbh[ni]);
    }
}

// stage one 128x32 K-chunk (A hi/lo + B hi/lo) via cp.async; CONV = im2col A
template<bool CONV>
__device__ __forceinline__ void stage_chunk(
    uint32_t sdst,
    const __nv_bfloat16* __restrict__ Ah, const __nv_bfloat16* __restrict__ Al,
    const __nv_bfloat16* __restrict__ Bh, const __nv_bfloat16* __restrict__ Bl,
    const __nv_bfloat16* zb, int row0, int col0, int K, int kc, int tid)
{
#pragma unroll
    for (int i = 0; i < 2; i++) {
        int chunk = tid * 2 + i;
        int rr = chunk >> 2, sg = chunk & 3;
        uint32_t so = (uint32_t)(rr * 80 + sg * 16);
        const __nv_bfloat16 *pah, *pal;
        if (CONV) {
            int gk = kc * 32 + sg * 8;
            int tap = gk >> 10, ci = gk & 1023;
            int m = row0 + rr;
            int t2 = (m & 255) + tap - 1;
            if (t2 >= 0 && t2 < 256) {
                size_t o = ((size_t)((m >> 8) * 256 + t2)) * 1024 + ci;
                pah = Ah + o; pal = Al + o;
            } else { pah = zb; pal = zb; }
        } else {
            size_t oa = (size_t)(row0 + rr) * K + kc * 32 + sg * 8;
            pah = Ah + oa; pal = Al + oa;
        }
        CP16(sdst + so,         pah);
        CP16(sdst + SM_AL + so, pal);
        size_t ob = (size_t)(col0 + rr) * K + kc * 32 + sg * 8;
        CP16(sdst + SM_BH + so, Bh + ob);
        CP16(sdst + SM_BL + so, Bl + ob);
    }
    CP_COMMIT();
}

// ===========================================================================
// HMMA GEMM, cp.async double-buffered (all paths incl. conv-im2col)
// EPI: 0=none,1=+bias,2=+bias+residual,3=+bias+gelu->pair,4=+bias+relu,5=->pair
// ===========================================================================
template<int EPI, bool CONV>
__global__ void __launch_bounds__(256, 2) mgemm(
    const __nv_bfloat16* __restrict__ Ah, const __nv_bfloat16* __restrict__ Al,
    const __nv_bfloat16* __restrict__ Bh, const __nv_bfloat16* __restrict__ Bl,
    float* __restrict__ C,
    __nv_bfloat16* __restrict__ Chi, __nv_bfloat16* __restrict__ Clo,
    const float* __restrict__ bias,
    int M, int N, int K)
{
    extern __shared__ char smem[];
    const int tid  = threadIdx.x;
    const int wid  = tid >> 5;
    const int lane = tid & 31;
    const int g = lane >> 2, t = lane & 3;
    const int wm = wid >> 2, wn = wid & 3;
    const int row0 = blockIdx.y * 128;
    const int col0 = blockIdx.x * 128;
    const uint32_t sb0 = cvt_smem(smem);

    const int arow  = wm * 64 + (lane & 7) + ((lane >> 3) & 1) * 8;
    const int acolB = ((lane >> 4) & 1) * 8;
    const int brow  = wn * 32 + ((lane >> 4) & 1) * 8 + (lane & 7);
    const int bcolB = ((lane >> 3) & 1) * 8;

    float acc[4][4][4];
#pragma unroll
    for (int mi = 0; mi < 4; mi++)
#pragma unroll
        for (int ni = 0; ni < 4; ni++)
#pragma unroll
            for (int q = 0; q < 4; q++) acc[mi][ni][q] = 0.f;

    const int nchunks = K >> 5;

    stage_chunk<CONV>(sb0, Ah, Al, Bh, Bl, g_zero, row0, col0, K, 0, tid);

    for (int kc = 0; kc < nchunks; kc++) {
        const uint32_t sb = sb0 + (uint32_t)(kc & 1) * STAGE_BYTES;
        if (kc + 1 < nchunks) {
            const uint32_t sn = sb0 + (uint32_t)((kc + 1) & 1) * STAGE_BYTES;
            stage_chunk<CONV>(sn, Ah, Al, Bh, Bl, g_zero, row0, col0, K, kc + 1, tid);
            CP_WAIT1();
        } else {
            CP_WAIT0();
        }
        __syncthreads();
        mma_tile_ldsm(sb, acc, arow, acolB, brow, bcolB);
        __syncthreads();
    }

#pragma unroll
    for (int mi = 0; mi < 4; mi++) {
#pragma unroll
        for (int ni = 0; ni < 4; ni++) {
#pragma unroll
            for (int q = 0; q < 4; q++) {
                int r = row0 + wm * 64 + mi * 16 + g + (q >> 1) * 8;
                int c = col0 + wn * 32 + ni * 8 + t * 2 + (q & 1);
                float v = acc[mi][ni][q];
                size_t o = (size_t)r * N + c;
                if (EPI != 0 && EPI != 5) v += bias[c];
                if (EPI == 2) v += C[o];
                if (EPI == 3 || EPI == 5) {
                    if (EPI == 3) v = 0.5f * v * (1.f + erff(v * 0.70710678118654752f));
                    __nv_bfloat16 hb, lb; split2(v, hb, lb);
                    Chi[o] = hb; Clo[o] = lb;
                } else {
                    if (EPI == 4) v = fmaxf(v, 0.f);
                    C[o] = v;
                }
            }
        }
    }
}

// ===========================================================================
// Batched QK^T  (static 40KB single-stage, ldmatrix core)
// ===========================================================================
__global__ void __launch_bounds__(256, 2) bqk_kernel(
    const __nv_bfloat16* __restrict__ Qh, const __nv_bfloat16* __restrict__ Ql,
    float* __restrict__ S)
{
    __shared__ alignas(16) char smem[40960];
    const int tid  = threadIdx.x;
    const int wid  = tid >> 5;
    const int lane = tid & 31;
    const int g = lane >> 2, t = lane & 3;
    const int wm = wid >> 2, wn = wid & 3;
    const int bh = blockIdx.z, b = bh >> 2, h = bh & 3;
    const int i0 = blockIdx.x * 128, j0 = blockIdx.y * 128;
    const __nv_bfloat16* Ah = Qh + (size_t)b * 256 * 1536 + h * 128;
    const __nv_bfloat16* Al = Ql + (size_t)b * 256 * 1536 + h * 128;
    const uint32_t sb = cvt_smem(smem);

    const int arow  = wm * 64 + (lane & 7) + ((lane >> 3) & 1) * 8;
    const int acolB = ((lane >> 4) & 1) * 8;
    const int brow  = wn * 32 + ((lane >> 4) & 1) * 8 + (lane & 7);
    const int bcolB = ((lane >> 3) & 1) * 8;

    float acc[4][4][4];
#pragma unroll
    for (int mi = 0; mi < 4; mi++)
#pragma unroll
        for (int ni = 0; ni < 4; ni++)
#pragma unroll
            for (int q = 0; q < 4; q++) acc[mi][ni][q] = 0.f;

    for (int kc = 0; kc < 4; kc++) {
#pragma unroll
        for (int i = 0; i < 2; i++) {
            int chunk = tid * 2 + i;
            int rr = chunk >> 2, sg = chunk & 3;
            uint32_t so = (uint32_t)(rr * 80 + sg * 16);
            size_t oa = (size_t)(i0 + rr) * 1536 + kc * 32 + sg * 8;
            size_t ob = (size_t)(j0 + rr) * 1536 + 512 + kc * 32 + sg * 8;
            *(uint4*)(smem + so)         = *(const uint4*)(Ah + oa);
            *(uint4*)(smem + SM_AL + so) = *(const uint4*)(Al + oa);
            *(uint4*)(smem + SM_BH + so) = *(const uint4*)(Ah + ob);
            *(uint4*)(smem + SM_BL + so) = *(const uint4*)(Al + ob);
        }
        __syncthreads();
        mma_tile_ldsm(sb, acc, arow, acolB, brow, bcolB);
        __syncthreads();
    }

    float* so2 = S + (size_t)bh * 65536;
    const float scale = 0.08838834764831845f;
#pragma unroll
    for (int mi = 0; mi < 4; mi++)
#pragma unroll
        for (int ni = 0; ni < 4; ni++)
#pragma unroll
            for (int q = 0; q < 4; q++) {
                int r = i0 + wm * 64 + mi * 16 + g + (q >> 1) * 8;
                int c = j0 + wn * 32 + ni * 8 + t * 2 + (q & 1);
                so2[(size_t)r * 256 + c] = acc[mi][ni][q] * scale;
            }
}

// row softmax -> bf16 pair
__global__ void __launch_bounds__(256) softmaxp_kernel(const float* __restrict__ S,
                                                       __nv_bfloat16* __restrict__ Ph,
                                                       __nv_bfloat16* __restrict__ Pl)
{
    const int row  = blockIdx.x * 8 + (threadIdx.x >> 5);
    const int lane = threadIdx.x & 31;
    const float* p = S + (size_t)row * 256;
    float v[8]; float mx = -1e30f;
#pragma unroll
    for (int j = 0; j < 8; j++) { v[j] = p[lane + 32 * j]; mx = fmaxf(mx, v[j]); }
#pragma unroll
    for (int o = 16; o; o >>= 1) mx = fmaxf(mx, __shfl_xor_sync(0xffffffffu, mx, o));
    float s = 0.f;
#pragma unroll
    for (int j = 0; j < 8; j++) { v[j] = expf(v[j] - mx); s += v[j]; }
#pragma unroll
    for (int o = 16; o; o >>= 1) s += __shfl_xor_sync(0xffffffffu, s, o);
    const float inv = 1.f / s;
#pragma unroll
    for (int j = 0; j < 8; j++) {
        __nv_bfloat16 hb, lb; split2(v[j] * inv, hb, lb);
        Ph[(size_t)row * 256 + lane + 32 * j] = hb;
        Pl[(size_t)row * 256 + lane + 32 * j] = lb;
    }
}

// V transpose
__global__ void vtrans_kernel(const __nv_bfloat16* __restrict__ Vh,
                              const __nv_bfloat16* __restrict__ Vl,
                              __nv_bfloat16* __restrict__ vth,
                              __nv_bfloat16* __restrict__ vtl)
{
    __shared__ __nv_bfloat16 th[32][33], tl[32][33];
    const int bh = blockIdx.x, b = bh >> 2, h = bh & 3;
    const int d0 = blockIdx.y * 32, j0 = blockIdx.z * 32;
    const int tx = threadIdx.x, ty = threadIdx.y;
    const size_t base = (size_t)b * 256 * 1536 + 1024 + h * 128;
    for (int r = ty; r < 32; r += 8) {
        size_t o = base + (size_t)(j0 + r) * 1536 + d0 + tx;
        th[r][tx] = Vh[o]; tl[r][tx] = Vl[o];
    }
    __syncthreads();
    const size_t obase = (size_t)bh * 32768;
    for (int r = ty; r < 32; r += 8) {
        size_t o = obase + (size_t)(d0 + r) * 256 + j0 + tx;
        vth[o] = th[tx][r]; vtl[o] = tl[tx][r];
    }
}

// Batched PV
__global__ void __launch_bounds__(256, 2) bpv_kernel(
    const __nv_bfloat16* __restrict__ Ph, const __nv_bfloat16* __restrict__ Pl,
    const __nv_bfloat16* __restrict__ vth, const __nv_bfloat16* __restrict__ vtl,
    __nv_bfloat16* __restrict__ Oh, __nv_bfloat16* __restrict__ Ol)
{
    __shared__ alignas(16) char smem[40960];
    const int tid  = threadIdx.x;
    const int wid  = tid >> 5;
    const int lane = tid & 31;
    const int g = lane >> 2, t = lane & 3;
    const int wm = wid >> 2, wn = wid & 3;
    const int bh = blockIdx.z, b = bh >> 2, h = bh & 3;
    const int i0 = blockIdx.x * 128;
    const __nv_bfloat16* Ah = Ph + (size_t)bh * 65536 + (size_t)i0 * 256;
    const __nv_bfloat16* Al = Pl + (size_t)bh * 65536 + (size_t)i0 * 256;
    const __nv_bfloat16* Bh = vth + (size_t)bh * 32768;
    const __nv_bfloat16* Bl = vtl + (size_t)bh * 32768;
    const uint32_t sb = cvt_smem(smem);

    const int arow  = wm * 64 + (lane & 7) + ((lane >> 3) & 1) * 8;
    const int acolB = ((lane >> 4) & 1) * 8;
    const int brow  = wn * 32 + ((lane >> 4) & 1) * 8 + (lane & 7);
    const int bcolB = ((lane >> 3) & 1) * 8;

    float acc[4][4][4];
#pragma unroll
    for (int mi = 0; mi < 4; mi++)
#pragma unroll
        for (int ni = 0; ni < 4; ni++)
#pragma unroll
            for (int q = 0; q < 4; q++) acc[mi][ni][q] = 0.f;

    for (int kc = 0; kc < 8; kc++) {
#pragma unroll
        for (int i = 0; i < 2; i++) {
            int chunk = tid * 2 + i;
            int rr = chunk >> 2, sg = chunk & 3;
            uint32_t so = (uint32_t)(rr * 80 + sg * 16);
            size_t oa = (size_t)rr * 256 + kc * 32 + sg * 8;
            *(uint4*)(smem + so)         = *(const uint4*)(Ah + oa);
            *(uint4*)(smem + SM_AL + so) = *(const uint4*)(Al + oa);
            *(uint4*)(smem + SM_BH + so) = *(const uint4*)(Bh + oa);
            *(uint4*)(smem + SM_BL + so) = *(const uint4*)(Bl + oa);
        }
        __syncthreads();
        mma_tile_ldsm(sb, acc, arow, acolB, brow, bcolB);
        __syncthreads();
    }

#pragma unroll
    for (int mi = 0; mi < 4; mi++)
#pragma unroll
        for (int ni = 0; ni < 4; ni++)
#pragma unroll
            for (int q = 0; q < 4; q++) {
                int r = i0 + wm * 64 + mi * 16 + g + (q >> 1) * 8;
                int c = wn * 32 + ni * 8 + t * 2 + (q & 1);
                size_t o = ((size_t)b * 256 + r) * 512 + h * 128 + c;
                __nv_bfloat16 hb, lb; split2(acc[mi][ni][q], hb, lb);
                Oh[o] = hb; Ol[o] = lb;
            }
}

// ===========================================================================
// Prep kernels
// ===========================================================================
__global__ void wprep_t(const float* __restrict__ W, __nv_bfloat16* __restrict__ Wh,
                        __nv_bfloat16* __restrict__ Wl, int K, int N)
{
    __shared__ float tile[32][33];
    const int k0 = blockIdx.x * 32, n0 = blockIdx.y * 32;
    const int tx = threadIdx.x, ty = threadIdx.y;
    for (int r = ty; r < 32; r += 8)
        tile[r][tx] = W[(size_t)(k0 + r) * N + n0 + tx];
    __syncthreads();
    for (int r = ty; r < 32; r += 8) {
        float v = tile[tx][r];
        size_t o = (size_t)(n0 + r) * K + k0 + tx;
        __nv_bfloat16 hb, lb; split2(v, hb, lb);
        Wh[o] = hb; Wl[o] = lb;
    }
}

__global__ void convprep(const float* __restrict__ w, __nv_bfloat16* __restrict__ Wh,
                         __nv_bfloat16* __restrict__ Wl)
{
    const int n = 512 * 3072;
    for (int idx = blockIdx.x * blockDim.x + threadIdx.x; idx < n; idx += gridDim.x * blockDim.x) {
        int d = idx / 3072, k = idx % 3072;
        int tap = k >> 10, ci = k & 1023;
        float v = w[(size_t)d * 3072 + ci * 3 + tap];
        __nv_bfloat16 hb, lb; split2(v, hb, lb);
        Wh[idx] = hb; Wl[idx] = lb;
    }
}

__global__ void xsplit(const float* __restrict__ x, __nv_bfloat16* __restrict__ xh,
                       __nv_bfloat16* __restrict__ xl)
{
    const int n = 64 * 256 * 1024;
    for (int i = blockIdx.x * blockDim.x + threadIdx.x; i < n; i += gridDim.x * blockDim.x) {
        __nv_bfloat16 hb, lb; split2(x[i], hb, lb);
        xh[i] = hb; xl[i] = lb;
    }
}

__device__ __forceinline__ float wsum(float v)
{
#pragma unroll
    for (int o = 16; o; o >>= 1) v += __shfl_xor_sync(0xffffffffu, v, o);
    return v;
}

// ===========================================================================
// LayerNorm -> bf16 hi/lo pair (one warp per row)
// ===========================================================================
__global__ void __launch_bounds__(256) ln_kernel(const float* __restrict__ x,
                                                 const float* __restrict__ g,
                                                 const float* __restrict__ bb,
                                                 __nv_bfloat16* __restrict__ yh,
                                                 __nv_bfloat16* __restrict__ yl)
{
    const int w = threadIdx.x >> 5, lane = threadIdx.x & 31;
    const int row = blockIdx.x * 8 + w;
    const float* xr = x + (size_t)row * 512;
    float v[16];
    float s = 0.f;
#pragma unroll
    for (int j = 0; j < 16; j++) { v[j] = xr[lane + 32 * j]; s += v[j]; }
    s = wsum(s);
    const float mean = s * (1.f / 512.f);
    float q = 0.f;
#pragma unroll
    for (int j = 0; j < 16; j++) { float d = v[j] - mean; q += d * d; }
    q = wsum(q);
    const float inv = rsqrtf(q * (1.f / 512.f) + 1e-5f);
#pragma unroll
    for (int j = 0; j < 16; j++) {
        int c = lane + 32 * j;
        float val = (v[j] - mean) * inv * g[c] + bb[c];
        __nv_bfloat16 hb, lb; split2(val, hb, lb);
        yh[(size_t)row * 512 + c] = hb;
        yl[(size_t)row * 512 + c] = lb;
    }
}

// ===========================================================================
// Memory attention v2: 16 rows/block (warp per row), mem staged via smem,
// single pass produces att (top-4 mean) and aug (bf16 pair).
// grid (512, 4 combos), block 512.
// ===========================================================================
__global__ void __launch_bounds__(512) memory_kernel(const float* __restrict__ Nx,
                                                     const float* __restrict__ Ax,
                                                     const float* __restrict__ a_mem,
                                                     const float* __restrict__ n_mem,
                                                     float* __restrict__ att_base,
                                                     __nv_bfloat16* __restrict__ augh_base,
                                                     __nv_bfloat16* __restrict__ augl_base)
{
    __shared__ float mch[20][512];
    const int w = threadIdx.x >> 5, lane = threadIdx.x & 31;
    const int combo = blockIdx.y;       // 0:A(Ax,a) 1:NA(Ax,n) 2:AN(Nx,a) 3:N(Nx,n)
    const int row = blockIdx.x * 16 + w;
    const float* x   = (combo < 2) ? Ax : Nx;
    const float* mem = (combo & 1) ? n_mem : a_mem;
    const int att_off[4] = {0, 24576, 16384, 8192};
    float* att_out = att_base + att_off[combo];
    __nv_bfloat16* augh = augh_base + (size_t)combo * SZ_AUG;
    __nv_bfloat16* augl = augl_base + (size_t)combo * SZ_AUG;

    float xr[16], facc[16];
#pragma unroll
    for (int j = 0; j < 16; j++) {
        xr[j] = x[(size_t)row * 512 + lane + 32 * j];
        facc[j] = 0.f;
    }
    float t0 = -1e30f, t1 = -1e30f, t2 = -1e30f, t3 = -1e30f;

    for (int c = 0; c < 3; c++) {
        for (int i = threadIdx.x; i < 20 * 512; i += 512)
            ((float*)mch)[i] = mem[c * 20 * 512 + i];
        __syncthreads();
#pragma unroll 4
        for (int n = 0; n < 20; n++) {
            float s = 0.f;
#pragma unroll
            for (int j = 0; j < 16; j++) s = fmaf(xr[j], mch[n][lane + 32 * j], s);
            s = wsum(s);
            float att = 1.f / (1.f + expf(-s * 0.044194173824159216f));
            if (att > t0)      { t3 = t2; t2 = t1; t1 = t0; t0 = att; }
            else if (att > t1) { t3 = t2; t2 = t1; t1 = att; }
            else if (att > t2) { t3 = t2; t2 = att; }
            else if (att > t3) { t3 = att; }
#pragma unroll
            for (int j = 0; j < 16; j++)
                facc[j] = fmaf(att, mch[n][lane + 32 * j], facc[j]);
        }
        __syncthreads();
    }

    if (lane == 0) att_out[row] = (t0 + t1 + t2 + t3) * 0.25f;
#pragma unroll
    for (int j = 0; j < 16; j++) {
        __nv_bfloat16 hb, lb; split2(facc[j], hb, lb);
        augh[(size_t)row * 512 + lane + 32 * j] = hb;
        augl[(size_t)row * 512 + lane + 32 * j] = lb;
    }
}

// ===========================================================================
// top-k / losses / misc
// ===========================================================================
__global__ void __launch_bounds__(256) topk_gather(const float* __restrict__ att,
                                                   const float* __restrict__ feats,
                                                   float* __restrict__ meanv,
                                                   int* __restrict__ idx_out)
{
    __shared__ float vals[256], rv[256];
    __shared__ int ri[256], ids[17];
    const int b = blockIdx.x, tid = threadIdx.x;
    vals[tid] = att[b * 256 + tid];
    __syncthreads();
    for (int it = 0; it < 17; it++) {
        rv[tid] = vals[tid]; ri[tid] = tid;
        __syncthreads();
        for (int s = 128; s; s >>= 1) {
            if (tid < s) {
                float ov = rv[tid + s]; int oi = ri[tid + s];
                if (ov > rv[tid] || (ov == rv[tid] && oi < ri[tid])) { rv[tid] = ov; ri[tid] = oi; }
            }
            __syncthreads();
        }
        if (tid == 0) {
            ids[it] = ri[0];
            vals[ri[0]] = -1e30f;
            if (idx_out) idx_out[b * 17 + it] = ri[0];
        }
        __syncthreads();
    }
    for (int d = tid; d < 512; d += 256) {
        float s = 0.f;
        for (int j = 0; j < 17; j++) s += feats[((size_t)b * 256 + ids[j]) * 512 + d];
        meanv[b * 512 + d] = s * (1.f / 17.f);
    }
}

__global__ void __launch_bounds__(1024) triplet_cos_kernel(const float* __restrict__ anchor,
                                                           const float* __restrict__ pos,
                                                           const float* __restrict__ neg,
                                                           float* __restrict__ trip_out,
                                                           float* __restrict__ cos_out)
{
    __shared__ float st[32], sc[32];
    const int w = threadIdx.x >> 5, lane = threadIdx.x & 31;
    float sa = 0, sp = 0, sn = 0, dan = 0;
    for (int d = lane; d < 512; d += 32) {
        float a = anchor[w * 512 + d], p = pos[w * 512 + d], n = neg[w * 512 + d];
        sa += a * a; sp += p * p; sn += n * n; dan += a * n;
    }
    sa = wsum(sa); sp = wsum(sp); sn = wsum(sn); dan = wsum(dan);
    float na = sqrtf(sa), npp = sqrtf(sp), ng = sqrtf(sn);
    float ina = 1.f / na, inp = 1.f / npp, ing = 1.f / ng;
    float dp2 = 0, dn2 = 0;
    for (int d = lane; d < 512; d += 32) {
        float a  = anchor[w * 512 + d] * ina;
        float dpv = a - pos[w * 512 + d] * inp + 1e-6f;
        float dnv = a - neg[w * 512 + d] * ing + 1e-6f;
        dp2 += dpv * dpv; dn2 += dnv * dnv;
    }
    dp2 = wsum(dp2); dn2 = wsum(dn2);
    if (lane == 0) {
        st[w] = fmaxf(sqrtf(dp2) - sqrtf(dn2) + 1.f, 0.f);
        sc[w] = 1.f - dan / (fmaxf(na, 1e-6f) * fmaxf(ng, 1e-6f));
    }
    __syncthreads();
    if (threadIdx.x == 0) {
        float a = 0, c = 0;
        for (int i = 0; i < 32; i++) { a += st[i]; c += sc[i]; }
        trip_out[0] = a * (1.f / 32.f);
        cos_out[0]  = c * (1.f / 32.f);
    }
}

__global__ void __launch_bounds__(1024) distance_kernel(const float* __restrict__ anew,
                                                        const float* __restrict__ nnew,
                                                        float* __restrict__ out)
{
    __shared__ float sd[32];
    const int w = threadIdx.x >> 5, lane = threadIdx.x & 31;
    float sa = 0, sn = 0;
    for (int d = lane; d < 512; d += 32) {
        float a = anew[w * 512 + d], n = nnew[w * 512 + d];
        sa += a * a; sn += n * n;
    }
    sa = wsum(sa); sn = wsum(sn);
    if (lane == 0) sd[w] = fmaxf(100.f - sqrtf(sn) + sqrtf(sa), 0.f);
    __syncthreads();
    if (threadIdx.x == 0) {
        float s = 0;
        for (int i = 0; i < 32; i++) s += sd[i];
        out[0] = s * (1.f / 32.f);
    }
}

__global__ void vae_kernel(const float* __restrict__ mu, const float* __restrict__ var,
                           const float* __restrict__ eps, float* __restrict__ o, int n)
{
    for (int i = blockIdx.x * blockDim.x + threadIdx.x; i < n; i += gridDim.x * blockDim.x)
        o[i] = mu[i] + eps[i] * sqrtf(expf(var[i]));
}

__global__ void __launch_bounds__(256) kl_part_kernel(const float* __restrict__ mu,
                                                      const float* __restrict__ var,
                                                      float* __restrict__ part, int n)
{
    __shared__ float red[256];
    float s = 0.f;
    for (int i = blockIdx.x * 256 + threadIdx.x; i < n; i += gridDim.x * 256) {
        float m = mu[i], v = var[i];
        s += 1.f + v - m * m - expf(v);
    }
    red[threadIdx.x] = s; __syncthreads();
    for (int t = 128; t; t >>= 1) { if (threadIdx.x < t) red[threadIdx.x] += red[threadIdx.x + t]; __syncthreads(); }
    if (threadIdx.x == 0) part[blockIdx.x] = red[0];
}

__global__ void __launch_bounds__(1024) kl_final_kernel(const float* __restrict__ part,
                                                        float* __restrict__ out)
{
    __shared__ float red[1024];
    red[threadIdx.x] = part[threadIdx.x]; __syncthreads();
    for (int t = 512; t; t >>= 1) { if (threadIdx.x < t) red[threadIdx.x] += red[threadIdx.x + t]; __syncthreads(); }
    if (threadIdx.x == 0) out[0] = -0.5f * red[0] * (1.f / 16384.f);
}

__global__ void __launch_bounds__(512) gather_mean_kernel(const float* __restrict__ src,
                                                          const int* __restrict__ idx,
                                                          float* __restrict__ out)
{
    __shared__ int ids[17];
    const int b = blockIdx.x, tid = threadIdx.x;
    if (tid < 17) ids[tid] = idx[b * 17 + tid];
    __syncthreads();
    float s = 0.f;
    for (int j = 0; j < 17; j++) s += src[((size_t)b * 256 + ids[j]) * 512 + tid];
    out[b * 512 + tid] = s * (1.f / 17.f);
}

__global__ void xout_kernel(const float* __restrict__ h, const float* __restrict__ nnew,
                            const float* __restrict__ anm, const float* __restrict__ anew,
                            const float* __restrict__ nam, float* __restrict__ xout)
{
    const int n = 64 * 256 * 1024;
    for (int i = blockIdx.x * blockDim.x + threadIdx.x; i < n; i += gridDim.x * blockDim.x) {
        int c  = i & 1023;
        int rt = i >> 10;
        float v;
        if (c < 512) v = h[(size_t)rt * 512 + c];
        else {
            int cc = c - 512;
            if (rt < 8192) v = nnew[(size_t)rt * 512 + cc] + anm[(size_t)rt * 512 + cc];
            else {
                size_t o = (size_t)(rt - 8192) * 512 + cc;
                v = anew[o] + nam[o];
            }
        }
        xout[i] = v;
    }
}

__global__ void vfeat_kernel(const float* __restrict__ h, float* __restrict__ v)
{
    __shared__ float tile[32][33];
    const int b = blockIdx.x, d0 = blockIdx.y * 32, t0 = blockIdx.z * 32;
    for (int r = threadIdx.y; r < 32; r += 8)
        tile[r][threadIdx.x] = h[((size_t)b * 256 + t0 + r) * 512 + d0 + threadIdx.x];
    __syncthreads();
    for (int r = threadIdx.y; r < 32; r += 8)
        v[((size_t)b * 512 + d0 + r) * 256 + t0 + threadIdx.x] = tile[threadIdx.x][r];
}

// ===========================================================================
extern "C" void kernel_launch(void* const* d_in, const int* in_sizes, int n_in,
                              void* d_out, int out_size)
{
    const float* x      = (const float*)d_in[0];
    const float* eps_in = (const float*)d_in[1];
    const float* conv_w = (const float*)d_in[2];
    const float* conv_b = (const float*)d_in[3];
    const float* ln1_g  = (const float*)d_in[4];
    const float* ln1_b  = (const float*)d_in[5];
    const float* qkv_w  = (const float*)d_in[6];
    const float* out_w  = (const float*)d_in[7];
    const float* out_b  = (const float*)d_in[8];
    const float* ln2_g  = (const float*)d_in[9];
    const float* ln2_b  = (const float*)d_in[10];
    const float* ff1_w  = (const float*)d_in[11];
    const float* ff1_b  = (const float*)d_in[12];
    const float* ff2_w  = (const float*)d_in[13];
    const float* ff2_b  = (const float*)d_in[14];
    const float* a_mem  = (const float*)d_in[15];
    const float* n_mem  = (const float*)d_in[16];
    const float* mu_w   = (const float*)d_in[17];
    const float* mu_b   = (const float*)d_in[18];
    const float* var_w  = (const float*)d_in[19];
    const float* var_b  = (const float*)d_in[20];
    float* out = (float*)d_out;

    float* S = nullptr;
    cudaGetSymbolAddress((void**)&S, g_scratch);
    __nv_bfloat16* BF = nullptr;
    cudaGetSymbolAddress((void**)&BF, g_bf);

    float* h     = S + OFF_H;
    float* sc    = S + OFF_SC;
    float* stack = S + OFF_STACK;
    float* Anew  = stack;
    float* NAm   = stack + 1ull * 8192 * 512;
    float* ANm   = stack + 2ull * 8192 * 512;
    float* muB   = stack + 3ull * 8192 * 512;
    float* varB  = S + OFF_VAR;
    float* newN  = S + OFF_NEW;
    float* anch  = S + OFF_ANCH;
    float* negv  = S + OFF_NEG;
    float* posv  = S + OFF_POS;
    float* anchN = S + OFF_ANCHN;
    float* negN  = S + OFF_NEGN;
    int*   idxA  = (int*)(S + OFF_IDXA);
    int*   idxN  = (int*)(S + OFF_IDXN);
    float* klp   = S + OFF_KLP;

    __nv_bfloat16* lnh = BF + B_LNH;  __nv_bfloat16* lnl = BF + B_LNL;
    __nv_bfloat16* aoh = BF + B_AOH;  __nv_bfloat16* aol = BF + B_AOL;
    __nv_bfloat16* ffh = BF + B_FFH;  __nv_bfloat16* ffl = BF + B_FFL;
    __nv_bfloat16* qkvh = BF + B_QKVH; __nv_bfloat16* qkvl = BF + B_QKVL;
    __nv_bfloat16* ph = BF + B_PH;     __nv_bfloat16* pl = BF + B_PL;
    __nv_bfloat16* vth = BF + B_VTH;   __nv_bfloat16* vtl = BF + B_VTL;
    __nv_bfloat16* xh = BF + B_XH;     __nv_bfloat16* xl = BF + B_XL;

    constexpr int MG_SMEM = 81920;
    cudaFuncSetAttribute(mgemm<0,false>, cudaFuncAttributeMaxDynamicSharedMemorySize, MG_SMEM);
    cudaFuncSetAttribute(mgemm<1,false>, cudaFuncAttributeMaxDynamicSharedMemorySize, MG_SMEM);
    cudaFuncSetAttribute(mgemm<2,false>, cudaFuncAttributeMaxDynamicSharedMemorySize, MG_SMEM);
    cudaFuncSetAttribute(mgemm<3,false>, cudaFuncAttributeMaxDynamicSharedMemorySize, MG_SMEM);
    cudaFuncSetAttribute(mgemm<5,false>, cudaFuncAttributeMaxDynamicSharedMemorySize, MG_SMEM);
    cudaFuncSetAttribute(mgemm<4,true>,  cudaFuncAttributeMaxDynamicSharedMemorySize, MG_SMEM);

    // 1-3: prep
    convprep<<<1024, 256>>>(conv_w, BF + B_CNVWH, BF + B_CNVWL);
    xsplit<<<8192, 256>>>(x, xh, xl);
    wprep_t<<<dim3(16, 48), dim3(32, 8)>>>(qkv_w, BF + B_QKVWH, BF + B_QKVWL, 512, 1536);

    // 4: conv (implicit im2col, relu+bias), pipelined
    mgemm<4, true><<<dim3(4, 128), 256, MG_SMEM>>>(
        xh, xl, BF + B_CNVWH, BF + B_CNVWL,
        h, nullptr, nullptr, conv_b, 16384, 512, 3072);

    // 5: ln (layer 0)
    ln_kernel<<<2048, 256>>>(h, ln1_g, ln1_b, lnh, lnl);

    // 6: qkv mgemm (layer 0) — profiler candidate
    mgemm<5, false><<<dim3(12, 128), 256, MG_SMEM>>>(
        lnh, lnl, BF + B_QKVWH, BF + B_QKVWL,
        nullptr, qkvh, qkvl, nullptr, 16384, 1536, 512);

    // remaining weight prep
    wprep_t<<<dim3(16, 16), dim3(32, 8)>>>(out_w, BF + B_OUTWH, BF + B_OUTWL, 512, 512);
    wprep_t<<<dim3(16, 16), dim3(32, 8)>>>(ff1_w, BF + B_FF1WH, BF + B_FF1WL, 512, 512);
    wprep_t<<<dim3(16, 16), dim3(32, 8)>>>(ff2_w, BF + B_FF2WH, BF + B_FF2WL, 512, 512);
    wprep_t<<<dim3(16, 48), dim3(32, 8)>>>(qkv_w + 786432,
                                           BF + B_QKVWH + 786432, BF + B_QKVWL + 786432, 512, 1536);
    wprep_t<<<dim3(16, 16), dim3(32, 8)>>>(out_w + 262144,
                                           BF + B_OUTWH + 262144, BF + B_OUTWL + 262144, 512, 512);
    wprep_t<<<dim3(16, 16), dim3(32, 8)>>>(ff1_w + 262144,
                                           BF + B_FF1WH + 262144, BF + B_FF1WL + 262144, 512, 512);
    wprep_t<<<dim3(16, 16), dim3(32, 8)>>>(ff2_w + 262144,
                                           BF + B_FF2WH + 262144, BF + B_FF2WL + 262144, 512, 512);
    wprep_t<<<dim3(16, 16), dim3(32, 8)>>>(mu_w,  BF + B_MUWH,  BF + B_MUWL,  512, 512);
    wprep_t<<<dim3(16, 16), dim3(32, 8)>>>(var_w, BF + B_VARWH, BF + B_VARWL, 512, 512);

    // ---- transformer (layer 0 continues, then layer 1)
    for (int i = 0; i < 2; i++) {
        if (i == 1) {
            ln_kernel<<<2048, 256>>>(h, ln1_g + 512, ln1_b + 512, lnh, lnl);
            mgemm<5, false><<<dim3(12, 128), 256, MG_SMEM>>>(
                lnh, lnl, BF + B_QKVWH + 786432, BF + B_QKVWL + 786432,
                nullptr, qkvh, qkvl, nullptr, 16384, 1536, 512);
        }
        vtrans_kernel<<<dim3(256, 4, 8), dim3(32, 8)>>>(qkvh, qkvl, vth, vtl);
        bqk_kernel<<<dim3(2, 2, 256), 256>>>(qkvh, qkvl, sc);
        softmaxp_kernel<<<8192, 256>>>(sc, ph, pl);
        bpv_kernel<<<dim3(2, 1, 256), 256>>>(ph, pl, vth, vtl, aoh, aol);
        mgemm<2, false><<<dim3(4, 128), 256, MG_SMEM>>>(
            aoh, aol, BF + B_OUTWH + (size_t)i * 262144, BF + B_OUTWL + (size_t)i * 262144,
            h, nullptr, nullptr, out_b + i * 512, 16384, 512, 512);
        ln_kernel<<<2048, 256>>>(h, ln2_g + i * 512, ln2_b + i * 512, lnh, lnl);
        mgemm<3, false><<<dim3(4, 128), 256, MG_SMEM>>>(
            lnh, lnl, BF + B_FF1WH + (size_t)i * 262144, BF + B_FF1WL + (size_t)i * 262144,
            nullptr, ffh, ffl, ff1_b + i * 512, 16384, 512, 512);
        mgemm<2, false><<<dim3(4, 128), 256, MG_SMEM>>>(
            ffh, ffl, BF + B_FF2WH + (size_t)i * 262144, BF + B_FF2WL + (size_t)i * 262144,
            h, nullptr, nullptr, ff2_b + i * 512, 16384, 512, 512);
    }

    const float* Nx = h;                       // x_emb[:32]
    const float* Ax = h + (size_t)8192 * 512;  // x_emb[32:]

    memory_kernel<<<dim3(512, 4), 512>>>(Nx, Ax, a_mem, n_mem,
                                         out + O_AATT, BF + B_AUGH, BF + B_AUGL);

    topk_gather<<<32, 256>>>(out + O_AATT,  Ax, negv, idxA);
    topk_gather<<<32, 256>>>(out + O_NATT,  Nx, anch, idxN);
    topk_gather<<<32, 256>>>(out + O_NAATT, Ax, posv, nullptr);

    triplet_cos_kernel<<<1, 1024>>>(anch, posv, negv, out + O_TRIP, out + O_COS);

    // stacked mu projection: [augA; augNA; augAN; augN] @ mu -> [Anew; NAm; ANm; muB]
    mgemm<1, false><<<dim3(4, 256), 256, MG_SMEM>>>(
        BF + B_AUGH, BF + B_AUGL, BF + B_MUWH, BF + B_MUWL,
        stack, nullptr, nullptr, mu_b, 32768, 512, 512);
    mgemm<1, false><<<dim3(4, 64), 256, MG_SMEM>>>(
        BF + B_AUGH + 3 * SZ_AUG, BF + B_AUGL + 3 * SZ_AUG,
        BF + B_VARWH, BF + B_VARWL, varB, nullptr, nullptr, var_b, 8192, 512, 512);

    vae_kernel<<<4096, 256>>>(muB, varB, eps_in, newN, 8192 * 512);
    kl_part_kernel<<<1024, 256>>>(muB, varB, klp, 8192 * 512);
    kl_final_kernel<<<1, 1024>>>(klp, out + O_KL);

    gather_mean_kernel<<<32, 512>>>(newN, idxN, anchN);
    gather_mean_kernel<<<32, 512>>>(Anew, idxA, negN);
    distance_kernel<<<1, 1024>>>(anchN, negN, out + O_DIST);

    xout_kernel<<<8192, 256>>>(h, newN, ANm, Anew, NAm, out + O_XOUT);
    vfeat_kernel<<<dim3(64, 16, 8), dim3(32, 8)>>>(h, out + O_VFEAT);
}

// round 11
// speedup vs baseline: 3.0147x; 1.0131x over previous
#include <cuda_runtime.h>
#include <cuda_bf16.h>
#include <math.h>
#include <stdint.h>

// ===========================================================================
// fp32 scratch
// ===========================================================================
constexpr size_t OFF_H     = 0;                         // 16384*512
constexpr size_t OFF_SC    = 8388608;                   // 256*256*256 (S fp32)
constexpr size_t OFF_STACK = OFF_SC + 16777216;         // 32768*512: Anew,NAm,ANm,muB
constexpr size_t OFF_VAR   = OFF_STACK + 16777216;      // 8192*512
constexpr size_t OFF_NEW   = OFF_VAR + 4194304;         // 8192*512
constexpr size_t OFF_ANCH  = OFF_NEW + 4194304;         // 32*512 each below
constexpr size_t OFF_NEG   = OFF_ANCH + 16384;
constexpr size_t OFF_POS   = OFF_NEG  + 16384;
constexpr size_t OFF_ANCHN = OFF_POS  + 16384;
constexpr size_t OFF_NEGN  = OFF_ANCHN + 16384;
constexpr size_t OFF_IDXA  = OFF_NEGN + 16384;
constexpr size_t OFF_IDXN  = OFF_IDXA + 1024;
constexpr size_t OFF_KLP   = OFF_IDXN + 1024;
constexpr size_t SCRATCH_TOTAL = OFF_KLP + 1024;
__device__ float g_scratch[SCRATCH_TOTAL];

// ===========================================================================
// bf16 scratch
// ===========================================================================
constexpr size_t SZ_TOK  = 16384ull * 512;
constexpr size_t SZ_QKV  = 16384ull * 1536;
constexpr size_t SZ_P    = 256ull * 65536;
constexpr size_t SZ_VT   = 256ull * 32768;
constexpr size_t SZ_AUG  = 8192ull * 512;
constexpr size_t SZ_X    = 64ull * 256 * 1024;   // 16777216

constexpr size_t B_LNH  = 0;
constexpr size_t B_LNL  = B_LNH + SZ_TOK;
constexpr size_t B_AOH  = B_LNL + SZ_TOK;
constexpr size_t B_AOL  = B_AOH + SZ_TOK;
constexpr size_t B_FFH  = B_AOL + SZ_TOK;
constexpr size_t B_FFL  = B_FFH + SZ_TOK;
constexpr size_t B_QKVH = B_FFL + SZ_TOK;
constexpr size_t B_QKVL = B_QKVH + SZ_QKV;
constexpr size_t B_PH   = B_QKVL + SZ_QKV;
constexpr size_t B_PL   = B_PH + SZ_P;
constexpr size_t B_VTH  = B_PL + SZ_P;
constexpr size_t B_VTL  = B_VTH + SZ_VT;
constexpr size_t B_AUGH = B_VTL + SZ_VT;      // [A, NA, AN, N] stacked
constexpr size_t B_AUGL = B_AUGH + 4 * SZ_AUG;
constexpr size_t B_QKVWH = B_AUGL + 4 * SZ_AUG;
constexpr size_t B_QKVWL = B_QKVWH + 2ull * 786432;
constexpr size_t B_OUTWH = B_QKVWL + 2ull * 786432;
constexpr size_t B_OUTWL = B_OUTWH + 2ull * 262144;
constexpr size_t B_FF1WH = B_OUTWL + 2ull * 262144;
constexpr size_t B_FF1WL = B_FF1WH + 2ull * 262144;
constexpr size_t B_FF2WH = B_FF1WL + 2ull * 262144;
constexpr size_t B_FF2WL = B_FF2WH + 2ull * 262144;
constexpr size_t B_MUWH  = B_FF2WL + 2ull * 262144;
constexpr size_t B_MUWL  = B_MUWH + 262144;
constexpr size_t B_VARWH = B_MUWL + 262144;
constexpr size_t B_VARWL = B_VARWH + 262144;
constexpr size_t B_CNVWH = B_VARWL + 262144;
constexpr size_t B_CNVWL = B_CNVWH + 1572864;
constexpr size_t B_XH    = B_CNVWL + 1572864;
constexpr size_t B_XL    = B_XH + SZ_X;
constexpr size_t BF_TOTAL = B_XL + SZ_X;
__device__ __nv_bfloat16 g_bf[BF_TOTAL];

__device__ __align__(16) __nv_bfloat16 g_zero[8];   // zero-initialized

// output offsets (triplet, kl, distance, A_att, N_att, A_Natt, N_Aatt, cos, x_out, v_feat)
constexpr size_t O_TRIP  = 0;
constexpr size_t O_KL    = 1;
constexpr size_t O_DIST  = 2;
constexpr size_t O_AATT  = 3;
constexpr size_t O_NATT  = 3 + 8192;
constexpr size_t O_ANATT = 3 + 16384;
constexpr size_t O_NAATT = 3 + 24576;
constexpr size_t O_COS   = 3 + 32768;
constexpr size_t O_XOUT  = 4 + 32768;
constexpr size_t O_VFEAT = O_XOUT + 64ull * 256 * 1024;

// ===========================================================================
// mma / smem helpers
// ===========================================================================
__device__ __forceinline__ void mma16816(float* c, const uint32_t* a, const uint32_t* b)
{
    asm volatile(
        "mma.sync.aligned.m16n8k16.row.col.f32.bf16.bf16.f32 "
        "{%0,%1,%2,%3}, {%4,%5,%6,%7}, {%8,%9}, {%0,%1,%2,%3};"
        : "+f"(c[0]), "+f"(c[1]), "+f"(c[2]), "+f"(c[3])
        : "r"(a[0]), "r"(a[1]), "r"(a[2]), "r"(a[3]), "r"(b[0]), "r"(b[1]));
}

__device__ __forceinline__ void split2(float v, __nv_bfloat16& h, __nv_bfloat16& l) {
    h = __float2bfloat16(v);
    l = __float2bfloat16(v - __bfloat162float(h));
}

__device__ __forceinline__ uint32_t cvt_smem(const void* p) {
    uint32_t a;
    asm("{ .reg .u64 t; cvta.to.shared.u64 t, %1; cvt.u32.u64 %0, t; }" : "=r"(a) : "l"(p));
    return a;
}

#define LDSM4(r0, r1, r2, r3, a) \
    asm volatile("ldmatrix.sync.aligned.m8n8.x4.shared.b16 {%0,%1,%2,%3}, [%4];" \
        : "=r"(r0), "=r"(r1), "=r"(r2), "=r"(r3) : "r"(a))

#define CP16(sa, gp) \
    asm volatile("cp.async.cg.shared.global [%0], [%1], 16;" :: "r"(sa), "l"(gp))
#define CP_COMMIT() asm volatile("cp.async.commit_group;" ::: "memory")
#define CP_WAIT1()  asm volatile("cp.async.wait_group 1;" ::: "memory")
#define CP_WAIT0()  asm volatile("cp.async.wait_group 0;" ::: "memory")

// one stage layout (bytes): Ah @0, Al @10240, Bh @20480, Bl @30720; rows pad 40 elem (80B)
constexpr uint32_t SM_AL = 10240, SM_BH = 20480, SM_BL = 30720;
constexpr uint32_t STAGE_BYTES = 40960;

// 128x32 tile MMA via ldmatrix + 3-term split.
// Term-grouped ordering: 16x hh, 16x hl, 16x lh — accumulator reuse distance 16
// (vs 1 in the naive pairing) so dependent HMMAs run at pipe throughput.
__device__ __forceinline__ void mma_tile_ldsm(uint32_t sb, float acc[4][4][4],
                                              int arow, int acolB, int brow, int bcolB)
{
#pragma unroll
    for (int ks = 0; ks < 32; ks += 16) {
        uint32_t fa[4][4], fbh[4][2], fbl[4][2];
#pragma unroll
        for (int mi = 0; mi < 4; mi++) {
            uint32_t ad = sb + (uint32_t)((arow + mi * 16) * 80 + (ks + acolB) * 2);
            LDSM4(fa[mi][0], fa[mi][1], fa[mi][2], fa[mi][3], ad);
        }
#pragma unroll
        for (int np = 0; np < 2; np++) {
            uint32_t bd = sb + SM_BH + (uint32_t)((brow + np * 16) * 80 + (ks + bcolB) * 2);
            LDSM4(fbh[np * 2][0], fbh[np * 2][1], fbh[np * 2 + 1][0], fbh[np * 2 + 1][1], bd);
            LDSM4(fbl[np * 2][0], fbl[np * 2][1], fbl[np * 2 + 1][0], fbl[np * 2 + 1][1],
                  bd + (SM_BL - SM_BH));
        }
        // term 1: hh (16 independent MMAs)
#pragma unroll
        for (int mi = 0; mi < 4; mi++)
#pragma unroll
            for (int ni = 0; ni < 4; ni++)
                mma16816(acc[mi][ni], fa[mi], fbh[ni]);
        // term 2: hl (A-hi x B-lo)
#pragma unroll
        for (int mi = 0; mi < 4; mi++)
#pragma unroll
            for (int ni = 0; ni < 4; ni++)
                mma16816(acc[mi][ni], fa[mi], fbl[ni]);
        // reload A-lo, term 3: lh
#pragma unroll
        for (int mi = 0; mi < 4; mi++) {
            uint32_t ad = sb + SM_AL + (uint32_t)((arow + mi * 16) * 80 + (ks + acolB) * 2);
            LDSM4(fa[mi][0], fa[mi][1], fa[mi][2], fa[mi][3], ad);
        }
#pragma unroll
        for (int mi = 0; mi < 4; mi++)
#pragma unroll
            for (int ni = 0; ni < 4; ni++)
                mma16816(acc[mi][ni], fa[mi], fbh[ni]);
    }
}

// stage one 128x32 K-chunk (A hi/lo + B hi/lo) via cp.async; CONV = im2col A
template<bool CONV>
__device__ __forceinline__ void stage_chunk(
    uint32_t sdst,
    const __nv_bfloat16* __restrict__ Ah, const __nv_bfloat16* __restrict__ Al,
    const __nv_bfloat16* __restrict__ Bh, const __nv_bfloat16* __restrict__ Bl,
    const __nv_bfloat16* zb, int row0, int col0, int K, int kc, int tid)
{
#pragma unroll
    for (int i = 0; i < 2; i++) {
        int chunk = tid * 2 + i;
        int rr = chunk >> 2, sg = chunk & 3;
        uint32_t so = (uint32_t)(rr * 80 + sg * 16);
        const __nv_bfloat16 *pah, *pal;
        if (CONV) {
            int gk = kc * 32 + sg * 8;
            int tap = gk >> 10, ci = gk & 1023;
            int m = row0 + rr;
            int t2 = (m & 255) + tap - 1;
            if (t2 >= 0 && t2 < 256) {
                size_t o = ((size_t)((m >> 8) * 256 + t2)) * 1024 + ci;
                pah = Ah + o; pal = Al + o;
            } else { pah = zb; pal = zb; }
        } else {
            size_t oa = (size_t)(row0 + rr) * K + kc * 32 + sg * 8;
            pah = Ah + oa; pal = Al + oa;
        }
        CP16(sdst + so,         pah);
        CP16(sdst + SM_AL + so, pal);
        size_t ob = (size_t)(col0 + rr) * K + kc * 32 + sg * 8;
        CP16(sdst + SM_BH + so, Bh + ob);
        CP16(sdst + SM_BL + so, Bl + ob);
    }
    CP_COMMIT();
}

// ===========================================================================
// HMMA GEMM, cp.async double-buffered (all paths incl. conv-im2col)
// EPI: 0=none,1=+bias,2=+bias+residual,3=+bias+gelu->pair,4=+bias+relu,5=->pair
// ===========================================================================
template<int EPI, bool CONV>
__global__ void __launch_bounds__(256, 2) mgemm(
    const __nv_bfloat16* __restrict__ Ah, const __nv_bfloat16* __restrict__ Al,
    const __nv_bfloat16* __restrict__ Bh, const __nv_bfloat16* __restrict__ Bl,
    float* __restrict__ C,
    __nv_bfloat16* __restrict__ Chi, __nv_bfloat16* __restrict__ Clo,
    const float* __restrict__ bias,
    int M, int N, int K)
{
    extern __shared__ char smem[];
    const int tid  = threadIdx.x;
    const int wid  = tid >> 5;
    const int lane = tid & 31;
    const int g = lane >> 2, t = lane & 3;
    const int wm = wid >> 2, wn = wid & 3;
    const int row0 = blockIdx.y * 128;
    const int col0 = blockIdx.x * 128;
    const uint32_t sb0 = cvt_smem(smem);

    const int arow  = wm * 64 + (lane & 7) + ((lane >> 3) & 1) * 8;
    const int acolB = ((lane >> 4) & 1) * 8;
    const int brow  = wn * 32 + ((lane >> 4) & 1) * 8 + (lane & 7);
    const int bcolB = ((lane >> 3) & 1) * 8;

    float acc[4][4][4];
#pragma unroll
    for (int mi = 0; mi < 4; mi++)
#pragma unroll
        for (int ni = 0; ni < 4; ni++)
#pragma unroll
            for (int q = 0; q < 4; q++) acc[mi][ni][q] = 0.f;

    const int nchunks = K >> 5;

    stage_chunk<CONV>(sb0, Ah, Al, Bh, Bl, g_zero, row0, col0, K, 0, tid);

    for (int kc = 0; kc < nchunks; kc++) {
        const uint32_t sb = sb0 + (uint32_t)(kc & 1) * STAGE_BYTES;
        if (kc + 1 < nchunks) {
            const uint32_t sn = sb0 + (uint32_t)((kc + 1) & 1) * STAGE_BYTES;
            stage_chunk<CONV>(sn, Ah, Al, Bh, Bl, g_zero, row0, col0, K, kc + 1, tid);
            CP_WAIT1();
        } else {
            CP_WAIT0();
        }
        __syncthreads();
        mma_tile_ldsm(sb, acc, arow, acolB, brow, bcolB);
        __syncthreads();
    }

#pragma unroll
    for (int mi = 0; mi < 4; mi++) {
#pragma unroll
        for (int ni = 0; ni < 4; ni++) {
#pragma unroll
            for (int q = 0; q < 4; q++) {
                int r = row0 + wm * 64 + mi * 16 + g + (q >> 1) * 8;
                int c = col0 + wn * 32 + ni * 8 + t * 2 + (q & 1);
                float v = acc[mi][ni][q];
                size_t o = (size_t)r * N + c;
                if (EPI != 0 && EPI != 5) v += bias[c];
                if (EPI == 2) v += C[o];
                if (EPI == 3 || EPI == 5) {
                    if (EPI == 3) v = 0.5f * v * (1.f + erff(v * 0.70710678118654752f));
                    __nv_bfloat16 hb, lb; split2(v, hb, lb);
                    Chi[o] = hb; Clo[o] = lb;
                } else {
                    if (EPI == 4) v = fmaxf(v, 0.f);
                    C[o] = v;
                }
            }
        }
    }
}

// ===========================================================================
// Batched QK^T  (static 40KB single-stage, ldmatrix core)
// ===========================================================================
__global__ void __launch_bounds__(256, 2) bqk_kernel(
    const __nv_bfloat16* __restrict__ Qh, const __nv_bfloat16* __restrict__ Ql,
    float* __restrict__ S)
{
    __shared__ alignas(16) char smem[40960];
    const int tid  = threadIdx.x;
    const int wid  = tid >> 5;
    const int lane = tid & 31;
    const int g = lane >> 2, t = lane & 3;
    const int wm = wid >> 2, wn = wid & 3;
    const int bh = blockIdx.z, b = bh >> 2, h = bh & 3;
    const int i0 = blockIdx.x * 128, j0 = blockIdx.y * 128;
    const __nv_bfloat16* Ah = Qh + (size_t)b * 256 * 1536 + h * 128;
    const __nv_bfloat16* Al = Ql + (size_t)b * 256 * 1536 + h * 128;
    const uint32_t sb = cvt_smem(smem);

    const int arow  = wm * 64 + (lane & 7) + ((lane >> 3) & 1) * 8;
    const int acolB = ((lane >> 4) & 1) * 8;
    const int brow  = wn * 32 + ((lane >> 4) & 1) * 8 + (lane & 7);
    const int bcolB = ((lane >> 3) & 1) * 8;

    float acc[4][4][4];
#pragma unroll
    for (int mi = 0; mi < 4; mi++)
#pragma unroll
        for (int ni = 0; ni < 4; ni++)
#pragma unroll
            for (int q = 0; q < 4; q++) acc[mi][ni][q] = 0.f;

    for (int kc = 0; kc < 4; kc++) {
#pragma unroll
        for (int i = 0; i < 2; i++) {
            int chunk = tid * 2 + i;
            int rr = chunk >> 2, sg = chunk & 3;
            uint32_t so = (uint32_t)(rr * 80 + sg * 16);
            size_t oa = (size_t)(i0 + rr) * 1536 + kc * 32 + sg * 8;
            size_t ob = (size_t)(j0 + rr) * 1536 + 512 + kc * 32 + sg * 8;
            *(uint4*)(smem + so)         = *(const uint4*)(Ah + oa);
            *(uint4*)(smem + SM_AL + so) = *(const uint4*)(Al + oa);
            *(uint4*)(smem + SM_BH + so) = *(const uint4*)(Ah + ob);
            *(uint4*)(smem + SM_BL + so) = *(const uint4*)(Al + ob);
        }
        __syncthreads();
        mma_tile_ldsm(sb, acc, arow, acolB, brow, bcolB);
        __syncthreads();
    }

    float* so2 = S + (size_t)bh * 65536;
    const float scale = 0.08838834764831845f;
#pragma unroll
    for (int mi = 0; mi < 4; mi++)
#pragma unroll
        for (int ni = 0; ni < 4; ni++)
#pragma unroll
            for (int q = 0; q < 4; q++) {
                int r = i0 + wm * 64 + mi * 16 + g + (q >> 1) * 8;
                int c = j0 + wn * 32 + ni * 8 + t * 2 + (q & 1);
                so2[(size_t)r * 256 + c] = acc[mi][ni][q] * scale;
            }
}

// row softmax -> bf16 pair
__global__ void __launch_bounds__(256) softmaxp_kernel(const float* __restrict__ S,
                                                       __nv_bfloat16* __restrict__ Ph,
                                                       __nv_bfloat16* __restrict__ Pl)
{
    const int row  = blockIdx.x * 8 + (threadIdx.x >> 5);
    const int lane = threadIdx.x & 31;
    const float* p = S + (size_t)row * 256;
    float v[8]; float mx = -1e30f;
#pragma unroll
    for (int j = 0; j < 8; j++) { v[j] = p[lane + 32 * j]; mx = fmaxf(mx, v[j]); }
#pragma unroll
    for (int o = 16; o; o >>= 1) mx = fmaxf(mx, __shfl_xor_sync(0xffffffffu, mx, o));
    float s = 0.f;
#pragma unroll
    for (int j = 0; j < 8; j++) { v[j] = expf(v[j] - mx); s += v[j]; }
#pragma unroll
    for (int o = 16; o; o >>= 1) s += __shfl_xor_sync(0xffffffffu, s, o);
    const float inv = 1.f / s;
#pragma unroll
    for (int j = 0; j < 8; j++) {
        __nv_bfloat16 hb, lb; split2(v[j] * inv, hb, lb);
        Ph[(size_t)row * 256 + lane + 32 * j] = hb;
        Pl[(size_t)row * 256 + lane + 32 * j] = lb;
    }
}

// V transpose
__global__ void vtrans_kernel(const __nv_bfloat16* __restrict__ Vh,
                              const __nv_bfloat16* __restrict__ Vl,
                              __nv_bfloat16* __restrict__ vth,
                              __nv_bfloat16* __restrict__ vtl)
{
    __shared__ __nv_bfloat16 th[32][33], tl[32][33];
    const int bh = blockIdx.x, b = bh >> 2, h = bh & 3;
    const int d0 = blockIdx.y * 32, j0 = blockIdx.z * 32;
    const int tx = threadIdx.x, ty = threadIdx.y;
    const size_t base = (size_t)b * 256 * 1536 + 1024 + h * 128;
    for (int r = ty; r < 32; r += 8) {
        size_t o = base + (size_t)(j0 + r) * 1536 + d0 + tx;
        th[r][tx] = Vh[o]; tl[r][tx] = Vl[o];
    }
    __syncthreads();
    const size_t obase = (size_t)bh * 32768;
    for (int r = ty; r < 32; r += 8) {
        size_t o = obase + (size_t)(d0 + r) * 256 + j0 + tx;
        vth[o] = th[tx][r]; vtl[o] = tl[tx][r];
    }
}

// Batched PV
__global__ void __launch_bounds__(256, 2) bpv_kernel(
    const __nv_bfloat16* __restrict__ Ph, const __nv_bfloat16* __restrict__ Pl,
    const __nv_bfloat16* __restrict__ vth, const __nv_bfloat16* __restrict__ vtl,
    __nv_bfloat16* __restrict__ Oh, __nv_bfloat16* __restrict__ Ol)
{
    __shared__ alignas(16) char smem[40960];
    const int tid  = threadIdx.x;
    const int wid  = tid >> 5;
    const int lane = tid & 31;
    const int g = lane >> 2, t = lane & 3;
    const int wm = wid >> 2, wn = wid & 3;
    const int bh = blockIdx.z, b = bh >> 2, h = bh & 3;
    const int i0 = blockIdx.x * 128;
    const __nv_bfloat16* Ah = Ph + (size_t)bh * 65536 + (size_t)i0 * 256;
    const __nv_bfloat16* Al = Pl + (size_t)bh * 65536 + (size_t)i0 * 256;
    const __nv_bfloat16* Bh = vth + (size_t)bh * 32768;
    const __nv_bfloat16* Bl = vtl + (size_t)bh * 32768;
    const uint32_t sb = cvt_smem(smem);

    const int arow  = wm * 64 + (lane & 7) + ((lane >> 3) & 1) * 8;
    const int acolB = ((lane >> 4) & 1) * 8;
    const int brow  = wn * 32 + ((lane >> 4) & 1) * 8 + (lane & 7);
    const int bcolB = ((lane >> 3) & 1) * 8;

    float acc[4][4][4];
#pragma unroll
    for (int mi = 0; mi < 4; mi++)
#pragma unroll
        for (int ni = 0; ni < 4; ni++)
#pragma unroll
            for (int q = 0; q < 4; q++) acc[mi][ni][q] = 0.f;

    for (int kc = 0; kc < 8; kc++) {
#pragma unroll
        for (int i = 0; i < 2; i++) {
            int chunk = tid * 2 + i;
            int rr = chunk >> 2, sg = chunk & 3;
            uint32_t so = (uint32_t)(rr * 80 + sg * 16);
            size_t oa = (size_t)rr * 256 + kc * 32 + sg * 8;
            *(uint4*)(smem + so)         = *(const uint4*)(Ah + oa);
            *(uint4*)(smem + SM_AL + so) = *(const uint4*)(Al + oa);
            *(uint4*)(smem + SM_BH + so) = *(const uint4*)(Bh + oa);
            *(uint4*)(smem + SM_BL + so) = *(const uint4*)(Bl + oa);
        }
        __syncthreads();
        mma_tile_ldsm(sb, acc, arow, acolB, brow, bcolB);
        __syncthreads();
    }

#pragma unroll
    for (int mi = 0; mi < 4; mi++)
#pragma unroll
        for (int ni = 0; ni < 4; ni++)
#pragma unroll
            for (int q = 0; q < 4; q++) {
                int r = i0 + wm * 64 + mi * 16 + g + (q >> 1) * 8;
                int c = wn * 32 + ni * 8 + t * 2 + (q & 1);
                size_t o = ((size_t)b * 256 + r) * 512 + h * 128 + c;
                __nv_bfloat16 hb, lb; split2(acc[mi][ni][q], hb, lb);
                Oh[o] = hb; Ol[o] = lb;
            }
}

// ===========================================================================
// Prep kernels
// ===========================================================================
__global__ void wprep_t(const float* __restrict__ W, __nv_bfloat16* __restrict__ Wh,
                        __nv_bfloat16* __restrict__ Wl, int K, int N)
{
    __shared__ float tile[32][33];
    const int k0 = blockIdx.x * 32, n0 = blockIdx.y * 32;
    const int tx = threadIdx.x, ty = threadIdx.y;
    for (int r = ty; r < 32; r += 8)
        tile[r][tx] = W[(size_t)(k0 + r) * N + n0 + tx];
    __syncthreads();
    for (int r = ty; r < 32; r += 8) {
        float v = tile[tx][r];
        size_t o = (size_t)(n0 + r) * K + k0 + tx;
        __nv_bfloat16 hb, lb; split2(v, hb, lb);
        Wh[o] = hb; Wl[o] = lb;
    }
}

__global__ void convprep(const float* __restrict__ w, __nv_bfloat16* __restrict__ Wh,
                         __nv_bfloat16* __restrict__ Wl)
{
    const int n = 512 * 3072;
    for (int idx = blockIdx.x * blockDim.x + threadIdx.x; idx < n; idx += gridDim.x * blockDim.x) {
        int d = idx / 3072, k = idx % 3072;
        int tap = k >> 10, ci = k & 1023;
        float v = w[(size_t)d * 3072 + ci * 3 + tap];
        __nv_bfloat16 hb, lb; split2(v, hb, lb);
        Wh[idx] = hb; Wl[idx] = lb;
    }
}

__global__ void xsplit(const float* __restrict__ x, __nv_bfloat16* __restrict__ xh,
                       __nv_bfloat16* __restrict__ xl)
{
    const int n = 64 * 256 * 1024;
    for (int i = blockIdx.x * blockDim.x + threadIdx.x; i < n; i += gridDim.x * blockDim.x) {
        __nv_bfloat16 hb, lb; split2(x[i], hb, lb);
        xh[i] = hb; xl[i] = lb;
    }
}

__device__ __forceinline__ float wsum(float v)
{
#pragma unroll
    for (int o = 16; o; o >>= 1) v += __shfl_xor_sync(0xffffffffu, v, o);
    return v;
}

// ===========================================================================
// LayerNorm -> bf16 hi/lo pair (one warp per row)
// ===========================================================================
__global__ void __launch_bounds__(256) ln_kernel(const float* __restrict__ x,
                                                 const float* __restrict__ g,
                                                 const float* __restrict__ bb,
                                                 __nv_bfloat16* __restrict__ yh,
                                                 __nv_bfloat16* __restrict__ yl)
{
    const int w = threadIdx.x >> 5, lane = threadIdx.x & 31;
    const int row = blockIdx.x * 8 + w;
    const float* xr = x + (size_t)row * 512;
    float v[16];
    float s = 0.f;
#pragma unroll
    for (int j = 0; j < 16; j++) { v[j] = xr[lane + 32 * j]; s += v[j]; }
    s = wsum(s);
    const float mean = s * (1.f / 512.f);
    float q = 0.f;
#pragma unroll
    for (int j = 0; j < 16; j++) { float d = v[j] - mean; q += d * d; }
    q = wsum(q);
    const float inv = rsqrtf(q * (1.f / 512.f) + 1e-5f);
#pragma unroll
    for (int j = 0; j < 16; j++) {
        int c = lane + 32 * j;
        float val = (v[j] - mean) * inv * g[c] + bb[c];
        __nv_bfloat16 hb, lb; split2(val, hb, lb);
        yh[(size_t)row * 512 + c] = hb;
        yl[(size_t)row * 512 + c] = lb;
    }
}

// ===========================================================================
// Memory attention v2: 16 rows/block (warp per row), mem staged via smem
// ===========================================================================
__global__ void __launch_bounds__(512) memory_kernel(const float* __restrict__ Nx,
                                                     const float* __restrict__ Ax,
                                                     const float* __restrict__ a_mem,
                                                     const float* __restrict__ n_mem,
                                                     float* __restrict__ att_base,
                                                     __nv_bfloat16* __restrict__ augh_base,
                                                     __nv_bfloat16* __restrict__ augl_base)
{
    __shared__ float mch[20][512];
    const int w = threadIdx.x >> 5, lane = threadIdx.x & 31;
    const int combo = blockIdx.y;       // 0:A(Ax,a) 1:NA(Ax,n) 2:AN(Nx,a) 3:N(Nx,n)
    const int row = blockIdx.x * 16 + w;
    const float* x   = (combo < 2) ? Ax : Nx;
    const float* mem = (combo & 1) ? n_mem : a_mem;
    const int att_off[4] = {0, 24576, 16384, 8192};
    float* att_out = att_base + att_off[combo];
    __nv_bfloat16* augh = augh_base + (size_t)combo * SZ_AUG;
    __nv_bfloat16* augl = augl_base + (size_t)combo * SZ_AUG;

    float xr[16], facc[16];
#pragma unroll
    for (int j = 0; j < 16; j++) {
        xr[j] = x[(size_t)row * 512 + lane + 32 * j];
        facc[j] = 0.f;
    }
    float t0 = -1e30f, t1 = -1e30f, t2 = -1e30f, t3 = -1e30f;

    for (int c = 0; c < 3; c++) {
        for (int i = threadIdx.x; i < 20 * 512; i += 512)
            ((float*)mch)[i] = mem[c * 20 * 512 + i];
        __syncthreads();
#pragma unroll 4
        for (int n = 0; n < 20; n++) {
            float s = 0.f;
#pragma unroll
            for (int j = 0; j < 16; j++) s = fmaf(xr[j], mch[n][lane + 32 * j], s);
            s = wsum(s);
            float att = 1.f / (1.f + expf(-s * 0.044194173824159216f));
            if (att > t0)      { t3 = t2; t2 = t1; t1 = t0; t0 = att; }
            else if (att > t1) { t3 = t2; t2 = t1; t1 = att; }
            else if (att > t2) { t3 = t2; t2 = att; }
            else if (att > t3) { t3 = att; }
#pragma unroll
            for (int j = 0; j < 16; j++)
                facc[j] = fmaf(att, mch[n][lane + 32 * j], facc[j]);
        }
        __syncthreads();
    }

    if (lane == 0) att_out[row] = (t0 + t1 + t2 + t3) * 0.25f;
#pragma unroll
    for (int j = 0; j < 16; j++) {
        __nv_bfloat16 hb, lb; split2(facc[j], hb, lb);
        augh[(size_t)row * 512 + lane + 32 * j] = hb;
        augl[(size_t)row * 512 + lane + 32 * j] = lb;
    }
}

// ===========================================================================
// top-k (3 combos batched via grid.y) / losses / misc
// ===========================================================================
__global__ void __launch_bounds__(256) topk_gather3(
    const float* __restrict__ attA, const float* __restrict__ attN,
    const float* __restrict__ attNA,
    const float* __restrict__ Ax, const float* __restrict__ Nx,
    float* __restrict__ negv, float* __restrict__ anch, float* __restrict__ posv,
    int* __restrict__ idxA, int* __restrict__ idxN)
{
    __shared__ float vals[256], rv[256];
    __shared__ int ri[256], ids[17];
    const int b = blockIdx.x, tid = threadIdx.x;
    const int combo = blockIdx.y;
    const float* att   = (combo == 0) ? attA : (combo == 1) ? attN : attNA;
    const float* feats = (combo == 1) ? Nx : Ax;
    float* meanv = (combo == 0) ? negv : (combo == 1) ? anch : posv;
    int* idx_out = (combo == 0) ? idxA : (combo == 1) ? idxN : nullptr;

    vals[tid] = att[b * 256 + tid];
    __syncthreads();
    for (int it = 0; it < 17; it++) {
        rv[tid] = vals[tid]; ri[tid] = tid;
        __syncthreads();
        for (int s = 128; s; s >>= 1) {
            if (tid < s) {
                float ov = rv[tid + s]; int oi = ri[tid + s];
                if (ov > rv[tid] || (ov == rv[tid] && oi < ri[tid])) { rv[tid] = ov; ri[tid] = oi; }
            }
            __syncthreads();
        }
        if (tid == 0) {
            ids[it] = ri[0];
            vals[ri[0]] = -1e30f;
            if (idx_out) idx_out[b * 17 + it] = ri[0];
        }
        __syncthreads();
    }
    for (int d = tid; d < 512; d += 256) {
        float s = 0.f;
        for (int j = 0; j < 17; j++) s += feats[((size_t)b * 256 + ids[j]) * 512 + d];
        meanv[b * 512 + d] = s * (1.f / 17.f);
    }
}

__global__ void __launch_bounds__(1024) triplet_cos_kernel(const float* __restrict__ anchor,
                                                           const float* __restrict__ pos,
                                                           const float* __restrict__ neg,
                                                           float* __restrict__ trip_out,
                                                           float* __restrict__ cos_out)
{
    __shared__ float st[32], sc[32];
    const int w = threadIdx.x >> 5, lane = threadIdx.x & 31;
    float sa = 0, sp = 0, sn = 0, dan = 0;
    for (int d = lane; d < 512; d += 32) {
        float a = anchor[w * 512 + d], p = pos[w * 512 + d], n = neg[w * 512 + d];
        sa += a * a; sp += p * p; sn += n * n; dan += a * n;
    }
    sa = wsum(sa); sp = wsum(sp); sn = wsum(sn); dan = wsum(dan);
    float na = sqrtf(sa), npp = sqrtf(sp), ng = sqrtf(sn);
    float ina = 1.f / na, inp = 1.f / npp, ing = 1.f / ng;
    float dp2 = 0, dn2 = 0;
    for (int d = lane; d < 512; d += 32) {
        float a  = anchor[w * 512 + d] * ina;
        float dpv = a - pos[w * 512 + d] * inp + 1e-6f;
        float dnv = a - neg[w * 512 + d] * ing + 1e-6f;
        dp2 += dpv * dpv; dn2 += dnv * dnv;
    }
    dp2 = wsum(dp2); dn2 = wsum(dn2);
    if (lane == 0) {
        st[w] = fmaxf(sqrtf(dp2) - sqrtf(dn2) + 1.f, 0.f);
        sc[w] = 1.f - dan / (fmaxf(na, 1e-6f) * fmaxf(ng, 1e-6f));
    }
    __syncthreads();
    if (threadIdx.x == 0) {
        float a = 0, c = 0;
        for (int i = 0; i < 32; i++) { a += st[i]; c += sc[i]; }
        trip_out[0] = a * (1.f / 32.f);
        cos_out[0]  = c * (1.f / 32.f);
    }
}

__global__ void __launch_bounds__(1024) distance_kernel(const float* __restrict__ anew,
                                                        const float* __restrict__ nnew,
                                                        float* __restrict__ out)
{
    __shared__ float sd[32];
    const int w = threadIdx.x >> 5, lane = threadIdx.x & 31;
    float sa = 0, sn = 0;
    for (int d = lane; d < 512; d += 32) {
        float a = anew[w * 512 + d], n = nnew[w * 512 + d];
        sa += a * a; sn += n * n;
    }
    sa = wsum(sa); sn = wsum(sn);
    if (lane == 0) sd[w] = fmaxf(100.f - sqrtf(sn) + sqrtf(sa), 0.f);
    __syncthreads();
    if (threadIdx.x == 0) {
        float s = 0;
        for (int i = 0; i < 32; i++) s += sd[i];
        out[0] = s * (1.f / 32.f);
    }
}

// fused VAE reparam + KL partial sums (one pass over mu/var)
__global__ void __launch_bounds__(256) vaekl_kernel(const float* __restrict__ mu,
                                                    const float* __restrict__ var,
                                                    const float* __restrict__ eps,
                                                    float* __restrict__ o,
                                                    float* __restrict__ part, int n)
{
    __shared__ float red[256];
    float s = 0.f;
    for (int i = blockIdx.x * 256 + threadIdx.x; i < n; i += gridDim.x * 256) {
        float m = mu[i], v = var[i];
        float ev = expf(v);
        o[i] = m + eps[i] * sqrtf(ev);
        s += 1.f + v - m * m - ev;
    }
    red[threadIdx.x] = s; __syncthreads();
    for (int t = 128; t; t >>= 1) { if (threadIdx.x < t) red[threadIdx.x] += red[threadIdx.x + t]; __syncthreads(); }
    if (threadIdx.x == 0) part[blockIdx.x] = red[0];
}

__global__ void __launch_bounds__(1024) kl_final_kernel(const float* __restrict__ part,
                                                        float* __restrict__ out)
{
    __shared__ float red[1024];
    red[threadIdx.x] = part[threadIdx.x]; __syncthreads();
    for (int t = 512; t; t >>= 1) { if (threadIdx.x < t) red[threadIdx.x] += red[threadIdx.x + t]; __syncthreads(); }
    if (threadIdx.x == 0) out[0] = -0.5f * red[0] * (1.f / 16384.f);
}

__global__ void __launch_bounds__(512) gather_mean_kernel(const float* __restrict__ src,
                                                          const int* __restrict__ idx,
                                                          float* __restrict__ out)
{
    __shared__ int ids[17];
    const int b = blockIdx.x, tid = threadIdx.x;
    if (tid < 17) ids[tid] = idx[b * 17 + tid];
    __syncthreads();
    float s = 0.f;
    for (int j = 0; j < 17; j++) s += src[((size_t)b * 256 + ids[j]) * 512 + tid];
    out[b * 512 + tid] = s * (1.f / 17.f);
}

__global__ void xout_kernel(const float* __restrict__ h, const float* __restrict__ nnew,
                            const float* __restrict__ anm, const float* __restrict__ anew,
                            const float* __restrict__ nam, float* __restrict__ xout)
{
    const int n = 64 * 256 * 1024;
    for (int i = blockIdx.x * blockDim.x + threadIdx.x; i < n; i += gridDim.x * blockDim.x) {
        int c  = i & 1023;
        int rt = i >> 10;
        float v;
        if (c < 512) v = h[(size_t)rt * 512 + c];
        else {
            int cc = c - 512;
            if (rt < 8192) v = nnew[(size_t)rt * 512 + cc] + anm[(size_t)rt * 512 + cc];
            else {
                size_t o = (size_t)(rt - 8192) * 512 + cc;
                v = anew[o] + nam[o];
            }
        }
        xout[i] = v;
    }
}

__global__ void vfeat_kernel(const float* __restrict__ h, float* __restrict__ v)
{
    __shared__ float tile[32][33];
    const int b = blockIdx.x, d0 = blockIdx.y * 32, t0 = blockIdx.z * 32;
    for (int r = threadIdx.y; r < 32; r += 8)
        tile[r][threadIdx.x] = h[((size_t)b * 256 + t0 + r) * 512 + d0 + threadIdx.x];
    __syncthreads();
    for (int r = threadIdx.y; r < 32; r += 8)
        v[((size_t)b * 512 + d0 + r) * 256 + t0 + threadIdx.x] = tile[threadIdx.x][r];
}

// ===========================================================================
extern "C" void kernel_launch(void* const* d_in, const int* in_sizes, int n_in,
                              void* d_out, int out_size)
{
    const float* x      = (const float*)d_in[0];
    const float* eps_in = (const float*)d_in[1];
    const float* conv_w = (const float*)d_in[2];
    const float* conv_b = (const float*)d_in[3];
    const float* ln1_g  = (const float*)d_in[4];
    const float* ln1_b  = (const float*)d_in[5];
    const float* qkv_w  = (const float*)d_in[6];
    const float* out_w  = (const float*)d_in[7];
    const float* out_b  = (const float*)d_in[8];
    const float* ln2_g  = (const float*)d_in[9];
    const float* ln2_b  = (const float*)d_in[10];
    const float* ff1_w  = (const float*)d_in[11];
    const float* ff1_b  = (const float*)d_in[12];
    const float* ff2_w  = (const float*)d_in[13];
    const float* ff2_b  = (const float*)d_in[14];
    const float* a_mem  = (const float*)d_in[15];
    const float* n_mem  = (const float*)d_in[16];
    const float* mu_w   = (const float*)d_in[17];
    const float* mu_b   = (const float*)d_in[18];
    const float* var_w  = (const float*)d_in[19];
    const float* var_b  = (const float*)d_in[20];
    float* out = (float*)d_out;

    float* S = nullptr;
    cudaGetSymbolAddress((void**)&S, g_scratch);
    __nv_bfloat16* BF = nullptr;
    cudaGetSymbolAddress((void**)&BF, g_bf);

    float* h     = S + OFF_H;
    float* sc    = S + OFF_SC;
    float* stack = S + OFF_STACK;
    float* Anew  = stack;
    float* NAm   = stack + 1ull * 8192 * 512;
    float* ANm   = stack + 2ull * 8192 * 512;
    float* muB   = stack + 3ull * 8192 * 512;
    float* varB  = S + OFF_VAR;
    float* newN  = S + OFF_NEW;
    float* anch  = S + OFF_ANCH;
    float* negv  = S + OFF_NEG;
    float* posv  = S + OFF_POS;
    float* anchN = S + OFF_ANCHN;
    float* negN  = S + OFF_NEGN;
    int*   idxA  = (int*)(S + OFF_IDXA);
    int*   idxN  = (int*)(S + OFF_IDXN);
    float* klp   = S + OFF_KLP;

    __nv_bfloat16* lnh = BF + B_LNH;  __nv_bfloat16* lnl = BF + B_LNL;
    __nv_bfloat16* aoh = BF + B_AOH;  __nv_bfloat16* aol = BF + B_AOL;
    __nv_bfloat16* ffh = BF + B_FFH;  __nv_bfloat16* ffl = BF + B_FFL;
    __nv_bfloat16* qkvh = BF + B_QKVH; __nv_bfloat16* qkvl = BF + B_QKVL;
    __nv_bfloat16* ph = BF + B_PH;     __nv_bfloat16* pl = BF + B_PL;
    __nv_bfloat16* vth = BF + B_VTH;   __nv_bfloat16* vtl = BF + B_VTL;
    __nv_bfloat16* xh = BF + B_XH;     __nv_bfloat16* xl = BF + B_XL;

    constexpr int MG_SMEM = 81920;
    cudaFuncSetAttribute(mgemm<0,false>, cudaFuncAttributeMaxDynamicSharedMemorySize, MG_SMEM);
    cudaFuncSetAttribute(mgemm<1,false>, cudaFuncAttributeMaxDynamicSharedMemorySize, MG_SMEM);
    cudaFuncSetAttribute(mgemm<2,false>, cudaFuncAttributeMaxDynamicSharedMemorySize, MG_SMEM);
    cudaFuncSetAttribute(mgemm<3,false>, cudaFuncAttributeMaxDynamicSharedMemorySize, MG_SMEM);
    cudaFuncSetAttribute(mgemm<5,false>, cudaFuncAttributeMaxDynamicSharedMemorySize, MG_SMEM);
    cudaFuncSetAttribute(mgemm<4,true>,  cudaFuncAttributeMaxDynamicSharedMemorySize, MG_SMEM);

    // 1-3: prep
    convprep<<<1024, 256>>>(conv_w, BF + B_CNVWH, BF + B_CNVWL);
    xsplit<<<8192, 256>>>(x, xh, xl);
    wprep_t<<<dim3(16, 48), dim3(32, 8)>>>(qkv_w, BF + B_QKVWH, BF + B_QKVWL, 512, 1536);

    // 4: conv (implicit im2col, relu+bias), pipelined — profiler target
    mgemm<4, true><<<dim3(4, 128), 256, MG_SMEM>>>(
        xh, xl, BF + B_CNVWH, BF + B_CNVWL,
        h, nullptr, nullptr, conv_b, 16384, 512, 3072);

    // 5: ln (layer 0)
    ln_kernel<<<2048, 256>>>(h, ln1_g, ln1_b, lnh, lnl);

    // 6: qkv mgemm (layer 0)
    mgemm<5, false><<<dim3(12, 128), 256, MG_SMEM>>>(
        lnh, lnl, BF + B_QKVWH, BF + B_QKVWL,
        nullptr, qkvh, qkvl, nullptr, 16384, 1536, 512);

    // remaining weight prep
    wprep_t<<<dim3(16, 16), dim3(32, 8)>>>(out_w, BF + B_OUTWH, BF + B_OUTWL, 512, 512);
    wprep_t<<<dim3(16, 16), dim3(32, 8)>>>(ff1_w, BF + B_FF1WH, BF + B_FF1WL, 512, 512);
    wprep_t<<<dim3(16, 16), dim3(32, 8)>>>(ff2_w, BF + B_FF2WH, BF + B_FF2WL, 512, 512);
    wprep_t<<<dim3(16, 48), dim3(32, 8)>>>(qkv_w + 786432,
                                           BF + B_QKVWH + 786432, BF + B_QKVWL + 786432, 512, 1536);
    wprep_t<<<dim3(16, 16), dim3(32, 8)>>>(out_w + 262144,
                                           BF + B_OUTWH + 262144, BF + B_OUTWL + 262144, 512, 512);
    wprep_t<<<dim3(16, 16), dim3(32, 8)>>>(ff1_w + 262144,
                                           BF + B_FF1WH + 262144, BF + B_FF1WL + 262144, 512, 512);
    wprep_t<<<dim3(16, 16), dim3(32, 8)>>>(ff2_w + 262144,
                                           BF + B_FF2WH + 262144, BF + B_FF2WL + 262144, 512, 512);
    wprep_t<<<dim3(16, 16), dim3(32, 8)>>>(mu_w,  BF + B_MUWH,  BF + B_MUWL,  512, 512);
    wprep_t<<<dim3(16, 16), dim3(32, 8)>>>(var_w, BF + B_VARWH, BF + B_VARWL, 512, 512);

    // ---- transformer (layer 0 continues, then layer 1)
    for (int i = 0; i < 2; i++) {
        if (i == 1) {
            ln_kernel<<<2048, 256>>>(h, ln1_g + 512, ln1_b + 512, lnh, lnl);
            mgemm<5, false><<<dim3(12, 128), 256, MG_SMEM>>>(
                lnh, lnl, BF + B_QKVWH + 786432, BF + B_QKVWL + 786432,
                nullptr, qkvh, qkvl, nullptr, 16384, 1536, 512);
        }
        vtrans_kernel<<<dim3(256, 4, 8), dim3(32, 8)>>>(qkvh, qkvl, vth, vtl);
        bqk_kernel<<<dim3(2, 2, 256), 256>>>(qkvh, qkvl, sc);
        softmaxp_kernel<<<8192, 256>>>(sc, ph, pl);
        bpv_kernel<<<dim3(2, 1, 256), 256>>>(ph, pl, vth, vtl, aoh, aol);
        mgemm<2, false><<<dim3(4, 128), 256, MG_SMEM>>>(
            aoh, aol, BF + B_OUTWH + (size_t)i * 262144, BF + B_OUTWL + (size_t)i * 262144,
            h, nullptr, nullptr, out_b + i * 512, 16384, 512, 512);
        ln_kernel<<<2048, 256>>>(h, ln2_g + i * 512, ln2_b + i * 512, lnh, lnl);
        mgemm<3, false><<<dim3(4, 128), 256, MG_SMEM>>>(
            lnh, lnl, BF + B_FF1WH + (size_t)i * 262144, BF + B_FF1WL + (size_t)i * 262144,
            nullptr, ffh, ffl, ff1_b + i * 512, 16384, 512, 512);
        mgemm<2, false><<<dim3(4, 128), 256, MG_SMEM>>>(
            ffh, ffl, BF + B_FF2WH + (size_t)i * 262144, BF + B_FF2WL + (size_t)i * 262144,
            h, nullptr, nullptr, ff2_b + i * 512, 16384, 512, 512);
    }

    const float* Nx = h;                       // x_emb[:32]
    const float* Ax = h + (size_t)8192 * 512;  // x_emb[32:]

    memory_kernel<<<dim3(512, 4), 512>>>(Nx, Ax, a_mem, n_mem,
                                         out + O_AATT, BF + B_AUGH, BF + B_AUGL);

    topk_gather3<<<dim3(32, 3), 256>>>(out + O_AATT, out + O_NATT, out + O_NAATT,
                                       Ax, Nx, negv, anch, posv, idxA, idxN);

    triplet_cos_kernel<<<1, 1024>>>(anch, posv, negv, out + O_TRIP, out + O_COS);

    // stacked mu projection: [augA; augNA; augAN; augN] @ mu -> [Anew; NAm; ANm; muB]
    mgemm<1, false><<<dim3(4, 256), 256, MG_SMEM>>>(
        BF + B_AUGH, BF + B_AUGL, BF + B_MUWH, BF + B_MUWL,
        stack, nullptr, nullptr, mu_b, 32768, 512, 512);
    mgemm<1, false><<<dim3(4, 64), 256, MG_SMEM>>>(
        BF + B_AUGH + 3 * SZ_AUG, BF + B_AUGL + 3 * SZ_AUG,
        BF + B_VARWH, BF + B_VARWL, varB, nullptr, nullptr, var_b, 8192, 512, 512);

    vaekl_kernel<<<1024, 256>>>(muB, varB, eps_in, newN, klp, 8192 * 512);
    kl_final_kernel<<<1, 1024>>>(klp, out + O_KL);

    gather_mean_kernel<<<32, 512>>>(newN, idxN, anchN);
    gather_mean_kernel<<<32, 512>>>(Anew, idxA, negN);
    distance_kernel<<<1, 1024>>>(anchN, negN, out + O_DIST);

    xout_kernel<<<8192, 256>>>(h, newN, ANm, Anew, NAm, out + O_XOUT);
    vfeat_kernel<<<dim3(64, 16, 8), dim3(32, 8)>>>(h, out + O_VFEAT);
}

// round 13
// speedup vs baseline: 3.6792x; 1.2204x over previous
#include <cuda_runtime.h>
#include <cuda_fp16.h>
#include <math.h>
#include <stdint.h>

// ===========================================================================
// fp32 scratch
// ===========================================================================
constexpr size_t OFF_H     = 0;                         // 16384*512
constexpr size_t OFF_SC    = 8388608;                   // 256*256*256 (S fp32)
constexpr size_t OFF_STACK = OFF_SC + 16777216;         // 32768*512: Anew,NAm,ANm,muB
constexpr size_t OFF_VAR   = OFF_STACK + 16777216;      // 8192*512
constexpr size_t OFF_NEW   = OFF_VAR + 4194304;         // 8192*512
constexpr size_t OFF_ANCH  = OFF_NEW + 4194304;         // 32*512 each below
constexpr size_t OFF_NEG   = OFF_ANCH + 16384;
constexpr size_t OFF_POS   = OFF_NEG  + 16384;
constexpr size_t OFF_ANCHN = OFF_POS  + 16384;
constexpr size_t OFF_NEGN  = OFF_ANCHN + 16384;
constexpr size_t OFF_IDXA  = OFF_NEGN + 16384;
constexpr size_t OFF_IDXN  = OFF_IDXA + 1024;
constexpr size_t OFF_KLP   = OFF_IDXN + 1024;
constexpr size_t SCRATCH_TOTAL = OFF_KLP + 1024;
__device__ float g_scratch[SCRATCH_TOTAL];

// ===========================================================================
// fp16 scratch
// ===========================================================================
constexpr size_t SZ_TOK  = 16384ull * 512;
constexpr size_t SZ_QKV  = 16384ull * 1536;
constexpr size_t SZ_P    = 256ull * 65536;
constexpr size_t SZ_VT   = 256ull * 32768;
constexpr size_t SZ_AUG  = 8192ull * 512;
constexpr size_t SZ_X    = 64ull * 256 * 1024;   // 16777216

constexpr size_t B_LNH  = 0;
constexpr size_t B_LNL  = B_LNH + SZ_TOK;
constexpr size_t B_AOH  = B_LNL + SZ_TOK;
constexpr size_t B_AOL  = B_AOH + SZ_TOK;
constexpr size_t B_FFH  = B_AOL + SZ_TOK;
constexpr size_t B_FFL  = B_FFH + SZ_TOK;
constexpr size_t B_QKVH = B_FFL + SZ_TOK;
constexpr size_t B_QKVL = B_QKVH + SZ_QKV;
constexpr size_t B_PH   = B_QKVL + SZ_QKV;
constexpr size_t B_PL   = B_PH + SZ_P;
constexpr size_t B_VTH  = B_PL + SZ_P;
constexpr size_t B_AUGH = B_VTH + SZ_VT;      // [A, NA, AN, N] stacked
constexpr size_t B_AUGL = B_AUGH + 4 * SZ_AUG;
constexpr size_t B_QKVW = B_AUGL + 4 * SZ_AUG;      // 2*786432
constexpr size_t B_OUTW = B_QKVW + 2ull * 786432;   // 2*262144
constexpr size_t B_FF1W = B_OUTW + 2ull * 262144;
constexpr size_t B_FF2W = B_FF1W + 2ull * 262144;
constexpr size_t B_MUW  = B_FF2W + 2ull * 262144;   // 262144
constexpr size_t B_VARW = B_MUW + 262144;
constexpr size_t B_CNVW = B_VARW + 262144;          // 1572864
constexpr size_t B_XH   = B_CNVW + 1572864;
constexpr size_t B_XL   = B_XH + SZ_X;
constexpr size_t HF_TOTAL = B_XL + SZ_X;
__device__ __half g_hf[HF_TOTAL];

__device__ __align__(16) __half g_zero[8];   // zero-initialized

// output offsets (triplet, kl, distance, A_att, N_att, A_Natt, N_Aatt, cos, x_out, v_feat)
constexpr size_t O_TRIP  = 0;
constexpr size_t O_KL    = 1;
constexpr size_t O_DIST  = 2;
constexpr size_t O_AATT  = 3;
constexpr size_t O_NATT  = 3 + 8192;
constexpr size_t O_ANATT = 3 + 16384;
constexpr size_t O_NAATT = 3 + 24576;
constexpr size_t O_COS   = 3 + 32768;
constexpr size_t O_XOUT  = 4 + 32768;
constexpr size_t O_VFEAT = O_XOUT + 64ull * 256 * 1024;

// ===========================================================================
// mma / smem helpers
// ===========================================================================
__device__ __forceinline__ void mma16816(float* c, const uint32_t* a, const uint32_t* b)
{
    asm volatile(
        "mma.sync.aligned.m16n8k16.row.col.f32.f16.f16.f32 "
        "{%0,%1,%2,%3}, {%4,%5,%6,%7}, {%8,%9}, {%0,%1,%2,%3};"
        : "+f"(c[0]), "+f"(c[1]), "+f"(c[2]), "+f"(c[3])
        : "r"(a[0]), "r"(a[1]), "r"(a[2]), "r"(a[3]), "r"(b[0]), "r"(b[1]));
}

// fp16 2-term split: h = fp16(v), l = fp16(v - h).  11+11 mantissa bits ~ fp32.
__device__ __forceinline__ void split2(float v, __half& h, __half& l) {
    h = __float2half_rn(v);
    l = __float2half_rn(v - __half2float(h));
}

__device__ __forceinline__ uint32_t cvt_smem(const void* p) {
    uint32_t a;
    asm("{ .reg .u64 t; cvta.to.shared.u64 t, %1; cvt.u32.u64 %0, t; }" : "=r"(a) : "l"(p));
    return a;
}

#define LDSM4(r0, r1, r2, r3, a) \
    asm volatile("ldmatrix.sync.aligned.m8n8.x4.shared.b16 {%0,%1,%2,%3}, [%4];" \
        : "=r"(r0), "=r"(r1), "=r"(r2), "=r"(r3) : "r"(a))

#define CP16(sa, gp) \
    asm volatile("cp.async.cg.shared.global [%0], [%1], 16;" :: "r"(sa), "l"(gp))
#define CP_COMMIT() asm volatile("cp.async.commit_group;" ::: "memory")
#define CP_WAIT1()  asm volatile("cp.async.wait_group 1;" ::: "memory")
#define CP_WAIT0()  asm volatile("cp.async.wait_group 0;" ::: "memory")

// one stage layout (bytes): Ah @0, Al @10240, Bh @20480; rows pad 40 elem (80B)
constexpr uint32_t SM_AL = 10240, SM_BH = 20480;
constexpr uint32_t STAGE_BYTES = 30720;

// 128x32 tile MMA, fp16 2-term: hh + lh (A split, B single).
__device__ __forceinline__ void mma_tile_ldsm(uint32_t sb, float acc[4][4][4],
                                              int arow, int acolB, int brow, int bcolB)
{
#pragma unroll
    for (int ks = 0; ks < 32; ks += 16) {
        uint32_t fa[4][4], fbh[4][2];
#pragma unroll
        for (int mi = 0; mi < 4; mi++) {
            uint32_t ad = sb + (uint32_t)((arow + mi * 16) * 80 + (ks + acolB) * 2);
            LDSM4(fa[mi][0], fa[mi][1], fa[mi][2], fa[mi][3], ad);
        }
#pragma unroll
        for (int np = 0; np < 2; np++) {
            uint32_t bd = sb + SM_BH + (uint32_t)((brow + np * 16) * 80 + (ks + bcolB) * 2);
            LDSM4(fbh[np * 2][0], fbh[np * 2][1], fbh[np * 2 + 1][0], fbh[np * 2 + 1][1], bd);
        }
        // term 1: A-hi x B
#pragma unroll
        for (int mi = 0; mi < 4; mi++)
#pragma unroll
            for (int ni = 0; ni < 4; ni++)
                mma16816(acc[mi][ni], fa[mi], fbh[ni]);
        // term 2: A-lo x B
#pragma unroll
        for (int mi = 0; mi < 4; mi++) {
            uint32_t ad = sb + SM_AL + (uint32_t)((arow + mi * 16) * 80 + (ks + acolB) * 2);
            LDSM4(fa[mi][0], fa[mi][1], fa[mi][2], fa[mi][3], ad);
        }
#pragma unroll
        for (int mi = 0; mi < 4; mi++)
#pragma unroll
            for (int ni = 0; ni < 4; ni++)
                mma16816(acc[mi][ni], fa[mi], fbh[ni]);
    }
}

// stage one 128x32 K-chunk (A hi/lo + B hi) via cp.async; CONV = im2col A
template<bool CONV>
__device__ __forceinline__ void stage_chunk(
    uint32_t sdst,
    const __half* __restrict__ Ah, const __half* __restrict__ Al,
    const __half* __restrict__ Bh,
    const __half* zb, int row0, int col0, int K, int kc, int tid)
{
#pragma unroll
    for (int i = 0; i < 2; i++) {
        int chunk = tid * 2 + i;
        int rr = chunk >> 2, sg = chunk & 3;
        uint32_t so = (uint32_t)(rr * 80 + sg * 16);
        const __half *pah, *pal;
        if (CONV) {
            int gk = kc * 32 + sg * 8;
            int tap = gk >> 10, ci = gk & 1023;
            int m = row0 + rr;
            int t2 = (m & 255) + tap - 1;
            if (t2 >= 0 && t2 < 256) {
                size_t o = ((size_t)((m >> 8) * 256 + t2)) * 1024 + ci;
                pah = Ah + o; pal = Al + o;
            } else { pah = zb; pal = zb; }
        } else {
            size_t oa = (size_t)(row0 + rr) * K + kc * 32 + sg * 8;
            pah = Ah + oa; pal = Al + oa;
        }
        CP16(sdst + so,         pah);
        CP16(sdst + SM_AL + so, pal);
        size_t ob = (size_t)(col0 + rr) * K + kc * 32 + sg * 8;
        CP16(sdst + SM_BH + so, Bh + ob);
    }
    CP_COMMIT();
}

// ===========================================================================
// HMMA GEMM, cp.async double-buffered
// EPI: 0=none,1=+bias,2=+bias+residual,3=+bias+gelu->pair,4=+bias+relu,5=->pair
// ===========================================================================
template<int EPI, bool CONV>
__global__ void __launch_bounds__(256, 2) mgemm(
    const __half* __restrict__ Ah, const __half* __restrict__ Al,
    const __half* __restrict__ Bh,
    float* __restrict__ C,
    __half* __restrict__ Chi, __half* __restrict__ Clo,
    const float* __restrict__ bias,
    int M, int N, int K)
{
    extern __shared__ char smem[];
    const int tid  = threadIdx.x;
    const int wid  = tid >> 5;
    const int lane = tid & 31;
    const int g = lane >> 2, t = lane & 3;
    const int wm = wid >> 2, wn = wid & 3;
    const int row0 = blockIdx.y * 128;
    const int col0 = blockIdx.x * 128;
    const uint32_t sb0 = cvt_smem(smem);

    const int arow  = wm * 64 + (lane & 7) + ((lane >> 3) & 1) * 8;
    const int acolB = ((lane >> 4) & 1) * 8;
    const int brow  = wn * 32 + ((lane >> 4) & 1) * 8 + (lane & 7);
    const int bcolB = ((lane >> 3) & 1) * 8;

    float acc[4][4][4];
#pragma unroll
    for (int mi = 0; mi < 4; mi++)
#pragma unroll
        for (int ni = 0; ni < 4; ni++)
#pragma unroll
            for (int q = 0; q < 4; q++) acc[mi][ni][q] = 0.f;

    const int nchunks = K >> 5;

    stage_chunk<CONV>(sb0, Ah, Al, Bh, g_zero, row0, col0, K, 0, tid);

    for (int kc = 0; kc < nchunks; kc++) {
        const uint32_t sb = sb0 + (uint32_t)(kc & 1) * STAGE_BYTES;
        if (kc + 1 < nchunks) {
            const uint32_t sn = sb0 + (uint32_t)((kc + 1) & 1) * STAGE_BYTES;
            stage_chunk<CONV>(sn, Ah, Al, Bh, g_zero, row0, col0, K, kc + 1, tid);
            CP_WAIT1();
        } else {
            CP_WAIT0();
        }
        __syncthreads();
        mma_tile_ldsm(sb, acc, arow, acolB, brow, bcolB);
        __syncthreads();
    }

#pragma unroll
    for (int mi = 0; mi < 4; mi++) {
#pragma unroll
        for (int ni = 0; ni < 4; ni++) {
#pragma unroll
            for (int q = 0; q < 4; q++) {
                int r = row0 + wm * 64 + mi * 16 + g + (q >> 1) * 8;
                int c = col0 + wn * 32 + ni * 8 + t * 2 + (q & 1);
                float v = acc[mi][ni][q];
                size_t o = (size_t)r * N + c;
                if (EPI != 0 && EPI != 5) v += bias[c];
                if (EPI == 2) v += C[o];
                if (EPI == 3 || EPI == 5) {
                    if (EPI == 3) v = 0.5f * v * (1.f + erff(v * 0.70710678118654752f));
                    __half hb, lb; split2(v, hb, lb);
                    Chi[o] = hb; Clo[o] = lb;
                } else {
                    if (EPI == 4) v = fmaxf(v, 0.f);
                    C[o] = v;
                }
            }
        }
    }
}

// ===========================================================================
// Batched QK^T (static 30KB single-stage): A = Q hi/lo, B = K hi
// ===========================================================================
__global__ void __launch_bounds__(256, 2) bqk_kernel(
    const __half* __restrict__ Qh, const __half* __restrict__ Ql,
    float* __restrict__ S)
{
    __shared__ alignas(16) char smem[30720];
    const int tid  = threadIdx.x;
    const int wid  = tid >> 5;
    const int lane = tid & 31;
    const int g = lane >> 2, t = lane & 3;
    const int wm = wid >> 2, wn = wid & 3;
    const int bh = blockIdx.z, b = bh >> 2, h = bh & 3;
    const int i0 = blockIdx.x * 128, j0 = blockIdx.y * 128;
    const __half* Ah = Qh + (size_t)b * 256 * 1536 + h * 128;
    const __half* Al = Ql + (size_t)b * 256 * 1536 + h * 128;
    const uint32_t sb = cvt_smem(smem);

    const int arow  = wm * 64 + (lane & 7) + ((lane >> 3) & 1) * 8;
    const int acolB = ((lane >> 4) & 1) * 8;
    const int brow  = wn * 32 + ((lane >> 4) & 1) * 8 + (lane & 7);
    const int bcolB = ((lane >> 3) & 1) * 8;

    float acc[4][4][4];
#pragma unroll
    for (int mi = 0; mi < 4; mi++)
#pragma unroll
        for (int ni = 0; ni < 4; ni++)
#pragma unroll
            for (int q = 0; q < 4; q++) acc[mi][ni][q] = 0.f;

    for (int kc = 0; kc < 4; kc++) {
#pragma unroll
        for (int i = 0; i < 2; i++) {
            int chunk = tid * 2 + i;
            int rr = chunk >> 2, sg = chunk & 3;
            uint32_t so = (uint32_t)(rr * 80 + sg * 16);
            size_t oa = (size_t)(i0 + rr) * 1536 + kc * 32 + sg * 8;
            size_t ob = (size_t)(j0 + rr) * 1536 + 512 + kc * 32 + sg * 8;
            *(uint4*)(smem + so)         = *(const uint4*)(Ah + oa);
            *(uint4*)(smem + SM_AL + so) = *(const uint4*)(Al + oa);
            *(uint4*)(smem + SM_BH + so) = *(const uint4*)(Ah + ob);
        }
        __syncthreads();
        mma_tile_ldsm(sb, acc, arow, acolB, brow, bcolB);
        __syncthreads();
    }

    float* so2 = S + (size_t)bh * 65536;
    const float scale = 0.08838834764831845f;
#pragma unroll
    for (int mi = 0; mi < 4; mi++)
#pragma unroll
        for (int ni = 0; ni < 4; ni++)
#pragma unroll
            for (int q = 0; q < 4; q++) {
                int r = i0 + wm * 64 + mi * 16 + g + (q >> 1) * 8;
                int c = j0 + wn * 32 + ni * 8 + t * 2 + (q & 1);
                so2[(size_t)r * 256 + c] = acc[mi][ni][q] * scale;
            }
}

// row softmax -> fp16 pair
__global__ void __launch_bounds__(256) softmaxp_kernel(const float* __restrict__ S,
                                                       __half* __restrict__ Ph,
                                                       __half* __restrict__ Pl)
{
    const int row  = blockIdx.x * 8 + (threadIdx.x >> 5);
    const int lane = threadIdx.x & 31;
    const float* p = S + (size_t)row * 256;
    float v[8]; float mx = -1e30f;
#pragma unroll
    for (int j = 0; j < 8; j++) { v[j] = p[lane + 32 * j]; mx = fmaxf(mx, v[j]); }
#pragma unroll
    for (int o = 16; o; o >>= 1) mx = fmaxf(mx, __shfl_xor_sync(0xffffffffu, mx, o));
    float s = 0.f;
#pragma unroll
    for (int j = 0; j < 8; j++) { v[j] = expf(v[j] - mx); s += v[j]; }
#pragma unroll
    for (int o = 16; o; o >>= 1) s += __shfl_xor_sync(0xffffffffu, s, o);
    const float inv = 1.f / s;
#pragma unroll
    for (int j = 0; j < 8; j++) {
        __half hb, lb; split2(v[j] * inv, hb, lb);
        Ph[(size_t)row * 256 + lane + 32 * j] = hb;
        Pl[(size_t)row * 256 + lane + 32 * j] = lb;
    }
}

// V transpose (hi only — V is a B-side operand)
__global__ void vtrans_kernel(const __half* __restrict__ Vh,
                              __half* __restrict__ vth)
{
    __shared__ __half th[32][33];
    const int bh = blockIdx.x, b = bh >> 2, h = bh & 3;
    const int d0 = blockIdx.y * 32, j0 = blockIdx.z * 32;
    const int tx = threadIdx.x, ty = threadIdx.y;
    const size_t base = (size_t)b * 256 * 1536 + 1024 + h * 128;
    for (int r = ty; r < 32; r += 8) {
        size_t o = base + (size_t)(j0 + r) * 1536 + d0 + tx;
        th[r][tx] = Vh[o];
    }
    __syncthreads();
    const size_t obase = (size_t)bh * 32768;
    for (int r = ty; r < 32; r += 8) {
        size_t o = obase + (size_t)(d0 + r) * 256 + j0 + tx;
        vth[o] = th[tx][r];
    }
}

// Batched PV: A = P hi/lo, B = Vt hi
__global__ void __launch_bounds__(256, 2) bpv_kernel(
    const __half* __restrict__ Ph, const __half* __restrict__ Pl,
    const __half* __restrict__ vth,
    __half* __restrict__ Oh, __half* __restrict__ Ol)
{
    __shared__ alignas(16) char smem[30720];
    const int tid  = threadIdx.x;
    const int wid  = tid >> 5;
    const int lane = tid & 31;
    const int g = lane >> 2, t = lane & 3;
    const int wm = wid >> 2, wn = wid & 3;
    const int bh = blockIdx.z, b = bh >> 2, h = bh & 3;
    const int i0 = blockIdx.x * 128;
    const __half* Ah = Ph + (size_t)bh * 65536 + (size_t)i0 * 256;
    const __half* Al = Pl + (size_t)bh * 65536 + (size_t)i0 * 256;
    const __half* Bh = vth + (size_t)bh * 32768;
    const uint32_t sb = cvt_smem(smem);

    const int arow  = wm * 64 + (lane & 7) + ((lane >> 3) & 1) * 8;
    const int acolB = ((lane >> 4) & 1) * 8;
    const int brow  = wn * 32 + ((lane >> 4) & 1) * 8 + (lane & 7);
    const int bcolB = ((lane >> 3) & 1) * 8;

    float acc[4][4][4];
#pragma unroll
    for (int mi = 0; mi < 4; mi++)
#pragma unroll
        for (int ni = 0; ni < 4; ni++)
#pragma unroll
            for (int q = 0; q < 4; q++) acc[mi][ni][q] = 0.f;

    for (int kc = 0; kc < 8; kc++) {
#pragma unroll
        for (int i = 0; i < 2; i++) {
            int chunk = tid * 2 + i;
            int rr = chunk >> 2, sg = chunk & 3;
            uint32_t so = (uint32_t)(rr * 80 + sg * 16);
            size_t oa = (size_t)rr * 256 + kc * 32 + sg * 8;
            *(uint4*)(smem + so)         = *(const uint4*)(Ah + oa);
            *(uint4*)(smem + SM_AL + so) = *(const uint4*)(Al + oa);
            *(uint4*)(smem + SM_BH + so) = *(const uint4*)(Bh + oa);
        }
        __syncthreads();
        mma_tile_ldsm(sb, acc, arow, acolB, brow, bcolB);
        __syncthreads();
    }

#pragma unroll
    for (int mi = 0; mi < 4; mi++)
#pragma unroll
        for (int ni = 0; ni < 4; ni++)
#pragma unroll
            for (int q = 0; q < 4; q++) {
                int r = i0 + wm * 64 + mi * 16 + g + (q >> 1) * 8;
                int c = wn * 32 + ni * 8 + t * 2 + (q & 1);
                size_t o = ((size_t)b * 256 + r) * 512 + h * 128 + c;
                __half hb, lb; split2(acc[mi][ni][q], hb, lb);
                Oh[o] = hb; Ol[o] = lb;
            }
}

// ===========================================================================
// Prep kernels
// ===========================================================================
__global__ void wprep_t(const float* __restrict__ W, __half* __restrict__ Wh,
                        int K, int N)
{
    __shared__ float tile[32][33];
    const int k0 = blockIdx.x * 32, n0 = blockIdx.y * 32;
    const int tx = threadIdx.x, ty = threadIdx.y;
    for (int r = ty; r < 32; r += 8)
        tile[r][tx] = W[(size_t)(k0 + r) * N + n0 + tx];
    __syncthreads();
    for (int r = ty; r < 32; r += 8)
        Wh[(size_t)(n0 + r) * K + k0 + tx] = __float2half_rn(tile[tx][r]);
}

__global__ void convprep(const float* __restrict__ w, __half* __restrict__ Wh)
{
    const int n = 512 * 3072;
    for (int idx = blockIdx.x * blockDim.x + threadIdx.x; idx < n; idx += gridDim.x * blockDim.x) {
        int d = idx / 3072, k = idx % 3072;
        int tap = k >> 10, ci = k & 1023;
        Wh[idx] = __float2half_rn(w[(size_t)d * 3072 + ci * 3 + tap]);
    }
}

__global__ void xsplit(const float* __restrict__ x, __half* __restrict__ xh,
                       __half* __restrict__ xl)
{
    const int n = 64 * 256 * 1024;
    for (int i = blockIdx.x * blockDim.x + threadIdx.x; i < n; i += gridDim.x * blockDim.x) {
        __half hb, lb; split2(x[i], hb, lb);
        xh[i] = hb; xl[i] = lb;
    }
}

__device__ __forceinline__ float wsum(float v)
{
#pragma unroll
    for (int o = 16; o; o >>= 1) v += __shfl_xor_sync(0xffffffffu, v, o);
    return v;
}

// ===========================================================================
// LayerNorm -> fp16 hi/lo pair (one warp per row)
// ===========================================================================
__global__ void __launch_bounds__(256) ln_kernel(const float* __restrict__ x,
                                                 const float* __restrict__ g,
                                                 const float* __restrict__ bb,
                                                 __half* __restrict__ yh,
                                                 __half* __restrict__ yl)
{
    const int w = threadIdx.x >> 5, lane = threadIdx.x & 31;
    const int row = blockIdx.x * 8 + w;
    const float* xr = x + (size_t)row * 512;
    float v[16];
    float s = 0.f;
#pragma unroll
    for (int j = 0; j < 16; j++) { v[j] = xr[lane + 32 * j]; s += v[j]; }
    s = wsum(s);
    const float mean = s * (1.f / 512.f);
    float q = 0.f;
#pragma unroll
    for (int j = 0; j < 16; j++) { float d = v[j] - mean; q += d * d; }
    q = wsum(q);
    const float inv = rsqrtf(q * (1.f / 512.f) + 1e-5f);
#pragma unroll
    for (int j = 0; j < 16; j++) {
        int c = lane + 32 * j;
        float val = (v[j] - mean) * inv * g[c] + bb[c];
        __half hb, lb; split2(val, hb, lb);
        yh[(size_t)row * 512 + c] = hb;
        yl[(size_t)row * 512 + c] = lb;
    }
}

// ===========================================================================
// Memory attention: 16 rows/block (warp per row), mem staged via smem
// ===========================================================================
__global__ void __launch_bounds__(512) memory_kernel(const float* __restrict__ Nx,
                                                     const float* __restrict__ Ax,
                                                     const float* __restrict__ a_mem,
                                                     const float* __restrict__ n_mem,
                                                     float* __restrict__ att_base,
                                                     __half* __restrict__ augh_base,
                                                     __half* __restrict__ augl_base)
{
    __shared__ float mch[20][512];
    const int w = threadIdx.x >> 5, lane = threadIdx.x & 31;
    const int combo = blockIdx.y;       // 0:A(Ax,a) 1:NA(Ax,n) 2:AN(Nx,a) 3:N(Nx,n)
    const int row = blockIdx.x * 16 + w;
    const float* x   = (combo < 2) ? Ax : Nx;
    const float* mem = (combo & 1) ? n_mem : a_mem;
    const int att_off[4] = {0, 24576, 16384, 8192};
    float* att_out = att_base + att_off[combo];
    __half* augh = augh_base + (size_t)combo * SZ_AUG;
    __half* augl = augl_base + (size_t)combo * SZ_AUG;

    float xr[16], facc[16];
#pragma unroll
    for (int j = 0; j < 16; j++) {
        xr[j] = x[(size_t)row * 512 + lane + 32 * j];
        facc[j] = 0.f;
    }
    float t0 = -1e30f, t1 = -1e30f, t2 = -1e30f, t3 = -1e30f;

    for (int c = 0; c < 3; c++) {
        for (int i = threadIdx.x; i < 20 * 512; i += 512)
            ((float*)mch)[i] = mem[c * 20 * 512 + i];
        __syncthreads();
#pragma unroll 4
        for (int n = 0; n < 20; n++) {
            float s = 0.f;
#pragma unroll
            for (int j = 0; j < 16; j++) s = fmaf(xr[j], mch[n][lane + 32 * j], s);
            s = wsum(s);
            float att = 1.f / (1.f + expf(-s * 0.044194173824159216f));
            if (att > t0)      { t3 = t2; t2 = t1; t1 = t0; t0 = att; }
            else if (att > t1) { t3 = t2; t2 = t1; t1 = att; }
            else if (att > t2) { t3 = t2; t2 = att; }
            else if (att > t3) { t3 = att; }
#pragma unroll
            for (int j = 0; j < 16; j++)
                facc[j] = fmaf(att, mch[n][lane + 32 * j], facc[j]);
        }
        __syncthreads();
    }

    if (lane == 0) att_out[row] = (t0 + t1 + t2 + t3) * 0.25f;
#pragma unroll
    for (int j = 0; j < 16; j++) {
        __half hb, lb; split2(facc[j], hb, lb);
        augh[(size_t)row * 512 + lane + 32 * j] = hb;
        augl[(size_t)row * 512 + lane + 32 * j] = lb;
    }
}

// ===========================================================================
// top-k (3 combos batched via grid.y) / losses / misc
// ===========================================================================
__global__ void __launch_bounds__(256) topk_gather3(
    const float* __restrict__ attA, const float* __restrict__ attN,
    const float* __restrict__ attNA,
    const float* __restrict__ Ax, const float* __restrict__ Nx,
    float* __restrict__ negv, float* __restrict__ anch, float* __restrict__ posv,
    int* __restrict__ idxA, int* __restrict__ idxN)
{
    __shared__ float vals[256], rv[256];
    __shared__ int ri[256], ids[17];
    const int b = blockIdx.x, tid = threadIdx.x;
    const int combo = blockIdx.y;
    const float* att   = (combo == 0) ? attA : (combo == 1) ? attN : attNA;
    const float* feats = (combo == 1) ? Nx : Ax;
    float* meanv = (combo == 0) ? negv : (combo == 1) ? anch : posv;
    int* idx_out = (combo == 0) ? idxA : (combo == 1) ? idxN : nullptr;

    vals[tid] = att[b * 256 + tid];
    __syncthreads();
    for (int it = 0; it < 17; it++) {
        rv[tid] = vals[tid]; ri[tid] = tid;
        __syncthreads();
        for (int s = 128; s; s >>= 1) {
            if (tid < s) {
                float ov = rv[tid + s]; int oi = ri[tid + s];
                if (ov > rv[tid] || (ov == rv[tid] && oi < ri[tid])) { rv[tid] = ov; ri[tid] = oi; }
            }
            __syncthreads();
        }
        if (tid == 0) {
            ids[it] = ri[0];
            vals[ri[0]] = -1e30f;
            if (idx_out) idx_out[b * 17 + it] = ri[0];
        }
        __syncthreads();
    }
    for (int d = tid; d < 512; d += 256) {
        float s = 0.f;
        for (int j = 0; j < 17; j++) s += feats[((size_t)b * 256 + ids[j]) * 512 + d];
        meanv[b * 512 + d] = s * (1.f / 17.f);
    }
}

__global__ void __launch_bounds__(1024) triplet_cos_kernel(const float* __restrict__ anchor,
                                                           const float* __restrict__ pos,
                                                           const float* __restrict__ neg,
                                                           float* __restrict__ trip_out,
                                                           float* __restrict__ cos_out)
{
    __shared__ float st[32], sc[32];
    const int w = threadIdx.x >> 5, lane = threadIdx.x & 31;
    float sa = 0, sp = 0, sn = 0, dan = 0;
    for (int d = lane; d < 512; d += 32) {
        float a = anchor[w * 512 + d], p = pos[w * 512 + d], n = neg[w * 512 + d];
        sa += a * a; sp += p * p; sn += n * n; dan += a * n;
    }
    sa = wsum(sa); sp = wsum(sp); sn = wsum(sn); dan = wsum(dan);
    float na = sqrtf(sa), npp = sqrtf(sp), ng = sqrtf(sn);
    float ina = 1.f / na, inp = 1.f / npp, ing = 1.f / ng;
    float dp2 = 0, dn2 = 0;
    for (int d = lane; d < 512; d += 32) {
        float a  = anchor[w * 512 + d] * ina;
        float dpv = a - pos[w * 512 + d] * inp + 1e-6f;
        float dnv = a - neg[w * 512 + d] * ing + 1e-6f;
        dp2 += dpv * dpv; dn2 += dnv * dnv;
    }
    dp2 = wsum(dp2); dn2 = wsum(dn2);
    if (lane == 0) {
        st[w] = fmaxf(sqrtf(dp2) - sqrtf(dn2) + 1.f, 0.f);
        sc[w] = 1.f - dan / (fmaxf(na, 1e-6f) * fmaxf(ng, 1e-6f));
    }
    __syncthreads();
    if (threadIdx.x == 0) {
        float a = 0, c = 0;
        for (int i = 0; i < 32; i++) { a += st[i]; c += sc[i]; }
        trip_out[0] = a * (1.f / 32.f);
        cos_out[0]  = c * (1.f / 32.f);
    }
}

__global__ void __launch_bounds__(1024) distance_kernel(const float* __restrict__ anew,
                                                        const float* __restrict__ nnew,
                                                        float* __restrict__ out)
{
    __shared__ float sd[32];
    const int w = threadIdx.x >> 5, lane = threadIdx.x & 31;
    float sa = 0, sn = 0;
    for (int d = lane; d < 512; d += 32) {
        float a = anew[w * 512 + d], n = nnew[w * 512 + d];
        sa += a * a; sn += n * n;
    }
    sa = wsum(sa); sn = wsum(sn);
    if (lane == 0) sd[w] = fmaxf(100.f - sqrtf(sn) + sqrtf(sa), 0.f);
    __syncthreads();
    if (threadIdx.x == 0) {
        float s = 0;
        for (int i = 0; i < 32; i++) s += sd[i];
        out[0] = s * (1.f / 32.f);
    }
}

// fused VAE reparam + KL partial sums
__global__ void __launch_bounds__(256) vaekl_kernel(const float* __restrict__ mu,
                                                    const float* __restrict__ var,
                                                    const float* __restrict__ eps,
                                                    float* __restrict__ o,
                                                    float* __restrict__ part, int n)
{
    __shared__ float red[256];
    float s = 0.f;
    for (int i = blockIdx.x * 256 + threadIdx.x; i < n; i += gridDim.x * 256) {
        float m = mu[i], v = var[i];
        float ev = expf(v);
        o[i] = m + eps[i] * sqrtf(ev);
        s += 1.f + v - m * m - ev;
    }
    red[threadIdx.x] = s; __syncthreads();
    for (int t = 128; t; t >>= 1) { if (threadIdx.x < t) red[threadIdx.x] += red[threadIdx.x + t]; __syncthreads(); }
    if (threadIdx.x == 0) part[blockIdx.x] = red[0];
}

__global__ void __launch_bounds__(1024) kl_final_kernel(const float* __restrict__ part,
                                                        float* __restrict__ out)
{
    __shared__ float red[1024];
    red[threadIdx.x] = part[threadIdx.x]; __syncthreads();
    for (int t = 512; t; t >>= 1) { if (threadIdx.x < t) red[threadIdx.x] += red[threadIdx.x + t]; __syncthreads(); }
    if (threadIdx.x == 0) out[0] = -0.5f * red[0] * (1.f / 16384.f);
}

__global__ void __launch_bounds__(512) gather_mean_kernel(const float* __restrict__ src,
                                                          const int* __restrict__ idx,
                                                          float* __restrict__ out)
{
    __shared__ int ids[17];
    const int b = blockIdx.x, tid = threadIdx.x;
    if (tid < 17) ids[tid] = idx[b * 17 + tid];
    __syncthreads();
    float s = 0.f;
    for (int j = 0; j < 17; j++) s += src[((size_t)b * 256 + ids[j]) * 512 + tid];
    out[b * 512 + tid] = s * (1.f / 17.f);
}

__global__ void xout_kernel(const float* __restrict__ h, const float* __restrict__ nnew,
                            const float* __restrict__ anm, const float* __restrict__ anew,
                            const float* __restrict__ nam, float* __restrict__ xout)
{
    const int n = 64 * 256 * 1024;
    for (int i = blockIdx.x * blockDim.x + threadIdx.x; i < n; i += gridDim.x * blockDim.x) {
        int c  = i & 1023;
        int rt = i >> 10;
        float v;
        if (c < 512) v = h[(size_t)rt * 512 + c];
        else {
            int cc = c - 512;
            if (rt < 8192) v = nnew[(size_t)rt * 512 + cc] + anm[(size_t)rt * 512 + cc];
            else {
                size_t o = (size_t)(rt - 8192) * 512 + cc;
                v = anew[o] + nam[o];
            }
        }
        xout[i] = v;
    }
}

__global__ void vfeat_kernel(const float* __restrict__ h, float* __restrict__ v)
{
    __shared__ float tile[32][33];
    const int b = blockIdx.x, d0 = blockIdx.y * 32, t0 = blockIdx.z * 32;
    for (int r = threadIdx.y; r < 32; r += 8)
        tile[r][threadIdx.x] = h[((size_t)b * 256 + t0 + r) * 512 + d0 + threadIdx.x];
    __syncthreads();
    for (int r = threadIdx.y; r < 32; r += 8)
        v[((size_t)b * 512 + d0 + r) * 256 + t0 + threadIdx.x] = tile[threadIdx.x][r];
}

// ===========================================================================
extern "C" void kernel_launch(void* const* d_in, const int* in_sizes, int n_in,
                              void* d_out, int out_size)
{
    const float* x      = (const float*)d_in[0];
    const float* eps_in = (const float*)d_in[1];
    const float* conv_w = (const float*)d_in[2];
    const float* conv_b = (const float*)d_in[3];
    const float* ln1_g  = (const float*)d_in[4];
    const float* ln1_b  = (const float*)d_in[5];
    const float* qkv_w  = (const float*)d_in[6];
    const float* out_w  = (const float*)d_in[7];
    const float* out_b  = (const float*)d_in[8];
    const float* ln2_g  = (const float*)d_in[9];
    const float* ln2_b  = (const float*)d_in[10];
    const float* ff1_w  = (const float*)d_in[11];
    const float* ff1_b  = (const float*)d_in[12];
    const float* ff2_w  = (const float*)d_in[13];
    const float* ff2_b  = (const float*)d_in[14];
    const float* a_mem  = (const float*)d_in[15];
    const float* n_mem  = (const float*)d_in[16];
    const float* mu_w   = (const float*)d_in[17];
    const float* mu_b   = (const float*)d_in[18];
    const float* var_w  = (const float*)d_in[19];
    const float* var_b  = (const float*)d_in[20];
    float* out = (float*)d_out;

    float* S = nullptr;
    cudaGetSymbolAddress((void**)&S, g_scratch);
    __half* HF = nullptr;
    cudaGetSymbolAddress((void**)&HF, g_hf);

    float* h     = S + OFF_H;
    float* sc    = S + OFF_SC;
    float* stack = S + OFF_STACK;
    float* Anew  = stack;
    float* NAm   = stack + 1ull * 8192 * 512;
    float* ANm   = stack + 2ull * 8192 * 512;
    float* muB   = stack + 3ull * 8192 * 512;
    float* varB  = S + OFF_VAR;
    float* newN  = S + OFF_NEW;
    float* anch  = S + OFF_ANCH;
    float* negv  = S + OFF_NEG;
    float* posv  = S + OFF_POS;
    float* anchN = S + OFF_ANCHN;
    float* negN  = S + OFF_NEGN;
    int*   idxA  = (int*)(S + OFF_IDXA);
    int*   idxN  = (int*)(S + OFF_IDXN);
    float* klp   = S + OFF_KLP;

    __half* lnh = HF + B_LNH;  __half* lnl = HF + B_LNL;
    __half* aoh = HF + B_AOH;  __half* aol = HF + B_AOL;
    __half* ffh = HF + B_FFH;  __half* ffl = HF + B_FFL;
    __half* qkvh = HF + B_QKVH; __half* qkvl = HF + B_QKVL;
    __half* ph = HF + B_PH;     __half* pl = HF + B_PL;
    __half* vth = HF + B_VTH;
    __half* xh = HF + B_XH;     __half* xl = HF + B_XL;

    constexpr int MG_SMEM = 61440;   // 2 stages x 30720
    cudaFuncSetAttribute(mgemm<0,false>, cudaFuncAttributeMaxDynamicSharedMemorySize, MG_SMEM);
    cudaFuncSetAttribute(mgemm<1,false>, cudaFuncAttributeMaxDynamicSharedMemorySize, MG_SMEM);
    cudaFuncSetAttribute(mgemm<2,false>, cudaFuncAttributeMaxDynamicSharedMemorySize, MG_SMEM);
    cudaFuncSetAttribute(mgemm<3,false>, cudaFuncAttributeMaxDynamicSharedMemorySize, MG_SMEM);
    cudaFuncSetAttribute(mgemm<5,false>, cudaFuncAttributeMaxDynamicSharedMemorySize, MG_SMEM);
    cudaFuncSetAttribute(mgemm<4,true>,  cudaFuncAttributeMaxDynamicSharedMemorySize, MG_SMEM);

    // 1-3: prep
    convprep<<<1024, 256>>>(conv_w, HF + B_CNVW);
    xsplit<<<8192, 256>>>(x, xh, xl);
    wprep_t<<<dim3(16, 48), dim3(32, 8)>>>(qkv_w, HF + B_QKVW, 512, 1536);

    // 4: conv (implicit im2col, relu+bias) — profiler target
    mgemm<4, true><<<dim3(4, 128), 256, MG_SMEM>>>(
        xh, xl, HF + B_CNVW,
        h, nullptr, nullptr, conv_b, 16384, 512, 3072);

    // 5: ln (layer 0)
    ln_kernel<<<2048, 256>>>(h, ln1_g, ln1_b, lnh, lnl);

    // 6: qkv mgemm (layer 0)
    mgemm<5, false><<<dim3(12, 128), 256, MG_SMEM>>>(
        lnh, lnl, HF + B_QKVW,
        nullptr, qkvh, qkvl, nullptr, 16384, 1536, 512);

    // remaining weight prep
    wprep_t<<<dim3(16, 16), dim3(32, 8)>>>(out_w, HF + B_OUTW, 512, 512);
    wprep_t<<<dim3(16, 16), dim3(32, 8)>>>(ff1_w, HF + B_FF1W, 512, 512);
    wprep_t<<<dim3(16, 16), dim3(32, 8)>>>(ff2_w, HF + B_FF2W, 512, 512);
    wprep_t<<<dim3(16, 48), dim3(32, 8)>>>(qkv_w + 786432, HF + B_QKVW + 786432, 512, 1536);
    wprep_t<<<dim3(16, 16), dim3(32, 8)>>>(out_w + 262144, HF + B_OUTW + 262144, 512, 512);
    wprep_t<<<dim3(16, 16), dim3(32, 8)>>>(ff1_w + 262144, HF + B_FF1W + 262144, 512, 512);
    wprep_t<<<dim3(16, 16), dim3(32, 8)>>>(ff2_w + 262144, HF + B_FF2W + 262144, 512, 512);
    wprep_t<<<dim3(16, 16), dim3(32, 8)>>>(mu_w,  HF + B_MUW,  512, 512);
    wprep_t<<<dim3(16, 16), dim3(32, 8)>>>(var_w, HF + B_VARW, 512, 512);

    // ---- transformer (layer 0 continues, then layer 1)
    for (int i = 0; i < 2; i++) {
        if (i == 1) {
            ln_kernel<<<2048, 256>>>(h, ln1_g + 512, ln1_b + 512, lnh, lnl);
            mgemm<5, false><<<dim3(12, 128), 256, MG_SMEM>>>(
                lnh, lnl, HF + B_QKVW + 786432,
                nullptr, qkvh, qkvl, nullptr, 16384, 1536, 512);
        }
        vtrans_kernel<<<dim3(256, 4, 8), dim3(32, 8)>>>(qkvh, vth);
        bqk_kernel<<<dim3(2, 2, 256), 256>>>(qkvh, qkvl, sc);
        softmaxp_kernel<<<8192, 256>>>(sc, ph, pl);
        bpv_kernel<<<dim3(2, 1, 256), 256>>>(ph, pl, vth, aoh, aol);
        mgemm<2, false><<<dim3(4, 128), 256, MG_SMEM>>>(
            aoh, aol, HF + B_OUTW + (size_t)i * 262144,
            h, nullptr, nullptr, out_b + i * 512, 16384, 512, 512);
        ln_kernel<<<2048, 256>>>(h, ln2_g + i * 512, ln2_b + i * 512, lnh, lnl);
        mgemm<3, false><<<dim3(4, 128), 256, MG_SMEM>>>(
            lnh, lnl, HF + B_FF1W + (size_t)i * 262144,
            nullptr, ffh, ffl, ff1_b + i * 512, 16384, 512, 512);
        mgemm<2, false><<<dim3(4, 128), 256, MG_SMEM>>>(
            ffh, ffl, HF + B_FF2W + (size_t)i * 262144,
            h, nullptr, nullptr, ff2_b + i * 512, 16384, 512, 512);
    }

    const float* Nx = h;                       // x_emb[:32]
    const float* Ax = h + (size_t)8192 * 512;  // x_emb[32:]

    memory_kernel<<<dim3(512, 4), 512>>>(Nx, Ax, a_mem, n_mem,
                                         out + O_AATT, HF + B_AUGH, HF + B_AUGL);

    topk_gather3<<<dim3(32, 3), 256>>>(out + O_AATT, out + O_NATT, out + O_NAATT,
                                       Ax, Nx, negv, anch, posv, idxA, idxN);

    triplet_cos_kernel<<<1, 1024>>>(anch, posv, negv, out + O_TRIP, out + O_COS);

    // stacked mu projection: [augA; augNA; augAN; augN] @ mu -> [Anew; NAm; ANm; muB]
    mgemm<1, false><<<dim3(4, 256), 256, MG_SMEM>>>(
        HF + B_AUGH, HF + B_AUGL, HF + B_MUW,
        stack, nullptr, nullptr, mu_b, 32768, 512, 512);
    mgemm<1, false><<<dim3(4, 64), 256, MG_SMEM>>>(
        HF + B_AUGH + 3 * SZ_AUG, HF + B_AUGL + 3 * SZ_AUG,
        HF + B_VARW, varB, nullptr, nullptr, var_b, 8192, 512, 512);

    vaekl_kernel<<<1024, 256>>>(muB, varB, eps_in, newN, klp, 8192 * 512);
    kl_final_kernel<<<1, 1024>>>(klp, out + O_KL);

    gather_mean_kernel<<<32, 512>>>(newN, idxN, anchN);
    gather_mean_kernel<<<32, 512>>>(Anew, idxA, negN);
    distance_kernel<<<1, 1024>>>(anchN, negN, out + O_DIST);

    xout_kernel<<<8192, 256>>>(h, newN, ANm, Anew, NAm, out + O_XOUT);
    vfeat_kernel<<<dim3(64, 16, 8), dim3(32, 8)>>>(h, out + O_VFEAT);
}

// round 14
// speedup vs baseline: 5.3114x; 1.4436x over previous
#include <cuda_runtime.h>
#include <cuda_fp16.h>
#include <math.h>
#include <stdint.h>

// ===========================================================================
// fp32 scratch
// ===========================================================================
constexpr size_t OFF_H     = 0;                         // 16384*512
constexpr size_t OFF_SC    = 8388608;                   // 256*256*256 (S fp32)
constexpr size_t OFF_STACK = OFF_SC + 16777216;         // 32768*512: Anew,NAm,ANm,muB
constexpr size_t OFF_VAR   = OFF_STACK + 16777216;      // 8192*512
constexpr size_t OFF_NEW   = OFF_VAR + 4194304;         // 8192*512
constexpr size_t OFF_ANCH  = OFF_NEW + 4194304;         // 32*512 each below
constexpr size_t OFF_NEG   = OFF_ANCH + 16384;
constexpr size_t OFF_POS   = OFF_NEG  + 16384;
constexpr size_t OFF_ANCHN = OFF_POS  + 16384;
constexpr size_t OFF_NEGN  = OFF_ANCHN + 16384;
constexpr size_t OFF_IDXA  = OFF_NEGN + 16384;
constexpr size_t OFF_IDXN  = OFF_IDXA + 1024;
constexpr size_t OFF_KLP   = OFF_IDXN + 1024;
constexpr size_t SCRATCH_TOTAL = OFF_KLP + 1024;
__device__ float g_scratch[SCRATCH_TOTAL];

// ===========================================================================
// fp16 scratch (single-precision operands, no hi/lo pairs)
// ===========================================================================
constexpr size_t SZ_TOK  = 16384ull * 512;
constexpr size_t SZ_QKV  = 16384ull * 1536;
constexpr size_t SZ_P    = 256ull * 65536;
constexpr size_t SZ_VT   = 256ull * 32768;
constexpr size_t SZ_AUG  = 8192ull * 512;
constexpr size_t SZ_X    = 64ull * 256 * 1024;   // 16777216

constexpr size_t B_LN   = 0;
constexpr size_t B_AO   = B_LN + SZ_TOK;
constexpr size_t B_FF   = B_AO + SZ_TOK;
constexpr size_t B_QKV  = B_FF + SZ_TOK;
constexpr size_t B_P    = B_QKV + SZ_QKV;
constexpr size_t B_VT   = B_P + SZ_P;
constexpr size_t B_AUG  = B_VT + SZ_VT;              // [A, NA, AN, N] stacked
constexpr size_t B_QKVW = B_AUG + 4 * SZ_AUG;        // 2*786432
constexpr size_t B_OUTW = B_QKVW + 2ull * 786432;    // 2*262144
constexpr size_t B_FF1W = B_OUTW + 2ull * 262144;
constexpr size_t B_FF2W = B_FF1W + 2ull * 262144;
constexpr size_t B_MUW  = B_FF2W + 2ull * 262144;    // 262144
constexpr size_t B_VARW = B_MUW + 262144;
constexpr size_t B_CNVW = B_VARW + 262144;           // 1572864
constexpr size_t B_X    = B_CNVW + 1572864;
constexpr size_t HF_TOTAL = B_X + SZ_X;
__device__ __half g_hf[HF_TOTAL];

__device__ __align__(16) __half g_zero[8];   // zero-initialized

// output offsets (triplet, kl, distance, A_att, N_att, A_Natt, N_Aatt, cos, x_out, v_feat)
constexpr size_t O_TRIP  = 0;
constexpr size_t O_KL    = 1;
constexpr size_t O_DIST  = 2;
constexpr size_t O_AATT  = 3;
constexpr size_t O_NATT  = 3 + 8192;
constexpr size_t O_ANATT = 3 + 16384;
constexpr size_t O_NAATT = 3 + 24576;
constexpr size_t O_COS   = 3 + 32768;
constexpr size_t O_XOUT  = 4 + 32768;
constexpr size_t O_VFEAT = O_XOUT + 64ull * 256 * 1024;

// ===========================================================================
// mma / smem helpers
// ===========================================================================
__device__ __forceinline__ void mma16816(float* c, const uint32_t* a, const uint32_t* b)
{
    asm volatile(
        "mma.sync.aligned.m16n8k16.row.col.f32.f16.f16.f32 "
        "{%0,%1,%2,%3}, {%4,%5,%6,%7}, {%8,%9}, {%0,%1,%2,%3};"
        : "+f"(c[0]), "+f"(c[1]), "+f"(c[2]), "+f"(c[3])
        : "r"(a[0]), "r"(a[1]), "r"(a[2]), "r"(a[3]), "r"(b[0]), "r"(b[1]));
}

__device__ __forceinline__ uint32_t cvt_smem(const void* p) {
    uint32_t a;
    asm("{ .reg .u64 t; cvta.to.shared.u64 t, %1; cvt.u32.u64 %0, t; }" : "=r"(a) : "l"(p));
    return a;
}

#define LDSM4(r0, r1, r2, r3, a) \
    asm volatile("ldmatrix.sync.aligned.m8n8.x4.shared.b16 {%0,%1,%2,%3}, [%4];" \
        : "=r"(r0), "=r"(r1), "=r"(r2), "=r"(r3) : "r"(a))

#define CP16(sa, gp) \
    asm volatile("cp.async.cg.shared.global [%0], [%1], 16;" :: "r"(sa), "l"(gp))
#define CP_COMMIT() asm volatile("cp.async.commit_group;" ::: "memory")
#define CP_WAIT1()  asm volatile("cp.async.wait_group 1;" ::: "memory")
#define CP_WAIT0()  asm volatile("cp.async.wait_group 0;" ::: "memory")

// one stage layout (bytes): A @0, B @10240; rows pad 40 elem (80B)
constexpr uint32_t SM_B = 10240;
constexpr uint32_t STAGE_BYTES = 20480;

// 128x32 tile MMA, pure fp16 (single term)
__device__ __forceinline__ void mma_tile_ldsm(uint32_t sb, float acc[4][4][4],
                                              int arow, int acolB, int brow, int bcolB)
{
#pragma unroll
    for (int ks = 0; ks < 32; ks += 16) {
        uint32_t fa[4][4], fb[4][2];
#pragma unroll
        for (int mi = 0; mi < 4; mi++) {
            uint32_t ad = sb + (uint32_t)((arow + mi * 16) * 80 + (ks + acolB) * 2);
            LDSM4(fa[mi][0], fa[mi][1], fa[mi][2], fa[mi][3], ad);
        }
#pragma unroll
        for (int np = 0; np < 2; np++) {
            uint32_t bd = sb + SM_B + (uint32_t)((brow + np * 16) * 80 + (ks + bcolB) * 2);
            LDSM4(fb[np * 2][0], fb[np * 2][1], fb[np * 2 + 1][0], fb[np * 2 + 1][1], bd);
        }
#pragma unroll
        for (int mi = 0; mi < 4; mi++)
#pragma unroll
            for (int ni = 0; ni < 4; ni++)
                mma16816(acc[mi][ni], fa[mi], fb[ni]);
    }
}

// stage one 128x32 K-chunk (A + B) via cp.async; CONV = im2col A
template<bool CONV>
__device__ __forceinline__ void stage_chunk(
    uint32_t sdst,
    const __half* __restrict__ A, const __half* __restrict__ B,
    const __half* zb, int row0, int col0, int K, int kc, int tid)
{
#pragma unroll
    for (int i = 0; i < 2; i++) {
        int chunk = tid * 2 + i;
        int rr = chunk >> 2, sg = chunk & 3;
        uint32_t so = (uint32_t)(rr * 80 + sg * 16);
        const __half* pa;
        if (CONV) {
            int gk = kc * 32 + sg * 8;
            int tap = gk >> 10, ci = gk & 1023;
            int m = row0 + rr;
            int t2 = (m & 255) + tap - 1;
            if (t2 >= 0 && t2 < 256) {
                pa = A + ((size_t)((m >> 8) * 256 + t2)) * 1024 + ci;
            } else { pa = zb; }
        } else {
            pa = A + (size_t)(row0 + rr) * K + kc * 32 + sg * 8;
        }
        CP16(sdst + so, pa);
        size_t ob = (size_t)(col0 + rr) * K + kc * 32 + sg * 8;
        CP16(sdst + SM_B + so, B + ob);
    }
    CP_COMMIT();
}

// ===========================================================================
// HMMA GEMM, cp.async double-buffered, pure fp16 operands, fp32 accum.
// EPI: 0=none,1=+bias,2=+bias+residual,3=+bias+gelu->fp16,4=+bias+relu,5=->fp16
// ===========================================================================
template<int EPI, bool CONV>
__global__ void __launch_bounds__(256, 2) mgemm(
    const __half* __restrict__ A, const __half* __restrict__ B,
    float* __restrict__ C, __half* __restrict__ Ch,
    const float* __restrict__ bias,
    int M, int N, int K)
{
    extern __shared__ char smem[];
    const int tid  = threadIdx.x;
    const int wid  = tid >> 5;
    const int lane = tid & 31;
    const int g = lane >> 2, t = lane & 3;
    const int wm = wid >> 2, wn = wid & 3;
    const int row0 = blockIdx.y * 128;
    const int col0 = blockIdx.x * 128;
    const uint32_t sb0 = cvt_smem(smem);

    const int arow  = wm * 64 + (lane & 7) + ((lane >> 3) & 1) * 8;
    const int acolB = ((lane >> 4) & 1) * 8;
    const int brow  = wn * 32 + ((lane >> 4) & 1) * 8 + (lane & 7);
    const int bcolB = ((lane >> 3) & 1) * 8;

    float acc[4][4][4];
#pragma unroll
    for (int mi = 0; mi < 4; mi++)
#pragma unroll
        for (int ni = 0; ni < 4; ni++)
#pragma unroll
            for (int q = 0; q < 4; q++) acc[mi][ni][q] = 0.f;

    const int nchunks = K >> 5;

    stage_chunk<CONV>(sb0, A, B, g_zero, row0, col0, K, 0, tid);

    for (int kc = 0; kc < nchunks; kc++) {
        const uint32_t sb = sb0 + (uint32_t)(kc & 1) * STAGE_BYTES;
        if (kc + 1 < nchunks) {
            const uint32_t sn = sb0 + (uint32_t)((kc + 1) & 1) * STAGE_BYTES;
            stage_chunk<CONV>(sn, A, B, g_zero, row0, col0, K, kc + 1, tid);
            CP_WAIT1();
        } else {
            CP_WAIT0();
        }
        __syncthreads();
        mma_tile_ldsm(sb, acc, arow, acolB, brow, bcolB);
        __syncthreads();
    }

#pragma unroll
    for (int mi = 0; mi < 4; mi++) {
#pragma unroll
        for (int ni = 0; ni < 4; ni++) {
#pragma unroll
            for (int q = 0; q < 4; q++) {
                int r = row0 + wm * 64 + mi * 16 + g + (q >> 1) * 8;
                int c = col0 + wn * 32 + ni * 8 + t * 2 + (q & 1);
                float v = acc[mi][ni][q];
                size_t o = (size_t)r * N + c;
                if (EPI != 0 && EPI != 5) v += bias[c];
                if (EPI == 2) v += C[o];
                if (EPI == 3 || EPI == 5) {
                    if (EPI == 3) v = 0.5f * v * (1.f + erff(v * 0.70710678118654752f));
                    Ch[o] = __float2half_rn(v);
                } else {
                    if (EPI == 4) v = fmaxf(v, 0.f);
                    C[o] = v;
                }
            }
        }
    }
}

// ===========================================================================
// Batched QK^T (static 20KB single-stage)
// ===========================================================================
__global__ void __launch_bounds__(256, 2) bqk_kernel(
    const __half* __restrict__ Q, float* __restrict__ S)
{
    __shared__ alignas(16) char smem[20480];
    const int tid  = threadIdx.x;
    const int wid  = tid >> 5;
    const int lane = tid & 31;
    const int g = lane >> 2, t = lane & 3;
    const int wm = wid >> 2, wn = wid & 3;
    const int bh = blockIdx.z, b = bh >> 2, h = bh & 3;
    const int i0 = blockIdx.x * 128, j0 = blockIdx.y * 128;
    const __half* Ah = Q + (size_t)b * 256 * 1536 + h * 128;
    const uint32_t sb = cvt_smem(smem);

    const int arow  = wm * 64 + (lane & 7) + ((lane >> 3) & 1) * 8;
    const int acolB = ((lane >> 4) & 1) * 8;
    const int brow  = wn * 32 + ((lane >> 4) & 1) * 8 + (lane & 7);
    const int bcolB = ((lane >> 3) & 1) * 8;

    float acc[4][4][4];
#pragma unroll
    for (int mi = 0; mi < 4; mi++)
#pragma unroll
        for (int ni = 0; ni < 4; ni++)
#pragma unroll
            for (int q = 0; q < 4; q++) acc[mi][ni][q] = 0.f;

    for (int kc = 0; kc < 4; kc++) {
#pragma unroll
        for (int i = 0; i < 2; i++) {
            int chunk = tid * 2 + i;
            int rr = chunk >> 2, sg = chunk & 3;
            uint32_t so = (uint32_t)(rr * 80 + sg * 16);
            size_t oa = (size_t)(i0 + rr) * 1536 + kc * 32 + sg * 8;
            size_t ob = (size_t)(j0 + rr) * 1536 + 512 + kc * 32 + sg * 8;
            *(uint4*)(smem + so)        = *(const uint4*)(Ah + oa);
            *(uint4*)(smem + SM_B + so) = *(const uint4*)(Ah + ob);
        }
        __syncthreads();
        mma_tile_ldsm(sb, acc, arow, acolB, brow, bcolB);
        __syncthreads();
    }

    float* so2 = S + (size_t)bh * 65536;
    const float scale = 0.08838834764831845f;
#pragma unroll
    for (int mi = 0; mi < 4; mi++)
#pragma unroll
        for (int ni = 0; ni < 4; ni++)
#pragma unroll
            for (int q = 0; q < 4; q++) {
                int r = i0 + wm * 64 + mi * 16 + g + (q >> 1) * 8;
                int c = j0 + wn * 32 + ni * 8 + t * 2 + (q & 1);
                so2[(size_t)r * 256 + c] = acc[mi][ni][q] * scale;
            }
}

// row softmax -> fp16
__global__ void __launch_bounds__(256) softmaxp_kernel(const float* __restrict__ S,
                                                       __half* __restrict__ P)
{
    const int row  = blockIdx.x * 8 + (threadIdx.x >> 5);
    const int lane = threadIdx.x & 31;
    const float* p = S + (size_t)row * 256;
    float v[8]; float mx = -1e30f;
#pragma unroll
    for (int j = 0; j < 8; j++) { v[j] = p[lane + 32 * j]; mx = fmaxf(mx, v[j]); }
#pragma unroll
    for (int o = 16; o; o >>= 1) mx = fmaxf(mx, __shfl_xor_sync(0xffffffffu, mx, o));
    float s = 0.f;
#pragma unroll
    for (int j = 0; j < 8; j++) { v[j] = expf(v[j] - mx); s += v[j]; }
#pragma unroll
    for (int o = 16; o; o >>= 1) s += __shfl_xor_sync(0xffffffffu, s, o);
    const float inv = 1.f / s;
#pragma unroll
    for (int j = 0; j < 8; j++)
        P[(size_t)row * 256 + lane + 32 * j] = __float2half_rn(v[j] * inv);
}

// V transpose
__global__ void vtrans_kernel(const __half* __restrict__ V, __half* __restrict__ vt)
{
    __shared__ __half th[32][33];
    const int bh = blockIdx.x, b = bh >> 2, h = bh & 3;
    const int d0 = blockIdx.y * 32, j0 = blockIdx.z * 32;
    const int tx = threadIdx.x, ty = threadIdx.y;
    const size_t base = (size_t)b * 256 * 1536 + 1024 + h * 128;
    for (int r = ty; r < 32; r += 8) {
        size_t o = base + (size_t)(j0 + r) * 1536 + d0 + tx;
        th[r][tx] = V[o];
    }
    __syncthreads();
    const size_t obase = (size_t)bh * 32768;
    for (int r = ty; r < 32; r += 8) {
        size_t o = obase + (size_t)(d0 + r) * 256 + j0 + tx;
        vt[o] = th[tx][r];
    }
}

// Batched PV
__global__ void __launch_bounds__(256, 2) bpv_kernel(
    const __half* __restrict__ P, const __half* __restrict__ vt,
    __half* __restrict__ O)
{
    __shared__ alignas(16) char smem[20480];
    const int tid  = threadIdx.x;
    const int wid  = tid >> 5;
    const int lane = tid & 31;
    const int g = lane >> 2, t = lane & 3;
    const int wm = wid >> 2, wn = wid & 3;
    const int bh = blockIdx.z, b = bh >> 2, h = bh & 3;
    const int i0 = blockIdx.x * 128;
    const __half* Ah = P + (size_t)bh * 65536 + (size_t)i0 * 256;
    const __half* Bh = vt + (size_t)bh * 32768;
    const uint32_t sb = cvt_smem(smem);

    const int arow  = wm * 64 + (lane & 7) + ((lane >> 3) & 1) * 8;
    const int acolB = ((lane >> 4) & 1) * 8;
    const int brow  = wn * 32 + ((lane >> 4) & 1) * 8 + (lane & 7);
    const int bcolB = ((lane >> 3) & 1) * 8;

    float acc[4][4][4];
#pragma unroll
    for (int mi = 0; mi < 4; mi++)
#pragma unroll
        for (int ni = 0; ni < 4; ni++)
#pragma unroll
            for (int q = 0; q < 4; q++) acc[mi][ni][q] = 0.f;

    for (int kc = 0; kc < 8; kc++) {
#pragma unroll
        for (int i = 0; i < 2; i++) {
            int chunk = tid * 2 + i;
            int rr = chunk >> 2, sg = chunk & 3;
            uint32_t so = (uint32_t)(rr * 80 + sg * 16);
            size_t oa = (size_t)rr * 256 + kc * 32 + sg * 8;
            *(uint4*)(smem + so)        = *(const uint4*)(Ah + oa);
            *(uint4*)(smem + SM_B + so) = *(const uint4*)(Bh + oa);
        }
        __syncthreads();
        mma_tile_ldsm(sb, acc, arow, acolB, brow, bcolB);
        __syncthreads();
    }

#pragma unroll
    for (int mi = 0; mi < 4; mi++)
#pragma unroll
        for (int ni = 0; ni < 4; ni++)
#pragma unroll
            for (int q = 0; q < 4; q++) {
                int r = i0 + wm * 64 + mi * 16 + g + (q >> 1) * 8;
                int c = wn * 32 + ni * 8 + t * 2 + (q & 1);
                size_t o = ((size_t)b * 256 + r) * 512 + h * 128 + c;
                O[o] = __float2half_rn(acc[mi][ni][q]);
            }
}

// ===========================================================================
// Prep kernels
// ===========================================================================
__global__ void wprep_t(const float* __restrict__ W, __half* __restrict__ Wh,
                        int K, int N)
{
    __shared__ float tile[32][33];
    const int k0 = blockIdx.x * 32, n0 = blockIdx.y * 32;
    const int tx = threadIdx.x, ty = threadIdx.y;
    for (int r = ty; r < 32; r += 8)
        tile[r][tx] = W[(size_t)(k0 + r) * N + n0 + tx];
    __syncthreads();
    for (int r = ty; r < 32; r += 8)
        Wh[(size_t)(n0 + r) * K + k0 + tx] = __float2half_rn(tile[tx][r]);
}

__global__ void convprep(const float* __restrict__ w, __half* __restrict__ Wh)
{
    const int n = 512 * 3072;
    for (int idx = blockIdx.x * blockDim.x + threadIdx.x; idx < n; idx += gridDim.x * blockDim.x) {
        int d = idx / 3072, k = idx % 3072;
        int tap = k >> 10, ci = k & 1023;
        Wh[idx] = __float2half_rn(w[(size_t)d * 3072 + ci * 3 + tap]);
    }
}

__global__ void xcvt(const float* __restrict__ x, __half* __restrict__ xh)
{
    const int n = 64 * 256 * 1024;
    for (int i = blockIdx.x * blockDim.x + threadIdx.x; i < n; i += gridDim.x * blockDim.x)
        xh[i] = __float2half_rn(x[i]);
}

__device__ __forceinline__ float wsum(float v)
{
#pragma unroll
    for (int o = 16; o; o >>= 1) v += __shfl_xor_sync(0xffffffffu, v, o);
    return v;
}

// ===========================================================================
// LayerNorm -> fp16 (one warp per row)
// ===========================================================================
__global__ void __launch_bounds__(256) ln_kernel(const float* __restrict__ x,
                                                 const float* __restrict__ g,
                                                 const float* __restrict__ bb,
                                                 __half* __restrict__ y)
{
    const int w = threadIdx.x >> 5, lane = threadIdx.x & 31;
    const int row = blockIdx.x * 8 + w;
    const float* xr = x + (size_t)row * 512;
    float v[16];
    float s = 0.f;
#pragma unroll
    for (int j = 0; j < 16; j++) { v[j] = xr[lane + 32 * j]; s += v[j]; }
    s = wsum(s);
    const float mean = s * (1.f / 512.f);
    float q = 0.f;
#pragma unroll
    for (int j = 0; j < 16; j++) { float d = v[j] - mean; q += d * d; }
    q = wsum(q);
    const float inv = rsqrtf(q * (1.f / 512.f) + 1e-5f);
#pragma unroll
    for (int j = 0; j < 16; j++) {
        int c = lane + 32 * j;
        y[(size_t)row * 512 + c] = __float2half_rn((v[j] - mean) * inv * g[c] + bb[c]);
    }
}

// ===========================================================================
// Memory attention: 16 rows/block (warp per row), mem staged via smem
// ===========================================================================
__global__ void __launch_bounds__(512) memory_kernel(const float* __restrict__ Nx,
                                                     const float* __restrict__ Ax,
                                                     const float* __restrict__ a_mem,
                                                     const float* __restrict__ n_mem,
                                                     float* __restrict__ att_base,
                                                     __half* __restrict__ aug_base)
{
    __shared__ float mch[20][512];
    const int w = threadIdx.x >> 5, lane = threadIdx.x & 31;
    const int combo = blockIdx.y;       // 0:A(Ax,a) 1:NA(Ax,n) 2:AN(Nx,a) 3:N(Nx,n)
    const int row = blockIdx.x * 16 + w;
    const float* x   = (combo < 2) ? Ax : Nx;
    const float* mem = (combo & 1) ? n_mem : a_mem;
    const int att_off[4] = {0, 24576, 16384, 8192};
    float* att_out = att_base + att_off[combo];
    __half* aug = aug_base + (size_t)combo * SZ_AUG;

    float xr[16], facc[16];
#pragma unroll
    for (int j = 0; j < 16; j++) {
        xr[j] = x[(size_t)row * 512 + lane + 32 * j];
        facc[j] = 0.f;
    }
    float t0 = -1e30f, t1 = -1e30f, t2 = -1e30f, t3 = -1e30f;

    for (int c = 0; c < 3; c++) {
        for (int i = threadIdx.x; i < 20 * 512; i += 512)
            ((float*)mch)[i] = mem[c * 20 * 512 + i];
        __syncthreads();
#pragma unroll 4
        for (int n = 0; n < 20; n++) {
            float s = 0.f;
#pragma unroll
            for (int j = 0; j < 16; j++) s = fmaf(xr[j], mch[n][lane + 32 * j], s);
            s = wsum(s);
            float att = 1.f / (1.f + expf(-s * 0.044194173824159216f));
            if (att > t0)      { t3 = t2; t2 = t1; t1 = t0; t0 = att; }
            else if (att > t1) { t3 = t2; t2 = t1; t1 = att; }
            else if (att > t2) { t3 = t2; t2 = att; }
            else if (att > t3) { t3 = att; }
#pragma unroll
            for (int j = 0; j < 16; j++)
                facc[j] = fmaf(att, mch[n][lane + 32 * j], facc[j]);
        }
        __syncthreads();
    }

    if (lane == 0) att_out[row] = (t0 + t1 + t2 + t3) * 0.25f;
#pragma unroll
    for (int j = 0; j < 16; j++)
        aug[(size_t)row * 512 + lane + 32 * j] = __float2half_rn(facc[j]);
}

// ===========================================================================
// top-k (3 combos batched via grid.y) / losses / misc
// ===========================================================================
__global__ void __launch_bounds__(256) topk_gather3(
    const float* __restrict__ attA, const float* __restrict__ attN,
    const float* __restrict__ attNA,
    const float* __restrict__ Ax, const float* __restrict__ Nx,
    float* __restrict__ negv, float* __restrict__ anch, float* __restrict__ posv,
    int* __restrict__ idxA, int* __restrict__ idxN)
{
    __shared__ float vals[256], rv[256];
    __shared__ int ri[256], ids[17];
    const int b = blockIdx.x, tid = threadIdx.x;
    const int combo = blockIdx.y;
    const float* att   = (combo == 0) ? attA : (combo == 1) ? attN : attNA;
    const float* feats = (combo == 1) ? Nx : Ax;
    float* meanv = (combo == 0) ? negv : (combo == 1) ? anch : posv;
    int* idx_out = (combo == 0) ? idxA : (combo == 1) ? idxN : nullptr;

    vals[tid] = att[b * 256 + tid];
    __syncthreads();
    for (int it = 0; it < 17; it++) {
        rv[tid] = vals[tid]; ri[tid] = tid;
        __syncthreads();
        for (int s = 128; s; s >>= 1) {
            if (tid < s) {
                float ov = rv[tid + s]; int oi = ri[tid + s];
                if (ov > rv[tid] || (ov == rv[tid] && oi < ri[tid])) { rv[tid] = ov; ri[tid] = oi; }
            }
            __syncthreads();
        }
        if (tid == 0) {
            ids[it] = ri[0];
            vals[ri[0]] = -1e30f;
            if (idx_out) idx_out[b * 17 + it] = ri[0];
        }
        __syncthreads();
    }
    for (int d = tid; d < 512; d += 256) {
        float s = 0.f;
        for (int j = 0; j < 17; j++) s += feats[((size_t)b * 256 + ids[j]) * 512 + d];
        meanv[b * 512 + d] = s * (1.f / 17.f);
    }
}

__global__ void __launch_bounds__(1024) triplet_cos_kernel(const float* __restrict__ anchor,
                                                           const float* __restrict__ pos,
                                                           const float* __restrict__ neg,
                                                           float* __restrict__ trip_out,
                                                           float* __restrict__ cos_out)
{
    __shared__ float st[32], sc[32];
    const int w = threadIdx.x >> 5, lane = threadIdx.x & 31;
    float sa = 0, sp = 0, sn = 0, dan = 0;
    for (int d = lane; d < 512; d += 32) {
        float a = anchor[w * 512 + d], p = pos[w * 512 + d], n = neg[w * 512 + d];
        sa += a * a; sp += p * p; sn += n * n; dan += a * n;
    }
    sa = wsum(sa); sp = wsum(sp); sn = wsum(sn); dan = wsum(dan);
    float na = sqrtf(sa), npp = sqrtf(sp), ng = sqrtf(sn);
    float ina = 1.f / na, inp = 1.f / npp, ing = 1.f / ng;
    float dp2 = 0, dn2 = 0;
    for (int d = lane; d < 512; d += 32) {
        float a  = anchor[w * 512 + d] * ina;
        float dpv = a - pos[w * 512 + d] * inp + 1e-6f;
        float dnv = a - neg[w * 512 + d] * ing + 1e-6f;
        dp2 += dpv * dpv; dn2 += dnv * dnv;
    }
    dp2 = wsum(dp2); dn2 = wsum(dn2);
    if (lane == 0) {
        st[w] = fmaxf(sqrtf(dp2) - sqrtf(dn2) + 1.f, 0.f);
        sc[w] = 1.f - dan / (fmaxf(na, 1e-6f) * fmaxf(ng, 1e-6f));
    }
    __syncthreads();
    if (threadIdx.x == 0) {
        float a = 0, c = 0;
        for (int i = 0; i < 32; i++) { a += st[i]; c += sc[i]; }
        trip_out[0] = a * (1.f / 32.f);
        cos_out[0]  = c * (1.f / 32.f);
    }
}

__global__ void __launch_bounds__(1024) distance_kernel(const float* __restrict__ anew,
                                                        const float* __restrict__ nnew,
                                                        float* __restrict__ out)
{
    __shared__ float sd[32];
    const int w = threadIdx.x >> 5, lane = threadIdx.x & 31;
    float sa = 0, sn = 0;
    for (int d = lane; d < 512; d += 32) {
        float a = anew[w * 512 + d], n = nnew[w * 512 + d];
        sa += a * a; sn += n * n;
    }
    sa = wsum(sa); sn = wsum(sn);
    if (lane == 0) sd[w] = fmaxf(100.f - sqrtf(sn) + sqrtf(sa), 0.f);
    __syncthreads();
    if (threadIdx.x == 0) {
        float s = 0;
        for (int i = 0; i < 32; i++) s += sd[i];
        out[0] = s * (1.f / 32.f);
    }
}

// fused VAE reparam + KL partial sums
__global__ void __launch_bounds__(256) vaekl_kernel(const float* __restrict__ mu,
                                                    const float* __restrict__ var,
                                                    const float* __restrict__ eps,
                                                    float* __restrict__ o,
                                                    float* __restrict__ part, int n)
{
    __shared__ float red[256];
    float s = 0.f;
    for (int i = blockIdx.x * 256 + threadIdx.x; i < n; i += gridDim.x * 256) {
        float m = mu[i], v = var[i];
        float ev = expf(v);
        o[i] = m + eps[i] * sqrtf(ev);
        s += 1.f + v - m * m - ev;
    }
    red[threadIdx.x] = s; __syncthreads();
    for (int t = 128; t; t >>= 1) { if (threadIdx.x < t) red[threadIdx.x] += red[threadIdx.x + t]; __syncthreads(); }
    if (threadIdx.x == 0) part[blockIdx.x] = red[0];
}

__global__ void __launch_bounds__(1024) kl_final_kernel(const float* __restrict__ part,
                                                        float* __restrict__ out)
{
    __shared__ float red[1024];
    red[threadIdx.x] = part[threadIdx.x]; __syncthreads();
    for (int t = 512; t; t >>= 1) { if (threadIdx.x < t) red[threadIdx.x] += red[threadIdx.x + t]; __syncthreads(); }
    if (threadIdx.x == 0) out[0] = -0.5f * red[0] * (1.f / 16384.f);
}

__global__ void __launch_bounds__(512) gather_mean_kernel(const float* __restrict__ src,
                                                          const int* __restrict__ idx,
                                                          float* __restrict__ out)
{
    __shared__ int ids[17];
    const int b = blockIdx.x, tid = threadIdx.x;
    if (tid < 17) ids[tid] = idx[b * 17 + tid];
    __syncthreads();
    float s = 0.f;
    for (int j = 0; j < 17; j++) s += src[((size_t)b * 256 + ids[j]) * 512 + tid];
    out[b * 512 + tid] = s * (1.f / 17.f);
}

__global__ void xout_kernel(const float* __restrict__ h, const float* __restrict__ nnew,
                            const float* __restrict__ anm, const float* __restrict__ anew,
                            const float* __restrict__ nam, float* __restrict__ xout)
{
    const int n = 64 * 256 * 1024;
    for (int i = blockIdx.x * blockDim.x + threadIdx.x; i < n; i += gridDim.x * blockDim.x) {
        int c  = i & 1023;
        int rt = i >> 10;
        float v;
        if (c < 512) v = h[(size_t)rt * 512 + c];
        else {
            int cc = c - 512;
            if (rt < 8192) v = nnew[(size_t)rt * 512 + cc] + anm[(size_t)rt * 512 + cc];
            else {
                size_t o = (size_t)(rt - 8192) * 512 + cc;
                v = anew[o] + nam[o];
            }
        }
        xout[i] = v;
    }
}

__global__ void vfeat_kernel(const float* __restrict__ h, float* __restrict__ v)
{
    __shared__ float tile[32][33];
    const int b = blockIdx.x, d0 = blockIdx.y * 32, t0 = blockIdx.z * 32;
    for (int r = threadIdx.y; r < 32; r += 8)
        tile[r][threadIdx.x] = h[((size_t)b * 256 + t0 + r) * 512 + d0 + threadIdx.x];
    __syncthreads();
    for (int r = threadIdx.y; r < 32; r += 8)
        v[((size_t)b * 512 + d0 + r) * 256 + t0 + threadIdx.x] = tile[threadIdx.x][r];
}

// ===========================================================================
extern "C" void kernel_launch(void* const* d_in, const int* in_sizes, int n_in,
                              void* d_out, int out_size)
{
    const float* x      = (const float*)d_in[0];
    const float* eps_in = (const float*)d_in[1];
    const float* conv_w = (const float*)d_in[2];
    const float* conv_b = (const float*)d_in[3];
    const float* ln1_g  = (const float*)d_in[4];
    const float* ln1_b  = (const float*)d_in[5];
    const float* qkv_w  = (const float*)d_in[6];
    const float* out_w  = (const float*)d_in[7];
    const float* out_b  = (const float*)d_in[8];
    const float* ln2_g  = (const float*)d_in[9];
    const float* ln2_b  = (const float*)d_in[10];
    const float* ff1_w  = (const float*)d_in[11];
    const float* ff1_b  = (const float*)d_in[12];
    const float* ff2_w  = (const float*)d_in[13];
    const float* ff2_b  = (const float*)d_in[14];
    const float* a_mem  = (const float*)d_in[15];
    const float* n_mem  = (const float*)d_in[16];
    const float* mu_w   = (const float*)d_in[17];
    const float* mu_b   = (const float*)d_in[18];
    const float* var_w  = (const float*)d_in[19];
    const float* var_b  = (const float*)d_in[20];
    float* out = (float*)d_out;

    float* S = nullptr;
    cudaGetSymbolAddress((void**)&S, g_scratch);
    __half* HF = nullptr;
    cudaGetSymbolAddress((void**)&HF, g_hf);

    float* h     = S + OFF_H;
    float* sc    = S + OFF_SC;
    float* stack = S + OFF_STACK;
    float* Anew  = stack;
    float* NAm   = stack + 1ull * 8192 * 512;
    float* ANm   = stack + 2ull * 8192 * 512;
    float* muB   = stack + 3ull * 8192 * 512;
    float* varB  = S + OFF_VAR;
    float* newN  = S + OFF_NEW;
    float* anch  = S + OFF_ANCH;
    float* negv  = S + OFF_NEG;
    float* posv  = S + OFF_POS;
    float* anchN = S + OFF_ANCHN;
    float* negN  = S + OFF_NEGN;
    int*   idxA  = (int*)(S + OFF_IDXA);
    int*   idxN  = (int*)(S + OFF_IDXN);
    float* klp   = S + OFF_KLP;

    __half* lnb  = HF + B_LN;
    __half* aob  = HF + B_AO;
    __half* ffb  = HF + B_FF;
    __half* qkvb = HF + B_QKV;
    __half* pb   = HF + B_P;
    __half* vtb  = HF + B_VT;
    __half* xh   = HF + B_X;

    constexpr int MG_SMEM = 40960;   // 2 stages x 20480
    cudaFuncSetAttribute(mgemm<0,false>, cudaFuncAttributeMaxDynamicSharedMemorySize, MG_SMEM);
    cudaFuncSetAttribute(mgemm<1,false>, cudaFuncAttributeMaxDynamicSharedMemorySize, MG_SMEM);
    cudaFuncSetAttribute(mgemm<2,false>, cudaFuncAttributeMaxDynamicSharedMemorySize, MG_SMEM);
    cudaFuncSetAttribute(mgemm<3,false>, cudaFuncAttributeMaxDynamicSharedMemorySize, MG_SMEM);
    cudaFuncSetAttribute(mgemm<5,false>, cudaFuncAttributeMaxDynamicSharedMemorySize, MG_SMEM);
    cudaFuncSetAttribute(mgemm<4,true>,  cudaFuncAttributeMaxDynamicSharedMemorySize, MG_SMEM);

    // 1-3: prep
    convprep<<<1024, 256>>>(conv_w, HF + B_CNVW);
    xcvt<<<8192, 256>>>(x, xh);
    wprep_t<<<dim3(16, 48), dim3(32, 8)>>>(qkv_w, HF + B_QKVW, 512, 1536);

    // 4: conv (implicit im2col, relu+bias) — profiler target
    mgemm<4, true><<<dim3(4, 128), 256, MG_SMEM>>>(
        xh, HF + B_CNVW, h, nullptr, conv_b, 16384, 512, 3072);

    // 5: ln (layer 0)
    ln_kernel<<<2048, 256>>>(h, ln1_g, ln1_b, lnb);

    // 6: qkv mgemm (layer 0)
    mgemm<5, false><<<dim3(12, 128), 256, MG_SMEM>>>(
        lnb, HF + B_QKVW, nullptr, qkvb, nullptr, 16384, 1536, 512);

    // remaining weight prep
    wprep_t<<<dim3(16, 16), dim3(32, 8)>>>(out_w, HF + B_OUTW, 512, 512);
    wprep_t<<<dim3(16, 16), dim3(32, 8)>>>(ff1_w, HF + B_FF1W, 512, 512);
    wprep_t<<<dim3(16, 16), dim3(32, 8)>>>(ff2_w, HF + B_FF2W, 512, 512);
    wprep_t<<<dim3(16, 48), dim3(32, 8)>>>(qkv_w + 786432, HF + B_QKVW + 786432, 512, 1536);
    wprep_t<<<dim3(16, 16), dim3(32, 8)>>>(out_w + 262144, HF + B_OUTW + 262144, 512, 512);
    wprep_t<<<dim3(16, 16), dim3(32, 8)>>>(ff1_w + 262144, HF + B_FF1W + 262144, 512, 512);
    wprep_t<<<dim3(16, 16), dim3(32, 8)>>>(ff2_w + 262144, HF + B_FF2W + 262144, 512, 512);
    wprep_t<<<dim3(16, 16), dim3(32, 8)>>>(mu_w,  HF + B_MUW,  512, 512);
    wprep_t<<<dim3(16, 16), dim3(32, 8)>>>(var_w, HF + B_VARW, 512, 512);

    // ---- transformer (layer 0 continues, then layer 1)
    for (int i = 0; i < 2; i++) {
        if (i == 1) {
            ln_kernel<<<2048, 256>>>(h, ln1_g + 512, ln1_b + 512, lnb);
            mgemm<5, false><<<dim3(12, 128), 256, MG_SMEM>>>(
                lnb, HF + B_QKVW + 786432, nullptr, qkvb, nullptr, 16384, 1536, 512);
        }
        vtrans_kernel<<<dim3(256, 4, 8), dim3(32, 8)>>>(qkvb, vtb);
        bqk_kernel<<<dim3(2, 2, 256), 256>>>(qkvb, sc);
        softmaxp_kernel<<<8192, 256>>>(sc, pb);
        bpv_kernel<<<dim3(2, 1, 256), 256>>>(pb, vtb, aob);
        mgemm<2, false><<<dim3(4, 128), 256, MG_SMEM>>>(
            aob, HF + B_OUTW + (size_t)i * 262144, h, nullptr, out_b + i * 512, 16384, 512, 512);
        ln_kernel<<<2048, 256>>>(h, ln2_g + i * 512, ln2_b + i * 512, lnb);
        mgemm<3, false><<<dim3(4, 128), 256, MG_SMEM>>>(
            lnb, HF + B_FF1W + (size_t)i * 262144, nullptr, ffb, ff1_b + i * 512, 16384, 512, 512);
        mgemm<2, false><<<dim3(4, 128), 256, MG_SMEM>>>(
            ffb, HF + B_FF2W + (size_t)i * 262144, h, nullptr, ff2_b + i * 512, 16384, 512, 512);
    }

    const float* Nx = h;                       // x_emb[:32]
    const float* Ax = h + (size_t)8192 * 512;  // x_emb[32:]

    memory_kernel<<<dim3(512, 4), 512>>>(Nx, Ax, a_mem, n_mem,
                                         out + O_AATT, HF + B_AUG);

    topk_gather3<<<dim3(32, 3), 256>>>(out + O_AATT, out + O_NATT, out + O_NAATT,
                                       Ax, Nx, negv, anch, posv, idxA, idxN);

    triplet_cos_kernel<<<1, 1024>>>(anch, posv, negv, out + O_TRIP, out + O_COS);

    // stacked mu projection: [augA; augNA; augAN; augN] @ mu -> [Anew; NAm; ANm; muB]
    mgemm<1, false><<<dim3(4, 256), 256, MG_SMEM>>>(
        HF + B_AUG, HF + B_MUW, stack, nullptr, mu_b, 32768, 512, 512);
    mgemm<1, false><<<dim3(4, 64), 256, MG_SMEM>>>(
        HF + B_AUG + 3 * SZ_AUG, HF + B_VARW, varB, nullptr, var_b, 8192, 512, 512);

    vaekl_kernel<<<1024, 256>>>(muB, varB, eps_in, newN, klp, 8192 * 512);
    kl_final_kernel<<<1, 1024>>>(klp, out + O_KL);

    gather_mean_kernel<<<32, 512>>>(newN, idxN, anchN);
    gather_mean_kernel<<<32, 512>>>(Anew, idxA, negN);
    distance_kernel<<<1, 1024>>>(anchN, negN, out + O_DIST);

    xout_kernel<<<8192, 256>>>(h, newN, ANm, Anew, NAm, out + O_XOUT);
    vfeat_kernel<<<dim3(64, 16, 8), dim3(32, 8)>>>(h, out + O_VFEAT);
}

// round 15
// speedup vs baseline: 6.3674x; 1.1988x over previous
#include <cuda_runtime.h>
#include <cuda_fp16.h>
#include <math.h>
#include <stdint.h>

// ===========================================================================
// fp32 scratch
// ===========================================================================
constexpr size_t OFF_H     = 0;                         // 16384*512
constexpr size_t OFF_SC    = 8388608;                   // S as fp16 (reuse)
constexpr size_t OFF_STACK = OFF_SC + 16777216;         // 32768*512: Anew,NAm,ANm,muB
constexpr size_t OFF_VAR   = OFF_STACK + 16777216;      // 8192*512
constexpr size_t OFF_NEW   = OFF_VAR + 4194304;         // 8192*512
constexpr size_t OFF_ANCH  = OFF_NEW + 4194304;         // 32*512 each below
constexpr size_t OFF_NEG   = OFF_ANCH + 16384;
constexpr size_t OFF_POS   = OFF_NEG  + 16384;
constexpr size_t OFF_ANCHN = OFF_POS  + 16384;
constexpr size_t OFF_NEGN  = OFF_ANCHN + 16384;
constexpr size_t OFF_IDXA  = OFF_NEGN + 16384;
constexpr size_t OFF_IDXN  = OFF_IDXA + 1024;
constexpr size_t OFF_KLP   = OFF_IDXN + 1024;
constexpr size_t SCRATCH_TOTAL = OFF_KLP + 1024;
__device__ float g_scratch[SCRATCH_TOTAL];

// ===========================================================================
// fp16 scratch
// ===========================================================================
constexpr size_t SZ_TOK  = 16384ull * 512;
constexpr size_t SZ_QKV  = 16384ull * 1536;
constexpr size_t SZ_P    = 256ull * 65536;
constexpr size_t SZ_VT   = 256ull * 32768;
constexpr size_t SZ_AUG  = 8192ull * 512;
constexpr size_t SZ_X    = 64ull * 256 * 1024;   // 16777216

constexpr size_t B_LN   = 0;
constexpr size_t B_AO   = B_LN + SZ_TOK;
constexpr size_t B_FF   = B_AO + SZ_TOK;
constexpr size_t B_QKV  = B_FF + SZ_TOK;
constexpr size_t B_P    = B_QKV + SZ_QKV;
constexpr size_t B_VT   = B_P + SZ_P;
constexpr size_t B_AUG  = B_VT + SZ_VT;              // [A, NA, AN, N] stacked
constexpr size_t B_QKVW = B_AUG + 4 * SZ_AUG;        // 2*786432
constexpr size_t B_OUTW = B_QKVW + 2ull * 786432;    // 2*262144
constexpr size_t B_FF1W = B_OUTW + 2ull * 262144;
constexpr size_t B_FF2W = B_FF1W + 2ull * 262144;
constexpr size_t B_MUW  = B_FF2W + 2ull * 262144;    // 262144
constexpr size_t B_VARW = B_MUW + 262144;
constexpr size_t B_CNVW = B_VARW + 262144;           // 1572864
constexpr size_t B_X    = B_CNVW + 1572864;
constexpr size_t HF_TOTAL = B_X + SZ_X;
__device__ __half g_hf[HF_TOTAL];

__device__ __align__(16) __half g_zero[8];   // zero-initialized

// output offsets (triplet, kl, distance, A_att, N_att, A_Natt, N_Aatt, cos, x_out, v_feat)
constexpr size_t O_TRIP  = 0;
constexpr size_t O_KL    = 1;
constexpr size_t O_DIST  = 2;
constexpr size_t O_AATT  = 3;
constexpr size_t O_NATT  = 3 + 8192;
constexpr size_t O_ANATT = 3 + 16384;
constexpr size_t O_NAATT = 3 + 24576;
constexpr size_t O_COS   = 3 + 32768;
constexpr size_t O_XOUT  = 4 + 32768;
constexpr size_t O_VFEAT = O_XOUT + 64ull * 256 * 1024;

// ===========================================================================
// mma / smem helpers
// ===========================================================================
__device__ __forceinline__ void mma16816(float* c, const uint32_t* a, const uint32_t* b)
{
    asm volatile(
        "mma.sync.aligned.m16n8k16.row.col.f32.f16.f16.f32 "
        "{%0,%1,%2,%3}, {%4,%5,%6,%7}, {%8,%9}, {%0,%1,%2,%3};"
        : "+f"(c[0]), "+f"(c[1]), "+f"(c[2]), "+f"(c[3])
        : "r"(a[0]), "r"(a[1]), "r"(a[2]), "r"(a[3]), "r"(b[0]), "r"(b[1]));
}

__device__ __forceinline__ uint32_t cvt_smem(const void* p) {
    uint32_t a;
    asm("{ .reg .u64 t; cvta.to.shared.u64 t, %1; cvt.u32.u64 %0, t; }" : "=r"(a) : "l"(p));
    return a;
}

#define LDSM4(r0, r1, r2, r3, a) \
    asm volatile("ldmatrix.sync.aligned.m8n8.x4.shared.b16 {%0,%1,%2,%3}, [%4];" \
        : "=r"(r0), "=r"(r1), "=r"(r2), "=r"(r3) : "r"(a))

#define CP16(sa, gp) \
    asm volatile("cp.async.cg.shared.global [%0], [%1], 16;" :: "r"(sa), "l"(gp))
#define CP_COMMIT() asm volatile("cp.async.commit_group;" ::: "memory")
#define CP_WAIT0()  asm volatile("cp.async.wait_group 0;" ::: "memory")

// one stage layout (bytes): A @0, B @10240; rows pad 40 elem (80B)
constexpr uint32_t SM_B = 10240;
constexpr uint32_t STAGE_BYTES = 20480;

// 128x32 tile MMA, pure fp16
__device__ __forceinline__ void mma_tile_ldsm(uint32_t sb, float acc[4][4][4],
                                              int arow, int acolB, int brow, int bcolB)
{
#pragma unroll
    for (int ks = 0; ks < 32; ks += 16) {
        uint32_t fa[4][4], fb[4][2];
#pragma unroll
        for (int mi = 0; mi < 4; mi++) {
            uint32_t ad = sb + (uint32_t)((arow + mi * 16) * 80 + (ks + acolB) * 2);
            LDSM4(fa[mi][0], fa[mi][1], fa[mi][2], fa[mi][3], ad);
        }
#pragma unroll
        for (int np = 0; np < 2; np++) {
            uint32_t bd = sb + SM_B + (uint32_t)((brow + np * 16) * 80 + (ks + bcolB) * 2);
            LDSM4(fb[np * 2][0], fb[np * 2][1], fb[np * 2 + 1][0], fb[np * 2 + 1][1], bd);
        }
#pragma unroll
        for (int mi = 0; mi < 4; mi++)
#pragma unroll
            for (int ni = 0; ni < 4; ni++)
                mma16816(acc[mi][ni], fa[mi], fb[ni]);
    }
}

// stage one 128x32 K-chunk (A + B) via cp.async; CONV = im2col A
template<bool CONV>
__device__ __forceinline__ void stage_chunk(
    uint32_t sdst,
    const __half* __restrict__ A, const __half* __restrict__ B,
    const __half* zb, int row0, int col0, int K, int kc, int tid)
{
#pragma unroll
    for (int i = 0; i < 2; i++) {
        int chunk = tid * 2 + i;
        int rr = chunk >> 2, sg = chunk & 3;
        uint32_t so = (uint32_t)(rr * 80 + sg * 16);
        const __half* pa;
        if (CONV) {
            int gk = kc * 32 + sg * 8;
            int tap = gk >> 10, ci = gk & 1023;
            int m = row0 + rr;
            int t2 = (m & 255) + tap - 1;
            if (t2 >= 0 && t2 < 256) {
                pa = A + ((size_t)((m >> 8) * 256 + t2)) * 1024 + ci;
            } else { pa = zb; }
        } else {
            pa = A + (size_t)(row0 + rr) * K + kc * 32 + sg * 8;
        }
        CP16(sdst + so, pa);
        size_t ob = (size_t)(col0 + rr) * K + kc * 32 + sg * 8;
        CP16(sdst + SM_B + so, B + ob);
    }
    CP_COMMIT();
}

// ===========================================================================
// HMMA GEMM, cp.async double-buffered, single sync per chunk.
// Loop order: wait(kc) -> sync -> stage(kc+1) -> mma(kc).
// Stage writes slot (kc+1)%2 (disjoint from mma's kc%2); that slot was last
// read in iter kc-1 which all threads completed (they passed this sync).
// EPI: 0=none,1=+bias,2=+bias+residual,3=+bias+gelu->fp16,4=+bias+relu,5=->fp16
// ===========================================================================
template<int EPI, bool CONV>
__global__ void __launch_bounds__(256, 2) mgemm(
    const __half* __restrict__ A, const __half* __restrict__ B,
    float* __restrict__ C, __half* __restrict__ Ch,
    const float* __restrict__ bias,
    int M, int N, int K)
{
    extern __shared__ char smem[];
    const int tid  = threadIdx.x;
    const int wid  = tid >> 5;
    const int lane = tid & 31;
    const int g = lane >> 2, t = lane & 3;
    const int wm = wid >> 2, wn = wid & 3;
    const int row0 = blockIdx.y * 128;
    const int col0 = blockIdx.x * 128;
    const uint32_t sb0 = cvt_smem(smem);

    const int arow  = wm * 64 + (lane & 7) + ((lane >> 3) & 1) * 8;
    const int acolB = ((lane >> 4) & 1) * 8;
    const int brow  = wn * 32 + ((lane >> 4) & 1) * 8 + (lane & 7);
    const int bcolB = ((lane >> 3) & 1) * 8;

    float acc[4][4][4];
#pragma unroll
    for (int mi = 0; mi < 4; mi++)
#pragma unroll
        for (int ni = 0; ni < 4; ni++)
#pragma unroll
            for (int q = 0; q < 4; q++) acc[mi][ni][q] = 0.f;

    const int nchunks = K >> 5;

    stage_chunk<CONV>(sb0, A, B, g_zero, row0, col0, K, 0, tid);

    for (int kc = 0; kc < nchunks; kc++) {
        const uint32_t sb = sb0 + (uint32_t)(kc & 1) * STAGE_BYTES;
        CP_WAIT0();
        __syncthreads();
        if (kc + 1 < nchunks) {
            const uint32_t sn = sb0 + (uint32_t)((kc + 1) & 1) * STAGE_BYTES;
            stage_chunk<CONV>(sn, A, B, g_zero, row0, col0, K, kc + 1, tid);
        }
        mma_tile_ldsm(sb, acc, arow, acolB, brow, bcolB);
    }

#pragma unroll
    for (int mi = 0; mi < 4; mi++) {
#pragma unroll
        for (int ni = 0; ni < 4; ni++) {
#pragma unroll
            for (int hh = 0; hh < 2; hh++) {
                int r = row0 + wm * 64 + mi * 16 + g + hh * 8;
                int c = col0 + wn * 32 + ni * 8 + t * 2;
                float v0 = acc[mi][ni][hh * 2 + 0];
                float v1 = acc[mi][ni][hh * 2 + 1];
                size_t o = (size_t)r * N + c;
                if (EPI != 0 && EPI != 5) { v0 += bias[c]; v1 += bias[c + 1]; }
                if (EPI == 2) {
                    float2 old = *(const float2*)&C[o];
                    v0 += old.x; v1 += old.y;
                }
                if (EPI == 3 || EPI == 5) {
                    if (EPI == 3) {
                        v0 = 0.5f * v0 * (1.f + erff(v0 * 0.70710678118654752f));
                        v1 = 0.5f * v1 * (1.f + erff(v1 * 0.70710678118654752f));
                    }
                    *(__half2*)&Ch[o] = __floats2half2_rn(v0, v1);
                } else {
                    if (EPI == 4) { v0 = fmaxf(v0, 0.f); v1 = fmaxf(v1, 0.f); }
                    *(float2*)&C[o] = make_float2(v0, v1);
                }
            }
        }
    }
}

// ===========================================================================
// Batched QK^T -> S fp16. Double-buffered direct stores, single sync/chunk.
// ===========================================================================
__global__ void __launch_bounds__(256, 2) bqk_kernel(
    const __half* __restrict__ Q, __half* __restrict__ S)
{
    __shared__ alignas(16) char smem[2 * 20480];
    const int tid  = threadIdx.x;
    const int wid  = tid >> 5;
    const int lane = tid & 31;
    const int g = lane >> 2, t = lane & 3;
    const int wm = wid >> 2, wn = wid & 3;
    const int bh = blockIdx.z, b = bh >> 2, h = bh & 3;
    const int i0 = blockIdx.x * 128, j0 = blockIdx.y * 128;
    const __half* Ah = Q + (size_t)b * 256 * 1536 + h * 128;
    const uint32_t sb0 = cvt_smem(smem);

    const int arow  = wm * 64 + (lane & 7) + ((lane >> 3) & 1) * 8;
    const int acolB = ((lane >> 4) & 1) * 8;
    const int brow  = wn * 32 + ((lane >> 4) & 1) * 8 + (lane & 7);
    const int bcolB = ((lane >> 3) & 1) * 8;

    float acc[4][4][4];
#pragma unroll
    for (int mi = 0; mi < 4; mi++)
#pragma unroll
        for (int ni = 0; ni < 4; ni++)
#pragma unroll
            for (int q = 0; q < 4; q++) acc[mi][ni][q] = 0.f;

    // stage chunk 0 into slot 0
#pragma unroll
    for (int i = 0; i < 2; i++) {
        int chunk = tid * 2 + i;
        int rr = chunk >> 2, sg = chunk & 3;
        uint32_t so = (uint32_t)(rr * 80 + sg * 16);
        size_t oa = (size_t)(i0 + rr) * 1536 + sg * 8;
        size_t ob = (size_t)(j0 + rr) * 1536 + 512 + sg * 8;
        *(uint4*)(smem + so)        = *(const uint4*)(Ah + oa);
        *(uint4*)(smem + SM_B + so) = *(const uint4*)(Ah + ob);
    }

    for (int kc = 0; kc < 4; kc++) {
        const uint32_t sb = sb0 + (uint32_t)(kc & 1) * STAGE_BYTES;
        __syncthreads();
        if (kc + 1 < 4) {
            char* sn = smem + ((kc + 1) & 1) * STAGE_BYTES;
#pragma unroll
            for (int i = 0; i < 2; i++) {
                int chunk = tid * 2 + i;
                int rr = chunk >> 2, sg = chunk & 3;
                uint32_t so = (uint32_t)(rr * 80 + sg * 16);
                size_t oa = (size_t)(i0 + rr) * 1536 + (kc + 1) * 32 + sg * 8;
                size_t ob = (size_t)(j0 + rr) * 1536 + 512 + (kc + 1) * 32 + sg * 8;
                *(uint4*)(sn + so)        = *(const uint4*)(Ah + oa);
                *(uint4*)(sn + SM_B + so) = *(const uint4*)(Ah + ob);
            }
        }
        mma_tile_ldsm(sb, acc, arow, acolB, brow, bcolB);
    }

    __half* so2 = S + (size_t)bh * 65536;
    const float scale = 0.08838834764831845f;
#pragma unroll
    for (int mi = 0; mi < 4; mi++)
#pragma unroll
        for (int ni = 0; ni < 4; ni++)
#pragma unroll
            for (int hh = 0; hh < 2; hh++) {
                int r = i0 + wm * 64 + mi * 16 + g + hh * 8;
                int c = j0 + wn * 32 + ni * 8 + t * 2;
                *(__half2*)&so2[(size_t)r * 256 + c] =
                    __floats2half2_rn(acc[mi][ni][hh * 2] * scale,
                                      acc[mi][ni][hh * 2 + 1] * scale);
            }
}

// row softmax (S fp16 in) -> P fp16
__global__ void __launch_bounds__(256) softmaxp_kernel(const __half* __restrict__ S,
                                                       __half* __restrict__ P)
{
    const int row  = blockIdx.x * 8 + (threadIdx.x >> 5);
    const int lane = threadIdx.x & 31;
    const __half* p = S + (size_t)row * 256;
    float v[8]; float mx = -1e30f;
#pragma unroll
    for (int j = 0; j < 8; j++) { v[j] = __half2float(p[lane + 32 * j]); mx = fmaxf(mx, v[j]); }
#pragma unroll
    for (int o = 16; o; o >>= 1) mx = fmaxf(mx, __shfl_xor_sync(0xffffffffu, mx, o));
    float s = 0.f;
#pragma unroll
    for (int j = 0; j < 8; j++) { v[j] = expf(v[j] - mx); s += v[j]; }
#pragma unroll
    for (int o = 16; o; o >>= 1) s += __shfl_xor_sync(0xffffffffu, s, o);
    const float inv = 1.f / s;
#pragma unroll
    for (int j = 0; j < 8; j++)
        P[(size_t)row * 256 + lane + 32 * j] = __float2half_rn(v[j] * inv);
}

// V transpose
__global__ void vtrans_kernel(const __half* __restrict__ V, __half* __restrict__ vt)
{
    __shared__ __half th[32][33];
    const int bh = blockIdx.x, b = bh >> 2, h = bh & 3;
    const int d0 = blockIdx.y * 32, j0 = blockIdx.z * 32;
    const int tx = threadIdx.x, ty = threadIdx.y;
    const size_t base = (size_t)b * 256 * 1536 + 1024 + h * 128;
    for (int r = ty; r < 32; r += 8) {
        size_t o = base + (size_t)(j0 + r) * 1536 + d0 + tx;
        th[r][tx] = V[o];
    }
    __syncthreads();
    const size_t obase = (size_t)bh * 32768;
    for (int r = ty; r < 32; r += 8) {
        size_t o = obase + (size_t)(d0 + r) * 256 + j0 + tx;
        vt[o] = th[tx][r];
    }
}

// Batched PV, double-buffered direct stores, single sync/chunk.
__global__ void __launch_bounds__(256, 2) bpv_kernel(
    const __half* __restrict__ P, const __half* __restrict__ vt,
    __half* __restrict__ O)
{
    __shared__ alignas(16) char smem[2 * 20480];
    const int tid  = threadIdx.x;
    const int wid  = tid >> 5;
    const int lane = tid & 31;
    const int g = lane >> 2, t = lane & 3;
    const int wm = wid >> 2, wn = wid & 3;
    const int bh = blockIdx.z, b = bh >> 2, h = bh & 3;
    const int i0 = blockIdx.x * 128;
    const __half* Ah = P + (size_t)bh * 65536 + (size_t)i0 * 256;
    const __half* Bh = vt + (size_t)bh * 32768;
    const uint32_t sb0 = cvt_smem(smem);

    const int arow  = wm * 64 + (lane & 7) + ((lane >> 3) & 1) * 8;
    const int acolB = ((lane >> 4) & 1) * 8;
    const int brow  = wn * 32 + ((lane >> 4) & 1) * 8 + (lane & 7);
    const int bcolB = ((lane >> 3) & 1) * 8;

    float acc[4][4][4];
#pragma unroll
    for (int mi = 0; mi < 4; mi++)
#pragma unroll
        for (int ni = 0; ni < 4; ni++)
#pragma unroll
            for (int q = 0; q < 4; q++) acc[mi][ni][q] = 0.f;

#pragma unroll
    for (int i = 0; i < 2; i++) {
        int chunk = tid * 2 + i;
        int rr = chunk >> 2, sg = chunk & 3;
        uint32_t so = (uint32_t)(rr * 80 + sg * 16);
        size_t oa = (size_t)rr * 256 + sg * 8;
        *(uint4*)(smem + so)        = *(const uint4*)(Ah + oa);
        *(uint4*)(smem + SM_B + so) = *(const uint4*)(Bh + oa);
    }

    for (int kc = 0; kc < 8; kc++) {
        const uint32_t sb = sb0 + (uint32_t)(kc & 1) * STAGE_BYTES;
        __syncthreads();
        if (kc + 1 < 8) {
            char* sn = smem + ((kc + 1) & 1) * STAGE_BYTES;
#pragma unroll
            for (int i = 0; i < 2; i++) {
                int chunk = tid * 2 + i;
                int rr = chunk >> 2, sg = chunk & 3;
                uint32_t so = (uint32_t)(rr * 80 + sg * 16);
                size_t oa = (size_t)rr * 256 + (kc + 1) * 32 + sg * 8;
                *(uint4*)(sn + so)        = *(const uint4*)(Ah + oa);
                *(uint4*)(sn + SM_B + so) = *(const uint4*)(Bh + oa);
            }
        }
        mma_tile_ldsm(sb, acc, arow, acolB, brow, bcolB);
    }

#pragma unroll
    for (int mi = 0; mi < 4; mi++)
#pragma unroll
        for (int ni = 0; ni < 4; ni++)
#pragma unroll
            for (int hh = 0; hh < 2; hh++) {
                int r = i0 + wm * 64 + mi * 16 + g + hh * 8;
                int c = wn * 32 + ni * 8 + t * 2;
                size_t o = ((size_t)b * 256 + r) * 512 + h * 128 + c;
                *(__half2*)&O[o] =
                    __floats2half2_rn(acc[mi][ni][hh * 2], acc[mi][ni][hh * 2 + 1]);
            }
}

// ===========================================================================
// Prep kernels
// ===========================================================================
__global__ void wprep_t(const float* __restrict__ W, __half* __restrict__ Wh,
                        int K, int N)
{
    __shared__ float tile[32][33];
    const int k0 = blockIdx.x * 32, n0 = blockIdx.y * 32;
    const int tx = threadIdx.x, ty = threadIdx.y;
    for (int r = ty; r < 32; r += 8)
        tile[r][tx] = W[(size_t)(k0 + r) * N + n0 + tx];
    __syncthreads();
    for (int r = ty; r < 32; r += 8)
        Wh[(size_t)(n0 + r) * K + k0 + tx] = __float2half_rn(tile[tx][r]);
}

__global__ void convprep(const float* __restrict__ w, __half* __restrict__ Wh)
{
    const int n = 512 * 3072;
    for (int idx = blockIdx.x * blockDim.x + threadIdx.x; idx < n; idx += gridDim.x * blockDim.x) {
        int d = idx / 3072, k = idx % 3072;
        int tap = k >> 10, ci = k & 1023;
        Wh[idx] = __float2half_rn(w[(size_t)d * 3072 + ci * 3 + tap]);
    }
}

__global__ void xcvt(const float* __restrict__ x, __half* __restrict__ xh)
{
    const int n4 = 64 * 256 * 1024 / 4;
    const float4* x4 = (const float4*)x;
    __half2* xh2 = (__half2*)xh;
    for (int i = blockIdx.x * blockDim.x + threadIdx.x; i < n4; i += gridDim.x * blockDim.x) {
        float4 f = x4[i];
        xh2[i * 2]     = __floats2half2_rn(f.x, f.y);
        xh2[i * 2 + 1] = __floats2half2_rn(f.z, f.w);
    }
}

__device__ __forceinline__ float wsum(float v)
{
#pragma unroll
    for (int o = 16; o; o >>= 1) v += __shfl_xor_sync(0xffffffffu, v, o);
    return v;
}

// ===========================================================================
// LayerNorm -> fp16 (one warp per row)
// ===========================================================================
__global__ void __launch_bounds__(256) ln_kernel(const float* __restrict__ x,
                                                 const float* __restrict__ g,
                                                 const float* __restrict__ bb,
                                                 __half* __restrict__ y)
{
    const int w = threadIdx.x >> 5, lane = threadIdx.x & 31;
    const int row = blockIdx.x * 8 + w;
    const float* xr = x + (size_t)row * 512;
    float v[16];
    float s = 0.f;
#pragma unroll
    for (int j = 0; j < 16; j++) { v[j] = xr[lane + 32 * j]; s += v[j]; }
    s = wsum(s);
    const float mean = s * (1.f / 512.f);
    float q = 0.f;
#pragma unroll
    for (int j = 0; j < 16; j++) { float d = v[j] - mean; q += d * d; }
    q = wsum(q);
    const float inv = rsqrtf(q * (1.f / 512.f) + 1e-5f);
#pragma unroll
    for (int j = 0; j < 16; j++) {
        int c = lane + 32 * j;
        y[(size_t)row * 512 + c] = __float2half_rn((v[j] - mean) * inv * g[c] + bb[c]);
    }
}

// ===========================================================================
// Memory attention: 16 rows/block (warp per row), mem staged via smem
// ===========================================================================
__global__ void __launch_bounds__(512) memory_kernel(const float* __restrict__ Nx,
                                                     const float* __restrict__ Ax,
                                                     const float* __restrict__ a_mem,
                                                     const float* __restrict__ n_mem,
                                                     float* __restrict__ att_base,
                                                     __half* __restrict__ aug_base)
{
    __shared__ float mch[20][512];
    const int w = threadIdx.x >> 5, lane = threadIdx.x & 31;
    const int combo = blockIdx.y;       // 0:A(Ax,a) 1:NA(Ax,n) 2:AN(Nx,a) 3:N(Nx,n)
    const int row = blockIdx.x * 16 + w;
    const float* x   = (combo < 2) ? Ax : Nx;
    const float* mem = (combo & 1) ? n_mem : a_mem;
    const int att_off[4] = {0, 24576, 16384, 8192};
    float* att_out = att_base + att_off[combo];
    __half* aug = aug_base + (size_t)combo * SZ_AUG;

    float xr[16], facc[16];
#pragma unroll
    for (int j = 0; j < 16; j++) {
        xr[j] = x[(size_t)row * 512 + lane + 32 * j];
        facc[j] = 0.f;
    }
    float t0 = -1e30f, t1 = -1e30f, t2 = -1e30f, t3 = -1e30f;

    for (int c = 0; c < 3; c++) {
        const float4* src4 = (const float4*)(mem + c * 20 * 512);
        float4* dst4 = (float4*)mch;
        for (int i = threadIdx.x; i < 20 * 512 / 4; i += 512)
            dst4[i] = src4[i];
        __syncthreads();
#pragma unroll 4
        for (int n = 0; n < 20; n++) {
            float s = 0.f;
#pragma unroll
            for (int j = 0; j < 16; j++) s = fmaf(xr[j], mch[n][lane + 32 * j], s);
            s = wsum(s);
            float att = 1.f / (1.f + expf(-s * 0.044194173824159216f));
            if (att > t0)      { t3 = t2; t2 = t1; t1 = t0; t0 = att; }
            else if (att > t1) { t3 = t2; t2 = t1; t1 = att; }
            else if (att > t2) { t3 = t2; t2 = att; }
            else if (att > t3) { t3 = att; }
#pragma unroll
            for (int j = 0; j < 16; j++)
                facc[j] = fmaf(att, mch[n][lane + 32 * j], facc[j]);
        }
        __syncthreads();
    }

    if (lane == 0) att_out[row] = (t0 + t1 + t2 + t3) * 0.25f;
#pragma unroll
    for (int j = 0; j < 16; j++)
        aug[(size_t)row * 512 + lane + 32 * j] = __float2half_rn(facc[j]);
}

// ===========================================================================
// top-k (3 combos batched via grid.y) / losses / misc
// ===========================================================================
__global__ void __launch_bounds__(256) topk_gather3(
    const float* __restrict__ attA, const float* __restrict__ attN,
    const float* __restrict__ attNA,
    const float* __restrict__ Ax, const float* __restrict__ Nx,
    float* __restrict__ negv, float* __restrict__ anch, float* __restrict__ posv,
    int* __restrict__ idxA, int* __restrict__ idxN)
{
    __shared__ float vals[256], rv[256];
    __shared__ int ri[256], ids[17];
    const int b = blockIdx.x, tid = threadIdx.x;
    const int combo = blockIdx.y;
    const float* att   = (combo == 0) ? attA : (combo == 1) ? attN : attNA;
    const float* feats = (combo == 1) ? Nx : Ax;
    float* meanv = (combo == 0) ? negv : (combo == 1) ? anch : posv;
    int* idx_out = (combo == 0) ? idxA : (combo == 1) ? idxN : nullptr;

    vals[tid] = att[b * 256 + tid];
    __syncthreads();
    for (int it = 0; it < 17; it++) {
        rv[tid] = vals[tid]; ri[tid] = tid;
        __syncthreads();
        for (int s = 128; s; s >>= 1) {
            if (tid < s) {
                float ov = rv[tid + s]; int oi = ri[tid + s];
                if (ov > rv[tid] || (ov == rv[tid] && oi < ri[tid])) { rv[tid] = ov; ri[tid] = oi; }
            }
            __syncthreads();
        }
        if (tid == 0) {
            ids[it] = ri[0];
            vals[ri[0]] = -1e30f;
            if (idx_out) idx_out[b * 17 + it] = ri[0];
        }
        __syncthreads();
    }
    for (int d = tid; d < 512; d += 256) {
        float s = 0.f;
        for (int j = 0; j < 17; j++) s += feats[((size_t)b * 256 + ids[j]) * 512 + d];
        meanv[b * 512 + d] = s * (1.f / 17.f);
    }
}

__global__ void __launch_bounds__(1024) triplet_cos_kernel(const float* __restrict__ anchor,
                                                           const float* __restrict__ pos,
                                                           const float* __restrict__ neg,
                                                           float* __restrict__ trip_out,
                                                           float* __restrict__ cos_out)
{
    __shared__ float st[32], sc[32];
    const int w = threadIdx.x >> 5, lane = threadIdx.x & 31;
    float sa = 0, sp = 0, sn = 0, dan = 0;
    for (int d = lane; d < 512; d += 32) {
        float a = anchor[w * 512 + d], p = pos[w * 512 + d], n = neg[w * 512 + d];
        sa += a * a; sp += p * p; sn += n * n; dan += a * n;
    }
    sa = wsum(sa); sp = wsum(sp); sn = wsum(sn); dan = wsum(dan);
    float na = sqrtf(sa), npp = sqrtf(sp), ng = sqrtf(sn);
    float ina = 1.f / na, inp = 1.f / npp, ing = 1.f / ng;
    float dp2 = 0, dn2 = 0;
    for (int d = lane; d < 512; d += 32) {
        float a  = anchor[w * 512 + d] * ina;
        float dpv = a - pos[w * 512 + d] * inp + 1e-6f;
        float dnv = a - neg[w * 512 + d] * ing + 1e-6f;
        dp2 += dpv * dpv; dn2 += dnv * dnv;
    }
    dp2 = wsum(dp2); dn2 = wsum(dn2);
    if (lane == 0) {
        st[w] = fmaxf(sqrtf(dp2) - sqrtf(dn2) + 1.f, 0.f);
        sc[w] = 1.f - dan / (fmaxf(na, 1e-6f) * fmaxf(ng, 1e-6f));
    }
    __syncthreads();
    if (threadIdx.x == 0) {
        float a = 0, c = 0;
        for (int i = 0; i < 32; i++) { a += st[i]; c += sc[i]; }
        trip_out[0] = a * (1.f / 32.f);
        cos_out[0]  = c * (1.f / 32.f);
    }
}

__global__ void __launch_bounds__(1024) distance_kernel(const float* __restrict__ anew,
                                                        const float* __restrict__ nnew,
                                                        float* __restrict__ out)
{
    __shared__ float sd[32];
    const int w = threadIdx.x >> 5, lane = threadIdx.x & 31;
    float sa = 0, sn = 0;
    for (int d = lane; d < 512; d += 32) {
        float a = anew[w * 512 + d], n = nnew[w * 512 + d];
        sa += a * a; sn += n * n;
    }
    sa = wsum(sa); sn = wsum(sn);
    if (lane == 0) sd[w] = fmaxf(100.f - sqrtf(sn) + sqrtf(sa), 0.f);
    __syncthreads();
    if (threadIdx.x == 0) {
        float s = 0;
        for (int i = 0; i < 32; i++) s += sd[i];
        out[0] = s * (1.f / 32.f);
    }
}

// fused VAE reparam + KL partial sums (float4)
__global__ void __launch_bounds__(256) vaekl_kernel(const float* __restrict__ mu,
                                                    const float* __restrict__ var,
                                                    const float* __restrict__ eps,
                                                    float* __restrict__ o,
                                                    float* __restrict__ part, int n)
{
    __shared__ float red[256];
    const int n4 = n / 4;
    const float4* mu4 = (const float4*)mu;
    const float4* var4 = (const float4*)var;
    const float4* eps4 = (const float4*)eps;
    float4* o4 = (float4*)o;
    float s = 0.f;
    for (int i = blockIdx.x * 256 + threadIdx.x; i < n4; i += gridDim.x * 256) {
        float4 m = mu4[i], v = var4[i], e = eps4[i];
        float4 r;
        float ev;
        ev = expf(v.x); r.x = m.x + e.x * sqrtf(ev); s += 1.f + v.x - m.x * m.x - ev;
        ev = expf(v.y); r.y = m.y + e.y * sqrtf(ev); s += 1.f + v.y - m.y * m.y - ev;
        ev = expf(v.z); r.z = m.z + e.z * sqrtf(ev); s += 1.f + v.z - m.z * m.z - ev;
        ev = expf(v.w); r.w = m.w + e.w * sqrtf(ev); s += 1.f + v.w - m.w * m.w - ev;
        o4[i] = r;
    }
    red[threadIdx.x] = s; __syncthreads();
    for (int t = 128; t; t >>= 1) { if (threadIdx.x < t) red[threadIdx.x] += red[threadIdx.x + t]; __syncthreads(); }
    if (threadIdx.x == 0) part[blockIdx.x] = red[0];
}

__global__ void __launch_bounds__(1024) kl_final_kernel(const float* __restrict__ part,
                                                        float* __restrict__ out)
{
    __shared__ float red[1024];
    red[threadIdx.x] = part[threadIdx.x]; __syncthreads();
    for (int t = 512; t; t >>= 1) { if (threadIdx.x < t) red[threadIdx.x] += red[threadIdx.x + t]; __syncthreads(); }
    if (threadIdx.x == 0) out[0] = -0.5f * red[0] * (1.f / 16384.f);
}

__global__ void __launch_bounds__(512) gather_mean_kernel(const float* __restrict__ src,
                                                          const int* __restrict__ idx,
                                                          float* __restrict__ out)
{
    __shared__ int ids[17];
    const int b = blockIdx.x, tid = threadIdx.x;
    if (tid < 17) ids[tid] = idx[b * 17 + tid];
    __syncthreads();
    float s = 0.f;
    for (int j = 0; j < 17; j++) s += src[((size_t)b * 256 + ids[j]) * 512 + tid];
    out[b * 512 + tid] = s * (1.f / 17.f);
}

// float4 xout
__global__ void xout_kernel(const float* __restrict__ h, const float* __restrict__ nnew,
                            const float* __restrict__ anm, const float* __restrict__ anew,
                            const float* __restrict__ nam, float* __restrict__ xout)
{
    const int n4 = 64 * 256 * 1024 / 4;
    const float4* h4    = (const float4*)h;
    const float4* nnew4 = (const float4*)nnew;
    const float4* anm4  = (const float4*)anm;
    const float4* anew4 = (const float4*)anew;
    const float4* nam4  = (const float4*)nam;
    float4* out4 = (float4*)xout;
    for (int i = blockIdx.x * blockDim.x + threadIdx.x; i < n4; i += gridDim.x * blockDim.x) {
        int c4 = i & 255;
        int rt = i >> 8;
        float4 v;
        if (c4 < 128) v = h4[(size_t)rt * 128 + c4];
        else {
            int cc = c4 - 128;
            if (rt < 8192) {
                float4 a = nnew4[(size_t)rt * 128 + cc];
                float4 bb = anm4[(size_t)rt * 128 + cc];
                v = make_float4(a.x + bb.x, a.y + bb.y, a.z + bb.z, a.w + bb.w);
            } else {
                size_t o = (size_t)(rt - 8192) * 128 + cc;
                float4 a = anew4[o];
                float4 bb = nam4[o];
                v = make_float4(a.x + bb.x, a.y + bb.y, a.z + bb.z, a.w + bb.w);
            }
        }
        out4[i] = v;
    }
}

__global__ void vfeat_kernel(const float* __restrict__ h, float* __restrict__ v)
{
    __shared__ float tile[32][33];
    const int b = blockIdx.x, d0 = blockIdx.y * 32, t0 = blockIdx.z * 32;
    for (int r = threadIdx.y; r < 32; r += 8)
        tile[r][threadIdx.x] = h[((size_t)b * 256 + t0 + r) * 512 + d0 + threadIdx.x];
    __syncthreads();
    for (int r = threadIdx.y; r < 32; r += 8)
        v[((size_t)b * 512 + d0 + r) * 256 + t0 + threadIdx.x] = tile[threadIdx.x][r];
}

// ===========================================================================
extern "C" void kernel_launch(void* const* d_in, const int* in_sizes, int n_in,
                              void* d_out, int out_size)
{
    const float* x      = (const float*)d_in[0];
    const float* eps_in = (const float*)d_in[1];
    const float* conv_w = (const float*)d_in[2];
    const float* conv_b = (const float*)d_in[3];
    const float* ln1_g  = (const float*)d_in[4];
    const float* ln1_b  = (const float*)d_in[5];
    const float* qkv_w  = (const float*)d_in[6];
    const float* out_w  = (const float*)d_in[7];
    const float* out_b  = (const float*)d_in[8];
    const float* ln2_g  = (const float*)d_in[9];
    const float* ln2_b  = (const float*)d_in[10];
    const float* ff1_w  = (const float*)d_in[11];
    const float* ff1_b  = (const float*)d_in[12];
    const float* ff2_w  = (const float*)d_in[13];
    const float* ff2_b  = (const float*)d_in[14];
    const float* a_mem  = (const float*)d_in[15];
    const float* n_mem  = (const float*)d_in[16];
    const float* mu_w   = (const float*)d_in[17];
    const float* mu_b   = (const float*)d_in[18];
    const float* var_w  = (const float*)d_in[19];
    const float* var_b  = (const float*)d_in[20];
    float* out = (float*)d_out;

    float* S = nullptr;
    cudaGetSymbolAddress((void**)&S, g_scratch);
    __half* HF = nullptr;
    cudaGetSymbolAddress((void**)&HF, g_hf);

    float* h     = S + OFF_H;
    __half* sc   = (__half*)(S + OFF_SC);
    float* stack = S + OFF_STACK;
    float* Anew  = stack;
    float* NAm   = stack + 1ull * 8192 * 512;
    float* ANm   = stack + 2ull * 8192 * 512;
    float* muB   = stack + 3ull * 8192 * 512;
    float* varB  = S + OFF_VAR;
    float* newN  = S + OFF_NEW;
    float* anch  = S + OFF_ANCH;
    float* negv  = S + OFF_NEG;
    float* posv  = S + OFF_POS;
    float* anchN = S + OFF_ANCHN;
    float* negN  = S + OFF_NEGN;
    int*   idxA  = (int*)(S + OFF_IDXA);
    int*   idxN  = (int*)(S + OFF_IDXN);
    float* klp   = S + OFF_KLP;

    __half* lnb  = HF + B_LN;
    __half* aob  = HF + B_AO;
    __half* ffb  = HF + B_FF;
    __half* qkvb = HF + B_QKV;
    __half* pb   = HF + B_P;
    __half* vtb  = HF + B_VT;
    __half* xh   = HF + B_X;

    constexpr int MG_SMEM = 40960;   // 2 stages x 20480
    cudaFuncSetAttribute(mgemm<0,false>, cudaFuncAttributeMaxDynamicSharedMemorySize, MG_SMEM);
    cudaFuncSetAttribute(mgemm<1,false>, cudaFuncAttributeMaxDynamicSharedMemorySize, MG_SMEM);
    cudaFuncSetAttribute(mgemm<2,false>, cudaFuncAttributeMaxDynamicSharedMemorySize, MG_SMEM);
    cudaFuncSetAttribute(mgemm<3,false>, cudaFuncAttributeMaxDynamicSharedMemorySize, MG_SMEM);
    cudaFuncSetAttribute(mgemm<5,false>, cudaFuncAttributeMaxDynamicSharedMemorySize, MG_SMEM);
    cudaFuncSetAttribute(mgemm<4,true>,  cudaFuncAttributeMaxDynamicSharedMemorySize, MG_SMEM);

    // 1-3: prep
    convprep<<<1024, 256>>>(conv_w, HF + B_CNVW);
    xcvt<<<4096, 256>>>(x, xh);
    wprep_t<<<dim3(16, 48), dim3(32, 8)>>>(qkv_w, HF + B_QKVW, 512, 1536);

    // 4: conv (implicit im2col, relu+bias) — profiler target
    mgemm<4, true><<<dim3(4, 128), 256, MG_SMEM>>>(
        xh, HF + B_CNVW, h, nullptr, conv_b, 16384, 512, 3072);

    // 5: ln (layer 0)
    ln_kernel<<<2048, 256>>>(h, ln1_g, ln1_b, lnb);

    // 6: qkv mgemm (layer 0)
    mgemm<5, false><<<dim3(12, 128), 256, MG_SMEM>>>(
        lnb, HF + B_QKVW, nullptr, qkvb, nullptr, 16384, 1536, 512);

    // remaining weight prep
    wprep_t<<<dim3(16, 16), dim3(32, 8)>>>(out_w, HF + B_OUTW, 512, 512);
    wprep_t<<<dim3(16, 16), dim3(32, 8)>>>(ff1_w, HF + B_FF1W, 512, 512);
    wprep_t<<<dim3(16, 16), dim3(32, 8)>>>(ff2_w, HF + B_FF2W, 512, 512);
    wprep_t<<<dim3(16, 48), dim3(32, 8)>>>(qkv_w + 786432, HF + B_QKVW + 786432, 512, 1536);
    wprep_t<<<dim3(16, 16), dim3(32, 8)>>>(out_w + 262144, HF + B_OUTW + 262144, 512, 512);
    wprep_t<<<dim3(16, 16), dim3(32, 8)>>>(ff1_w + 262144, HF + B_FF1W + 262144, 512, 512);
    wprep_t<<<dim3(16, 16), dim3(32, 8)>>>(ff2_w + 262144, HF + B_FF2W + 262144, 512, 512);
    wprep_t<<<dim3(16, 16), dim3(32, 8)>>>(mu_w,  HF + B_MUW,  512, 512);
    wprep_t<<<dim3(16, 16), dim3(32, 8)>>>(var_w, HF + B_VARW, 512, 512);

    // ---- transformer (layer 0 continues, then layer 1)
    for (int i = 0; i < 2; i++) {
        if (i == 1) {
            ln_kernel<<<2048, 256>>>(h, ln1_g + 512, ln1_b + 512, lnb);
            mgemm<5, false><<<dim3(12, 128), 256, MG_SMEM>>>(
                lnb, HF + B_QKVW + 786432, nullptr, qkvb, nullptr, 16384, 1536, 512);
        }
        vtrans_kernel<<<dim3(256, 4, 8), dim3(32, 8)>>>(qkvb, vtb);
        bqk_kernel<<<dim3(2, 2, 256), 256>>>(qkvb, sc);
        softmaxp_kernel<<<8192, 256>>>(sc, pb);
        bpv_kernel<<<dim3(2, 1, 256), 256>>>(pb, vtb, aob);
        mgemm<2, false><<<dim3(4, 128), 256, MG_SMEM>>>(
            aob, HF + B_OUTW + (size_t)i * 262144, h, nullptr, out_b + i * 512, 16384, 512, 512);
        ln_kernel<<<2048, 256>>>(h, ln2_g + i * 512, ln2_b + i * 512, lnb);
        mgemm<3, false><<<dim3(4, 128), 256, MG_SMEM>>>(
            lnb, HF + B_FF1W + (size_t)i * 262144, nullptr, ffb, ff1_b + i * 512, 16384, 512, 512);
        mgemm<2, false><<<dim3(4, 128), 256, MG_SMEM>>>(
            ffb, HF + B_FF2W + (size_t)i * 262144, h, nullptr, ff2_b + i * 512, 16384, 512, 512);
    }

    const float* Nx = h;                       // x_emb[:32]
    const float* Ax = h + (size_t)8192 * 512;  // x_emb[32:]

    memory_kernel<<<dim3(512, 4), 512>>>(Nx, Ax, a_mem, n_mem,
                                         out + O_AATT, HF + B_AUG);

    topk_gather3<<<dim3(32, 3), 256>>>(out + O_AATT, out + O_NATT, out + O_NAATT,
                                       Ax, Nx, negv, anch, posv, idxA, idxN);

    triplet_cos_kernel<<<1, 1024>>>(anch, posv, negv, out + O_TRIP, out + O_COS);

    // stacked mu projection: [augA; augNA; augAN; augN] @ mu -> [Anew; NAm; ANm; muB]
    mgemm<1, false><<<dim3(4, 256), 256, MG_SMEM>>>(
        HF + B_AUG, HF + B_MUW, stack, nullptr, mu_b, 32768, 512, 512);
    mgemm<1, false><<<dim3(4, 64), 256, MG_SMEM>>>(
        HF + B_AUG + 3 * SZ_AUG, HF + B_VARW, varB, nullptr, var_b, 8192, 512, 512);

    vaekl_kernel<<<1024, 256>>>(muB, varB, eps_in, newN, klp, 8192 * 512);
    kl_final_kernel<<<1, 1024>>>(klp, out + O_KL);

    gather_mean_kernel<<<32, 512>>>(newN, idxN, anchN);
    gather_mean_kernel<<<32, 512>>>(Anew, idxA, negN);
    distance_kernel<<<1, 1024>>>(anchN, negN, out + O_DIST);

    xout_kernel<<<8192, 256>>>(h, newN, ANm, Anew, NAm, out + O_XOUT);
    vfeat_kernel<<<dim3(64, 16, 8), dim3(32, 8)>>>(h, out + O_VFEAT);
}

// round 17
// speedup vs baseline: 6.4110x; 1.0068x over previous
#include <cuda_runtime.h>
#include <cuda_fp16.h>
#include <math.h>
#include <stdint.h>

// ===========================================================================
// fp32 scratch
// ===========================================================================
constexpr size_t OFF_H     = 0;                         // 16384*512
constexpr size_t OFF_STACK = 8388608;                   // 32768*512: Anew,NAm,ANm,muB
constexpr size_t OFF_VAR   = OFF_STACK + 16777216;      // 8192*512
constexpr size_t OFF_NEW   = OFF_VAR + 4194304;         // 8192*512
constexpr size_t OFF_ANCH  = OFF_NEW + 4194304;         // 32*512 each below
constexpr size_t OFF_NEG   = OFF_ANCH + 16384;
constexpr size_t OFF_POS   = OFF_NEG  + 16384;
constexpr size_t OFF_ANCHN = OFF_POS  + 16384;
constexpr size_t OFF_NEGN  = OFF_ANCHN + 16384;
constexpr size_t OFF_IDXA  = OFF_NEGN + 16384;
constexpr size_t OFF_IDXN  = OFF_IDXA + 1024;
constexpr size_t OFF_KLP   = OFF_IDXN + 1024;
constexpr size_t SCRATCH_TOTAL = OFF_KLP + 1024;
__device__ float g_scratch[SCRATCH_TOTAL];

// ===========================================================================
// fp16 scratch
// ===========================================================================
constexpr size_t SZ_TOK  = 16384ull * 512;
constexpr size_t SZ_QKV  = 16384ull * 1536;
constexpr size_t SZ_VT   = 256ull * 32768;
constexpr size_t SZ_AUG  = 8192ull * 512;
constexpr size_t SZ_X    = 64ull * 256 * 1024;   // 16777216

constexpr size_t B_LN   = 0;
constexpr size_t B_AO   = B_LN + SZ_TOK;
constexpr size_t B_FF   = B_AO + SZ_TOK;
constexpr size_t B_QKV  = B_FF + SZ_TOK;
constexpr size_t B_VT   = B_QKV + SZ_QKV;
constexpr size_t B_AUG  = B_VT + SZ_VT;              // [A, NA, AN, N] stacked
constexpr size_t B_QKVW = B_AUG + 4 * SZ_AUG;        // 2*786432
constexpr size_t B_OUTW = B_QKVW + 2ull * 786432;    // 2*262144
constexpr size_t B_FF1W = B_OUTW + 2ull * 262144;
constexpr size_t B_FF2W = B_FF1W + 2ull * 262144;
constexpr size_t B_MUW  = B_FF2W + 2ull * 262144;    // 262144
constexpr size_t B_VARW = B_MUW + 262144;
constexpr size_t B_CNVW = B_VARW + 262144;           // 1572864
constexpr size_t B_X    = B_CNVW + 1572864;
constexpr size_t HF_TOTAL = B_X + SZ_X;
__device__ __half g_hf[HF_TOTAL];

__device__ __align__(16) __half g_zero[8];   // zero-initialized

// output offsets (triplet, kl, distance, A_att, N_att, A_Natt, N_Aatt, cos, x_out, v_feat)
constexpr size_t O_TRIP  = 0;
constexpr size_t O_KL    = 1;
constexpr size_t O_DIST  = 2;
constexpr size_t O_AATT  = 3;
constexpr size_t O_NATT  = 3 + 8192;
constexpr size_t O_ANATT = 3 + 16384;
constexpr size_t O_NAATT = 3 + 24576;
constexpr size_t O_COS   = 3 + 32768;
constexpr size_t O_XOUT  = 4 + 32768;
constexpr size_t O_VFEAT = O_XOUT + 64ull * 256 * 1024;

// ===========================================================================
// mma / smem helpers
// ===========================================================================
__device__ __forceinline__ void mma16816(float* c, const uint32_t* a, const uint32_t* b)
{
    asm volatile(
        "mma.sync.aligned.m16n8k16.row.col.f32.f16.f16.f32 "
        "{%0,%1,%2,%3}, {%4,%5,%6,%7}, {%8,%9}, {%0,%1,%2,%3};"
        : "+f"(c[0]), "+f"(c[1]), "+f"(c[2]), "+f"(c[3])
        : "r"(a[0]), "r"(a[1]), "r"(a[2]), "r"(a[3]), "r"(b[0]), "r"(b[1]));
}

__device__ __forceinline__ uint32_t cvt_smem(const void* p) {
    uint32_t a;
    asm("{ .reg .u64 t; cvta.to.shared.u64 t, %1; cvt.u32.u64 %0, t; }" : "=r"(a) : "l"(p));
    return a;
}

#define LDSM4(r0, r1, r2, r3, a) \
    asm volatile("ldmatrix.sync.aligned.m8n8.x4.shared.b16 {%0,%1,%2,%3}, [%4];" \
        : "=r"(r0), "=r"(r1), "=r"(r2), "=r"(r3) : "r"(a))

#define CP16(sa, gp) \
    asm volatile("cp.async.cg.shared.global [%0], [%1], 16;" :: "r"(sa), "l"(gp))
#define CP_COMMIT() asm volatile("cp.async.commit_group;" ::: "memory")
#define CP_WAIT1()  asm volatile("cp.async.wait_group 1;" ::: "memory")
#define CP_WAIT0()  asm volatile("cp.async.wait_group 0;" ::: "memory")

// chunk layout (bytes): 128 rows x 32 halves, row stride 80B. A @0, B @10240.
constexpr uint32_t SM_B = 10240;
constexpr uint32_t STAGE_BYTES = 20480;

// 128x32 tile MMA, fp16, separate A/B smem bases
__device__ __forceinline__ void mma_tile_ab(uint32_t abase, uint32_t bbase,
                                            float acc[4][4][4],
                                            int arow, int acolB, int brow, int bcolB)
{
#pragma unroll
    for (int ks = 0; ks < 32; ks += 16) {
        uint32_t fa[4][4], fb[4][2];
#pragma unroll
        for (int mi = 0; mi < 4; mi++) {
            uint32_t ad = abase + (uint32_t)((arow + mi * 16) * 80 + (ks + acolB) * 2);
            LDSM4(fa[mi][0], fa[mi][1], fa[mi][2], fa[mi][3], ad);
        }
#pragma unroll
        for (int np = 0; np < 2; np++) {
            uint32_t bd = bbase + (uint32_t)((brow + np * 16) * 80 + (ks + bcolB) * 2);
            LDSM4(fb[np * 2][0], fb[np * 2][1], fb[np * 2 + 1][0], fb[np * 2 + 1][1], bd);
        }
#pragma unroll
        for (int mi = 0; mi < 4; mi++)
#pragma unroll
            for (int ni = 0; ni < 4; ni++)
                mma16816(acc[mi][ni], fa[mi], fb[ni]);
    }
}

// stage one 128x32 K-chunk (A + B) via cp.async; CONV = im2col A
template<bool CONV>
__device__ __forceinline__ void stage_chunk(
    uint32_t sdst,
    const __half* __restrict__ A, const __half* __restrict__ B,
    const __half* zb, int row0, int col0, int K, int kc, int tid)
{
#pragma unroll
    for (int i = 0; i < 2; i++) {
        int chunk = tid * 2 + i;
        int rr = chunk >> 2, sg = chunk & 3;
        uint32_t so = (uint32_t)(rr * 80 + sg * 16);
        const __half* pa;
        if (CONV) {
            int gk = kc * 32 + sg * 8;
            int tap = gk >> 10, ci = gk & 1023;
            int m = row0 + rr;
            int t2 = (m & 255) + tap - 1;
            if (t2 >= 0 && t2 < 256) {
                pa = A + ((size_t)((m >> 8) * 256 + t2)) * 1024 + ci;
            } else { pa = zb; }
        } else {
            pa = A + (size_t)(row0 + rr) * K + kc * 32 + sg * 8;
        }
        CP16(sdst + so, pa);
        size_t ob = (size_t)(col0 + rr) * K + kc * 32 + sg * 8;
        CP16(sdst + SM_B + so, B + ob);
    }
    CP_COMMIT();
}

// ===========================================================================
// HMMA GEMM, 3-stage cp.async, single sync per chunk.
// EPI: 0=none,1=+bias,2=+bias+residual,3=+bias+gelu->fp16,4=+bias+relu,5=->fp16
// ===========================================================================
template<int EPI, bool CONV>
__global__ void __launch_bounds__(256, 2) mgemm(
    const __half* __restrict__ A, const __half* __restrict__ B,
    float* __restrict__ C, __half* __restrict__ Ch,
    const float* __restrict__ bias,
    int M, int N, int K)
{
    extern __shared__ char smem[];
    const int tid  = threadIdx.x;
    const int wid  = tid >> 5;
    const int lane = tid & 31;
    const int g = lane >> 2, t = lane & 3;
    const int wm = wid >> 2, wn = wid & 3;
    const int row0 = blockIdx.y * 128;
    const int col0 = blockIdx.x * 128;
    const uint32_t sb0 = cvt_smem(smem);

    const int arow  = wm * 64 + (lane & 7) + ((lane >> 3) & 1) * 8;
    const int acolB = ((lane >> 4) & 1) * 8;
    const int brow  = wn * 32 + ((lane >> 4) & 1) * 8 + (lane & 7);
    const int bcolB = ((lane >> 3) & 1) * 8;

    float acc[4][4][4];
#pragma unroll
    for (int mi = 0; mi < 4; mi++)
#pragma unroll
        for (int ni = 0; ni < 4; ni++)
#pragma unroll
            for (int q = 0; q < 4; q++) acc[mi][ni][q] = 0.f;

    const int nchunks = K >> 5;

    stage_chunk<CONV>(sb0, A, B, g_zero, row0, col0, K, 0, tid);
    stage_chunk<CONV>(sb0 + STAGE_BYTES, A, B, g_zero, row0, col0, K, 1, tid);

    int slot = 0;
    for (int kc = 0; kc < nchunks; kc++) {
        const uint32_t sb = sb0 + (uint32_t)slot * STAGE_BYTES;
        if (kc + 2 < nchunks) CP_WAIT1(); else CP_WAIT0();
        __syncthreads();
        if (kc + 2 < nchunks) {
            int ns = slot + 2; if (ns >= 3) ns -= 3;
            stage_chunk<CONV>(sb0 + (uint32_t)ns * STAGE_BYTES, A, B, g_zero,
                              row0, col0, K, kc + 2, tid);
        }
        mma_tile_ab(sb, sb + SM_B, acc, arow, acolB, brow, bcolB);
        if (++slot == 3) slot = 0;
    }

#pragma unroll
    for (int mi = 0; mi < 4; mi++) {
#pragma unroll
        for (int ni = 0; ni < 4; ni++) {
#pragma unroll
            for (int hh = 0; hh < 2; hh++) {
                int r = row0 + wm * 64 + mi * 16 + g + hh * 8;
                int c = col0 + wn * 32 + ni * 8 + t * 2;
                float v0 = acc[mi][ni][hh * 2 + 0];
                float v1 = acc[mi][ni][hh * 2 + 1];
                size_t o = (size_t)r * N + c;
                if (EPI != 0 && EPI != 5) { v0 += bias[c]; v1 += bias[c + 1]; }
                if (EPI == 2) {
                    float2 old = *(const float2*)&C[o];
                    v0 += old.x; v1 += old.y;
                }
                if (EPI == 3 || EPI == 5) {
                    if (EPI == 3) {
                        v0 = 0.5f * v0 * (1.f + erff(v0 * 0.70710678118654752f));
                        v1 = 0.5f * v1 * (1.f + erff(v1 * 0.70710678118654752f));
                    }
                    *(__half2*)&Ch[o] = __floats2half2_rn(v0, v1);
                } else {
                    if (EPI == 4) { v0 = fmaxf(v0, 0.f); v1 = fmaxf(v1, 0.f); }
                    *(float2*)&C[o] = make_float2(v0, v1);
                }
            }
        }
    }
}

// ===========================================================================
// Fused attention: per (bh, i-tile 128): S=scale*QK^T -> smem (fp16, chunked),
// softmax in smem, O = P @ V^T (P from smem, V^T staged from vt).
// smem: Sbuf 8*10240 @0, stage 2*20480 @81920. Total 122880 -> 1 CTA/SM.
// ===========================================================================
__global__ void __launch_bounds__(256, 1) attn_kernel(
    const __half* __restrict__ Q, const __half* __restrict__ vt,
    __half* __restrict__ O)
{
    extern __shared__ char smem[];
    const uint32_t sbS = cvt_smem(smem);
    const uint32_t sbStage = sbS + 81920;
    __half* Sh = (__half*)smem;

    const int tid  = threadIdx.x;
    const int wid  = tid >> 5;
    const int lane = tid & 31;
    const int g = lane >> 2, t = lane & 3;
    const int wm = wid >> 2, wn = wid & 3;
    const int bh = blockIdx.z, b = bh >> 2, h = bh & 3;
    const int i0 = blockIdx.x * 128;
    const __half* base = Q + (size_t)b * 256 * 1536 + h * 128;

    const int arow  = wm * 64 + (lane & 7) + ((lane >> 3) & 1) * 8;
    const int acolB = ((lane >> 4) & 1) * 8;
    const int brow  = wn * 32 + ((lane >> 4) & 1) * 8 + (lane & 7);
    const int bcolB = ((lane >> 3) & 1) * 8;

    float acc[4][4][4];
#pragma unroll
    for (int mi = 0; mi < 4; mi++)
#pragma unroll
        for (int ni = 0; ni < 4; ni++)
#pragma unroll
            for (int q = 0; q < 4; q++) acc[mi][ni][q] = 0.f;

    const float scale = 0.08838834764831845f;

    // ---- phase 1: S = QK^T for j-tiles 0,1 (8 linear chunks, 2-stage)
    {
        // stage chunk idx=0
#pragma unroll
        for (int i = 0; i < 2; i++) {
            int chunk = tid * 2 + i;
            int rr = chunk >> 2, sg = chunk & 3;
            uint32_t so = (uint32_t)(rr * 80 + sg * 16);
            CP16(sbStage + so,        base + (size_t)(i0 + rr) * 1536 + sg * 8);
            CP16(sbStage + SM_B + so, base + (size_t)rr * 1536 + 512 + sg * 8);
        }
        CP_COMMIT();

        for (int idx = 0; idx < 8; idx++) {
            const uint32_t sb = sbStage + (uint32_t)(idx & 1) * STAGE_BYTES;
            CP_WAIT0();
            __syncthreads();
            if (idx + 1 < 8) {
                int j0n = (idx + 1) >> 2 << 7, kcn = (idx + 1) & 3;
                const uint32_t sn = sbStage + (uint32_t)((idx + 1) & 1) * STAGE_BYTES;
#pragma unroll
                for (int i = 0; i < 2; i++) {
                    int chunk = tid * 2 + i;
                    int rr = chunk >> 2, sg = chunk & 3;
                    uint32_t so = (uint32_t)(rr * 80 + sg * 16);
                    CP16(sn + so,        base + (size_t)(i0 + rr) * 1536 + kcn * 32 + sg * 8);
                    CP16(sn + SM_B + so, base + (size_t)(j0n + rr) * 1536 + 512 + kcn * 32 + sg * 8);
                }
                CP_COMMIT();
            }
            mma_tile_ab(sb, sb + SM_B, acc, arow, acolB, brow, bcolB);

            if ((idx & 3) == 3) {
                // write S j-tile to Sbuf (scaled, fp16), reset acc
                int j = idx >> 2;
#pragma unroll
                for (int mi = 0; mi < 4; mi++)
#pragma unroll
                    for (int ni = 0; ni < 4; ni++)
#pragma unroll
                        for (int hh = 0; hh < 2; hh++) {
                            int r = wm * 64 + mi * 16 + g + hh * 8;
                            int k = ni * 8 + t * 2;
                            int cj = j * 4 + wn;
                            *(__half2*)&Sh[(size_t)cj * 5120 + r * 40 + k] =
                                __floats2half2_rn(acc[mi][ni][hh * 2] * scale,
                                                  acc[mi][ni][hh * 2 + 1] * scale);
                            acc[mi][ni][hh * 2] = 0.f;
                            acc[mi][ni][hh * 2 + 1] = 0.f;
                        }
            }
        }
    }
    __syncthreads();

    // ---- phase 2: softmax over 256 cols, warp w handles rows w*16..+15
    for (int r0 = 0; r0 < 16; r0++) {
        int r = wid * 16 + r0;
        float v[8]; float mx = -1e30f;
#pragma unroll
        for (int jc = 0; jc < 8; jc++) {
            v[jc] = __half2float(Sh[(size_t)jc * 5120 + r * 40 + lane]);
            mx = fmaxf(mx, v[jc]);
        }
#pragma unroll
        for (int o = 16; o; o >>= 1) mx = fmaxf(mx, __shfl_xor_sync(0xffffffffu, mx, o));
        float s = 0.f;
#pragma unroll
        for (int jc = 0; jc < 8; jc++) { v[jc] = expf(v[jc] - mx); s += v[jc]; }
#pragma unroll
        for (int o = 16; o; o >>= 1) s += __shfl_xor_sync(0xffffffffu, s, o);
        const float inv = 1.f / s;
#pragma unroll
        for (int jc = 0; jc < 8; jc++)
            Sh[(size_t)jc * 5120 + r * 40 + lane] = __float2half_rn(v[jc] * inv);
    }
    __syncthreads();

    // ---- phase 3: O = P @ V^T. A = Sbuf chunks, B = vt chunks (2-stage)
    {
        const __half* Vb = vt + (size_t)bh * 32768;
#pragma unroll
        for (int i = 0; i < 2; i++) {
            int chunk = tid * 2 + i;
            int rr = chunk >> 2, sg = chunk & 3;
            uint32_t so = (uint32_t)(rr * 80 + sg * 16);
            CP16(sbStage + so, Vb + (size_t)rr * 256 + sg * 8);
        }
        CP_COMMIT();

        for (int kc = 0; kc < 8; kc++) {
            const uint32_t vbuf = sbStage + (uint32_t)(kc & 1) * STAGE_BYTES;
            CP_WAIT0();
            __syncthreads();
            if (kc + 1 < 8) {
                const uint32_t sn = sbStage + (uint32_t)((kc + 1) & 1) * STAGE_BYTES;
#pragma unroll
                for (int i = 0; i < 2; i++) {
                    int chunk = tid * 2 + i;
                    int rr = chunk >> 2, sg = chunk & 3;
                    uint32_t so = (uint32_t)(rr * 80 + sg * 16);
                    CP16(sn + so, Vb + (size_t)rr * 256 + (kc + 1) * 32 + sg * 8);
                }
                CP_COMMIT();
            }
            mma_tile_ab(sbS + (uint32_t)kc * 10240, vbuf, acc, arow, acolB, brow, bcolB);
        }
    }

#pragma unroll
    for (int mi = 0; mi < 4; mi++)
#pragma unroll
        for (int ni = 0; ni < 4; ni++)
#pragma unroll
            for (int hh = 0; hh < 2; hh++) {
                int r = i0 + wm * 64 + mi * 16 + g + hh * 8;
                int c = wn * 32 + ni * 8 + t * 2;
                size_t o = ((size_t)b * 256 + r) * 512 + h * 128 + c;
                *(__half2*)&O[o] =
                    __floats2half2_rn(acc[mi][ni][hh * 2], acc[mi][ni][hh * 2 + 1]);
            }
}

// V transpose
__global__ void vtrans_kernel(const __half* __restrict__ V, __half* __restrict__ vt)
{
    __shared__ __half th[32][33];
    const int bh = blockIdx.x, b = bh >> 2, h = bh & 3;
    const int d0 = blockIdx.y * 32, j0 = blockIdx.z * 32;
    const int tx = threadIdx.x, ty = threadIdx.y;
    const size_t base = (size_t)b * 256 * 1536 + 1024 + h * 128;
    for (int r = ty; r < 32; r += 8) {
        size_t o = base + (size_t)(j0 + r) * 1536 + d0 + tx;
        th[r][tx] = V[o];
    }
    __syncthreads();
    const size_t obase = (size_t)bh * 32768;
    for (int r = ty; r < 32; r += 8) {
        size_t o = obase + (size_t)(d0 + r) * 256 + j0 + tx;
        vt[o] = th[tx][r];
    }
}

// ===========================================================================
// Prep kernels
// ===========================================================================
struct WPtrs { const float* qkv; const float* outw; const float* ff1;
               const float* ff2; const float* mu; const float* var; };

// batched weight transpose+cvt: 10 matrices, all K=512. grid (16, 48, 10).
__global__ void wprep_all(WPtrs ws, __half* __restrict__ HF)
{
    const int m = blockIdx.z;
    const float* W; __half* D; int N;
    switch (m) {
        case 0: W = ws.qkv;            D = HF + B_QKVW;          N = 1536; break;
        case 1: W = ws.qkv + 786432;   D = HF + B_QKVW + 786432; N = 1536; break;
        case 2: W = ws.outw;           D = HF + B_OUTW;          N = 512;  break;
        case 3: W = ws.outw + 262144;  D = HF + B_OUTW + 262144; N = 512;  break;
        case 4: W = ws.ff1;            D = HF + B_FF1W;          N = 512;  break;
        case 5: W = ws.ff1 + 262144;   D = HF + B_FF1W + 262144; N = 512;  break;
        case 6: W = ws.ff2;            D = HF + B_FF2W;          N = 512;  break;
        case 7: W = ws.ff2 + 262144;   D = HF + B_FF2W + 262144; N = 512;  break;
        case 8: W = ws.mu;             D = HF + B_MUW;           N = 512;  break;
        default: W = ws.var;           D = HF + B_VARW;          N = 512;  break;
    }
    const int k0 = blockIdx.x * 32, n0 = blockIdx.y * 32;
    if (n0 >= N) return;
    __shared__ float tile[32][33];
    const int tx = threadIdx.x, ty = threadIdx.y;
    for (int r = ty; r < 32; r += 8)
        tile[r][tx] = W[(size_t)(k0 + r) * N + n0 + tx];
    __syncthreads();
    for (int r = ty; r < 32; r += 8)
        D[(size_t)(n0 + r) * 512 + k0 + tx] = __float2half_rn(tile[tx][r]);
}

__global__ void convprep(const float* __restrict__ w, __half* __restrict__ Wh)
{
    const int n = 512 * 3072;
    for (int idx = blockIdx.x * blockDim.x + threadIdx.x; idx < n; idx += gridDim.x * blockDim.x) {
        int d = idx / 3072, k = idx % 3072;
        int tap = k >> 10, ci = k & 1023;
        Wh[idx] = __float2half_rn(w[(size_t)d * 3072 + ci * 3 + tap]);
    }
}

__global__ void xcvt(const float* __restrict__ x, __half* __restrict__ xh)
{
    const int n4 = 64 * 256 * 1024 / 4;
    const float4* x4 = (const float4*)x;
    __half2* xh2 = (__half2*)xh;
    for (int i = blockIdx.x * blockDim.x + threadIdx.x; i < n4; i += gridDim.x * blockDim.x) {
        float4 f = x4[i];
        xh2[i * 2]     = __floats2half2_rn(f.x, f.y);
        xh2[i * 2 + 1] = __floats2half2_rn(f.z, f.w);
    }
}

__device__ __forceinline__ float wsum(float v)
{
#pragma unroll
    for (int o = 16; o; o >>= 1) v += __shfl_xor_sync(0xffffffffu, v, o);
    return v;
}

// ===========================================================================
// LayerNorm -> fp16 (one warp per row)
// ===========================================================================
__global__ void __launch_bounds__(256) ln_kernel(const float* __restrict__ x,
                                                 const float* __restrict__ g,
                                                 const float* __restrict__ bb,
                                                 __half* __restrict__ y)
{
    const int w = threadIdx.x >> 5, lane = threadIdx.x & 31;
    const int row = blockIdx.x * 8 + w;
    const float* xr = x + (size_t)row * 512;
    float v[16];
    float s = 0.f;
#pragma unroll
    for (int j = 0; j < 16; j++) { v[j] = xr[lane + 32 * j]; s += v[j]; }
    s = wsum(s);
    const float mean = s * (1.f / 512.f);
    float q = 0.f;
#pragma unroll
    for (int j = 0; j < 16; j++) { float d = v[j] - mean; q += d * d; }
    q = wsum(q);
    const float inv = rsqrtf(q * (1.f / 512.f) + 1e-5f);
#pragma unroll
    for (int j = 0; j < 16; j++) {
        int c = lane + 32 * j;
        y[(size_t)row * 512 + c] = __float2half_rn((v[j] - mean) * inv * g[c] + bb[c]);
    }
}

// ===========================================================================
// Memory attention: 16 rows/block (warp per row), mem staged via smem
// ===========================================================================
__global__ void __launch_bounds__(512) memory_kernel(const float* __restrict__ Nx,
                                                     const float* __restrict__ Ax,
                                                     const float* __restrict__ a_mem,
                                                     const float* __restrict__ n_mem,
                                                     float* __restrict__ att_base,
                                                     __half* __restrict__ aug_base)
{
    __shared__ float mch[20][512];
    const int w = threadIdx.x >> 5, lane = threadIdx.x & 31;
    const int combo = blockIdx.y;       // 0:A(Ax,a) 1:NA(Ax,n) 2:AN(Nx,a) 3:N(Nx,n)
    const int row = blockIdx.x * 16 + w;
    const float* x   = (combo < 2) ? Ax : Nx;
    const float* mem = (combo & 1) ? n_mem : a_mem;
    const int att_off[4] = {0, 24576, 16384, 8192};
    float* att_out = att_base + att_off[combo];
    __half* aug = aug_base + (size_t)combo * SZ_AUG;

    float xr[16], facc[16];
#pragma unroll
    for (int j = 0; j < 16; j++) {
        xr[j] = x[(size_t)row * 512 + lane + 32 * j];
        facc[j] = 0.f;
    }
    float t0 = -1e30f, t1 = -1e30f, t2 = -1e30f, t3 = -1e30f;

    for (int c = 0; c < 3; c++) {
        const float4* src4 = (const float4*)(mem + c * 20 * 512);
        float4* dst4 = (float4*)mch;
        for (int i = threadIdx.x; i < 20 * 512 / 4; i += 512)
            dst4[i] = src4[i];
        __syncthreads();
#pragma unroll 4
        for (int n = 0; n < 20; n++) {
            float s = 0.f;
#pragma unroll
            for (int j = 0; j < 16; j++) s = fmaf(xr[j], mch[n][lane + 32 * j], s);
            s = wsum(s);
            float att = 1.f / (1.f + expf(-s * 0.044194173824159216f));
            if (att > t0)      { t3 = t2; t2 = t1; t1 = t0; t0 = att; }
            else if (att > t1) { t3 = t2; t2 = t1; t1 = att; }
            else if (att > t2) { t3 = t2; t2 = att; }
            else if (att > t3) { t3 = att; }
#pragma unroll
            for (int j = 0; j < 16; j++)
                facc[j] = fmaf(att, mch[n][lane + 32 * j], facc[j]);
        }
        __syncthreads();
    }

    if (lane == 0) att_out[row] = (t0 + t1 + t2 + t3) * 0.25f;
#pragma unroll
    for (int j = 0; j < 16; j++)
        aug[(size_t)row * 512 + lane + 32 * j] = __float2half_rn(facc[j]);
}

// ===========================================================================
// top-k (3 combos batched via grid.y) / losses / misc
// ===========================================================================
__global__ void __launch_bounds__(256) topk_gather3(
    const float* __restrict__ attA, const float* __restrict__ attN,
    const float* __restrict__ attNA,
    const float* __restrict__ Ax, const float* __restrict__ Nx,
    float* __restrict__ negv, float* __restrict__ anch, float* __restrict__ posv,
    int* __restrict__ idxA, int* __restrict__ idxN)
{
    __shared__ float vals[256], rv[256];
    __shared__ int ri[256], ids[17];
    const int b = blockIdx.x, tid = threadIdx.x;
    const int combo = blockIdx.y;
    const float* att   = (combo == 0) ? attA : (combo == 1) ? attN : attNA;
    const float* feats = (combo == 1) ? Nx : Ax;
    float* meanv = (combo == 0) ? negv : (combo == 1) ? anch : posv;
    int* idx_out = (combo == 0) ? idxA : (combo == 1) ? idxN : nullptr;

    vals[tid] = att[b * 256 + tid];
    __syncthreads();
    for (int it = 0; it < 17; it++) {
        rv[tid] = vals[tid]; ri[tid] = tid;
        __syncthreads();
        for (int s = 128; s; s >>= 1) {
            if (tid < s) {
                float ov = rv[tid + s]; int oi = ri[tid + s];
                if (ov > rv[tid] || (ov == rv[tid] && oi < ri[tid])) { rv[tid] = ov; ri[tid] = oi; }
            }
            __syncthreads();
        }
        if (tid == 0) {
            ids[it] = ri[0];
            vals[ri[0]] = -1e30f;
            if (idx_out) idx_out[b * 17 + it] = ri[0];
        }
        __syncthreads();
    }
    for (int d = tid; d < 512; d += 256) {
        float s = 0.f;
        for (int j = 0; j < 17; j++) s += feats[((size_t)b * 256 + ids[j]) * 512 + d];
        meanv[b * 512 + d] = s * (1.f / 17.f);
    }
}

__global__ void __launch_bounds__(1024) triplet_cos_kernel(const float* __restrict__ anchor,
                                                           const float* __restrict__ pos,
                                                           const float* __restrict__ neg,
                                                           float* __restrict__ trip_out,
                                                           float* __restrict__ cos_out)
{
    __shared__ float st[32], sc[32];
    const int w = threadIdx.x >> 5, lane = threadIdx.x & 31;
    float sa = 0, sp = 0, sn = 0, dan = 0;
    for (int d = lane; d < 512; d += 32) {
        float a = anchor[w * 512 + d], p = pos[w * 512 + d], n = neg[w * 512 + d];
        sa += a * a; sp += p * p; sn += n * n; dan += a * n;
    }
    sa = wsum(sa); sp = wsum(sp); sn = wsum(sn); dan = wsum(dan);
    float na = sqrtf(sa), npp = sqrtf(sp), ng = sqrtf(sn);
    float ina = 1.f / na, inp = 1.f / npp, ing = 1.f / ng;
    float dp2 = 0, dn2 = 0;
    for (int d = lane; d < 512; d += 32) {
        float a  = anchor[w * 512 + d] * ina;
        float dpv = a - pos[w * 512 + d] * inp + 1e-6f;
        float dnv = a - neg[w * 512 + d] * ing + 1e-6f;
        dp2 += dpv * dpv; dn2 += dnv * dnv;
    }
    dp2 = wsum(dp2); dn2 = wsum(dn2);
    if (lane == 0) {
        st[w] = fmaxf(sqrtf(dp2) - sqrtf(dn2) + 1.f, 0.f);
        sc[w] = 1.f - dan / (fmaxf(na, 1e-6f) * fmaxf(ng, 1e-6f));
    }
    __syncthreads();
    if (threadIdx.x == 0) {
        float a = 0, c = 0;
        for (int i = 0; i < 32; i++) { a += st[i]; c += sc[i]; }
        trip_out[0] = a * (1.f / 32.f);
        cos_out[0]  = c * (1.f / 32.f);
    }
}

__global__ void __launch_bounds__(1024) distance_kernel(const float* __restrict__ anew,
                                                        const float* __restrict__ nnew,
                                                        float* __restrict__ out)
{
    __shared__ float sd[32];
    const int w = threadIdx.x >> 5, lane = threadIdx.x & 31;
    float sa = 0, sn = 0;
    for (int d = lane; d < 512; d += 32) {
        float a = anew[w * 512 + d], n = nnew[w * 512 + d];
        sa += a * a; sn += n * n;
    }
    sa = wsum(sa); sn = wsum(sn);
    if (lane == 0) sd[w] = fmaxf(100.f - sqrtf(sn) + sqrtf(sa), 0.f);
    __syncthreads();
    if (threadIdx.x == 0) {
        float s = 0;
        for (int i = 0; i < 32; i++) s += sd[i];
        out[0] = s * (1.f / 32.f);
    }
}

// fused VAE reparam + KL partial sums (float4)
__global__ void __launch_bounds__(256) vaekl_kernel(const float* __restrict__ mu,
                                                    const float* __restrict__ var,
                                                    const float* __restrict__ eps,
                                                    float* __restrict__ o,
                                                    float* __restrict__ part, int n)
{
    __shared__ float red[256];
    const int n4 = n / 4;
    const float4* mu4 = (const float4*)mu;
    const float4* var4 = (const float4*)var;
    const float4* eps4 = (const float4*)eps;
    float4* o4 = (float4*)o;
    float s = 0.f;
    for (int i = blockIdx.x * 256 + threadIdx.x; i < n4; i += gridDim.x * 256) {
        float4 m = mu4[i], v = var4[i], e = eps4[i];
        float4 r;
        float ev;
        ev = expf(v.x); r.x = m.x + e.x * sqrtf(ev); s += 1.f + v.x - m.x * m.x - ev;
        ev = expf(v.y); r.y = m.y + e.y * sqrtf(ev); s += 1.f + v.y - m.y * m.y - ev;
        ev = expf(v.z); r.z = m.z + e.z * sqrtf(ev); s += 1.f + v.z - m.z * m.z - ev;
        ev = expf(v.w); r.w = m.w + e.w * sqrtf(ev); s += 1.f + v.w - m.w * m.w - ev;
        o4[i] = r;
    }
    red[threadIdx.x] = s; __syncthreads();
    for (int t = 128; t; t >>= 1) { if (threadIdx.x < t) red[threadIdx.x] += red[threadIdx.x + t]; __syncthreads(); }
    if (threadIdx.x == 0) part[blockIdx.x] = red[0];
}

__global__ void __launch_bounds__(1024) kl_final_kernel(const float* __restrict__ part,
                                                        float* __restrict__ out)
{
    __shared__ float red[1024];
    red[threadIdx.x] = part[threadIdx.x]; __syncthreads();
    for (int t = 512; t; t >>= 1) { if (threadIdx.x < t) red[threadIdx.x] += red[threadIdx.x + t]; __syncthreads(); }
    if (threadIdx.x == 0) out[0] = -0.5f * red[0] * (1.f / 16384.f);
}

__global__ void __launch_bounds__(512) gather_mean_kernel(const float* __restrict__ src,
                                                          const int* __restrict__ idx,
                                                          float* __restrict__ out)
{
    __shared__ int ids[17];
    const int b = blockIdx.x, tid = threadIdx.x;
    if (tid < 17) ids[tid] = idx[b * 17 + tid];
    __syncthreads();
    float s = 0.f;
    for (int j = 0; j < 17; j++) s += src[((size_t)b * 256 + ids[j]) * 512 + tid];
    out[b * 512 + tid] = s * (1.f / 17.f);
}

// float4 xout
__global__ void xout_kernel(const float* __restrict__ h, const float* __restrict__ nnew,
                            const float* __restrict__ anm, const float* __restrict__ anew,
                            const float* __restrict__ nam, float* __restrict__ xout)
{
    const int n4 = 64 * 256 * 1024 / 4;
    const float4* h4    = (const float4*)h;
    const float4* nnew4 = (const float4*)nnew;
    const float4* anm4  = (const float4*)anm;
    const float4* anew4 = (const float4*)anew;
    const float4* nam4  = (const float4*)nam;
    float4* out4 = (float4*)xout;
    for (int i = blockIdx.x * blockDim.x + threadIdx.x; i < n4; i += gridDim.x * blockDim.x) {
        int c4 = i & 255;
        int rt = i >> 8;
        float4 v;
        if (c4 < 128) v = h4[(size_t)rt * 128 + c4];
        else {
            int cc = c4 - 128;
            if (rt < 8192) {
                float4 a = nnew4[(size_t)rt * 128 + cc];
                float4 bb = anm4[(size_t)rt * 128 + cc];
                v = make_float4(a.x + bb.x, a.y + bb.y, a.z + bb.z, a.w + bb.w);
            } else {
                size_t o = (size_t)(rt - 8192) * 128 + cc;
                float4 a = anew4[o];
                float4 bb = nam4[o];
                v = make_float4(a.x + bb.x, a.y + bb.y, a.z + bb.z, a.w + bb.w);
            }
        }
        out4[i] = v;
    }
}

__global__ void vfeat_kernel(const float* __restrict__ h, float* __restrict__ v)
{
    __shared__ float tile[32][33];
    const int b = blockIdx.x, d0 = blockIdx.y * 32, t0 = blockIdx.z * 32;
    for (int r = threadIdx.y; r < 32; r += 8)
        tile[r][threadIdx.x] = h[((size_t)b * 256 + t0 + r) * 512 + d0 + threadIdx.x];
    __syncthreads();
    for (int r = threadIdx.y; r < 32; r += 8)
        v[((size_t)b * 512 + d0 + r) * 256 + t0 + threadIdx.x] = tile[threadIdx.x][r];
}

// ===========================================================================
extern "C" void kernel_launch(void* const* d_in, const int* in_sizes, int n_in,
                              void* d_out, int out_size)
{
    const float* x      = (const float*)d_in[0];
    const float* eps_in = (const float*)d_in[1];
    const float* conv_w = (const float*)d_in[2];
    const float* conv_b = (const float*)d_in[3];
    const float* ln1_g  = (const float*)d_in[4];
    const float* ln1_b  = (const float*)d_in[5];
    const float* qkv_w  = (const float*)d_in[6];
    const float* out_w  = (const float*)d_in[7];
    const float* out_b  = (const float*)d_in[8];
    const float* ln2_g  = (const float*)d_in[9];
    const float* ln2_b  = (const float*)d_in[10];
    const float* ff1_w  = (const float*)d_in[11];
    const float* ff1_b  = (const float*)d_in[12];
    const float* ff2_w  = (const float*)d_in[13];
    const float* ff2_b  = (const float*)d_in[14];
    const float* a_mem  = (const float*)d_in[15];
    const float* n_mem  = (const float*)d_in[16];
    const float* mu_w   = (const float*)d_in[17];
    const float* mu_b   = (const float*)d_in[18];
    const float* var_w  = (const float*)d_in[19];
    const float* var_b  = (const float*)d_in[20];
    float* out = (float*)d_out;

    float* S = nullptr;
    cudaGetSymbolAddress((void**)&S, g_scratch);
    __half* HF = nullptr;
    cudaGetSymbolAddress((void**)&HF, g_hf);

    float* h     = S + OFF_H;
    float* stack = S + OFF_STACK;
    float* Anew  = stack;
    float* NAm   = stack + 1ull * 8192 * 512;
    float* ANm   = stack + 2ull * 8192 * 512;
    float* muB   = stack + 3ull * 8192 * 512;
    float* varB  = S + OFF_VAR;
    float* newN  = S + OFF_NEW;
    float* anch  = S + OFF_ANCH;
    float* negv  = S + OFF_NEG;
    float* posv  = S + OFF_POS;
    float* anchN = S + OFF_ANCHN;
    float* negN  = S + OFF_NEGN;
    int*   idxA  = (int*)(S + OFF_IDXA);
    int*   idxN  = (int*)(S + OFF_IDXN);
    float* klp   = S + OFF_KLP;

    __half* lnb  = HF + B_LN;
    __half* aob  = HF + B_AO;
    __half* ffb  = HF + B_FF;
    __half* qkvb = HF + B_QKV;
    __half* vtb  = HF + B_VT;
    __half* xh   = HF + B_X;

    constexpr int MG_SMEM = 61440;    // 3 stages x 20480
    constexpr int AT_SMEM = 122880;   // Sbuf 81920 + 2x20480
    cudaFuncSetAttribute(mgemm<0,false>, cudaFuncAttributeMaxDynamicSharedMemorySize, MG_SMEM);
    cudaFuncSetAttribute(mgemm<1,false>, cudaFuncAttributeMaxDynamicSharedMemorySize, MG_SMEM);
    cudaFuncSetAttribute(mgemm<2,false>, cudaFuncAttributeMaxDynamicSharedMemorySize, MG_SMEM);
    cudaFuncSetAttribute(mgemm<3,false>, cudaFuncAttributeMaxDynamicSharedMemorySize, MG_SMEM);
    cudaFuncSetAttribute(mgemm<5,false>, cudaFuncAttributeMaxDynamicSharedMemorySize, MG_SMEM);
    cudaFuncSetAttribute(mgemm<4,true>,  cudaFuncAttributeMaxDynamicSharedMemorySize, MG_SMEM);
    cudaFuncSetAttribute(attn_kernel,    cudaFuncAttributeMaxDynamicSharedMemorySize, AT_SMEM);

    WPtrs wp{qkv_w, out_w, ff1_w, ff2_w, mu_w, var_w};

    // 1-3: prep
    convprep<<<1024, 256>>>(conv_w, HF + B_CNVW);
    xcvt<<<4096, 256>>>(x, xh);
    wprep_all<<<dim3(16, 48, 10), dim3(32, 8)>>>(wp, HF);

    // 4: conv (implicit im2col, relu+bias) — profiler target
    mgemm<4, true><<<dim3(4, 128), 256, MG_SMEM>>>(
        xh, HF + B_CNVW, h, nullptr, conv_b, 16384, 512, 3072);

    // 5: ln (layer 0)
    ln_kernel<<<2048, 256>>>(h, ln1_g, ln1_b, lnb);

    // 6: qkv mgemm (layer 0)
    mgemm<5, false><<<dim3(12, 128), 256, MG_SMEM>>>(
        lnb, HF + B_QKVW, nullptr, qkvb, nullptr, 16384, 1536, 512);

    // ---- transformer (layer 0 continues, then layer 1)
    for (int i = 0; i < 2; i++) {
        if (i == 1) {
            ln_kernel<<<2048, 256>>>(h, ln1_g + 512, ln1_b + 512, lnb);
            mgemm<5, false><<<dim3(12, 128), 256, MG_SMEM>>>(
                lnb, HF + B_QKVW + 786432, nullptr, qkvb, nullptr, 16384, 1536, 512);
        }
        vtrans_kernel<<<dim3(256, 4, 8), dim3(32, 8)>>>(qkvb, vtb);
        attn_kernel<<<dim3(2, 1, 256), 256, AT_SMEM>>>(qkvb, vtb, aob);
        mgemm<2, false><<<dim3(4, 128), 256, MG_SMEM>>>(
            aob, HF + B_OUTW + (size_t)i * 262144, h, nullptr, out_b + i * 512, 16384, 512, 512);
        ln_kernel<<<2048, 256>>>(h, ln2_g + i * 512, ln2_b + i * 512, lnb);
        mgemm<3, false><<<dim3(4, 128), 256, MG_SMEM>>>(
            lnb, HF + B_FF1W + (size_t)i * 262144, nullptr, ffb, ff1_b + i * 512, 16384, 512, 512);
        mgemm<2, false><<<dim3(4, 128), 256, MG_SMEM>>>(
            ffb, HF + B_FF2W + (size_t)i * 262144, h, nullptr, ff2_b + i * 512, 16384, 512, 512);
    }

    const float* Nx = h;                       // x_emb[:32]
    const float* Ax = h + (size_t)8192 * 512;  // x_emb[32:]

    memory_kernel<<<dim3(512, 4), 512>>>(Nx, Ax, a_mem, n_mem,
                                         out + O_AATT, HF + B_AUG);

    topk_gather3<<<dim3(32, 3), 256>>>(out + O_AATT, out + O_NATT, out + O_NAATT,
                                       Ax, Nx, negv, anch, posv, idxA, idxN);

    triplet_cos_kernel<<<1, 1024>>>(anch, posv, negv, out + O_TRIP, out + O_COS);

    // stacked mu projection: [augA; augNA; augAN; augN] @ mu -> [Anew; NAm; ANm; muB]
    mgemm<1, false><<<dim3(4, 256), 256, MG_SMEM>>>(
        HF + B_AUG, HF + B_MUW, stack, nullptr, mu_b, 32768, 512, 512);
    mgemm<1, false><<<dim3(4, 64), 256, MG_SMEM>>>(
        HF + B_AUG + 3 * SZ_AUG, HF + B_VARW, varB, nullptr, var_b, 8192, 512, 512);

    vaekl_kernel<<<1024, 256>>>(muB, varB, eps_in, newN, klp, 8192 * 512);
    kl_final_kernel<<<1, 1024>>>(klp, out + O_KL);

    gather_mean_kernel<<<32, 512>>>(newN, idxN, anchN);
    gather_mean_kernel<<<32, 512>>>(Anew, idxA, negN);
    distance_kernel<<<1, 1024>>>(anchN, negN, out + O_DIST);

    xout_kernel<<<8192, 256>>>(h, newN, ANm, Anew, NAm, out + O_XOUT);
    vfeat_kernel<<<dim3(64, 16, 8), dim3(32, 8)>>>(h, out + O_VFEAT);
}